// round 1
// baseline (speedup 1.0000x reference)
#include <cuda_runtime.h>
#include <math.h>

#define T_LEN 16384
#define OBS_D 256
#define MLP_D 1024
#define REC_D 1024
#define G3_D  3072
#define ACT_D 18
#define STEPS 40

// ---------------- scratch (device globals; no allocation allowed) ----------------
__device__ __align__(16) float g_feat[(size_t)T_LEN * MLP_D];     // 64 MB
__device__ __align__(16) float g_igates[(size_t)T_LEN * G3_D];    // 192 MB
__device__ __align__(16) float g_states[(size_t)T_LEN * REC_D];   // 64 MB
__device__ __align__(16) float g_y1[(size_t)T_LEN * MLP_D];       // 64 MB
__device__ __align__(16) float g_y2[(size_t)T_LEN * MLP_D];       // 64 MB
__device__ float g_hg0[G3_D];
__device__ int   g_age[T_LEN];
__device__ int   g_perm[T_LEN];
__device__ int   g_counts[STEPS + 1];
__device__ int   g_offsets[STEPS + 1];
__device__ int   g_cursor[STEPS + 1];
__device__ int   g_flags[4];   // [0]=start dtype mode (0=u8,1=i32,2=f32), [1]=start[0] truth

// ---------------- helpers ----------------
__device__ __forceinline__ float sigf(float x) { return 1.0f / (1.0f + expf(-x)); }
__device__ __forceinline__ float mishf(float x) {
    float sp = (x > 15.0f) ? x : log1pf(expf(x));
    return x * tanhf(sp);
}

// ---------------- setup kernels ----------------
__global__ void init_kernel() {
    int t = threadIdx.x;
    if (t < STEPS + 1) { g_counts[t] = 0; g_cursor[t] = 0; }
    if (t < 4) g_flags[t] = 0;
}

// Detect how the bool `start` array was serialized.
__global__ void sniff_kernel(const unsigned char* __restrict__ p) {
    __shared__ int s_nz[4];
    int tid = threadIdx.x;
    if (tid < 4) s_nz[tid] = 0;
    __syncthreads();
    int cnt = 0;
    for (int i = tid; i < T_LEN; i += blockDim.x) cnt += (p[i] != 0);
    atomicAdd(&s_nz[tid & 3], cnt);
    __syncthreads();
    if (tid == 0) {
        int rest = s_nz[1] + s_nz[2] + s_nz[3];
        int mode;
        if (rest > 0)           mode = (s_nz[0] == 0) ? 2 : 0;  // f32 : u8
        else                    mode = (s_nz[0] > 0) ? 1 : 0;   // i32 : (all-zero -> safe u8)
        g_flags[0] = mode;
        bool s0;
        if (mode == 0)      s0 = p[0] != 0;
        else if (mode == 1) s0 = ((const int*)p)[0] != 0;
        else                s0 = ((const float*)p)[0] != 0.0f;
        g_flags[1] = s0 ? 1 : 0;
    }
}

__device__ __forceinline__ bool start_val(const void* p, int mode, int u) {
    if (mode == 0) return ((const unsigned char*)p)[u] != 0;
    if (mode == 1) return ((const int*)p)[u] != 0;
    return ((const float*)p)[u] != 0.0f;
}

__global__ void age_kernel(const void* __restrict__ startp) {
    int mode = g_flags[0];
    int stride = gridDim.x * blockDim.x;
    for (int t = blockIdx.x * blockDim.x + threadIdx.x; t < T_LEN; t += stride) {
        int k = 0, tt = t;
        while (tt > 0 && !start_val(startp, mode, tt)) { tt--; k++; }
        g_age[t] = k;
        int b = k < STEPS ? k : STEPS;
        atomicAdd(&g_counts[b], 1);
    }
}

__global__ void offsets_kernel() {
    if (threadIdx.x == 0 && blockIdx.x == 0) {
        int acc = 0;
        for (int b = 0; b <= STEPS; b++) { g_offsets[b] = acc; acc += g_counts[b]; }
    }
}

__global__ void scatter_kernel() {
    int stride = gridDim.x * blockDim.x;
    for (int t = blockIdx.x * blockDim.x + threadIdx.x; t < T_LEN; t += stride) {
        int a = g_age[t];
        int b = a < STEPS ? a : STEPS;
        int pos = g_offsets[b] + atomicAdd(&g_cursor[b], 1);
        g_perm[pos] = t;
    }
}

// ---------------- fp32 SGEMM: C[M,N] = act(A[M,K] @ B[N,K]^T + bias) ----------------
// BM=BN=128, BK=8, 256 threads, 8x8 per thread. M,N %128==0, K %8==0 required.
template <int MISH>
__global__ void __launch_bounds__(256)
sgemm_nt(const float* __restrict__ A, const float* __restrict__ B,
         const float* __restrict__ bias, float* __restrict__ C,
         int M, int N, int K) {
    __shared__ __align__(16) float As[8][128];
    __shared__ __align__(16) float Bs[8][128];
    int tid = threadIdx.x;
    int tx = tid & 15, ty = tid >> 4;
    int rowBase = blockIdx.y * 128;
    int colBase = blockIdx.x * 128;
    int arow = tid >> 1;
    int ak4 = (tid & 1) * 4;

    float acc[8][8];
#pragma unroll
    for (int i = 0; i < 8; i++)
#pragma unroll
        for (int j = 0; j < 8; j++) acc[i][j] = 0.0f;

    for (int k0 = 0; k0 < K; k0 += 8) {
        float4 av = *(const float4*)(A + (size_t)(rowBase + arow) * K + k0 + ak4);
        float4 bv = *(const float4*)(B + (size_t)(colBase + arow) * K + k0 + ak4);
        __syncthreads();
        As[ak4 + 0][arow] = av.x; As[ak4 + 1][arow] = av.y;
        As[ak4 + 2][arow] = av.z; As[ak4 + 3][arow] = av.w;
        Bs[ak4 + 0][arow] = bv.x; Bs[ak4 + 1][arow] = bv.y;
        Bs[ak4 + 2][arow] = bv.z; Bs[ak4 + 3][arow] = bv.w;
        __syncthreads();
#pragma unroll
        for (int kk = 0; kk < 8; kk++) {
            float4 a0 = *(const float4*)&As[kk][ty * 8];
            float4 a1 = *(const float4*)&As[kk][ty * 8 + 4];
            float4 b0 = *(const float4*)&Bs[kk][tx * 8];
            float4 b1 = *(const float4*)&Bs[kk][tx * 8 + 4];
            float a[8] = {a0.x, a0.y, a0.z, a0.w, a1.x, a1.y, a1.z, a1.w};
            float b[8] = {b0.x, b0.y, b0.z, b0.w, b1.x, b1.y, b1.z, b1.w};
#pragma unroll
            for (int i = 0; i < 8; i++)
#pragma unroll
                for (int j = 0; j < 8; j++) acc[i][j] += a[i] * b[j];
        }
    }

#pragma unroll
    for (int i = 0; i < 8; i++) {
        int row = rowBase + ty * 8 + i;
#pragma unroll
        for (int j4 = 0; j4 < 8; j4 += 4) {
            float4 v;
            float* vp = &v.x;
#pragma unroll
            for (int j = 0; j < 4; j++) {
                int col = colBase + tx * 8 + j4 + j;
                float c = acc[i][j4 + j] + bias[col];
                if (MISH) c = mishf(c);
                vp[j] = c;
            }
            *(float4*)(C + (size_t)row * N + colBase + tx * 8 + j4) = v;
        }
    }
}

// ---------------- GRU step k==0 (h_prev == 0, so hg == 0) ----------------
__global__ void step0_kernel(const float* __restrict__ b_n) {
    int count = g_counts[0];
    long total = (long)count * REC_D;
    long stride = (long)gridDim.x * blockDim.x;
    for (long idx = (long)blockIdx.x * blockDim.x + threadIdx.x; idx < total; idx += stride) {
        int i = (int)(idx >> 10);
        int j = (int)(idx & 1023);
        int t = g_perm[i];  // offsets[0] == 0
        float igr = g_igates[(size_t)t * G3_D + j];
        float igz = g_igates[(size_t)t * G3_D + 1024 + j];
        float ign = g_igates[(size_t)t * G3_D + 2048 + j];
        float r = sigf(igr);
        float z = sigf(igz);
        float n = tanhf(ign + r * b_n[j]);
        g_states[(size_t)t * REC_D + j] = n - z * n;  // n + z*(0-n)
    }
}

// t==0 with start[0] false uses the provided initial state (zeros in practice).
__global__ void fixA_kernel(const float* __restrict__ w_hh, const float* __restrict__ state) {
    if (g_flags[1]) return;  // start[0] true -> nothing to fix
    int j = blockIdx.x * 8 + (threadIdx.x >> 5);
    int lane = threadIdx.x & 31;
    float acc = 0.0f;
    const float* wr = w_hh + (size_t)j * REC_D;
    for (int k = lane; k < REC_D; k += 32) acc += wr[k] * state[k];
#pragma unroll
    for (int o = 16; o > 0; o >>= 1) acc += __shfl_down_sync(0xffffffffu, acc, o);
    if (lane == 0) g_hg0[j] = acc;
}

__global__ void fixB_kernel(const float* __restrict__ state, const float* __restrict__ b_n) {
    if (g_flags[1]) return;
    int j = threadIdx.x;
    float igr = g_igates[j], igz = g_igates[1024 + j], ign = g_igates[2048 + j];
    float r = sigf(igr + g_hg0[j]);
    float z = sigf(igz + g_hg0[1024 + j]);
    float n = tanhf(ign + r * (g_hg0[2048 + j] + b_n[j]));
    float hp = state[j];
    g_states[j] = n + z * (hp - n);
}

// ---------------- GRU step k>=1: batched gather-GEMM + fused gates ----------------
// 32 rows x 64 cols per block, BK=16, 256 threads (each: 8 rows x 1 col x 3 gates).
__global__ void __launch_bounds__(256)
gru_step_kernel(const float* __restrict__ w_hh, const float* __restrict__ b_n, int k) {
    int count = g_counts[k];
    if (count <= 0) return;
    int base = g_offsets[k];
    int colBase = blockIdx.x * 64;

    __shared__ float Hs[32][17];
    __shared__ float Ws[3][64][17];
    __shared__ int Ts[32];

    int tid = threadIdx.x;
    int c = tid & 63;
    int tr = tid >> 6;  // 0..3

    for (int rt = blockIdx.y; rt * 32 < count; rt += gridDim.y) {
        __syncthreads();
        int row0 = rt * 32;
        int nrows = min(32, count - row0);
        if (tid < 32) Ts[tid] = (tid < nrows) ? g_perm[base + row0 + tid] : -1;

        float aR[8], aZ[8], aN[8];
#pragma unroll
        for (int i = 0; i < 8; i++) { aR[i] = 0; aZ[i] = 0; aN[i] = 0; }

        for (int k0 = 0; k0 < REC_D; k0 += 16) {
            __syncthreads();
            for (int l = tid; l < 32 * 16; l += 256) {
                int i = l >> 4, kk = l & 15;
                int t = Ts[i];
                Hs[i][kk] = (t >= 0) ? g_states[(size_t)(t - 1) * REC_D + k0 + kk] : 0.0f;
            }
            for (int l = tid; l < 3 * 64 * 16; l += 256) {
                int g = l >> 10, r = (l >> 4) & 63, kk = l & 15;
                Ws[g][r][kk] = w_hh[(size_t)(g * 1024 + colBase + r) * REC_D + k0 + kk];
            }
            __syncthreads();
#pragma unroll
            for (int kk = 0; kk < 16; kk++) {
                float wr = Ws[0][c][kk], wz = Ws[1][c][kk], wn = Ws[2][c][kk];
#pragma unroll
                for (int i = 0; i < 8; i++) {
                    float h = Hs[tr * 8 + i][kk];
                    aR[i] += wr * h; aZ[i] += wz * h; aN[i] += wn * h;
                }
            }
        }
        int j = colBase + c;
        float bn = b_n[j];
#pragma unroll
        for (int i = 0; i < 8; i++) {
            int ri = tr * 8 + i;
            if (ri < nrows) {
                int t = Ts[ri];
                float igr = g_igates[(size_t)t * G3_D + j];
                float igz = g_igates[(size_t)t * G3_D + 1024 + j];
                float ign = g_igates[(size_t)t * G3_D + 2048 + j];
                float hp = g_states[(size_t)(t - 1) * REC_D + j];
                float r = sigf(igr + aR[i]);
                float z = sigf(igz + aZ[i]);
                float n = tanhf(ign + r * (aN[i] + bn));
                g_states[(size_t)t * REC_D + j] = n + z * (hp - n);
            }
        }
    }
}

// Correctness safety net: sequentially process any rows with age >= STEPS (count 0 in practice).
__global__ void __launch_bounds__(1024)
cleanup_kernel(const float* __restrict__ w_hh, const float* __restrict__ b_n) {
    if (g_counts[STEPS] == 0) return;
    __shared__ int s_t;
    __shared__ int s_cur;
    __shared__ float sh[REC_D];
    int tid = threadIdx.x;
    if (tid == 0) s_cur = STEPS;  // age[t] <= t, so first candidate is t = STEPS
    __syncthreads();
    while (true) {
        if (tid == 0) {
            s_t = -1;
            for (int u = s_cur; u < T_LEN; ++u) {
                if (g_age[u] >= STEPS) { s_t = u; s_cur = u + 1; break; }
            }
        }
        __syncthreads();
        int t = s_t;
        if (t < 0) break;
        sh[tid] = g_states[(size_t)(t - 1) * REC_D + tid];
        __syncthreads();
        float aRv = 0, aZv = 0, aNv = 0;
        const float* wr = w_hh + (size_t)tid * REC_D;
        const float* wz = w_hh + (size_t)(1024 + tid) * REC_D;
        const float* wn = w_hh + (size_t)(2048 + tid) * REC_D;
        for (int kk = 0; kk < REC_D; kk++) {
            float h = sh[kk];
            aRv += wr[kk] * h; aZv += wz[kk] * h; aNv += wn[kk] * h;
        }
        float igr = g_igates[(size_t)t * G3_D + tid];
        float igz = g_igates[(size_t)t * G3_D + 1024 + tid];
        float ign = g_igates[(size_t)t * G3_D + 2048 + tid];
        float r = sigf(igr + aRv);
        float z = sigf(igz + aZv);
        float n = tanhf(ign + r * (aNv + b_n[tid]));
        float hp = sh[tid];
        g_states[(size_t)t * REC_D + tid] = n + z * (hp - n);
        __syncthreads();
    }
}

// ---------------- small head: out[T,18] = y2 @ p3_w^T + p3_b ----------------
__global__ void __launch_bounds__(192)
p3_kernel(const float* __restrict__ A, const float* __restrict__ W,
          const float* __restrict__ bias, float* __restrict__ out) {
    __shared__ __align__(16) float Ys[128][68];
    __shared__ float Ws[18][129];
    int tid = threadIdx.x;
    int rowBase = blockIdx.x * 64;
    int a = tid % 18, rg = tid / 18;  // valid for tid < 144
    float acc[8];
#pragma unroll
    for (int i = 0; i < 8; i++) acc[i] = 0.0f;

    for (int k0 = 0; k0 < MLP_D; k0 += 128) {
        __syncthreads();
        for (int l = tid; l < 18 * 128; l += 192) {
            int aa = l / 128, kk = l % 128;
            Ws[aa][kk] = W[(size_t)aa * MLP_D + k0 + kk];
        }
        for (int l = tid; l < 64 * 128; l += 192) {
            int r = l / 128, kk = l % 128;
            Ys[kk][r] = A[(size_t)(rowBase + r) * MLP_D + k0 + kk];
        }
        __syncthreads();
        if (tid < 144) {
#pragma unroll 4
            for (int kk = 0; kk < 128; kk++) {
                float w = Ws[a][kk];
                float4 y0 = *(const float4*)&Ys[kk][rg * 8];
                float4 y1v = *(const float4*)&Ys[kk][rg * 8 + 4];
                acc[0] += w * y0.x;  acc[1] += w * y0.y;
                acc[2] += w * y0.z;  acc[3] += w * y0.w;
                acc[4] += w * y1v.x; acc[5] += w * y1v.y;
                acc[6] += w * y1v.z; acc[7] += w * y1v.w;
            }
        }
    }
    if (tid < 144) {
        float b = bias[a];
#pragma unroll
        for (int i = 0; i < 8; i++)
            out[(size_t)(rowBase + rg * 8 + i) * ACT_D + a] = acc[i] + b;
    }
}

__global__ void copy_state_kernel(float* __restrict__ out) {
    out[threadIdx.x] = g_states[(size_t)(T_LEN - 1) * REC_D + threadIdx.x];
}

// ---------------- host ----------------
extern "C" void kernel_launch(void* const* d_in, const int* in_sizes, int n_in,
                              void* d_out, int out_size) {
    const float* x     = (const float*)d_in[0];
    const float* state = (const float*)d_in[1];
    const void*  start = d_in[2];
    // d_in[3] = done (unused by the reference)
    const float* pre_w = (const float*)d_in[4];
    const float* pre_b = (const float*)d_in[5];
    const float* w_ih  = (const float*)d_in[6];
    const float* w_hh  = (const float*)d_in[7];
    const float* b_ih  = (const float*)d_in[8];
    const float* b_n   = (const float*)d_in[9];
    const float* p1_w  = (const float*)d_in[10];
    const float* p1_b  = (const float*)d_in[11];
    const float* p2_w  = (const float*)d_in[12];
    const float* p2_b  = (const float*)d_in[13];
    const float* p3_w  = (const float*)d_in[14];
    const float* p3_b  = (const float*)d_in[15];
    float* out = (float*)d_out;

    float *feat, *igates, *states, *y1, *y2;
    cudaGetSymbolAddress((void**)&feat, g_feat);
    cudaGetSymbolAddress((void**)&igates, g_igates);
    cudaGetSymbolAddress((void**)&states, g_states);
    cudaGetSymbolAddress((void**)&y1, g_y1);
    cudaGetSymbolAddress((void**)&y2, g_y2);

    // segment analysis
    init_kernel<<<1, 64>>>();
    sniff_kernel<<<1, 256>>>((const unsigned char*)start);
    age_kernel<<<64, 256>>>(start);
    offsets_kernel<<<1, 1>>>();
    scatter_kernel<<<64, 256>>>();

    // feat = mish(x @ pre_w^T + pre_b); igates = feat @ w_ih^T + b_ih
    sgemm_nt<1><<<dim3(MLP_D / 128, T_LEN / 128), 256>>>(x, pre_w, pre_b, feat, T_LEN, MLP_D, OBS_D);
    sgemm_nt<0><<<dim3(G3_D / 128, T_LEN / 128), 256>>>(feat, w_ih, b_ih, igates, T_LEN, G3_D, MLP_D);

    // segment-parallel GRU scan
    step0_kernel<<<2048, 256>>>(b_n);
    fixA_kernel<<<384, 256>>>(w_hh, state);
    fixB_kernel<<<1, 1024>>>(state, b_n);
    for (int k = 1; k < STEPS; k++) {
        int guess = T_LEN >> k;
        if (guess < 32) guess = 32;
        int gy = (guess + 31) / 32;
        gru_step_kernel<<<dim3(REC_D / 64, gy), 256>>>(w_hh, b_n, k);
    }
    cleanup_kernel<<<1, 1024>>>(w_hh, b_n);

    // post MLP
    sgemm_nt<1><<<dim3(MLP_D / 128, T_LEN / 128), 256>>>(states, p1_w, p1_b, y1, T_LEN, MLP_D, REC_D);
    sgemm_nt<1><<<dim3(MLP_D / 128, T_LEN / 128), 256>>>(y1, p2_w, p2_b, y2, T_LEN, MLP_D, MLP_D);
    p3_kernel<<<T_LEN / 64, 192>>>(y2, p3_w, p3_b, out);

    if (out_size >= T_LEN * ACT_D + REC_D)
        copy_state_kernel<<<1, 1024>>>(out + (size_t)T_LEN * ACT_D);
}

// round 2
// speedup vs baseline: 1.9834x; 1.9834x over previous
#include <cuda_runtime.h>
#include <cuda_bf16.h>
#include <math.h>
#include <stdint.h>

#define T_LEN 16384
#define OBS_D 256
#define MLP_D 1024
#define REC_D 1024
#define G3_D  3072
#define ACT_D 18
#define STEPS 40
#define GEMM_STEPS 8   // k = 1..GEMM_STEPS-1 use the tensor-core GEMM path

typedef __nv_bfloat16 bf16;

// ---------------- scratch (device globals; no allocation allowed) ----------------
__device__ __align__(16) bf16  g_x3[(size_t)T_LEN * 3 * OBS_D];      // 24 MB
__device__ __align__(16) bf16  g_prew3[(size_t)MLP_D * 3 * OBS_D];   // 1.5 MB
__device__ __align__(16) bf16  g_feat3[(size_t)T_LEN * 3 * MLP_D];   // 96 MB
__device__ __align__(16) bf16  g_wih3[(size_t)G3_D * 3 * MLP_D];     // 18 MB
__device__ __align__(16) bf16  g_whh3[(size_t)G3_D * 3 * REC_D];     // 18 MB
__device__ __align__(16) bf16  g_p1w3[(size_t)MLP_D * 3 * REC_D];    // 6 MB
__device__ __align__(16) bf16  g_p2w3[(size_t)MLP_D * 3 * MLP_D];    // 6 MB
__device__ __align__(16) bf16  g_states3[(size_t)T_LEN * 3 * REC_D]; // 96 MB
__device__ __align__(16) bf16  g_y13[(size_t)T_LEN * 3 * MLP_D];     // 96 MB
__device__ __align__(16) bf16  g_h3[(size_t)T_LEN * 3 * REC_D];      // 96 MB
__device__ __align__(16) float g_igates[(size_t)T_LEN * G3_D];       // 192 MB
__device__ __align__(16) float g_hg[(size_t)T_LEN * G3_D];           // 192 MB
__device__ __align__(16) float g_states[(size_t)T_LEN * REC_D];      // 64 MB
__device__ __align__(16) float g_y2[(size_t)T_LEN * MLP_D];          // 64 MB
__device__ float g_hg0[G3_D];
__device__ int   g_age[T_LEN];
__device__ int   g_perm[T_LEN];
__device__ int   g_counts[STEPS + 1];
__device__ int   g_offsets[STEPS + 1];
__device__ int   g_cursor[STEPS + 1];
__device__ int   g_flags[4];

// ---------------- helpers ----------------
__device__ __forceinline__ float sigf(float x) { return 1.0f / (1.0f + expf(-x)); }
__device__ __forceinline__ float mishf(float x) {
    float sp = (x > 15.0f) ? x : log1pf(expf(x));
    return x * tanhf(sp);
}
__device__ __forceinline__ void split2(float v, bf16& hi, bf16& lo) {
    hi = __float2bfloat16(v);
    lo = __float2bfloat16(v - __bfloat162float(hi));
}
__device__ __forceinline__ uint32_t smem_u32(const void* p) {
    return (uint32_t)__cvta_generic_to_shared(p);
}

// ---------------- setup kernels ----------------
__global__ void init_kernel() {
    int t = threadIdx.x;
    if (t < STEPS + 1) { g_counts[t] = 0; g_cursor[t] = 0; }
    if (t < 4) g_flags[t] = 0;
}

__global__ void sniff_kernel(const unsigned char* __restrict__ p) {
    __shared__ int s_nz[4];
    int tid = threadIdx.x;
    if (tid < 4) s_nz[tid] = 0;
    __syncthreads();
    int cnt = 0;
    for (int i = tid; i < T_LEN; i += blockDim.x) cnt += (p[i] != 0);
    atomicAdd(&s_nz[tid & 3], cnt);
    __syncthreads();
    if (tid == 0) {
        int rest = s_nz[1] + s_nz[2] + s_nz[3];
        int mode;
        if (rest > 0) mode = (s_nz[0] == 0) ? 2 : 0;
        else          mode = (s_nz[0] > 0) ? 1 : 0;
        g_flags[0] = mode;
        bool s0;
        if (mode == 0)      s0 = p[0] != 0;
        else if (mode == 1) s0 = ((const int*)p)[0] != 0;
        else                s0 = ((const float*)p)[0] != 0.0f;
        g_flags[1] = s0 ? 1 : 0;
    }
}

__device__ __forceinline__ bool start_val(const void* p, int mode, int u) {
    if (mode == 0) return ((const unsigned char*)p)[u] != 0;
    if (mode == 1) return ((const int*)p)[u] != 0;
    return ((const float*)p)[u] != 0.0f;
}

__global__ void age_kernel(const void* __restrict__ startp) {
    int mode = g_flags[0];
    int stride = gridDim.x * blockDim.x;
    for (int t = blockIdx.x * blockDim.x + threadIdx.x; t < T_LEN; t += stride) {
        int k = 0, tt = t;
        while (tt > 0 && !start_val(startp, mode, tt)) { tt--; k++; }
        g_age[t] = k;
        int b = k < STEPS ? k : STEPS;
        atomicAdd(&g_counts[b], 1);
    }
}

__global__ void offsets_kernel() {
    if (threadIdx.x == 0 && blockIdx.x == 0) {
        int acc = 0;
        for (int b = 0; b <= STEPS; b++) { g_offsets[b] = acc; acc += g_counts[b]; }
    }
}

__global__ void scatter_kernel() {
    int stride = gridDim.x * blockDim.x;
    for (int t = blockIdx.x * blockDim.x + threadIdx.x; t < T_LEN; t += stride) {
        int a = g_age[t];
        int b = a < STEPS ? a : STEPS;
        int pos = g_offsets[b] + atomicAdd(&g_cursor[b], 1);
        g_perm[pos] = t;
    }
}

// ---------------- bf16-split conversions ----------------
// Weights (B side): [N][K] fp32 -> [N][3K] bf16 as [hi | lo | hi]
__global__ void convert_w3(const float* __restrict__ src, bf16* __restrict__ dst, int N, int K) {
    size_t total = (size_t)N * K;
    size_t stride = (size_t)gridDim.x * blockDim.x;
    for (size_t idx = (size_t)blockIdx.x * blockDim.x + threadIdx.x; idx < total; idx += stride) {
        int r = (int)(idx / K), c = (int)(idx % K);
        float v = src[idx];
        bf16 hi, lo; split2(v, hi, lo);
        bf16* row = dst + (size_t)r * 3 * K;
        row[c] = hi; row[K + c] = lo; row[2 * K + c] = hi;
    }
}

// Activations (A side): [T][K] fp32 -> [T][3K] bf16 as [hi | hi | lo]
__global__ void convert_a3(const float* __restrict__ src, bf16* __restrict__ dst, int K) {
    size_t total = (size_t)T_LEN * K;
    size_t stride = (size_t)gridDim.x * blockDim.x;
    for (size_t idx = (size_t)blockIdx.x * blockDim.x + threadIdx.x; idx < total; idx += stride) {
        int r = (int)(idx / K), c = (int)(idx % K);
        float v = src[idx];
        bf16 hi, lo; split2(v, hi, lo);
        bf16* row = dst + (size_t)r * 3 * K;
        row[c] = hi; row[K + c] = hi; row[2 * K + c] = lo;
    }
}

// Gather h_{t-1} rows for step-k bucket into contiguous split-bf16 A matrix.
__global__ void gather_h3(int k) {
    int count = g_counts[k];
    int base = g_offsets[k];
    size_t total = (size_t)count * REC_D;
    size_t stride = (size_t)gridDim.x * blockDim.x;
    for (size_t idx = (size_t)blockIdx.x * blockDim.x + threadIdx.x; idx < total; idx += stride) {
        int i = (int)(idx >> 10);
        int c = (int)(idx & 1023);
        int t = g_perm[base + i];
        float v = g_states[(size_t)(t - 1) * REC_D + c];
        bf16 hi, lo; split2(v, hi, lo);
        bf16* row = g_h3 + (size_t)i * 3 * REC_D;
        row[c] = hi; row[REC_D + c] = hi; row[2 * REC_D + c] = lo;
    }
}

// ---------------- tensor-core GEMM: C[M,N] = act(A3[M,K3] @ B3[N,K3]^T + bias) ----------------
// bf16 mma.sync m16n8k16. BM=BN=128, BK=32, 256 threads (8 warps, 4x2), warp tile 32x64.
__device__ __forceinline__ void ldmx4(uint32_t addr, uint32_t& r0, uint32_t& r1, uint32_t& r2, uint32_t& r3) {
    asm volatile("ldmatrix.sync.aligned.m8n8.x4.shared.b16 {%0,%1,%2,%3}, [%4];"
                 : "=r"(r0), "=r"(r1), "=r"(r2), "=r"(r3) : "r"(addr));
}
__device__ __forceinline__ void mma16816(float* c, const uint32_t* a, const uint32_t* b) {
    asm volatile("mma.sync.aligned.m16n8k16.row.col.f32.bf16.bf16.f32 "
                 "{%0,%1,%2,%3}, {%4,%5,%6,%7}, {%8,%9}, {%0,%1,%2,%3};"
                 : "+f"(c[0]), "+f"(c[1]), "+f"(c[2]), "+f"(c[3])
                 : "r"(a[0]), "r"(a[1]), "r"(a[2]), "r"(a[3]), "r"(b[0]), "r"(b[1]));
}

__device__ __forceinline__ void store_split_pair(bf16* Cs, size_t r, int N, int col, float v0, float v1) {
    bf16 h0, l0, h1, l1;
    split2(v0, h0, l0); split2(v1, h1, l1);
    __nv_bfloat162 hh; hh.x = h0; hh.y = h1;
    __nv_bfloat162 ll; ll.x = l0; ll.y = l1;
    bf16* row = Cs + r * (size_t)(3 * N);
    *(__nv_bfloat162*)&row[col]         = hh;
    *(__nv_bfloat162*)&row[N + col]     = hh;
    *(__nv_bfloat162*)&row[2 * N + col] = ll;
}

template <int MISH, int SPLIT>
__global__ void __launch_bounds__(256, 2)
gemm_mma(const bf16* __restrict__ A, const bf16* __restrict__ B,
         const float* __restrict__ bias, float* __restrict__ Cf, bf16* __restrict__ Cs,
         int N, int K3, const int* __restrict__ Mptr, int Mfix) {
    __shared__ __align__(16) bf16 As[128][40];
    __shared__ __align__(16) bf16 Bs[128][40];
    int M = Mptr ? *Mptr : Mfix;
    int tid = threadIdx.x;
    int wid = tid >> 5, lane = tid & 31;
    int wm = wid >> 1, wn = wid & 1;
    int colBase = blockIdx.x * 128;
    int lr = tid >> 2;
    int lc = (tid & 3) * 8;

    for (int mtile = blockIdx.y; mtile * 128 < M; mtile += gridDim.y) {
        int rowBase = mtile * 128;
        float acc[2][8][4];
#pragma unroll
        for (int mt = 0; mt < 2; mt++)
#pragma unroll
            for (int nt = 0; nt < 8; nt++)
#pragma unroll
                for (int q = 0; q < 4; q++) acc[mt][nt][q] = 0.0f;

        const bf16* Arow0 = A + (size_t)(rowBase + lr) * K3 + lc;
        const bf16* Arow1 = A + (size_t)(rowBase + lr + 64) * K3 + lc;
        const bf16* Brow0 = B + (size_t)(colBase + lr) * K3 + lc;
        const bf16* Brow1 = B + (size_t)(colBase + lr + 64) * K3 + lc;

        uint4 av0 = *(const uint4*)Arow0;
        uint4 av1 = *(const uint4*)Arow1;
        uint4 bv0 = *(const uint4*)Brow0;
        uint4 bv1 = *(const uint4*)Brow1;

        for (int k0 = 0; k0 < K3; k0 += 32) {
            __syncthreads();
            *(uint4*)&As[lr][lc]      = av0;
            *(uint4*)&As[lr + 64][lc] = av1;
            *(uint4*)&Bs[lr][lc]      = bv0;
            *(uint4*)&Bs[lr + 64][lc] = bv1;
            __syncthreads();
            if (k0 + 32 < K3) {
                av0 = *(const uint4*)(Arow0 + k0 + 32);
                av1 = *(const uint4*)(Arow1 + k0 + 32);
                bv0 = *(const uint4*)(Brow0 + k0 + 32);
                bv1 = *(const uint4*)(Brow1 + k0 + 32);
            }
#pragma unroll
            for (int kh = 0; kh < 2; kh++) {
                int krow = kh * 16 + (lane >> 4) * 8;
                uint32_t af[2][4];
#pragma unroll
                for (int mt = 0; mt < 2; mt++) {
                    uint32_t addr = smem_u32(&As[wm * 32 + mt * 16 + (lane & 15)][krow]);
                    ldmx4(addr, af[mt][0], af[mt][1], af[mt][2], af[mt][3]);
                }
                uint32_t bb[8][2];
#pragma unroll
                for (int nb = 0; nb < 4; nb++) {
                    uint32_t r0, r1, r2, r3;
                    uint32_t addr = smem_u32(&Bs[wn * 64 + nb * 16 + (lane & 15)][krow]);
                    ldmx4(addr, r0, r1, r2, r3);
                    bb[2 * nb][0] = r0; bb[2 * nb][1] = r2;
                    bb[2 * nb + 1][0] = r1; bb[2 * nb + 1][1] = r3;
                }
#pragma unroll
                for (int mt = 0; mt < 2; mt++)
#pragma unroll
                    for (int nt = 0; nt < 8; nt++)
                        mma16816(acc[mt][nt], af[mt], bb[nt]);
            }
        }

        int rg = lane >> 2, cg = (lane & 3) * 2;
#pragma unroll
        for (int mt = 0; mt < 2; mt++) {
            int r0 = rowBase + wm * 32 + mt * 16 + rg;
#pragma unroll
            for (int nt = 0; nt < 8; nt++) {
                int col = colBase + wn * 64 + nt * 8 + cg;
                float b0 = bias ? bias[col] : 0.0f;
                float b1 = bias ? bias[col + 1] : 0.0f;
                float v00 = acc[mt][nt][0] + b0, v01 = acc[mt][nt][1] + b1;
                float v10 = acc[mt][nt][2] + b0, v11 = acc[mt][nt][3] + b1;
                if (MISH) { v00 = mishf(v00); v01 = mishf(v01); v10 = mishf(v10); v11 = mishf(v11); }
                if (SPLIT) {
                    store_split_pair(Cs, (size_t)r0, N, col, v00, v01);
                    store_split_pair(Cs, (size_t)(r0 + 8), N, col, v10, v11);
                } else {
                    float2 lo2; lo2.x = v00; lo2.y = v01;
                    float2 hi2; hi2.x = v10; hi2.y = v11;
                    *(float2*)&Cf[(size_t)r0 * N + col] = lo2;
                    *(float2*)&Cf[(size_t)(r0 + 8) * N + col] = hi2;
                }
            }
        }
    }
}

// ---------------- GRU step k==0 (h_prev == 0) ----------------
__global__ void step0_kernel(const float* __restrict__ b_n) {
    int count = g_counts[0];
    long total = (long)count * REC_D;
    long stride = (long)gridDim.x * blockDim.x;
    for (long idx = (long)blockIdx.x * blockDim.x + threadIdx.x; idx < total; idx += stride) {
        int i = (int)(idx >> 10);
        int j = (int)(idx & 1023);
        int t = g_perm[i];
        float igr = g_igates[(size_t)t * G3_D + j];
        float igz = g_igates[(size_t)t * G3_D + 1024 + j];
        float ign = g_igates[(size_t)t * G3_D + 2048 + j];
        float r = sigf(igr);
        float z = sigf(igz);
        float n = tanhf(ign + r * b_n[j]);
        g_states[(size_t)t * REC_D + j] = n - z * n;
    }
}

__global__ void fixA_kernel(const float* __restrict__ w_hh, const float* __restrict__ state) {
    if (g_flags[1]) return;
    int j = blockIdx.x * 8 + (threadIdx.x >> 5);
    int lane = threadIdx.x & 31;
    float acc = 0.0f;
    const float* wr = w_hh + (size_t)j * REC_D;
    for (int k = lane; k < REC_D; k += 32) acc += wr[k] * state[k];
#pragma unroll
    for (int o = 16; o > 0; o >>= 1) acc += __shfl_down_sync(0xffffffffu, acc, o);
    if (lane == 0) g_hg0[j] = acc;
}

__global__ void fixB_kernel(const float* __restrict__ state, const float* __restrict__ b_n) {
    if (g_flags[1]) return;
    int j = threadIdx.x;
    float igr = g_igates[j], igz = g_igates[1024 + j], ign = g_igates[2048 + j];
    float r = sigf(igr + g_hg0[j]);
    float z = sigf(igz + g_hg0[1024 + j]);
    float n = tanhf(ign + r * (g_hg0[2048 + j] + b_n[j]));
    float hp = state[j];
    g_states[j] = n + z * (hp - n);
}

// ---------------- tail steps: warp-per-column matvec (small counts) ----------------
__global__ void __launch_bounds__(256)
gru_tail_hg(const float* __restrict__ w_hh, int k) {
    int count = g_counts[k];
    if (count <= 0) return;
    int base = g_offsets[k];
    int j = blockIdx.x * 8 + (threadIdx.x >> 5);  // grid 384 -> 3072 cols
    int lane = threadIdx.x & 31;
    const float4* wr = (const float4*)(w_hh + (size_t)j * REC_D);
    float4 w[8];
#pragma unroll
    for (int q = 0; q < 8; q++) w[q] = wr[lane + q * 32];
    for (int i = 0; i < count; i++) {
        int t = g_perm[base + i];
        const float4* h = (const float4*)(g_states + (size_t)(t - 1) * REC_D);
        float acc = 0.0f;
#pragma unroll
        for (int q = 0; q < 8; q++) {
            float4 hv = h[lane + q * 32];
            acc += w[q].x * hv.x + w[q].y * hv.y + w[q].z * hv.z + w[q].w * hv.w;
        }
#pragma unroll
        for (int o = 16; o > 0; o >>= 1) acc += __shfl_xor_sync(0xffffffffu, acc, o);
        if (lane == 0) g_hg[(size_t)i * G3_D + j] = acc;
    }
}

// ---------------- fused gate math (consumes g_hg rows for bucket k) ----------------
__global__ void gru_gate(const float* __restrict__ b_n, int k) {
    int count = g_counts[k];
    int base = g_offsets[k];
    long total = (long)count * REC_D;
    long stride = (long)gridDim.x * blockDim.x;
    for (long idx = (long)blockIdx.x * blockDim.x + threadIdx.x; idx < total; idx += stride) {
        int i = (int)(idx >> 10);
        int j = (int)(idx & 1023);
        int t = g_perm[base + i];
        float hr = g_hg[(size_t)i * G3_D + j];
        float hz = g_hg[(size_t)i * G3_D + 1024 + j];
        float hn = g_hg[(size_t)i * G3_D + 2048 + j];
        float igr = g_igates[(size_t)t * G3_D + j];
        float igz = g_igates[(size_t)t * G3_D + 1024 + j];
        float ign = g_igates[(size_t)t * G3_D + 2048 + j];
        float hp = g_states[(size_t)(t - 1) * REC_D + j];
        float r = sigf(igr + hr);
        float z = sigf(igz + hz);
        float n = tanhf(ign + r * (hn + b_n[j]));
        g_states[(size_t)t * REC_D + j] = n + z * (hp - n);
    }
}

// Safety net for ages >= STEPS (count 0 in practice).
__global__ void __launch_bounds__(1024)
cleanup_kernel(const float* __restrict__ w_hh, const float* __restrict__ b_n) {
    if (g_counts[STEPS] == 0) return;
    __shared__ int s_t;
    __shared__ int s_cur;
    __shared__ float sh[REC_D];
    int tid = threadIdx.x;
    if (tid == 0) s_cur = STEPS;
    __syncthreads();
    while (true) {
        if (tid == 0) {
            s_t = -1;
            for (int u = s_cur; u < T_LEN; ++u)
                if (g_age[u] >= STEPS) { s_t = u; s_cur = u + 1; break; }
        }
        __syncthreads();
        int t = s_t;
        if (t < 0) break;
        sh[tid] = g_states[(size_t)(t - 1) * REC_D + tid];
        __syncthreads();
        float aRv = 0, aZv = 0, aNv = 0;
        const float* wr = w_hh + (size_t)tid * REC_D;
        const float* wz = w_hh + (size_t)(1024 + tid) * REC_D;
        const float* wn = w_hh + (size_t)(2048 + tid) * REC_D;
        for (int kk = 0; kk < REC_D; kk++) {
            float h = sh[kk];
            aRv += wr[kk] * h; aZv += wz[kk] * h; aNv += wn[kk] * h;
        }
        float igr = g_igates[(size_t)t * G3_D + tid];
        float igz = g_igates[(size_t)t * G3_D + 1024 + tid];
        float ign = g_igates[(size_t)t * G3_D + 2048 + tid];
        float r = sigf(igr + aRv);
        float z = sigf(igz + aZv);
        float n = tanhf(ign + r * (aNv + b_n[tid]));
        float hp = sh[tid];
        g_states[(size_t)t * REC_D + tid] = n + z * (hp - n);
        __syncthreads();
    }
}

// ---------------- small head: out[T,18] = y2 @ p3_w^T + p3_b ----------------
__global__ void __launch_bounds__(192)
p3_kernel(const float* __restrict__ A, const float* __restrict__ W,
          const float* __restrict__ bias, float* __restrict__ out) {
    __shared__ __align__(16) float Ys[128][68];
    __shared__ float Ws[18][129];
    int tid = threadIdx.x;
    int rowBase = blockIdx.x * 64;
    int a = tid % 18, rg = tid / 18;
    float acc[8];
#pragma unroll
    for (int i = 0; i < 8; i++) acc[i] = 0.0f;

    for (int k0 = 0; k0 < MLP_D; k0 += 128) {
        __syncthreads();
        for (int l = tid; l < 18 * 128; l += 192) {
            int aa = l / 128, kk = l % 128;
            Ws[aa][kk] = W[(size_t)aa * MLP_D + k0 + kk];
        }
        for (int l = tid; l < 64 * 128; l += 192) {
            int r = l / 128, kk = l % 128;
            Ys[kk][r] = A[(size_t)(rowBase + r) * MLP_D + k0 + kk];
        }
        __syncthreads();
        if (tid < 144) {
#pragma unroll 4
            for (int kk = 0; kk < 128; kk++) {
                float w = Ws[a][kk];
                float4 y0 = *(const float4*)&Ys[kk][rg * 8];
                float4 y1v = *(const float4*)&Ys[kk][rg * 8 + 4];
                acc[0] += w * y0.x;  acc[1] += w * y0.y;
                acc[2] += w * y0.z;  acc[3] += w * y0.w;
                acc[4] += w * y1v.x; acc[5] += w * y1v.y;
                acc[6] += w * y1v.z; acc[7] += w * y1v.w;
            }
        }
    }
    if (tid < 144) {
        float b = bias[a];
#pragma unroll
        for (int i = 0; i < 8; i++)
            out[(size_t)(rowBase + rg * 8 + i) * ACT_D + a] = acc[i] + b;
    }
}

__global__ void copy_state_kernel(float* __restrict__ out) {
    out[threadIdx.x] = g_states[(size_t)(T_LEN - 1) * REC_D + threadIdx.x];
}

// ---------------- host ----------------
extern "C" void kernel_launch(void* const* d_in, const int* in_sizes, int n_in,
                              void* d_out, int out_size) {
    const float* x     = (const float*)d_in[0];
    const float* state = (const float*)d_in[1];
    const void*  start = d_in[2];
    const float* pre_w = (const float*)d_in[4];
    const float* pre_b = (const float*)d_in[5];
    const float* w_ih  = (const float*)d_in[6];
    const float* w_hh  = (const float*)d_in[7];
    const float* b_ih  = (const float*)d_in[8];
    const float* b_n   = (const float*)d_in[9];
    const float* p1_w  = (const float*)d_in[10];
    const float* p1_b  = (const float*)d_in[11];
    const float* p2_w  = (const float*)d_in[12];
    const float* p2_b  = (const float*)d_in[13];
    const float* p3_w  = (const float*)d_in[14];
    const float* p3_b  = (const float*)d_in[15];
    float* out = (float*)d_out;

    float *igates, *hg, *states, *y2;
    bf16 *x3, *prew3, *feat3, *wih3, *whh3, *p1w3, *p2w3, *states3, *y13, *h3;
    int* counts_dev;
    cudaGetSymbolAddress((void**)&igates, g_igates);
    cudaGetSymbolAddress((void**)&hg, g_hg);
    cudaGetSymbolAddress((void**)&states, g_states);
    cudaGetSymbolAddress((void**)&y2, g_y2);
    cudaGetSymbolAddress((void**)&x3, g_x3);
    cudaGetSymbolAddress((void**)&prew3, g_prew3);
    cudaGetSymbolAddress((void**)&feat3, g_feat3);
    cudaGetSymbolAddress((void**)&wih3, g_wih3);
    cudaGetSymbolAddress((void**)&whh3, g_whh3);
    cudaGetSymbolAddress((void**)&p1w3, g_p1w3);
    cudaGetSymbolAddress((void**)&p2w3, g_p2w3);
    cudaGetSymbolAddress((void**)&states3, g_states3);
    cudaGetSymbolAddress((void**)&y13, g_y13);
    cudaGetSymbolAddress((void**)&h3, g_h3);
    cudaGetSymbolAddress((void**)&counts_dev, g_counts);

    // segment analysis
    init_kernel<<<1, 64>>>();
    sniff_kernel<<<1, 256>>>((const unsigned char*)start);
    age_kernel<<<64, 256>>>(start);
    offsets_kernel<<<1, 1>>>();
    scatter_kernel<<<64, 256>>>();

    // weight + input conversions to split-bf16
    convert_w3<<<256, 256>>>(pre_w, prew3, MLP_D, OBS_D);
    convert_w3<<<2048, 256>>>(w_ih, wih3, G3_D, MLP_D);
    convert_w3<<<2048, 256>>>(w_hh, whh3, G3_D, REC_D);
    convert_w3<<<1024, 256>>>(p1_w, p1w3, MLP_D, REC_D);
    convert_w3<<<1024, 256>>>(p2_w, p2w3, MLP_D, MLP_D);
    convert_a3<<<2048, 256>>>(x, x3, OBS_D);

    // feat = mish(x @ pre_w^T + pre_b)  (epilogue writes split-bf16 directly)
    gemm_mma<1, 1><<<dim3(MLP_D / 128, T_LEN / 128), 256>>>(
        x3, prew3, pre_b, nullptr, feat3, MLP_D, 3 * OBS_D, nullptr, T_LEN);
    // igates = feat @ w_ih^T + b_ih
    gemm_mma<0, 0><<<dim3(G3_D / 128, T_LEN / 128), 256>>>(
        feat3, wih3, b_ih, igates, nullptr, G3_D, 3 * MLP_D, nullptr, T_LEN);

    // segment-parallel GRU scan
    step0_kernel<<<2048, 256>>>(b_n);
    fixA_kernel<<<384, 256>>>(w_hh, state);
    fixB_kernel<<<1, 1024>>>(state, b_n);
    for (int k = 1; k < GEMM_STEPS; k++) {
        int est = T_LEN >> k;
        int gy = est / 64; if (gy < 1) gy = 1; if (gy > 128) gy = 128;
        gather_h3<<<1024, 256>>>(k);
        gemm_mma<0, 0><<<dim3(G3_D / 128, gy), 256>>>(
            h3, whh3, nullptr, hg, nullptr, G3_D, 3 * REC_D, counts_dev + k, 0);
        gru_gate<<<2048, 256>>>(b_n, k);
    }
    for (int k = GEMM_STEPS; k < STEPS; k++) {
        gru_tail_hg<<<384, 256>>>(w_hh, k);
        gru_gate<<<256, 256>>>(b_n, k);
    }
    cleanup_kernel<<<1, 1024>>>(w_hh, b_n);

    // post MLP
    convert_a3<<<4096, 256>>>(states, states3, REC_D);
    gemm_mma<1, 1><<<dim3(MLP_D / 128, T_LEN / 128), 256>>>(
        states3, p1w3, p1_b, nullptr, y13, MLP_D, 3 * REC_D, nullptr, T_LEN);
    gemm_mma<1, 0><<<dim3(MLP_D / 128, T_LEN / 128), 256>>>(
        y13, p2w3, p2_b, y2, nullptr, MLP_D, 3 * MLP_D, nullptr, T_LEN);
    p3_kernel<<<T_LEN / 64, 192>>>(y2, p3_w, p3_b, out);

    if (out_size >= T_LEN * ACT_D + REC_D)
        copy_state_kernel<<<1, 1024>>>(out + (size_t)T_LEN * ACT_D);
}

// round 4
// speedup vs baseline: 2.0504x; 1.0338x over previous
#include <cuda_runtime.h>
#include <cuda_bf16.h>
#include <math.h>
#include <stdint.h>

#define T_LEN 16384
#define OBS_D 256
#define MLP_D 1024
#define REC_D 1024
#define G3_D  3072
#define ACT_D 18
#define STEPS 40
#define GEMM_STEPS 8

typedef __nv_bfloat16 bf16;

// ---------------- scratch (device globals; no allocation allowed) ----------------
__device__ __align__(16) bf16  g_x3[(size_t)T_LEN * 3 * OBS_D];
__device__ __align__(16) bf16  g_prew3[(size_t)MLP_D * 3 * OBS_D];
__device__ __align__(16) bf16  g_feat3[(size_t)T_LEN * 3 * MLP_D];
__device__ __align__(16) bf16  g_wih3[(size_t)G3_D * 3 * MLP_D];
__device__ __align__(16) bf16  g_whh3[(size_t)G3_D * 3 * REC_D];
__device__ __align__(16) bf16  g_p1w3[(size_t)MLP_D * 3 * REC_D];
__device__ __align__(16) bf16  g_p2w3[(size_t)MLP_D * 3 * MLP_D];
__device__ __align__(16) bf16  g_states3[(size_t)T_LEN * 3 * REC_D];
__device__ __align__(16) bf16  g_y13[(size_t)T_LEN * 3 * MLP_D];
__device__ __align__(16) bf16  g_h3[(size_t)T_LEN * 3 * REC_D];
__device__ __align__(16) float g_igates[(size_t)T_LEN * G3_D];
__device__ __align__(16) float g_hg[(size_t)T_LEN * G3_D];
__device__ __align__(16) float g_states[(size_t)T_LEN * REC_D];
__device__ __align__(16) float g_y2[(size_t)T_LEN * MLP_D];
__device__ float g_hg0[G3_D];
__device__ int   g_age[T_LEN];
__device__ int   g_perm[T_LEN];
__device__ int   g_counts[STEPS + 1];
__device__ int   g_offsets[STEPS + 1];
__device__ int   g_cursor[STEPS + 1];
__device__ int   g_flags[4];

// ---------------- helpers ----------------
__device__ __forceinline__ float sigf(float x) { return 1.0f / (1.0f + expf(-x)); }
__device__ __forceinline__ float mishf(float x) {
    float sp = (x > 15.0f) ? x : log1pf(expf(x));
    return x * tanhf(sp);
}
__device__ __forceinline__ void split2(float v, bf16& hi, bf16& lo) {
    hi = __float2bfloat16(v);
    lo = __float2bfloat16(v - __bfloat162float(hi));
}
__device__ __forceinline__ uint32_t smem_u32(const void* p) {
    return (uint32_t)__cvta_generic_to_shared(p);
}
__device__ __forceinline__ uint32_t pack2bfx(bf16 a, bf16 b) {
    __nv_bfloat162 t; t.x = a; t.y = b;
    return *(uint32_t*)&t;
}

// ---------------- async / mma primitives (all plain compute_100-legal) ----------------
__device__ __forceinline__ void cpasync16(uint32_t sa, const void* ga) {
    asm volatile("cp.async.cg.shared.global [%0], [%1], 16;" :: "r"(sa), "l"(ga));
}
__device__ __forceinline__ void cp_commit() { asm volatile("cp.async.commit_group;" ::: "memory"); }
__device__ __forceinline__ void cp_wait2() { asm volatile("cp.async.wait_group 2;" ::: "memory"); }
__device__ __forceinline__ void cp_wait0() { asm volatile("cp.async.wait_group 0;" ::: "memory"); }

__device__ __forceinline__ void ldmx4(uint32_t addr, uint32_t& r0, uint32_t& r1, uint32_t& r2, uint32_t& r3) {
    asm volatile("ldmatrix.sync.aligned.m8n8.x4.shared.b16 {%0,%1,%2,%3}, [%4];"
                 : "=r"(r0), "=r"(r1), "=r"(r2), "=r"(r3) : "r"(addr));
}
__device__ __forceinline__ void mma16816(float* c, const uint32_t* a, const uint32_t* b) {
    asm volatile("mma.sync.aligned.m16n8k16.row.col.f32.bf16.bf16.f32 "
                 "{%0,%1,%2,%3}, {%4,%5,%6,%7}, {%8,%9}, {%0,%1,%2,%3};"
                 : "+f"(c[0]), "+f"(c[1]), "+f"(c[2]), "+f"(c[3])
                 : "r"(a[0]), "r"(a[1]), "r"(a[2]), "r"(a[3]), "r"(b[0]), "r"(b[1]));
}

// ---------------- setup kernels ----------------
__global__ void init_kernel() {
    int t = threadIdx.x;
    if (t < STEPS + 1) { g_counts[t] = 0; g_cursor[t] = 0; }
    if (t < 4) g_flags[t] = 0;
}

__global__ void sniff_kernel(const unsigned char* __restrict__ p) {
    __shared__ int s_nz[4];
    int tid = threadIdx.x;
    if (tid < 4) s_nz[tid] = 0;
    __syncthreads();
    int cnt = 0;
    for (int i = tid; i < T_LEN; i += blockDim.x) cnt += (p[i] != 0);
    atomicAdd(&s_nz[tid & 3], cnt);
    __syncthreads();
    if (tid == 0) {
        int rest = s_nz[1] + s_nz[2] + s_nz[3];
        int mode;
        if (rest > 0) mode = (s_nz[0] == 0) ? 2 : 0;
        else          mode = (s_nz[0] > 0) ? 1 : 0;
        g_flags[0] = mode;
        bool s0;
        if (mode == 0)      s0 = p[0] != 0;
        else if (mode == 1) s0 = ((const int*)p)[0] != 0;
        else                s0 = ((const float*)p)[0] != 0.0f;
        g_flags[1] = s0 ? 1 : 0;
    }
}

__device__ __forceinline__ bool start_val(const void* p, int mode, int u) {
    if (mode == 0) return ((const unsigned char*)p)[u] != 0;
    if (mode == 1) return ((const int*)p)[u] != 0;
    return ((const float*)p)[u] != 0.0f;
}

__global__ void age_kernel(const void* __restrict__ startp) {
    int mode = g_flags[0];
    int stride = gridDim.x * blockDim.x;
    for (int t = blockIdx.x * blockDim.x + threadIdx.x; t < T_LEN; t += stride) {
        int k = 0, tt = t;
        while (tt > 0 && !start_val(startp, mode, tt)) { tt--; k++; }
        g_age[t] = k;
        int b = k < STEPS ? k : STEPS;
        atomicAdd(&g_counts[b], 1);
    }
}

__global__ void offsets_kernel() {
    if (threadIdx.x == 0 && blockIdx.x == 0) {
        int acc = 0;
        for (int b = 0; b <= STEPS; b++) { g_offsets[b] = acc; acc += g_counts[b]; }
    }
}

__global__ void scatter_kernel() {
    int stride = gridDim.x * blockDim.x;
    for (int t = blockIdx.x * blockDim.x + threadIdx.x; t < T_LEN; t += stride) {
        int a = g_age[t];
        int b = a < STEPS ? a : STEPS;
        int pos = g_offsets[b] + atomicAdd(&g_cursor[b], 1);
        g_perm[pos] = t;
    }
}

// ---------------- bf16-split conversions ----------------
__global__ void convert_w3(const float* __restrict__ src, bf16* __restrict__ dst, int N, int K) {
    size_t total = (size_t)N * K;
    size_t stride = (size_t)gridDim.x * blockDim.x;
    for (size_t idx = (size_t)blockIdx.x * blockDim.x + threadIdx.x; idx < total; idx += stride) {
        int r = (int)(idx / K), c = (int)(idx % K);
        float v = src[idx];
        bf16 hi, lo; split2(v, hi, lo);
        bf16* row = dst + (size_t)r * 3 * K;
        row[c] = hi; row[K + c] = lo; row[2 * K + c] = hi;
    }
}

__global__ void convert_a3(const float* __restrict__ src, bf16* __restrict__ dst, int K) {
    size_t total = (size_t)T_LEN * K;
    size_t stride = (size_t)gridDim.x * blockDim.x;
    for (size_t idx = (size_t)blockIdx.x * blockDim.x + threadIdx.x; idx < total; idx += stride) {
        int r = (int)(idx / K), c = (int)(idx % K);
        float v = src[idx];
        bf16 hi, lo; split2(v, hi, lo);
        bf16* row = dst + (size_t)r * 3 * K;
        row[c] = hi; row[K + c] = hi; row[2 * K + c] = lo;
    }
}

__global__ void gather_h3(int k) {
    int count = g_counts[k];
    int base = g_offsets[k];
    size_t total = (size_t)count * REC_D;
    size_t stride = (size_t)gridDim.x * blockDim.x;
    for (size_t idx = (size_t)blockIdx.x * blockDim.x + threadIdx.x; idx < total; idx += stride) {
        int i = (int)(idx >> 10);
        int c = (int)(idx & 1023);
        int t = g_perm[base + i];
        float v = g_states[(size_t)(t - 1) * REC_D + c];
        bf16 hi, lo; split2(v, hi, lo);
        bf16* row = g_h3 + (size_t)i * 3 * REC_D;
        row[c] = hi; row[REC_D + c] = hi; row[2 * REC_D + c] = lo;
    }
}

// ---------------- mma.sync GEMM with cp.async pipeline ----------------
// C[M,Ntot] = act(A[M,K3] @ B[Ntot,K3]^T + bias). Tile 128x256, BK=32, 4 stages.
// 256 threads = 8 warps (2M x 4N), warp tile 64x64.
#define STG_A_SZ 8192
#define STG_B_SZ 16384
#define STG_SZ (STG_A_SZ + STG_B_SZ)
#define NSTG 4
#define SMEM_GEMM (NSTG * STG_SZ)

// SMEM addr for (row, 16B-segment): conflict-free XOR swizzle.
__device__ __forceinline__ uint32_t swz(uint32_t base, int r, int seg) {
    return base + r * 64 + 16 * (seg ^ ((r >> 1) & 3));
}

__device__ __forceinline__ void load_stage(const bf16* __restrict__ A, const bf16* __restrict__ B,
                                           int rowBase, int colBase, int K3, int chunk,
                                           uint32_t sA, uint32_t sB, int tid) {
    const bf16* Ab = A + (size_t)rowBase * K3 + chunk * 32;
    const bf16* Bb = B + (size_t)colBase * K3 + chunk * 32;
#pragma unroll
    for (int i = 0; i < 2; i++) {
        int o = tid + i * 256;
        int r = o >> 2, seg = o & 3;
        cpasync16(swz(sA, r, seg), Ab + (size_t)r * K3 + seg * 8);
    }
#pragma unroll
    for (int i = 0; i < 4; i++) {
        int o = tid + i * 256;
        int r = o >> 2, seg = o & 3;
        cpasync16(swz(sB, r, seg), Bb + (size_t)r * K3 + seg * 8);
    }
}

template <int MISH, int SPLIT>
__global__ void __launch_bounds__(256)
gemm_ca(const bf16* __restrict__ A, const bf16* __restrict__ B,
        const float* __restrict__ bias, float* __restrict__ Cf, bf16* __restrict__ Cs,
        int Ntot, int K3, const int* __restrict__ Mptr, int Mfix) {
    extern __shared__ __align__(16) char dsm[];
    int tid = threadIdx.x, wid = tid >> 5, lane = tid & 31;
    int wm = wid >> 2, wn = wid & 3;
    int M = Mptr ? *Mptr : Mfix;
    int colBase = blockIdx.x * 256;
    int NC = K3 >> 5;
    uint32_t sbase = smem_u32(dsm);

    for (int mtile = blockIdx.y; mtile * 128 < M; mtile += gridDim.y) {
        int rowBase = mtile * 128;
        float acc[4][8][4];
#pragma unroll
        for (int mt = 0; mt < 4; mt++)
#pragma unroll
            for (int nt = 0; nt < 8; nt++)
#pragma unroll
                for (int q = 0; q < 4; q++) acc[mt][nt][q] = 0.0f;

        // prologue: stages 0..2
#pragma unroll
        for (int p = 0; p < 3; p++) {
            uint32_t sg = sbase + p * STG_SZ;
            load_stage(A, B, rowBase, colBase, K3, p, sg, sg + STG_A_SZ, tid);
            cp_commit();
        }

        for (int c = 0; c < NC; c++) {
            cp_wait2();           // stage c resident
            __syncthreads();      // all warps done reading stage (c-1)%4
            if (c + 3 < NC) {
                int s = (c + 3) & 3;
                uint32_t sg = sbase + s * STG_SZ;
                load_stage(A, B, rowBase, colBase, K3, c + 3, sg, sg + STG_A_SZ, tid);
            }
            cp_commit();          // keep group count invariant (possibly empty)

            uint32_t sA = sbase + (c & 3) * STG_SZ;
            uint32_t sB = sA + STG_A_SZ;
#pragma unroll
            for (int kk2 = 0; kk2 < 2; kk2++) {
                int seg = kk2 * 2 + (lane >> 4);
                uint32_t af[4][4];
#pragma unroll
                for (int mt = 0; mt < 4; mt++) {
                    int r = wm * 64 + mt * 16 + (lane & 15);
                    ldmx4(swz(sA, r, seg), af[mt][0], af[mt][1], af[mt][2], af[mt][3]);
                }
                uint32_t bb[8][2];
#pragma unroll
                for (int nb = 0; nb < 4; nb++) {
                    int r = wn * 64 + nb * 16 + (lane & 15);
                    uint32_t r0, r1, r2, r3;
                    ldmx4(swz(sB, r, seg), r0, r1, r2, r3);
                    bb[2 * nb][0] = r0;     bb[2 * nb][1] = r2;
                    bb[2 * nb + 1][0] = r1; bb[2 * nb + 1][1] = r3;
                }
#pragma unroll
                for (int mt = 0; mt < 4; mt++)
#pragma unroll
                    for (int nt = 0; nt < 8; nt++)
                        mma16816(acc[mt][nt], af[mt], bb[nt]);
            }
        }
        cp_wait0();
        __syncthreads();

        // epilogue: direct register stores
        int rg = lane >> 2, cg = (lane & 3) * 2;
#pragma unroll
        for (int mt = 0; mt < 4; mt++) {
            int R0 = rowBase + wm * 64 + mt * 16 + rg;
#pragma unroll
            for (int nt = 0; nt < 8; nt++) {
                int C = colBase + wn * 64 + nt * 8 + cg;
                float b0 = bias ? bias[C] : 0.0f;
                float b1 = bias ? bias[C + 1] : 0.0f;
                float v00 = acc[mt][nt][0] + b0, v01 = acc[mt][nt][1] + b1;
                float v10 = acc[mt][nt][2] + b0, v11 = acc[mt][nt][3] + b1;
                if (MISH) { v00 = mishf(v00); v01 = mishf(v01); v10 = mishf(v10); v11 = mishf(v11); }
                if (SPLIT) {
                    bf16 h0, l0, h1, l1;
                    split2(v00, h0, l0); split2(v01, h1, l1);
                    uint32_t H = pack2bfx(h0, h1), L = pack2bfx(l0, l1);
                    bf16* row = Cs + (size_t)R0 * 3 * Ntot;
                    *(uint32_t*)&row[C] = H;
                    *(uint32_t*)&row[Ntot + C] = H;
                    *(uint32_t*)&row[2 * Ntot + C] = L;
                    split2(v10, h0, l0); split2(v11, h1, l1);
                    H = pack2bfx(h0, h1); L = pack2bfx(l0, l1);
                    bf16* row2 = Cs + (size_t)(R0 + 8) * 3 * Ntot;
                    *(uint32_t*)&row2[C] = H;
                    *(uint32_t*)&row2[Ntot + C] = H;
                    *(uint32_t*)&row2[2 * Ntot + C] = L;
                } else {
                    float2 a; a.x = v00; a.y = v01;
                    float2 b; b.x = v10; b.y = v11;
                    *(float2*)&Cf[(size_t)R0 * Ntot + C] = a;
                    *(float2*)&Cf[(size_t)(R0 + 8) * Ntot + C] = b;
                }
            }
        }
    }
}

// ---------------- GRU step k==0 (h_prev == 0) ----------------
__global__ void step0_kernel(const float* __restrict__ b_n) {
    int count = g_counts[0];
    long total = (long)count * REC_D;
    long stride = (long)gridDim.x * blockDim.x;
    for (long idx = (long)blockIdx.x * blockDim.x + threadIdx.x; idx < total; idx += stride) {
        int i = (int)(idx >> 10);
        int j = (int)(idx & 1023);
        int t = g_perm[i];
        float igr = g_igates[(size_t)t * G3_D + j];
        float igz = g_igates[(size_t)t * G3_D + 1024 + j];
        float ign = g_igates[(size_t)t * G3_D + 2048 + j];
        float r = sigf(igr);
        float z = sigf(igz);
        float n = tanhf(ign + r * b_n[j]);
        g_states[(size_t)t * REC_D + j] = n - z * n;
    }
}

__global__ void fixA_kernel(const float* __restrict__ w_hh, const float* __restrict__ state) {
    if (g_flags[1]) return;
    int j = blockIdx.x * 8 + (threadIdx.x >> 5);
    int lane = threadIdx.x & 31;
    float acc = 0.0f;
    const float* wr = w_hh + (size_t)j * REC_D;
    for (int k = lane; k < REC_D; k += 32) acc += wr[k] * state[k];
#pragma unroll
    for (int o = 16; o > 0; o >>= 1) acc += __shfl_down_sync(0xffffffffu, acc, o);
    if (lane == 0) g_hg0[j] = acc;
}

__global__ void fixB_kernel(const float* __restrict__ state, const float* __restrict__ b_n) {
    if (g_flags[1]) return;
    int j = threadIdx.x;
    float igr = g_igates[j], igz = g_igates[1024 + j], ign = g_igates[2048 + j];
    float r = sigf(igr + g_hg0[j]);
    float z = sigf(igz + g_hg0[1024 + j]);
    float n = tanhf(ign + r * (g_hg0[2048 + j] + b_n[j]));
    float hp = state[j];
    g_states[j] = n + z * (hp - n);
}

// ---------------- fused tail step: warp-per-output, all 3 gates + update ----------------
// grid 128 x 256 threads -> 1024 warps, warp w handles output column j = w.
__global__ void __launch_bounds__(256)
gru_tail_fused(const float* __restrict__ w_hh, const float* __restrict__ b_n, int k) {
    int count = g_counts[k];
    if (count <= 0) return;
    int base = g_offsets[k];
    int j = blockIdx.x * 8 + (threadIdx.x >> 5);
    int lane = threadIdx.x & 31;
    const float4* wrp = (const float4*)(w_hh + (size_t)j * REC_D);
    const float4* wzp = (const float4*)(w_hh + (size_t)(1024 + j) * REC_D);
    const float4* wnp = (const float4*)(w_hh + (size_t)(2048 + j) * REC_D);
    float4 wr[8], wz[8], wn[8];
#pragma unroll
    for (int q = 0; q < 8; q++) {
        wr[q] = wrp[lane + q * 32];
        wz[q] = wzp[lane + q * 32];
        wn[q] = wnp[lane + q * 32];
    }
    float bn = b_n[j];
    for (int i = 0; i < count; i++) {
        int t = g_perm[base + i];
        const float4* h = (const float4*)(g_states + (size_t)(t - 1) * REC_D);
        float aR = 0.0f, aZ = 0.0f, aN = 0.0f;
#pragma unroll
        for (int q = 0; q < 8; q++) {
            float4 hv = h[lane + q * 32];
            aR += wr[q].x * hv.x + wr[q].y * hv.y + wr[q].z * hv.z + wr[q].w * hv.w;
            aZ += wz[q].x * hv.x + wz[q].y * hv.y + wz[q].z * hv.z + wz[q].w * hv.w;
            aN += wn[q].x * hv.x + wn[q].y * hv.y + wn[q].z * hv.z + wn[q].w * hv.w;
        }
#pragma unroll
        for (int o = 16; o > 0; o >>= 1) {
            aR += __shfl_xor_sync(0xffffffffu, aR, o);
            aZ += __shfl_xor_sync(0xffffffffu, aZ, o);
            aN += __shfl_xor_sync(0xffffffffu, aN, o);
        }
        if (lane == 0) {
            float igr = g_igates[(size_t)t * G3_D + j];
            float igz = g_igates[(size_t)t * G3_D + 1024 + j];
            float ign = g_igates[(size_t)t * G3_D + 2048 + j];
            float hp = g_states[(size_t)(t - 1) * REC_D + j];
            float r = sigf(igr + aR);
            float z = sigf(igz + aZ);
            float n = tanhf(ign + r * (aN + bn));
            g_states[(size_t)t * REC_D + j] = n + z * (hp - n);
        }
    }
}

// gate math for GEMM steps (consumes g_hg)
__global__ void gru_gate(const float* __restrict__ b_n, int k) {
    int count = g_counts[k];
    int base = g_offsets[k];
    long total = (long)count * REC_D;
    long stride = (long)gridDim.x * blockDim.x;
    for (long idx = (long)blockIdx.x * blockDim.x + threadIdx.x; idx < total; idx += stride) {
        int i = (int)(idx >> 10);
        int j = (int)(idx & 1023);
        int t = g_perm[base + i];
        float hr = g_hg[(size_t)i * G3_D + j];
        float hz = g_hg[(size_t)i * G3_D + 1024 + j];
        float hn = g_hg[(size_t)i * G3_D + 2048 + j];
        float igr = g_igates[(size_t)t * G3_D + j];
        float igz = g_igates[(size_t)t * G3_D + 1024 + j];
        float ign = g_igates[(size_t)t * G3_D + 2048 + j];
        float hp = g_states[(size_t)(t - 1) * REC_D + j];
        float r = sigf(igr + hr);
        float z = sigf(igz + hz);
        float n = tanhf(ign + r * (hn + b_n[j]));
        g_states[(size_t)t * REC_D + j] = n + z * (hp - n);
    }
}

// safety net for age >= STEPS (empty in practice)
__global__ void __launch_bounds__(1024)
cleanup_kernel(const float* __restrict__ w_hh, const float* __restrict__ b_n) {
    if (g_counts[STEPS] == 0) return;
    __shared__ int s_t;
    __shared__ int s_cur;
    __shared__ float sh[REC_D];
    int tid = threadIdx.x;
    if (tid == 0) s_cur = STEPS;
    __syncthreads();
    while (true) {
        if (tid == 0) {
            s_t = -1;
            for (int u = s_cur; u < T_LEN; ++u)
                if (g_age[u] >= STEPS) { s_t = u; s_cur = u + 1; break; }
        }
        __syncthreads();
        int t = s_t;
        if (t < 0) break;
        sh[tid] = g_states[(size_t)(t - 1) * REC_D + tid];
        __syncthreads();
        float aRv = 0, aZv = 0, aNv = 0;
        const float* wr = w_hh + (size_t)tid * REC_D;
        const float* wz = w_hh + (size_t)(1024 + tid) * REC_D;
        const float* wn = w_hh + (size_t)(2048 + tid) * REC_D;
        for (int kk = 0; kk < REC_D; kk++) {
            float h = sh[kk];
            aRv += wr[kk] * h; aZv += wz[kk] * h; aNv += wn[kk] * h;
        }
        float igr = g_igates[(size_t)t * G3_D + tid];
        float igz = g_igates[(size_t)t * G3_D + 1024 + tid];
        float ign = g_igates[(size_t)t * G3_D + 2048 + tid];
        float r = sigf(igr + aRv);
        float z = sigf(igz + aZv);
        float n = tanhf(ign + r * (aNv + b_n[tid]));
        float hp = sh[tid];
        g_states[(size_t)t * REC_D + tid] = n + z * (hp - n);
        __syncthreads();
    }
}

// ---------------- small head ----------------
__global__ void __launch_bounds__(192)
p3_kernel(const float* __restrict__ A, const float* __restrict__ Wt,
          const float* __restrict__ bias, float* __restrict__ out) {
    __shared__ __align__(16) float Ys[128][68];
    __shared__ float Ws[18][129];
    int tid = threadIdx.x;
    int rowBase = blockIdx.x * 64;
    int a = tid % 18, rg = tid / 18;
    float acc[8];
#pragma unroll
    for (int i = 0; i < 8; i++) acc[i] = 0.0f;

    for (int k0 = 0; k0 < MLP_D; k0 += 128) {
        __syncthreads();
        for (int l = tid; l < 18 * 128; l += 192) {
            int aa = l / 128, kk = l % 128;
            Ws[aa][kk] = Wt[(size_t)aa * MLP_D + k0 + kk];
        }
        for (int l = tid; l < 64 * 128; l += 192) {
            int r = l / 128, kk = l % 128;
            Ys[kk][r] = A[(size_t)(rowBase + r) * MLP_D + k0 + kk];
        }
        __syncthreads();
        if (tid < 144) {
#pragma unroll 4
            for (int kk = 0; kk < 128; kk++) {
                float w = Ws[a][kk];
                float4 y0 = *(const float4*)&Ys[kk][rg * 8];
                float4 y1v = *(const float4*)&Ys[kk][rg * 8 + 4];
                acc[0] += w * y0.x;  acc[1] += w * y0.y;
                acc[2] += w * y0.z;  acc[3] += w * y0.w;
                acc[4] += w * y1v.x; acc[5] += w * y1v.y;
                acc[6] += w * y1v.z; acc[7] += w * y1v.w;
            }
        }
    }
    if (tid < 144) {
        float b = bias[a];
#pragma unroll
        for (int i = 0; i < 8; i++)
            out[(size_t)(rowBase + rg * 8 + i) * ACT_D + a] = acc[i] + b;
    }
}

__global__ void copy_state_kernel(float* __restrict__ out) {
    out[threadIdx.x] = g_states[(size_t)(T_LEN - 1) * REC_D + threadIdx.x];
}

// ---------------- host ----------------
extern "C" void kernel_launch(void* const* d_in, const int* in_sizes, int n_in,
                              void* d_out, int out_size) {
    const float* x     = (const float*)d_in[0];
    const float* state = (const float*)d_in[1];
    const void*  start = d_in[2];
    const float* pre_w = (const float*)d_in[4];
    const float* pre_b = (const float*)d_in[5];
    const float* w_ih  = (const float*)d_in[6];
    const float* w_hh  = (const float*)d_in[7];
    const float* b_ih  = (const float*)d_in[8];
    const float* b_n   = (const float*)d_in[9];
    const float* p1_w  = (const float*)d_in[10];
    const float* p1_b  = (const float*)d_in[11];
    const float* p2_w  = (const float*)d_in[12];
    const float* p2_b  = (const float*)d_in[13];
    const float* p3_w  = (const float*)d_in[14];
    const float* p3_b  = (const float*)d_in[15];
    float* out = (float*)d_out;

    float *igates, *hg, *states, *y2;
    bf16 *x3, *prew3, *feat3, *wih3, *whh3, *p1w3, *p2w3, *states3, *y13, *h3;
    int* counts_dev;
    cudaGetSymbolAddress((void**)&igates, g_igates);
    cudaGetSymbolAddress((void**)&hg, g_hg);
    cudaGetSymbolAddress((void**)&states, g_states);
    cudaGetSymbolAddress((void**)&y2, g_y2);
    cudaGetSymbolAddress((void**)&x3, g_x3);
    cudaGetSymbolAddress((void**)&prew3, g_prew3);
    cudaGetSymbolAddress((void**)&feat3, g_feat3);
    cudaGetSymbolAddress((void**)&wih3, g_wih3);
    cudaGetSymbolAddress((void**)&whh3, g_whh3);
    cudaGetSymbolAddress((void**)&p1w3, g_p1w3);
    cudaGetSymbolAddress((void**)&p2w3, g_p2w3);
    cudaGetSymbolAddress((void**)&states3, g_states3);
    cudaGetSymbolAddress((void**)&y13, g_y13);
    cudaGetSymbolAddress((void**)&h3, g_h3);
    cudaGetSymbolAddress((void**)&counts_dev, g_counts);

    cudaFuncSetAttribute(gemm_ca<1, 1>, cudaFuncAttributeMaxDynamicSharedMemorySize, SMEM_GEMM);
    cudaFuncSetAttribute(gemm_ca<0, 0>, cudaFuncAttributeMaxDynamicSharedMemorySize, SMEM_GEMM);
    cudaFuncSetAttribute(gemm_ca<1, 0>, cudaFuncAttributeMaxDynamicSharedMemorySize, SMEM_GEMM);

    // segment analysis
    init_kernel<<<1, 64>>>();
    sniff_kernel<<<1, 256>>>((const unsigned char*)start);
    age_kernel<<<64, 256>>>(start);
    offsets_kernel<<<1, 1>>>();
    scatter_kernel<<<64, 256>>>();

    // conversions to split-bf16
    convert_w3<<<256, 256>>>(pre_w, prew3, MLP_D, OBS_D);
    convert_w3<<<2048, 256>>>(w_ih, wih3, G3_D, MLP_D);
    convert_w3<<<2048, 256>>>(w_hh, whh3, G3_D, REC_D);
    convert_w3<<<1024, 256>>>(p1_w, p1w3, MLP_D, REC_D);
    convert_w3<<<1024, 256>>>(p2_w, p2w3, MLP_D, MLP_D);
    convert_a3<<<2048, 256>>>(x, x3, OBS_D);

    // feat = mish(x @ pre_w^T + pre_b)
    gemm_ca<1, 1><<<dim3(MLP_D / 256, 128), 256, SMEM_GEMM>>>(
        x3, prew3, pre_b, nullptr, feat3, MLP_D, 3 * OBS_D, nullptr, T_LEN);
    // igates = feat @ w_ih^T + b_ih
    gemm_ca<0, 0><<<dim3(G3_D / 256, 128), 256, SMEM_GEMM>>>(
        feat3, wih3, b_ih, igates, nullptr, G3_D, 3 * MLP_D, nullptr, T_LEN);

    // segment-parallel GRU scan
    step0_kernel<<<2048, 256>>>(b_n);
    fixA_kernel<<<384, 256>>>(w_hh, state);
    fixB_kernel<<<1, 1024>>>(state, b_n);
    for (int k = 1; k < GEMM_STEPS; k++) {
        int est = T_LEN >> k;
        int gy = est / 128; if (gy < 1) gy = 1; if (gy > 64) gy = 64;
        gather_h3<<<1024, 256>>>(k);
        gemm_ca<0, 0><<<dim3(G3_D / 256, gy), 256, SMEM_GEMM>>>(
            h3, whh3, nullptr, hg, nullptr, G3_D, 3 * REC_D, counts_dev + k, 0);
        gru_gate<<<2048, 256>>>(b_n, k);
    }
    for (int k = GEMM_STEPS; k < STEPS; k++) {
        gru_tail_fused<<<128, 256>>>(w_hh, b_n, k);
    }
    cleanup_kernel<<<1, 1024>>>(w_hh, b_n);

    // post MLP
    convert_a3<<<4096, 256>>>(states, states3, REC_D);
    gemm_ca<1, 1><<<dim3(MLP_D / 256, 128), 256, SMEM_GEMM>>>(
        states3, p1w3, p1_b, nullptr, y13, MLP_D, 3 * REC_D, nullptr, T_LEN);
    gemm_ca<1, 0><<<dim3(MLP_D / 256, 128), 256, SMEM_GEMM>>>(
        y13, p2w3, p2_b, y2, nullptr, MLP_D, 3 * MLP_D, nullptr, T_LEN);
    p3_kernel<<<T_LEN / 64, 192>>>(y2, p3_w, p3_b, out);

    if (out_size >= T_LEN * ACT_D + REC_D)
        copy_state_kernel<<<1, 1024>>>(out + (size_t)T_LEN * ACT_D);
}

// round 5
// speedup vs baseline: 2.4963x; 1.2174x over previous
#include <cuda_runtime.h>
#include <cuda_bf16.h>
#include <cuda_fp16.h>
#include <math.h>
#include <stdint.h>

#define T_LEN 16384
#define OBS_D 256
#define MLP_D 1024
#define REC_D 1024
#define G3_D  3072
#define ACT_D 18
#define STEPS 26
#define GEMM_STEPS 8

typedef __nv_bfloat16 bf16;
typedef __half f16;

// ---------------- scratch (device globals; no allocation allowed) ----------------
__device__ __align__(16) f16   g_x2[(size_t)T_LEN * 2 * OBS_D];
__device__ __align__(16) f16   g_prew2[(size_t)MLP_D * 2 * OBS_D];
__device__ __align__(16) f16   g_feat2[(size_t)T_LEN * 2 * MLP_D];
__device__ __align__(16) f16   g_wih2[(size_t)G3_D * 2 * MLP_D];
__device__ __align__(16) f16   g_p1w2[(size_t)MLP_D * 2 * REC_D];
__device__ __align__(16) f16   g_p2w2[(size_t)MLP_D * 2 * MLP_D];
__device__ __align__(16) f16   g_states2[(size_t)T_LEN * 2 * REC_D];
__device__ __align__(16) f16   g_y12[(size_t)T_LEN * 2 * MLP_D];
__device__ __align__(16) bf16  g_whh3[(size_t)G3_D * 3 * REC_D];
__device__ __align__(16) bf16  g_h3[(size_t)T_LEN * 3 * REC_D];
__device__ __align__(16) float g_igates[(size_t)T_LEN * G3_D];
__device__ __align__(16) float g_hg[(size_t)T_LEN * G3_D];
__device__ __align__(16) float g_states[(size_t)T_LEN * REC_D];
__device__ __align__(16) float g_y2[(size_t)T_LEN * MLP_D];
__device__ float g_hg0[G3_D];
__device__ int   g_age[T_LEN];
__device__ int   g_perm[T_LEN];
__device__ int   g_counts[STEPS + 1];
__device__ int   g_offsets[STEPS + 1];
__device__ int   g_cursor[STEPS + 1];
__device__ int   g_flags[4];

// ---------------- helpers ----------------
__device__ __forceinline__ float sigf(float x) { return 1.0f / (1.0f + expf(-x)); }
__device__ __forceinline__ float mishf(float x) {
    float sp = (x > 15.0f) ? x : log1pf(expf(x));
    return x * tanhf(sp);
}
__device__ __forceinline__ void split2b(float v, bf16& hi, bf16& lo) {
    hi = __float2bfloat16(v);
    lo = __float2bfloat16(v - __bfloat162float(hi));
}
__device__ __forceinline__ void split2h(float v, f16& hi, f16& lo) {
    hi = __float2half(v);
    lo = __float2half(v - __half2float(hi));
}
__device__ __forceinline__ uint32_t smem_u32(const void* p) {
    return (uint32_t)__cvta_generic_to_shared(p);
}
__device__ __forceinline__ uint32_t pack2h(f16 a, f16 b) {
    __half2 t; t.x = a; t.y = b;
    return *(uint32_t*)&t;
}

// ---------------- async / mma primitives (plain compute_100-legal) ----------------
__device__ __forceinline__ void cpasync16(uint32_t sa, const void* ga) {
    asm volatile("cp.async.cg.shared.global [%0], [%1], 16;" :: "r"(sa), "l"(ga));
}
__device__ __forceinline__ void cp_commit() { asm volatile("cp.async.commit_group;" ::: "memory"); }
__device__ __forceinline__ void cp_wait2() { asm volatile("cp.async.wait_group 2;" ::: "memory"); }
__device__ __forceinline__ void cp_wait0() { asm volatile("cp.async.wait_group 0;" ::: "memory"); }

__device__ __forceinline__ void ldmx4(uint32_t addr, uint32_t& r0, uint32_t& r1, uint32_t& r2, uint32_t& r3) {
    asm volatile("ldmatrix.sync.aligned.m8n8.x4.shared.b16 {%0,%1,%2,%3}, [%4];"
                 : "=r"(r0), "=r"(r1), "=r"(r2), "=r"(r3) : "r"(addr));
}
template <int HALF>
__device__ __forceinline__ void mma_any(float* c, const uint32_t* a, const uint32_t* b) {
    if (HALF)
        asm volatile("mma.sync.aligned.m16n8k16.row.col.f32.f16.f16.f32 "
                     "{%0,%1,%2,%3}, {%4,%5,%6,%7}, {%8,%9}, {%0,%1,%2,%3};"
                     : "+f"(c[0]), "+f"(c[1]), "+f"(c[2]), "+f"(c[3])
                     : "r"(a[0]), "r"(a[1]), "r"(a[2]), "r"(a[3]), "r"(b[0]), "r"(b[1]));
    else
        asm volatile("mma.sync.aligned.m16n8k16.row.col.f32.bf16.bf16.f32 "
                     "{%0,%1,%2,%3}, {%4,%5,%6,%7}, {%8,%9}, {%0,%1,%2,%3};"
                     : "+f"(c[0]), "+f"(c[1]), "+f"(c[2]), "+f"(c[3])
                     : "r"(a[0]), "r"(a[1]), "r"(a[2]), "r"(a[3]), "r"(b[0]), "r"(b[1]));
}

// ---------------- setup kernels ----------------
__global__ void init_kernel() {
    int t = threadIdx.x;
    if (t < STEPS + 1) { g_counts[t] = 0; g_cursor[t] = 0; }
    if (t < 4) g_flags[t] = 0;
}

__global__ void sniff_kernel(const unsigned char* __restrict__ p) {
    __shared__ int s_nz[4];
    int tid = threadIdx.x;
    if (tid < 4) s_nz[tid] = 0;
    __syncthreads();
    int cnt = 0;
    for (int i = tid; i < T_LEN; i += blockDim.x) cnt += (p[i] != 0);
    atomicAdd(&s_nz[tid & 3], cnt);
    __syncthreads();
    if (tid == 0) {
        int rest = s_nz[1] + s_nz[2] + s_nz[3];
        int mode;
        if (rest > 0) mode = (s_nz[0] == 0) ? 2 : 0;
        else          mode = (s_nz[0] > 0) ? 1 : 0;
        g_flags[0] = mode;
        bool s0;
        if (mode == 0)      s0 = p[0] != 0;
        else if (mode == 1) s0 = ((const int*)p)[0] != 0;
        else                s0 = ((const float*)p)[0] != 0.0f;
        g_flags[1] = s0 ? 1 : 0;
    }
}

__device__ __forceinline__ bool start_val(const void* p, int mode, int u) {
    if (mode == 0) return ((const unsigned char*)p)[u] != 0;
    if (mode == 1) return ((const int*)p)[u] != 0;
    return ((const float*)p)[u] != 0.0f;
}

__global__ void age_kernel(const void* __restrict__ startp) {
    int mode = g_flags[0];
    int stride = gridDim.x * blockDim.x;
    for (int t = blockIdx.x * blockDim.x + threadIdx.x; t < T_LEN; t += stride) {
        int k = 0, tt = t;
        while (tt > 0 && !start_val(startp, mode, tt)) { tt--; k++; }
        g_age[t] = k;
        int b = k < STEPS ? k : STEPS;
        atomicAdd(&g_counts[b], 1);
    }
}

__global__ void offsets_kernel() {
    if (threadIdx.x == 0 && blockIdx.x == 0) {
        int acc = 0;
        for (int b = 0; b <= STEPS; b++) { g_offsets[b] = acc; acc += g_counts[b]; }
    }
}

__global__ void scatter_kernel() {
    int stride = gridDim.x * blockDim.x;
    for (int t = blockIdx.x * blockDim.x + threadIdx.x; t < T_LEN; t += stride) {
        int a = g_age[t];
        int b = a < STEPS ? a : STEPS;
        int pos = g_offsets[b] + atomicAdd(&g_cursor[b], 1);
        g_perm[pos] = t;
    }
}

// ---------------- conversions ----------------
// fp16 weights: [N][K] fp32 -> [N][2K] fp16 as [hi | hi]
__global__ void convert_w2(const float* __restrict__ src, f16* __restrict__ dst, int N, int K) {
    size_t total = (size_t)N * K;
    size_t stride = (size_t)gridDim.x * blockDim.x;
    for (size_t idx = (size_t)blockIdx.x * blockDim.x + threadIdx.x; idx < total; idx += stride) {
        int r = (int)(idx / K), c = (int)(idx % K);
        f16 h = __float2half(src[idx]);
        f16* row = dst + (size_t)r * 2 * K;
        row[c] = h; row[K + c] = h;
    }
}
// fp16 activations: [T][K] fp32 -> [T][2K] fp16 as [hi | lo]
__global__ void convert_a2(const float* __restrict__ src, f16* __restrict__ dst, int K) {
    size_t total = (size_t)T_LEN * K;
    size_t stride = (size_t)gridDim.x * blockDim.x;
    for (size_t idx = (size_t)blockIdx.x * blockDim.x + threadIdx.x; idx < total; idx += stride) {
        int r = (int)(idx / K), c = (int)(idx % K);
        f16 hi, lo; split2h(src[idx], hi, lo);
        f16* row = dst + (size_t)r * 2 * K;
        row[c] = hi; row[K + c] = lo;
    }
}
// bf16 3-term weights for the GRU hh matrix: [hi | lo | hi]
__global__ void convert_w3(const float* __restrict__ src, bf16* __restrict__ dst, int N, int K) {
    size_t total = (size_t)N * K;
    size_t stride = (size_t)gridDim.x * blockDim.x;
    for (size_t idx = (size_t)blockIdx.x * blockDim.x + threadIdx.x; idx < total; idx += stride) {
        int r = (int)(idx / K), c = (int)(idx % K);
        bf16 hi, lo; split2b(src[idx], hi, lo);
        bf16* row = dst + (size_t)r * 3 * K;
        row[c] = hi; row[K + c] = lo; row[2 * K + c] = hi;
    }
}
// gather h_{t-1} rows -> bf16 3-term A: [hi | hi | lo]
__global__ void gather_h3(int k) {
    int count = g_counts[k];
    int base = g_offsets[k];
    size_t total = (size_t)count * REC_D;
    size_t stride = (size_t)gridDim.x * blockDim.x;
    for (size_t idx = (size_t)blockIdx.x * blockDim.x + threadIdx.x; idx < total; idx += stride) {
        int i = (int)(idx >> 10);
        int c = (int)(idx & 1023);
        int t = g_perm[base + i];
        bf16 hi, lo; split2b(g_states[(size_t)(t - 1) * REC_D + c], hi, lo);
        bf16* row = g_h3 + (size_t)i * 3 * REC_D;
        row[c] = hi; row[REC_D + c] = hi; row[2 * REC_D + c] = lo;
    }
}

// ---------------- mma.sync GEMM with cp.async pipeline ----------------
// C[M,Ntot] = act(A[M,K3] @ B[Ntot,K3]^T + bias). Tile 128x256, BK=32, 4 stages.
#define STG_A_SZ 8192
#define STG_B_SZ 16384
#define STG_SZ (STG_A_SZ + STG_B_SZ)
#define NSTG 4
#define SMEM_GEMM (NSTG * STG_SZ)

__device__ __forceinline__ uint32_t swz(uint32_t base, int r, int seg) {
    return base + r * 64 + 16 * (seg ^ ((r >> 1) & 3));
}

__device__ __forceinline__ void load_stage(const bf16* __restrict__ A, const bf16* __restrict__ B,
                                           int rowBase, int colBase, int K3, int chunk,
                                           uint32_t sA, uint32_t sB, int tid) {
    const bf16* Ab = A + (size_t)rowBase * K3 + chunk * 32;
    const bf16* Bb = B + (size_t)colBase * K3 + chunk * 32;
#pragma unroll
    for (int i = 0; i < 2; i++) {
        int o = tid + i * 256;
        int r = o >> 2, seg = o & 3;
        cpasync16(swz(sA, r, seg), Ab + (size_t)r * K3 + seg * 8);
    }
#pragma unroll
    for (int i = 0; i < 4; i++) {
        int o = tid + i * 256;
        int r = o >> 2, seg = o & 3;
        cpasync16(swz(sB, r, seg), Bb + (size_t)r * K3 + seg * 8);
    }
}

template <int HALF, int MISH, int SPLIT>
__global__ void __launch_bounds__(256)
gemm_ca(const bf16* __restrict__ A, const bf16* __restrict__ B,
        const float* __restrict__ bias, float* __restrict__ Cf, f16* __restrict__ Cs,
        int Ntot, int K3, const int* __restrict__ Mptr, int Mfix) {
    extern __shared__ __align__(16) char dsm[];
    int tid = threadIdx.x, wid = tid >> 5, lane = tid & 31;
    int wm = wid >> 2, wn = wid & 3;
    int M = Mptr ? *Mptr : Mfix;
    int colBase = blockIdx.x * 256;
    int NC = K3 >> 5;
    uint32_t sbase = smem_u32(dsm);

    for (int mtile = blockIdx.y; mtile * 128 < M; mtile += gridDim.y) {
        int rowBase = mtile * 128;
        float acc[4][8][4];
#pragma unroll
        for (int mt = 0; mt < 4; mt++)
#pragma unroll
            for (int nt = 0; nt < 8; nt++)
#pragma unroll
                for (int q = 0; q < 4; q++) acc[mt][nt][q] = 0.0f;

#pragma unroll
        for (int p = 0; p < 3; p++) {
            uint32_t sg = sbase + p * STG_SZ;
            load_stage(A, B, rowBase, colBase, K3, p, sg, sg + STG_A_SZ, tid);
            cp_commit();
        }

        for (int c = 0; c < NC; c++) {
            cp_wait2();
            __syncthreads();
            if (c + 3 < NC) {
                int s = (c + 3) & 3;
                uint32_t sg = sbase + s * STG_SZ;
                load_stage(A, B, rowBase, colBase, K3, c + 3, sg, sg + STG_A_SZ, tid);
            }
            cp_commit();

            uint32_t sA = sbase + (c & 3) * STG_SZ;
            uint32_t sB = sA + STG_A_SZ;
#pragma unroll
            for (int kk2 = 0; kk2 < 2; kk2++) {
                int seg = kk2 * 2 + (lane >> 4);
                uint32_t af[4][4];
#pragma unroll
                for (int mt = 0; mt < 4; mt++) {
                    int r = wm * 64 + mt * 16 + (lane & 15);
                    ldmx4(swz(sA, r, seg), af[mt][0], af[mt][1], af[mt][2], af[mt][3]);
                }
                uint32_t bb[8][2];
#pragma unroll
                for (int nb = 0; nb < 4; nb++) {
                    int r = wn * 64 + nb * 16 + (lane & 15);
                    uint32_t r0, r1, r2, r3;
                    ldmx4(swz(sB, r, seg), r0, r1, r2, r3);
                    bb[2 * nb][0] = r0;     bb[2 * nb][1] = r2;
                    bb[2 * nb + 1][0] = r1; bb[2 * nb + 1][1] = r3;
                }
#pragma unroll
                for (int mt = 0; mt < 4; mt++)
#pragma unroll
                    for (int nt = 0; nt < 8; nt++)
                        mma_any<HALF>(acc[mt][nt], af[mt], bb[nt]);
            }
        }
        cp_wait0();
        __syncthreads();

        int rg = lane >> 2, cg = (lane & 3) * 2;
#pragma unroll
        for (int mt = 0; mt < 4; mt++) {
            int R0 = rowBase + wm * 64 + mt * 16 + rg;
#pragma unroll
            for (int nt = 0; nt < 8; nt++) {
                int C = colBase + wn * 64 + nt * 8 + cg;
                float b0 = bias ? bias[C] : 0.0f;
                float b1 = bias ? bias[C + 1] : 0.0f;
                float v00 = acc[mt][nt][0] + b0, v01 = acc[mt][nt][1] + b1;
                float v10 = acc[mt][nt][2] + b0, v11 = acc[mt][nt][3] + b1;
                if (MISH) { v00 = mishf(v00); v01 = mishf(v01); v10 = mishf(v10); v11 = mishf(v11); }
                if (SPLIT) {
                    f16 h0, l0, h1, l1;
                    split2h(v00, h0, l0); split2h(v01, h1, l1);
                    f16* row = Cs + (size_t)R0 * 2 * Ntot;
                    *(uint32_t*)&row[C] = pack2h(h0, h1);
                    *(uint32_t*)&row[Ntot + C] = pack2h(l0, l1);
                    split2h(v10, h0, l0); split2h(v11, h1, l1);
                    f16* row2 = Cs + (size_t)(R0 + 8) * 2 * Ntot;
                    *(uint32_t*)&row2[C] = pack2h(h0, h1);
                    *(uint32_t*)&row2[Ntot + C] = pack2h(l0, l1);
                } else {
                    float2 a; a.x = v00; a.y = v01;
                    float2 b; b.x = v10; b.y = v11;
                    *(float2*)&Cf[(size_t)R0 * Ntot + C] = a;
                    *(float2*)&Cf[(size_t)(R0 + 8) * Ntot + C] = b;
                }
            }
        }
    }
}

// ---------------- GRU step k==0 (h_prev == 0) ----------------
__global__ void step0_kernel(const float* __restrict__ b_n) {
    int count = g_counts[0];
    long total = (long)count * REC_D;
    long stride = (long)gridDim.x * blockDim.x;
    for (long idx = (long)blockIdx.x * blockDim.x + threadIdx.x; idx < total; idx += stride) {
        int i = (int)(idx >> 10);
        int j = (int)(idx & 1023);
        int t = g_perm[i];
        float igr = g_igates[(size_t)t * G3_D + j];
        float igz = g_igates[(size_t)t * G3_D + 1024 + j];
        float ign = g_igates[(size_t)t * G3_D + 2048 + j];
        float r = sigf(igr);
        float z = sigf(igz);
        float n = tanhf(ign + r * b_n[j]);
        g_states[(size_t)t * REC_D + j] = n - z * n;
    }
}

__global__ void fixA_kernel(const float* __restrict__ w_hh, const float* __restrict__ state) {
    if (g_flags[1]) return;
    int j = blockIdx.x * 8 + (threadIdx.x >> 5);
    int lane = threadIdx.x & 31;
    float acc = 0.0f;
    const float* wr = w_hh + (size_t)j * REC_D;
    for (int k = lane; k < REC_D; k += 32) acc += wr[k] * state[k];
#pragma unroll
    for (int o = 16; o > 0; o >>= 1) acc += __shfl_down_sync(0xffffffffu, acc, o);
    if (lane == 0) g_hg0[j] = acc;
}

__global__ void fixB_kernel(const float* __restrict__ state, const float* __restrict__ b_n) {
    if (g_flags[1]) return;
    int j = threadIdx.x;
    float igr = g_igates[j], igz = g_igates[1024 + j], ign = g_igates[2048 + j];
    float r = sigf(igr + g_hg0[j]);
    float z = sigf(igz + g_hg0[1024 + j]);
    float n = tanhf(ign + r * (g_hg0[2048 + j] + b_n[j]));
    float hp = state[j];
    g_states[j] = n + z * (hp - n);
}

// ---------------- fused tail step ----------------
__global__ void __launch_bounds__(256)
gru_tail_fused(const float* __restrict__ w_hh, const float* __restrict__ b_n, int k) {
    int count = g_counts[k];
    if (count <= 0) return;
    int base = g_offsets[k];
    int j = blockIdx.x * 8 + (threadIdx.x >> 5);
    int lane = threadIdx.x & 31;
    const float4* wrp = (const float4*)(w_hh + (size_t)j * REC_D);
    const float4* wzp = (const float4*)(w_hh + (size_t)(1024 + j) * REC_D);
    const float4* wnp = (const float4*)(w_hh + (size_t)(2048 + j) * REC_D);
    float4 wr[8], wz[8], wn[8];
#pragma unroll
    for (int q = 0; q < 8; q++) {
        wr[q] = wrp[lane + q * 32];
        wz[q] = wzp[lane + q * 32];
        wn[q] = wnp[lane + q * 32];
    }
    float bn = b_n[j];
    for (int i = 0; i < count; i++) {
        int t = g_perm[base + i];
        const float4* h = (const float4*)(g_states + (size_t)(t - 1) * REC_D);
        float aR = 0.0f, aZ = 0.0f, aN = 0.0f;
#pragma unroll
        for (int q = 0; q < 8; q++) {
            float4 hv = h[lane + q * 32];
            aR += wr[q].x * hv.x + wr[q].y * hv.y + wr[q].z * hv.z + wr[q].w * hv.w;
            aZ += wz[q].x * hv.x + wz[q].y * hv.y + wz[q].z * hv.z + wz[q].w * hv.w;
            aN += wn[q].x * hv.x + wn[q].y * hv.y + wn[q].z * hv.z + wn[q].w * hv.w;
        }
#pragma unroll
        for (int o = 16; o > 0; o >>= 1) {
            aR += __shfl_xor_sync(0xffffffffu, aR, o);
            aZ += __shfl_xor_sync(0xffffffffu, aZ, o);
            aN += __shfl_xor_sync(0xffffffffu, aN, o);
        }
        if (lane == 0) {
            float igr = g_igates[(size_t)t * G3_D + j];
            float igz = g_igates[(size_t)t * G3_D + 1024 + j];
            float ign = g_igates[(size_t)t * G3_D + 2048 + j];
            float hp = g_states[(size_t)(t - 1) * REC_D + j];
            float r = sigf(igr + aR);
            float z = sigf(igz + aZ);
            float n = tanhf(ign + r * (aN + bn));
            g_states[(size_t)t * REC_D + j] = n + z * (hp - n);
        }
    }
}

// gate math for GEMM steps (consumes g_hg)
__global__ void gru_gate(const float* __restrict__ b_n, int k) {
    int count = g_counts[k];
    int base = g_offsets[k];
    long total = (long)count * REC_D;
    long stride = (long)gridDim.x * blockDim.x;
    for (long idx = (long)blockIdx.x * blockDim.x + threadIdx.x; idx < total; idx += stride) {
        int i = (int)(idx >> 10);
        int j = (int)(idx & 1023);
        int t = g_perm[base + i];
        float hr = g_hg[(size_t)i * G3_D + j];
        float hz = g_hg[(size_t)i * G3_D + 1024 + j];
        float hn = g_hg[(size_t)i * G3_D + 2048 + j];
        float igr = g_igates[(size_t)t * G3_D + j];
        float igz = g_igates[(size_t)t * G3_D + 1024 + j];
        float ign = g_igates[(size_t)t * G3_D + 2048 + j];
        float hp = g_states[(size_t)(t - 1) * REC_D + j];
        float r = sigf(igr + hr);
        float z = sigf(igz + hz);
        float n = tanhf(ign + r * (hn + b_n[j]));
        g_states[(size_t)t * REC_D + j] = n + z * (hp - n);
    }
}

// safety net for age >= STEPS (count ~0 in practice)
__global__ void __launch_bounds__(1024)
cleanup_kernel(const float* __restrict__ w_hh, const float* __restrict__ b_n) {
    if (g_counts[STEPS] == 0) return;
    __shared__ int s_t;
    __shared__ int s_cur;
    __shared__ float sh[REC_D];
    int tid = threadIdx.x;
    if (tid == 0) s_cur = STEPS;
    __syncthreads();
    while (true) {
        if (tid == 0) {
            s_t = -1;
            for (int u = s_cur; u < T_LEN; ++u)
                if (g_age[u] >= STEPS) { s_t = u; s_cur = u + 1; break; }
        }
        __syncthreads();
        int t = s_t;
        if (t < 0) break;
        sh[tid] = g_states[(size_t)(t - 1) * REC_D + tid];
        __syncthreads();
        float aRv = 0, aZv = 0, aNv = 0;
        const float* wr = w_hh + (size_t)tid * REC_D;
        const float* wz = w_hh + (size_t)(1024 + tid) * REC_D;
        const float* wn = w_hh + (size_t)(2048 + tid) * REC_D;
        for (int kk = 0; kk < REC_D; kk++) {
            float h = sh[kk];
            aRv += wr[kk] * h; aZv += wz[kk] * h; aNv += wn[kk] * h;
        }
        float igr = g_igates[(size_t)t * G3_D + tid];
        float igz = g_igates[(size_t)t * G3_D + 1024 + tid];
        float ign = g_igates[(size_t)t * G3_D + 2048 + tid];
        float r = sigf(igr + aRv);
        float z = sigf(igz + aZv);
        float n = tanhf(ign + r * (aNv + b_n[tid]));
        float hp = sh[tid];
        g_states[(size_t)t * REC_D + tid] = n + z * (hp - n);
        __syncthreads();
    }
}

// ---------------- small head ----------------
__global__ void __launch_bounds__(192)
p3_kernel(const float* __restrict__ A, const float* __restrict__ Wt,
          const float* __restrict__ bias, float* __restrict__ out) {
    __shared__ __align__(16) float Ys[128][68];
    __shared__ float Ws[18][129];
    int tid = threadIdx.x;
    int rowBase = blockIdx.x * 64;
    int a = tid % 18, rg = tid / 18;
    float acc[8];
#pragma unroll
    for (int i = 0; i < 8; i++) acc[i] = 0.0f;

    for (int k0 = 0; k0 < MLP_D; k0 += 128) {
        __syncthreads();
        for (int l = tid; l < 18 * 128; l += 192) {
            int aa = l / 128, kk = l % 128;
            Ws[aa][kk] = Wt[(size_t)aa * MLP_D + k0 + kk];
        }
        for (int l = tid; l < 64 * 128; l += 192) {
            int r = l / 128, kk = l % 128;
            Ys[kk][r] = A[(size_t)(rowBase + r) * MLP_D + k0 + kk];
        }
        __syncthreads();
        if (tid < 144) {
#pragma unroll 4
            for (int kk = 0; kk < 128; kk++) {
                float w = Ws[a][kk];
                float4 y0 = *(const float4*)&Ys[kk][rg * 8];
                float4 y1v = *(const float4*)&Ys[kk][rg * 8 + 4];
                acc[0] += w * y0.x;  acc[1] += w * y0.y;
                acc[2] += w * y0.z;  acc[3] += w * y0.w;
                acc[4] += w * y1v.x; acc[5] += w * y1v.y;
                acc[6] += w * y1v.z; acc[7] += w * y1v.w;
            }
        }
    }
    if (tid < 144) {
        float b = bias[a];
#pragma unroll
        for (int i = 0; i < 8; i++)
            out[(size_t)(rowBase + rg * 8 + i) * ACT_D + a] = acc[i] + b;
    }
}

__global__ void copy_state_kernel(float* __restrict__ out) {
    out[threadIdx.x] = g_states[(size_t)(T_LEN - 1) * REC_D + threadIdx.x];
}

// ---------------- host ----------------
extern "C" void kernel_launch(void* const* d_in, const int* in_sizes, int n_in,
                              void* d_out, int out_size) {
    const float* x     = (const float*)d_in[0];
    const float* state = (const float*)d_in[1];
    const void*  start = d_in[2];
    const float* pre_w = (const float*)d_in[4];
    const float* pre_b = (const float*)d_in[5];
    const float* w_ih  = (const float*)d_in[6];
    const float* w_hh  = (const float*)d_in[7];
    const float* b_ih  = (const float*)d_in[8];
    const float* b_n   = (const float*)d_in[9];
    const float* p1_w  = (const float*)d_in[10];
    const float* p1_b  = (const float*)d_in[11];
    const float* p2_w  = (const float*)d_in[12];
    const float* p2_b  = (const float*)d_in[13];
    const float* p3_w  = (const float*)d_in[14];
    const float* p3_b  = (const float*)d_in[15];
    float* out = (float*)d_out;

    float *igates, *hg, *states, *y2;
    f16 *x2, *prew2, *feat2, *wih2, *p1w2, *p2w2, *states2, *y12;
    bf16 *whh3, *h3;
    int* counts_dev;
    cudaGetSymbolAddress((void**)&igates, g_igates);
    cudaGetSymbolAddress((void**)&hg, g_hg);
    cudaGetSymbolAddress((void**)&states, g_states);
    cudaGetSymbolAddress((void**)&y2, g_y2);
    cudaGetSymbolAddress((void**)&x2, g_x2);
    cudaGetSymbolAddress((void**)&prew2, g_prew2);
    cudaGetSymbolAddress((void**)&feat2, g_feat2);
    cudaGetSymbolAddress((void**)&wih2, g_wih2);
    cudaGetSymbolAddress((void**)&whh3, g_whh3);
    cudaGetSymbolAddress((void**)&p1w2, g_p1w2);
    cudaGetSymbolAddress((void**)&p2w2, g_p2w2);
    cudaGetSymbolAddress((void**)&states2, g_states2);
    cudaGetSymbolAddress((void**)&y12, g_y12);
    cudaGetSymbolAddress((void**)&h3, g_h3);
    cudaGetSymbolAddress((void**)&counts_dev, g_counts);

    cudaFuncSetAttribute(gemm_ca<1, 1, 1>, cudaFuncAttributeMaxDynamicSharedMemorySize, SMEM_GEMM);
    cudaFuncSetAttribute(gemm_ca<1, 0, 0>, cudaFuncAttributeMaxDynamicSharedMemorySize, SMEM_GEMM);
    cudaFuncSetAttribute(gemm_ca<1, 1, 0>, cudaFuncAttributeMaxDynamicSharedMemorySize, SMEM_GEMM);
    cudaFuncSetAttribute(gemm_ca<0, 0, 0>, cudaFuncAttributeMaxDynamicSharedMemorySize, SMEM_GEMM);

    // segment analysis
    init_kernel<<<1, 64>>>();
    sniff_kernel<<<1, 256>>>((const unsigned char*)start);
    age_kernel<<<64, 256>>>(start);
    offsets_kernel<<<1, 1>>>();
    scatter_kernel<<<64, 256>>>();

    // conversions
    convert_w2<<<256, 256>>>(pre_w, prew2, MLP_D, OBS_D);
    convert_w2<<<2048, 256>>>(w_ih, wih2, G3_D, MLP_D);
    convert_w3<<<2048, 256>>>(w_hh, whh3, G3_D, REC_D);
    convert_w2<<<1024, 256>>>(p1_w, p1w2, MLP_D, REC_D);
    convert_w2<<<1024, 256>>>(p2_w, p2w2, MLP_D, MLP_D);
    convert_a2<<<2048, 256>>>(x, x2, OBS_D);

    // feat = mish(x @ pre_w^T + pre_b)  (fp16 2-term)
    gemm_ca<1, 1, 1><<<dim3(MLP_D / 256, 128), 256, SMEM_GEMM>>>(
        (const bf16*)x2, (const bf16*)prew2, pre_b, nullptr, feat2, MLP_D, 2 * OBS_D, nullptr, T_LEN);
    // igates = feat @ w_ih^T + b_ih  (fp16 2-term)
    gemm_ca<1, 0, 0><<<dim3(G3_D / 256, 128), 256, SMEM_GEMM>>>(
        (const bf16*)feat2, (const bf16*)wih2, b_ih, igates, nullptr, G3_D, 2 * MLP_D, nullptr, T_LEN);

    // segment-parallel GRU scan (hh GEMMs stay bf16 3-term)
    step0_kernel<<<2048, 256>>>(b_n);
    fixA_kernel<<<384, 256>>>(w_hh, state);
    fixB_kernel<<<1, 1024>>>(state, b_n);
    for (int k = 1; k < GEMM_STEPS; k++) {
        int est = T_LEN >> k;
        int gy = est / 128; if (gy < 1) gy = 1; if (gy > 64) gy = 64;
        gather_h3<<<1024, 256>>>(k);
        gemm_ca<0, 0, 0><<<dim3(G3_D / 256, gy), 256, SMEM_GEMM>>>(
            h3, whh3, nullptr, hg, nullptr, G3_D, 3 * REC_D, counts_dev + k, 0);
        gru_gate<<<2048, 256>>>(b_n, k);
    }
    for (int k = GEMM_STEPS; k < STEPS; k++) {
        gru_tail_fused<<<128, 256>>>(w_hh, b_n, k);
    }
    cleanup_kernel<<<1, 1024>>>(w_hh, b_n);

    // post MLP (fp16 2-term)
    convert_a2<<<4096, 256>>>(states, states2, REC_D);
    gemm_ca<1, 1, 1><<<dim3(MLP_D / 256, 128), 256, SMEM_GEMM>>>(
        (const bf16*)states2, (const bf16*)p1w2, p1_b, nullptr, y12, MLP_D, 2 * REC_D, nullptr, T_LEN);
    gemm_ca<1, 1, 0><<<dim3(MLP_D / 256, 128), 256, SMEM_GEMM>>>(
        (const bf16*)y12, (const bf16*)p2w2, p2_b, y2, nullptr, MLP_D, 2 * MLP_D, nullptr, T_LEN);
    p3_kernel<<<T_LEN / 64, 192>>>(y2, p3_w, p3_b, out);

    if (out_size >= T_LEN * ACT_D + REC_D)
        copy_state_kernel<<<1, 1024>>>(out + (size_t)T_LEN * ACT_D);
}

// round 6
// speedup vs baseline: 2.6648x; 1.0675x over previous
#include <cuda_runtime.h>
#include <cuda_bf16.h>
#include <cuda_fp16.h>
#include <math.h>
#include <stdint.h>

#define T_LEN 16384
#define OBS_D 256
#define MLP_D 1024
#define REC_D 1024
#define G3_D  3072
#define ACT_D 18
#define STEPS 26
#define GEMM_STEPS 6
#define TAIL_BLOCKS 128

typedef __nv_bfloat16 bf16;
typedef __half f16;

// ---------------- scratch (device globals; no allocation allowed) ----------------
__device__ __align__(16) f16   g_x2[(size_t)T_LEN * 2 * OBS_D];
__device__ __align__(16) f16   g_prew2[(size_t)MLP_D * 2 * OBS_D];
__device__ __align__(16) f16   g_feat2[(size_t)T_LEN * 2 * MLP_D];
__device__ __align__(16) f16   g_wih2[(size_t)G3_D * 2 * MLP_D];
__device__ __align__(16) f16   g_whh2[(size_t)G3_D * 2 * REC_D];
__device__ __align__(16) f16   g_p1w2[(size_t)MLP_D * 2 * REC_D];
__device__ __align__(16) f16   g_p2w2[(size_t)MLP_D * 2 * MLP_D];
__device__ __align__(16) f16   g_states2[(size_t)T_LEN * 2 * REC_D];
__device__ __align__(16) f16   g_y12[(size_t)T_LEN * 2 * MLP_D];
__device__ __align__(16) f16   g_h2[(size_t)T_LEN * 2 * REC_D];
__device__ __align__(16) float g_igates[(size_t)T_LEN * G3_D];
__device__ __align__(16) float g_hg[(size_t)T_LEN * G3_D];
__device__ __align__(16) float g_states[(size_t)T_LEN * REC_D];
__device__ __align__(16) float g_y2[(size_t)T_LEN * MLP_D];
__device__ float g_hg0[G3_D];
__device__ int   g_age[T_LEN];
__device__ int   g_perm[T_LEN];
__device__ int   g_counts[STEPS + 1];
__device__ int   g_offsets[STEPS + 1];
__device__ int   g_cursor[STEPS + 1];
__device__ int   g_flags[4];
__device__ unsigned g_bar;

// ---------------- helpers ----------------
__device__ __forceinline__ float sigf(float x) { return 1.0f / (1.0f + expf(-x)); }
__device__ __forceinline__ float mishf(float x) {
    float sp = (x > 15.0f) ? x : log1pf(expf(x));
    return x * tanhf(sp);
}
__device__ __forceinline__ void split2h(float v, f16& hi, f16& lo) {
    hi = __float2half(v);
    lo = __float2half(v - __half2float(hi));
}
__device__ __forceinline__ uint32_t smem_u32(const void* p) {
    return (uint32_t)__cvta_generic_to_shared(p);
}
__device__ __forceinline__ uint32_t pack2h(f16 a, f16 b) {
    __half2 t; t.x = a; t.y = b;
    return *(uint32_t*)&t;
}
// write h value into both fp32 state and fp16 split state
__device__ __forceinline__ void store_state(int t, int j, float v) {
    g_states[(size_t)t * REC_D + j] = v;
    f16 hi, lo; split2h(v, hi, lo);
    g_states2[(size_t)t * 2 * REC_D + j] = hi;
    g_states2[(size_t)t * 2 * REC_D + REC_D + j] = lo;
}

// ---------------- async / mma primitives (plain compute_100-legal) ----------------
__device__ __forceinline__ void cpasync16(uint32_t sa, const void* ga) {
    asm volatile("cp.async.cg.shared.global [%0], [%1], 16;" :: "r"(sa), "l"(ga));
}
__device__ __forceinline__ void cp_commit() { asm volatile("cp.async.commit_group;" ::: "memory"); }
__device__ __forceinline__ void cp_wait2() { asm volatile("cp.async.wait_group 2;" ::: "memory"); }
__device__ __forceinline__ void cp_wait0() { asm volatile("cp.async.wait_group 0;" ::: "memory"); }

__device__ __forceinline__ void ldmx4(uint32_t addr, uint32_t& r0, uint32_t& r1, uint32_t& r2, uint32_t& r3) {
    asm volatile("ldmatrix.sync.aligned.m8n8.x4.shared.b16 {%0,%1,%2,%3}, [%4];"
                 : "=r"(r0), "=r"(r1), "=r"(r2), "=r"(r3) : "r"(addr));
}
__device__ __forceinline__ void mma_h(float* c, const uint32_t* a, const uint32_t* b) {
    asm volatile("mma.sync.aligned.m16n8k16.row.col.f32.f16.f16.f32 "
                 "{%0,%1,%2,%3}, {%4,%5,%6,%7}, {%8,%9}, {%0,%1,%2,%3};"
                 : "+f"(c[0]), "+f"(c[1]), "+f"(c[2]), "+f"(c[3])
                 : "r"(a[0]), "r"(a[1]), "r"(a[2]), "r"(a[3]), "r"(b[0]), "r"(b[1]));
}

// ---------------- setup kernels ----------------
__global__ void init_kernel() {
    int t = threadIdx.x;
    if (t < STEPS + 1) { g_counts[t] = 0; g_cursor[t] = 0; }
    if (t < 4) g_flags[t] = 0;
    if (t == 0) g_bar = 0;
}

__global__ void sniff_kernel(const unsigned char* __restrict__ p) {
    __shared__ int s_nz[4];
    int tid = threadIdx.x;
    if (tid < 4) s_nz[tid] = 0;
    __syncthreads();
    int cnt = 0;
    for (int i = tid; i < T_LEN; i += blockDim.x) cnt += (p[i] != 0);
    atomicAdd(&s_nz[tid & 3], cnt);
    __syncthreads();
    if (tid == 0) {
        int rest = s_nz[1] + s_nz[2] + s_nz[3];
        int mode;
        if (rest > 0) mode = (s_nz[0] == 0) ? 2 : 0;
        else          mode = (s_nz[0] > 0) ? 1 : 0;
        g_flags[0] = mode;
        bool s0;
        if (mode == 0)      s0 = p[0] != 0;
        else if (mode == 1) s0 = ((const int*)p)[0] != 0;
        else                s0 = ((const float*)p)[0] != 0.0f;
        g_flags[1] = s0 ? 1 : 0;
    }
}

__device__ __forceinline__ bool start_val(const void* p, int mode, int u) {
    if (mode == 0) return ((const unsigned char*)p)[u] != 0;
    if (mode == 1) return ((const int*)p)[u] != 0;
    return ((const float*)p)[u] != 0.0f;
}

__global__ void age_kernel(const void* __restrict__ startp) {
    int mode = g_flags[0];
    int stride = gridDim.x * blockDim.x;
    for (int t = blockIdx.x * blockDim.x + threadIdx.x; t < T_LEN; t += stride) {
        int k = 0, tt = t;
        while (tt > 0 && !start_val(startp, mode, tt)) { tt--; k++; }
        g_age[t] = k;
        int b = k < STEPS ? k : STEPS;
        atomicAdd(&g_counts[b], 1);
    }
}

__global__ void offsets_kernel() {
    if (threadIdx.x == 0 && blockIdx.x == 0) {
        int acc = 0;
        for (int b = 0; b <= STEPS; b++) { g_offsets[b] = acc; acc += g_counts[b]; }
    }
}

__global__ void scatter_kernel() {
    int stride = gridDim.x * blockDim.x;
    for (int t = blockIdx.x * blockDim.x + threadIdx.x; t < T_LEN; t += stride) {
        int a = g_age[t];
        int b = a < STEPS ? a : STEPS;
        int pos = g_offsets[b] + atomicAdd(&g_cursor[b], 1);
        g_perm[pos] = t;
    }
}

// ---------------- conversions ----------------
// weights: [N][K] fp32 -> [N][2K] fp16 as [hi | hi]
__global__ void convert_w2(const float* __restrict__ src, f16* __restrict__ dst, int N, int K) {
    size_t total = (size_t)N * K;
    size_t stride = (size_t)gridDim.x * blockDim.x;
    for (size_t idx = (size_t)blockIdx.x * blockDim.x + threadIdx.x; idx < total; idx += stride) {
        int r = (int)(idx / K), c = (int)(idx % K);
        f16 h = __float2half(src[idx]);
        f16* row = dst + (size_t)r * 2 * K;
        row[c] = h; row[K + c] = h;
    }
}
// activations: [T][K] fp32 -> [T][2K] fp16 as [hi | lo]
__global__ void convert_a2(const float* __restrict__ src, f16* __restrict__ dst, int K) {
    size_t total = (size_t)T_LEN * K;
    size_t stride = (size_t)gridDim.x * blockDim.x;
    for (size_t idx = (size_t)blockIdx.x * blockDim.x + threadIdx.x; idx < total; idx += stride) {
        int r = (int)(idx / K), c = (int)(idx % K);
        f16 hi, lo; split2h(src[idx], hi, lo);
        f16* row = dst + (size_t)r * 2 * K;
        row[c] = hi; row[K + c] = lo;
    }
}
// gather h_{t-1} rows -> fp16 split A: [hi | lo]
__global__ void gather_h2(int k) {
    int count = g_counts[k];
    int base = g_offsets[k];
    size_t total = (size_t)count * REC_D;
    size_t stride = (size_t)gridDim.x * blockDim.x;
    for (size_t idx = (size_t)blockIdx.x * blockDim.x + threadIdx.x; idx < total; idx += stride) {
        int i = (int)(idx >> 10);
        int c = (int)(idx & 1023);
        int t = g_perm[base + i];
        f16 hi, lo; split2h(g_states[(size_t)(t - 1) * REC_D + c], hi, lo);
        f16* row = g_h2 + (size_t)i * 2 * REC_D;
        row[c] = hi; row[REC_D + c] = lo;
    }
}

// ---------------- mma.sync GEMM with cp.async pipeline ----------------
// C[M,Ntot] = act(A[M,K2] @ B[Ntot,K2]^T + bias). Tile 128x256, BK=32, 4 stages.
#define STG_A_SZ 8192
#define STG_B_SZ 16384
#define STG_SZ (STG_A_SZ + STG_B_SZ)
#define NSTG 4
#define SMEM_GEMM (NSTG * STG_SZ)

__device__ __forceinline__ uint32_t swz(uint32_t base, int r, int seg) {
    return base + r * 64 + 16 * (seg ^ ((r >> 1) & 3));
}

__device__ __forceinline__ void load_stage(const f16* __restrict__ A, const f16* __restrict__ B,
                                           int rowBase, int colBase, int K2, int chunk,
                                           uint32_t sA, uint32_t sB, int tid) {
    const f16* Ab = A + (size_t)rowBase * K2 + chunk * 32;
    const f16* Bb = B + (size_t)colBase * K2 + chunk * 32;
#pragma unroll
    for (int i = 0; i < 2; i++) {
        int o = tid + i * 256;
        int r = o >> 2, seg = o & 3;
        cpasync16(swz(sA, r, seg), Ab + (size_t)r * K2 + seg * 8);
    }
#pragma unroll
    for (int i = 0; i < 4; i++) {
        int o = tid + i * 256;
        int r = o >> 2, seg = o & 3;
        cpasync16(swz(sB, r, seg), Bb + (size_t)r * K2 + seg * 8);
    }
}

template <int MISH, int SPLIT>
__global__ void __launch_bounds__(256)
gemm_ca(const f16* __restrict__ A, const f16* __restrict__ B,
        const float* __restrict__ bias, float* __restrict__ Cf, f16* __restrict__ Cs,
        int Ntot, int K2, const int* __restrict__ Mptr, int Mfix) {
    extern __shared__ __align__(16) char dsm[];
    int tid = threadIdx.x, wid = tid >> 5, lane = tid & 31;
    int wm = wid >> 2, wn = wid & 3;
    int M = Mptr ? *Mptr : Mfix;
    int colBase = blockIdx.x * 256;
    int NC = K2 >> 5;
    uint32_t sbase = smem_u32(dsm);

    for (int mtile = blockIdx.y; mtile * 128 < M; mtile += gridDim.y) {
        int rowBase = mtile * 128;
        float acc[4][8][4];
#pragma unroll
        for (int mt = 0; mt < 4; mt++)
#pragma unroll
            for (int nt = 0; nt < 8; nt++)
#pragma unroll
                for (int q = 0; q < 4; q++) acc[mt][nt][q] = 0.0f;

#pragma unroll
        for (int p = 0; p < 3; p++) {
            uint32_t sg = sbase + p * STG_SZ;
            load_stage(A, B, rowBase, colBase, K2, p, sg, sg + STG_A_SZ, tid);
            cp_commit();
        }

        for (int c = 0; c < NC; c++) {
            cp_wait2();
            __syncthreads();
            if (c + 3 < NC) {
                int s = (c + 3) & 3;
                uint32_t sg = sbase + s * STG_SZ;
                load_stage(A, B, rowBase, colBase, K2, c + 3, sg, sg + STG_A_SZ, tid);
            }
            cp_commit();

            uint32_t sA = sbase + (c & 3) * STG_SZ;
            uint32_t sB = sA + STG_A_SZ;
#pragma unroll
            for (int kk2 = 0; kk2 < 2; kk2++) {
                int seg = kk2 * 2 + (lane >> 4);
                uint32_t af[4][4];
#pragma unroll
                for (int mt = 0; mt < 4; mt++) {
                    int r = wm * 64 + mt * 16 + (lane & 15);
                    ldmx4(swz(sA, r, seg), af[mt][0], af[mt][1], af[mt][2], af[mt][3]);
                }
                uint32_t bb[8][2];
#pragma unroll
                for (int nb = 0; nb < 4; nb++) {
                    int r = wn * 64 + nb * 16 + (lane & 15);
                    uint32_t r0, r1, r2, r3;
                    ldmx4(swz(sB, r, seg), r0, r1, r2, r3);
                    bb[2 * nb][0] = r0;     bb[2 * nb][1] = r2;
                    bb[2 * nb + 1][0] = r1; bb[2 * nb + 1][1] = r3;
                }
#pragma unroll
                for (int mt = 0; mt < 4; mt++)
#pragma unroll
                    for (int nt = 0; nt < 8; nt++)
                        mma_h(acc[mt][nt], af[mt], bb[nt]);
            }
        }
        cp_wait0();
        __syncthreads();

        int rg = lane >> 2, cg = (lane & 3) * 2;
#pragma unroll
        for (int mt = 0; mt < 4; mt++) {
            int R0 = rowBase + wm * 64 + mt * 16 + rg;
#pragma unroll
            for (int nt = 0; nt < 8; nt++) {
                int C = colBase + wn * 64 + nt * 8 + cg;
                float b0 = bias ? bias[C] : 0.0f;
                float b1 = bias ? bias[C + 1] : 0.0f;
                float v00 = acc[mt][nt][0] + b0, v01 = acc[mt][nt][1] + b1;
                float v10 = acc[mt][nt][2] + b0, v11 = acc[mt][nt][3] + b1;
                if (MISH) { v00 = mishf(v00); v01 = mishf(v01); v10 = mishf(v10); v11 = mishf(v11); }
                if (SPLIT) {
                    f16 h0, l0, h1, l1;
                    split2h(v00, h0, l0); split2h(v01, h1, l1);
                    f16* row = Cs + (size_t)R0 * 2 * Ntot;
                    *(uint32_t*)&row[C] = pack2h(h0, h1);
                    *(uint32_t*)&row[Ntot + C] = pack2h(l0, l1);
                    split2h(v10, h0, l0); split2h(v11, h1, l1);
                    f16* row2 = Cs + (size_t)(R0 + 8) * 2 * Ntot;
                    *(uint32_t*)&row2[C] = pack2h(h0, h1);
                    *(uint32_t*)&row2[Ntot + C] = pack2h(l0, l1);
                } else {
                    float2 a; a.x = v00; a.y = v01;
                    float2 b; b.x = v10; b.y = v11;
                    *(float2*)&Cf[(size_t)R0 * Ntot + C] = a;
                    *(float2*)&Cf[(size_t)(R0 + 8) * Ntot + C] = b;
                }
            }
        }
    }
}

// ---------------- GRU step k==0 (h_prev == 0) ----------------
__global__ void step0_kernel(const float* __restrict__ b_n) {
    int count = g_counts[0];
    long total = (long)count * REC_D;
    long stride = (long)gridDim.x * blockDim.x;
    for (long idx = (long)blockIdx.x * blockDim.x + threadIdx.x; idx < total; idx += stride) {
        int i = (int)(idx >> 10);
        int j = (int)(idx & 1023);
        int t = g_perm[i];
        float igr = g_igates[(size_t)t * G3_D + j];
        float igz = g_igates[(size_t)t * G3_D + 1024 + j];
        float ign = g_igates[(size_t)t * G3_D + 2048 + j];
        float r = sigf(igr);
        float z = sigf(igz);
        float n = tanhf(ign + r * b_n[j]);
        store_state(t, j, n - z * n);
    }
}

__global__ void fixA_kernel(const float* __restrict__ w_hh, const float* __restrict__ state) {
    if (g_flags[1]) return;
    int j = blockIdx.x * 8 + (threadIdx.x >> 5);
    int lane = threadIdx.x & 31;
    float acc = 0.0f;
    const float* wr = w_hh + (size_t)j * REC_D;
    for (int k = lane; k < REC_D; k += 32) acc += wr[k] * state[k];
#pragma unroll
    for (int o = 16; o > 0; o >>= 1) acc += __shfl_down_sync(0xffffffffu, acc, o);
    if (lane == 0) g_hg0[j] = acc;
}

__global__ void fixB_kernel(const float* __restrict__ state, const float* __restrict__ b_n) {
    if (g_flags[1]) return;
    int j = threadIdx.x;
    float igr = g_igates[j], igz = g_igates[1024 + j], ign = g_igates[2048 + j];
    float r = sigf(igr + g_hg0[j]);
    float z = sigf(igz + g_hg0[1024 + j]);
    float n = tanhf(ign + r * (g_hg0[2048 + j] + b_n[j]));
    float hp = state[j];
    store_state(0, j, n + z * (hp - n));
}

// gate math for GEMM steps (consumes g_hg)
__global__ void gru_gate(const float* __restrict__ b_n, int k) {
    int count = g_counts[k];
    int base = g_offsets[k];
    long total = (long)count * REC_D;
    long stride = (long)gridDim.x * blockDim.x;
    for (long idx = (long)blockIdx.x * blockDim.x + threadIdx.x; idx < total; idx += stride) {
        int i = (int)(idx >> 10);
        int j = (int)(idx & 1023);
        int t = g_perm[base + i];
        float hr = g_hg[(size_t)i * G3_D + j];
        float hz = g_hg[(size_t)i * G3_D + 1024 + j];
        float hn = g_hg[(size_t)i * G3_D + 2048 + j];
        float igr = g_igates[(size_t)t * G3_D + j];
        float igz = g_igates[(size_t)t * G3_D + 1024 + j];
        float ign = g_igates[(size_t)t * G3_D + 2048 + j];
        float hp = g_states[(size_t)(t - 1) * REC_D + j];
        float r = sigf(igr + hr);
        float z = sigf(igz + hz);
        float n = tanhf(ign + r * (hn + b_n[j]));
        store_state(t, j, n + z * (hp - n));
    }
}

// ---------------- persistent tail: steps GEMM_STEPS..STEPS-1, one launch ----------------
// 128 blocks x 256 threads = 1024 warps; warp w owns column j = w. Grid barrier between steps.
__global__ void __launch_bounds__(256)
gru_tail_persistent(const float* __restrict__ w_hh, const float* __restrict__ b_n) {
    int j = blockIdx.x * 8 + (threadIdx.x >> 5);
    int lane = threadIdx.x & 31;
    const float4* wrp = (const float4*)(w_hh + (size_t)j * REC_D);
    const float4* wzp = (const float4*)(w_hh + (size_t)(1024 + j) * REC_D);
    const float4* wnp = (const float4*)(w_hh + (size_t)(2048 + j) * REC_D);
    float4 wr[8], wz[8], wn[8];
#pragma unroll
    for (int q = 0; q < 8; q++) {
        wr[q] = wrp[lane + q * 32];
        wz[q] = wzp[lane + q * 32];
        wn[q] = wnp[lane + q * 32];
    }
    float bn = b_n[j];
    unsigned nb = gridDim.x;
    unsigned bc = 0;

    for (int k = GEMM_STEPS; k < STEPS; k++) {
        int count = g_counts[k];
        int base = g_offsets[k];
        for (int i = 0; i < count; i++) {
            int t = g_perm[base + i];
            const float4* h = (const float4*)(g_states + (size_t)(t - 1) * REC_D);
            float aR = 0.0f, aZ = 0.0f, aN = 0.0f;
#pragma unroll
            for (int q = 0; q < 8; q++) {
                float4 hv = __ldcg(&h[lane + q * 32]);   // L2 read: coherent across blocks
                aR += wr[q].x * hv.x + wr[q].y * hv.y + wr[q].z * hv.z + wr[q].w * hv.w;
                aZ += wz[q].x * hv.x + wz[q].y * hv.y + wz[q].z * hv.z + wz[q].w * hv.w;
                aN += wn[q].x * hv.x + wn[q].y * hv.y + wn[q].z * hv.z + wn[q].w * hv.w;
            }
#pragma unroll
            for (int o = 16; o > 0; o >>= 1) {
                aR += __shfl_xor_sync(0xffffffffu, aR, o);
                aZ += __shfl_xor_sync(0xffffffffu, aZ, o);
                aN += __shfl_xor_sync(0xffffffffu, aN, o);
            }
            if (lane == 0) {
                float igr = g_igates[(size_t)t * G3_D + j];
                float igz = g_igates[(size_t)t * G3_D + 1024 + j];
                float ign = g_igates[(size_t)t * G3_D + 2048 + j];
                float hp = g_states[(size_t)(t - 1) * REC_D + j];
                float r = sigf(igr + aR);
                float z = sigf(igz + aZ);
                float n = tanhf(ign + r * (aN + bn));
                store_state(t, j, n + z * (hp - n));
            }
        }
        // grid barrier (all TAIL_BLOCKS co-resident: grid <= SM count)
        bc++;
        __syncthreads();
        if (threadIdx.x == 0) {
            __threadfence();
            atomicAdd(&g_bar, 1u);
            while (*((volatile unsigned*)&g_bar) < bc * nb) {}
        }
        __syncthreads();
    }
}

// safety net for age >= STEPS (count ~0 in practice)
__global__ void __launch_bounds__(1024)
cleanup_kernel(const float* __restrict__ w_hh, const float* __restrict__ b_n) {
    if (g_counts[STEPS] == 0) return;
    __shared__ int s_t;
    __shared__ int s_cur;
    __shared__ float sh[REC_D];
    int tid = threadIdx.x;
    if (tid == 0) s_cur = STEPS;
    __syncthreads();
    while (true) {
        if (tid == 0) {
            s_t = -1;
            for (int u = s_cur; u < T_LEN; ++u)
                if (g_age[u] >= STEPS) { s_t = u; s_cur = u + 1; break; }
        }
        __syncthreads();
        int t = s_t;
        if (t < 0) break;
        sh[tid] = g_states[(size_t)(t - 1) * REC_D + tid];
        __syncthreads();
        float aRv = 0, aZv = 0, aNv = 0;
        const float* wr = w_hh + (size_t)tid * REC_D;
        const float* wz = w_hh + (size_t)(1024 + tid) * REC_D;
        const float* wn = w_hh + (size_t)(2048 + tid) * REC_D;
        for (int kk = 0; kk < REC_D; kk++) {
            float h = sh[kk];
            aRv += wr[kk] * h; aZv += wz[kk] * h; aNv += wn[kk] * h;
        }
        float igr = g_igates[(size_t)t * G3_D + tid];
        float igz = g_igates[(size_t)t * G3_D + 1024 + tid];
        float ign = g_igates[(size_t)t * G3_D + 2048 + tid];
        float r = sigf(igr + aRv);
        float z = sigf(igz + aZv);
        float n = tanhf(ign + r * (aNv + b_n[tid]));
        float hp = sh[tid];
        store_state(t, tid, n + z * (hp - n));
        __syncthreads();
    }
}

// ---------------- small head ----------------
__global__ void __launch_bounds__(192)
p3_kernel(const float* __restrict__ A, const float* __restrict__ Wt,
          const float* __restrict__ bias, float* __restrict__ out) {
    __shared__ __align__(16) float Ys[128][68];
    __shared__ float Ws[18][129];
    int tid = threadIdx.x;
    int rowBase = blockIdx.x * 64;
    int a = tid % 18, rg = tid / 18;
    float acc[8];
#pragma unroll
    for (int i = 0; i < 8; i++) acc[i] = 0.0f;

    for (int k0 = 0; k0 < MLP_D; k0 += 128) {
        __syncthreads();
        for (int l = tid; l < 18 * 128; l += 192) {
            int aa = l / 128, kk = l % 128;
            Ws[aa][kk] = Wt[(size_t)aa * MLP_D + k0 + kk];
        }
        for (int l = tid; l < 64 * 128; l += 192) {
            int r = l / 128, kk = l % 128;
            Ys[kk][r] = A[(size_t)(rowBase + r) * MLP_D + k0 + kk];
        }
        __syncthreads();
        if (tid < 144) {
#pragma unroll 4
            for (int kk = 0; kk < 128; kk++) {
                float w = Ws[a][kk];
                float4 y0 = *(const float4*)&Ys[kk][rg * 8];
                float4 y1v = *(const float4*)&Ys[kk][rg * 8 + 4];
                acc[0] += w * y0.x;  acc[1] += w * y0.y;
                acc[2] += w * y0.z;  acc[3] += w * y0.w;
                acc[4] += w * y1v.x; acc[5] += w * y1v.y;
                acc[6] += w * y1v.z; acc[7] += w * y1v.w;
            }
        }
    }
    if (tid < 144) {
        float b = bias[a];
#pragma unroll
        for (int i = 0; i < 8; i++)
            out[(size_t)(rowBase + rg * 8 + i) * ACT_D + a] = acc[i] + b;
    }
}

__global__ void copy_state_kernel(float* __restrict__ out) {
    out[threadIdx.x] = g_states[(size_t)(T_LEN - 1) * REC_D + threadIdx.x];
}

// ---------------- host ----------------
extern "C" void kernel_launch(void* const* d_in, const int* in_sizes, int n_in,
                              void* d_out, int out_size) {
    const float* x     = (const float*)d_in[0];
    const float* state = (const float*)d_in[1];
    const void*  start = d_in[2];
    const float* pre_w = (const float*)d_in[4];
    const float* pre_b = (const float*)d_in[5];
    const float* w_ih  = (const float*)d_in[6];
    const float* w_hh  = (const float*)d_in[7];
    const float* b_ih  = (const float*)d_in[8];
    const float* b_n   = (const float*)d_in[9];
    const float* p1_w  = (const float*)d_in[10];
    const float* p1_b  = (const float*)d_in[11];
    const float* p2_w  = (const float*)d_in[12];
    const float* p2_b  = (const float*)d_in[13];
    const float* p3_w  = (const float*)d_in[14];
    const float* p3_b  = (const float*)d_in[15];
    float* out = (float*)d_out;

    float *igates, *hg, *states, *y2;
    f16 *x2, *prew2, *feat2, *wih2, *whh2, *p1w2, *p2w2, *states2, *y12, *h2;
    int* counts_dev;
    cudaGetSymbolAddress((void**)&igates, g_igates);
    cudaGetSymbolAddress((void**)&hg, g_hg);
    cudaGetSymbolAddress((void**)&states, g_states);
    cudaGetSymbolAddress((void**)&y2, g_y2);
    cudaGetSymbolAddress((void**)&x2, g_x2);
    cudaGetSymbolAddress((void**)&prew2, g_prew2);
    cudaGetSymbolAddress((void**)&feat2, g_feat2);
    cudaGetSymbolAddress((void**)&wih2, g_wih2);
    cudaGetSymbolAddress((void**)&whh2, g_whh2);
    cudaGetSymbolAddress((void**)&p1w2, g_p1w2);
    cudaGetSymbolAddress((void**)&p2w2, g_p2w2);
    cudaGetSymbolAddress((void**)&states2, g_states2);
    cudaGetSymbolAddress((void**)&y12, g_y12);
    cudaGetSymbolAddress((void**)&h2, g_h2);
    cudaGetSymbolAddress((void**)&counts_dev, g_counts);

    cudaFuncSetAttribute(gemm_ca<1, 1>, cudaFuncAttributeMaxDynamicSharedMemorySize, SMEM_GEMM);
    cudaFuncSetAttribute(gemm_ca<0, 0>, cudaFuncAttributeMaxDynamicSharedMemorySize, SMEM_GEMM);
    cudaFuncSetAttribute(gemm_ca<1, 0>, cudaFuncAttributeMaxDynamicSharedMemorySize, SMEM_GEMM);

    // segment analysis
    init_kernel<<<1, 64>>>();
    sniff_kernel<<<1, 256>>>((const unsigned char*)start);
    age_kernel<<<64, 256>>>(start);
    offsets_kernel<<<1, 1>>>();
    scatter_kernel<<<64, 256>>>();

    // conversions (all fp16 2-term now)
    convert_w2<<<256, 256>>>(pre_w, prew2, MLP_D, OBS_D);
    convert_w2<<<2048, 256>>>(w_ih, wih2, G3_D, MLP_D);
    convert_w2<<<2048, 256>>>(w_hh, whh2, G3_D, REC_D);
    convert_w2<<<1024, 256>>>(p1_w, p1w2, MLP_D, REC_D);
    convert_w2<<<1024, 256>>>(p2_w, p2w2, MLP_D, MLP_D);
    convert_a2<<<2048, 256>>>(x, x2, OBS_D);

    // feat = mish(x @ pre_w^T + pre_b)
    gemm_ca<1, 1><<<dim3(MLP_D / 256, 128), 256, SMEM_GEMM>>>(
        x2, prew2, pre_b, nullptr, feat2, MLP_D, 2 * OBS_D, nullptr, T_LEN);
    // igates = feat @ w_ih^T + b_ih
    gemm_ca<0, 0><<<dim3(G3_D / 256, 128), 256, SMEM_GEMM>>>(
        feat2, wih2, b_ih, igates, nullptr, G3_D, 2 * MLP_D, nullptr, T_LEN);

    // segment-parallel GRU scan
    step0_kernel<<<2048, 256>>>(b_n);
    fixA_kernel<<<384, 256>>>(w_hh, state);
    fixB_kernel<<<1, 1024>>>(state, b_n);
    for (int k = 1; k < GEMM_STEPS; k++) {
        int est = T_LEN >> k;
        int gy = est / 128; if (gy < 1) gy = 1; if (gy > 64) gy = 64;
        gather_h2<<<1024, 256>>>(k);
        gemm_ca<0, 0><<<dim3(G3_D / 256, gy), 256, SMEM_GEMM>>>(
            h2, whh2, nullptr, hg, nullptr, G3_D, 2 * REC_D, counts_dev + k, 0);
        gru_gate<<<2048, 256>>>(b_n, k);
    }
    gru_tail_persistent<<<TAIL_BLOCKS, 256>>>(w_hh, b_n);
    cleanup_kernel<<<1, 1024>>>(w_hh, b_n);

    // post MLP (states2 written directly by gate kernels)
    gemm_ca<1, 1><<<dim3(MLP_D / 256, 128), 256, SMEM_GEMM>>>(
        states2, p1w2, p1_b, nullptr, y12, MLP_D, 2 * REC_D, nullptr, T_LEN);
    gemm_ca<1, 0><<<dim3(MLP_D / 256, 128), 256, SMEM_GEMM>>>(
        y12, p2w2, p2_b, y2, nullptr, MLP_D, 2 * MLP_D, nullptr, T_LEN);
    p3_kernel<<<T_LEN / 64, 192>>>(y2, p3_w, p3_b, out);

    if (out_size >= T_LEN * ACT_D + REC_D)
        copy_state_kernel<<<1, 1024>>>(out + (size_t)T_LEN * ACT_D);
}

// round 7
// speedup vs baseline: 3.9269x; 1.4736x over previous
#include <cuda_runtime.h>
#include <cuda_fp16.h>
#include <math.h>
#include <stdint.h>

#define T_LEN 16384
#define OBS_D 256
#define MLP_D 1024
#define REC_D 1024
#define G3_D  3072
#define ACT_D 18
#define STEPS 26
#define GEMM_STEPS 6
#define TAIL_BLOCKS 128

typedef __half f16;

// ---------------- scratch (device globals; no allocation allowed) ----------------
__device__ __align__(16) f16   g_x2[(size_t)T_LEN * OBS_D];
__device__ __align__(16) f16   g_prew2[(size_t)MLP_D * OBS_D];
__device__ __align__(16) f16   g_feat2[(size_t)T_LEN * MLP_D];
__device__ __align__(16) f16   g_wih2[(size_t)G3_D * MLP_D];
__device__ __align__(16) f16   g_whh2[(size_t)G3_D * REC_D];
__device__ __align__(16) f16   g_p1w2[(size_t)MLP_D * REC_D];
__device__ __align__(16) f16   g_p2w2[(size_t)MLP_D * MLP_D];
__device__ __align__(16) f16   g_states2[(size_t)T_LEN * REC_D];
__device__ __align__(16) f16   g_y12[(size_t)T_LEN * MLP_D];
__device__ __align__(16) f16   g_h2[(size_t)T_LEN * REC_D];
__device__ __align__(16) float g_igates[(size_t)T_LEN * G3_D];
__device__ __align__(16) float g_hg[(size_t)T_LEN * G3_D];
__device__ __align__(16) float g_states[(size_t)T_LEN * REC_D];
__device__ __align__(16) float g_y2[(size_t)T_LEN * MLP_D];
__device__ float g_hg0[G3_D];
__device__ int   g_age[T_LEN];
__device__ int   g_perm[T_LEN];
__device__ int   g_counts[STEPS + 1];
__device__ int   g_offsets[STEPS + 1];
__device__ int   g_cursor[STEPS + 1];
__device__ int   g_flags[4];
__device__ unsigned g_bar;

// ---------------- helpers ----------------
__device__ __forceinline__ float sigf(float x) { return 1.0f / (1.0f + expf(-x)); }
__device__ __forceinline__ float mishf(float x) {
    float sp = (x > 15.0f) ? x : log1pf(expf(x));
    return x * tanhf(sp);
}
__device__ __forceinline__ uint32_t smem_u32(const void* p) {
    return (uint32_t)__cvta_generic_to_shared(p);
}
__device__ __forceinline__ uint32_t pack2h(f16 a, f16 b) {
    __half2 t; t.x = a; t.y = b;
    return *(uint32_t*)&t;
}
// write h value into fp32 state + fp16 state
__device__ __forceinline__ void store_state(int t, int j, float v) {
    g_states[(size_t)t * REC_D + j] = v;
    g_states2[(size_t)t * REC_D + j] = __float2half(v);
}

// ---------------- async / mma primitives (plain compute_100-legal) ----------------
__device__ __forceinline__ void cpasync16(uint32_t sa, const void* ga) {
    asm volatile("cp.async.cg.shared.global [%0], [%1], 16;" :: "r"(sa), "l"(ga));
}
__device__ __forceinline__ void cp_commit() { asm volatile("cp.async.commit_group;" ::: "memory"); }
__device__ __forceinline__ void cp_wait2() { asm volatile("cp.async.wait_group 2;" ::: "memory"); }
__device__ __forceinline__ void cp_wait0() { asm volatile("cp.async.wait_group 0;" ::: "memory"); }

__device__ __forceinline__ void ldmx4(uint32_t addr, uint32_t& r0, uint32_t& r1, uint32_t& r2, uint32_t& r3) {
    asm volatile("ldmatrix.sync.aligned.m8n8.x4.shared.b16 {%0,%1,%2,%3}, [%4];"
                 : "=r"(r0), "=r"(r1), "=r"(r2), "=r"(r3) : "r"(addr));
}
__device__ __forceinline__ void mma_h(float* c, const uint32_t* a, const uint32_t* b) {
    asm volatile("mma.sync.aligned.m16n8k16.row.col.f32.f16.f16.f32 "
                 "{%0,%1,%2,%3}, {%4,%5,%6,%7}, {%8,%9}, {%0,%1,%2,%3};"
                 : "+f"(c[0]), "+f"(c[1]), "+f"(c[2]), "+f"(c[3])
                 : "r"(a[0]), "r"(a[1]), "r"(a[2]), "r"(a[3]), "r"(b[0]), "r"(b[1]));
}

// ---------------- setup kernels ----------------
__global__ void init_kernel() {
    int t = threadIdx.x;
    if (t < STEPS + 1) { g_counts[t] = 0; g_cursor[t] = 0; }
    if (t < 4) g_flags[t] = 0;
    if (t == 0) g_bar = 0;
}

__global__ void sniff_kernel(const unsigned char* __restrict__ p) {
    __shared__ int s_nz[4];
    int tid = threadIdx.x;
    if (tid < 4) s_nz[tid] = 0;
    __syncthreads();
    int cnt = 0;
    for (int i = tid; i < T_LEN; i += blockDim.x) cnt += (p[i] != 0);
    atomicAdd(&s_nz[tid & 3], cnt);
    __syncthreads();
    if (tid == 0) {
        int rest = s_nz[1] + s_nz[2] + s_nz[3];
        int mode;
        if (rest > 0) mode = (s_nz[0] == 0) ? 2 : 0;
        else          mode = (s_nz[0] > 0) ? 1 : 0;
        g_flags[0] = mode;
        bool s0;
        if (mode == 0)      s0 = p[0] != 0;
        else if (mode == 1) s0 = ((const int*)p)[0] != 0;
        else                s0 = ((const float*)p)[0] != 0.0f;
        g_flags[1] = s0 ? 1 : 0;
    }
}

__device__ __forceinline__ bool start_val(const void* p, int mode, int u) {
    if (mode == 0) return ((const unsigned char*)p)[u] != 0;
    if (mode == 1) return ((const int*)p)[u] != 0;
    return ((const float*)p)[u] != 0.0f;
}

__global__ void age_kernel(const void* __restrict__ startp) {
    int mode = g_flags[0];
    int stride = gridDim.x * blockDim.x;
    for (int t = blockIdx.x * blockDim.x + threadIdx.x; t < T_LEN; t += stride) {
        int k = 0, tt = t;
        while (tt > 0 && !start_val(startp, mode, tt)) { tt--; k++; }
        g_age[t] = k;
        int b = k < STEPS ? k : STEPS;
        atomicAdd(&g_counts[b], 1);
    }
}

__global__ void offsets_kernel() {
    if (threadIdx.x == 0 && blockIdx.x == 0) {
        int acc = 0;
        for (int b = 0; b <= STEPS; b++) { g_offsets[b] = acc; acc += g_counts[b]; }
    }
}

__global__ void scatter_kernel() {
    int stride = gridDim.x * blockDim.x;
    for (int t = blockIdx.x * blockDim.x + threadIdx.x; t < T_LEN; t += stride) {
        int a = g_age[t];
        int b = a < STEPS ? a : STEPS;
        int pos = g_offsets[b] + atomicAdd(&g_cursor[b], 1);
        g_perm[pos] = t;
    }
}

// ---------------- conversions (plain fp16) ----------------
__global__ void convert_f16(const float* __restrict__ src, f16* __restrict__ dst, size_t total) {
    size_t stride = (size_t)gridDim.x * blockDim.x;
    for (size_t idx = (size_t)blockIdx.x * blockDim.x + threadIdx.x; idx < total; idx += stride)
        dst[idx] = __float2half(src[idx]);
}
// gather h_{t-1} rows -> fp16 A matrix
__global__ void gather_h2(int k) {
    int count = g_counts[k];
    int base = g_offsets[k];
    size_t total = (size_t)count * REC_D;
    size_t stride = (size_t)gridDim.x * blockDim.x;
    for (size_t idx = (size_t)blockIdx.x * blockDim.x + threadIdx.x; idx < total; idx += stride) {
        int i = (int)(idx >> 10);
        int c = (int)(idx & 1023);
        int t = g_perm[base + i];
        g_h2[(size_t)i * REC_D + c] = g_states2[(size_t)(t - 1) * REC_D + c];
    }
}

// ---------------- mma.sync GEMM with cp.async pipeline ----------------
// C[M,Ntot] = act(A[M,K] @ B[Ntot,K]^T + bias). Tile 128x256, BK=32, 4 stages.
#define STG_A_SZ 8192
#define STG_B_SZ 16384
#define STG_SZ (STG_A_SZ + STG_B_SZ)
#define NSTG 4
#define SMEM_GEMM (NSTG * STG_SZ)

__device__ __forceinline__ uint32_t swz(uint32_t base, int r, int seg) {
    return base + r * 64 + 16 * (seg ^ ((r >> 1) & 3));
}

__device__ __forceinline__ void load_stage(const f16* __restrict__ A, const f16* __restrict__ B,
                                           int rowBase, int colBase, int K, int chunk,
                                           uint32_t sA, uint32_t sB, int tid) {
    const f16* Ab = A + (size_t)rowBase * K + chunk * 32;
    const f16* Bb = B + (size_t)colBase * K + chunk * 32;
#pragma unroll
    for (int i = 0; i < 2; i++) {
        int o = tid + i * 256;
        int r = o >> 2, seg = o & 3;
        cpasync16(swz(sA, r, seg), Ab + (size_t)r * K + seg * 8);
    }
#pragma unroll
    for (int i = 0; i < 4; i++) {
        int o = tid + i * 256;
        int r = o >> 2, seg = o & 3;
        cpasync16(swz(sB, r, seg), Bb + (size_t)r * K + seg * 8);
    }
}

template <int MISH, int HALFOUT>
__global__ void __launch_bounds__(256)
gemm_ca(const f16* __restrict__ A, const f16* __restrict__ B,
        const float* __restrict__ bias, float* __restrict__ Cf, f16* __restrict__ Cs,
        int Ntot, int K, const int* __restrict__ Mptr, int Mfix) {
    extern __shared__ __align__(16) char dsm[];
    int tid = threadIdx.x, wid = tid >> 5, lane = tid & 31;
    int wm = wid >> 2, wn = wid & 3;
    int M = Mptr ? *Mptr : Mfix;
    int colBase = blockIdx.x * 256;
    int NC = K >> 5;
    uint32_t sbase = smem_u32(dsm);

    for (int mtile = blockIdx.y; mtile * 128 < M; mtile += gridDim.y) {
        int rowBase = mtile * 128;
        float acc[4][8][4];
#pragma unroll
        for (int mt = 0; mt < 4; mt++)
#pragma unroll
            for (int nt = 0; nt < 8; nt++)
#pragma unroll
                for (int q = 0; q < 4; q++) acc[mt][nt][q] = 0.0f;

#pragma unroll
        for (int p = 0; p < 3; p++) {
            uint32_t sg = sbase + p * STG_SZ;
            load_stage(A, B, rowBase, colBase, K, p, sg, sg + STG_A_SZ, tid);
            cp_commit();
        }

        for (int c = 0; c < NC; c++) {
            cp_wait2();
            __syncthreads();
            if (c + 3 < NC) {
                int s = (c + 3) & 3;
                uint32_t sg = sbase + s * STG_SZ;
                load_stage(A, B, rowBase, colBase, K, c + 3, sg, sg + STG_A_SZ, tid);
            }
            cp_commit();

            uint32_t sA = sbase + (c & 3) * STG_SZ;
            uint32_t sB = sA + STG_A_SZ;
#pragma unroll
            for (int kk2 = 0; kk2 < 2; kk2++) {
                int seg = kk2 * 2 + (lane >> 4);
                uint32_t af[4][4];
#pragma unroll
                for (int mt = 0; mt < 4; mt++) {
                    int r = wm * 64 + mt * 16 + (lane & 15);
                    ldmx4(swz(sA, r, seg), af[mt][0], af[mt][1], af[mt][2], af[mt][3]);
                }
                uint32_t bb[8][2];
#pragma unroll
                for (int nb = 0; nb < 4; nb++) {
                    int r = wn * 64 + nb * 16 + (lane & 15);
                    uint32_t r0, r1, r2, r3;
                    ldmx4(swz(sB, r, seg), r0, r1, r2, r3);
                    bb[2 * nb][0] = r0;     bb[2 * nb][1] = r2;
                    bb[2 * nb + 1][0] = r1; bb[2 * nb + 1][1] = r3;
                }
#pragma unroll
                for (int mt = 0; mt < 4; mt++)
#pragma unroll
                    for (int nt = 0; nt < 8; nt++)
                        mma_h(acc[mt][nt], af[mt], bb[nt]);
            }
        }
        cp_wait0();
        __syncthreads();

        int rg = lane >> 2, cg = (lane & 3) * 2;
#pragma unroll
        for (int mt = 0; mt < 4; mt++) {
            int R0 = rowBase + wm * 64 + mt * 16 + rg;
#pragma unroll
            for (int nt = 0; nt < 8; nt++) {
                int C = colBase + wn * 64 + nt * 8 + cg;
                float b0 = bias ? bias[C] : 0.0f;
                float b1 = bias ? bias[C + 1] : 0.0f;
                float v00 = acc[mt][nt][0] + b0, v01 = acc[mt][nt][1] + b1;
                float v10 = acc[mt][nt][2] + b0, v11 = acc[mt][nt][3] + b1;
                if (MISH) { v00 = mishf(v00); v01 = mishf(v01); v10 = mishf(v10); v11 = mishf(v11); }
                if (HALFOUT) {
                    *(uint32_t*)&Cs[(size_t)R0 * Ntot + C] =
                        pack2h(__float2half(v00), __float2half(v01));
                    *(uint32_t*)&Cs[(size_t)(R0 + 8) * Ntot + C] =
                        pack2h(__float2half(v10), __float2half(v11));
                } else {
                    float2 a; a.x = v00; a.y = v01;
                    float2 b; b.x = v10; b.y = v11;
                    *(float2*)&Cf[(size_t)R0 * Ntot + C] = a;
                    *(float2*)&Cf[(size_t)(R0 + 8) * Ntot + C] = b;
                }
            }
        }
    }
}

// ---------------- GRU step k==0 (h_prev == 0) ----------------
__global__ void step0_kernel(const float* __restrict__ b_n) {
    int count = g_counts[0];
    long total = (long)count * REC_D;
    long stride = (long)gridDim.x * blockDim.x;
    for (long idx = (long)blockIdx.x * blockDim.x + threadIdx.x; idx < total; idx += stride) {
        int i = (int)(idx >> 10);
        int j = (int)(idx & 1023);
        int t = g_perm[i];
        float igr = g_igates[(size_t)t * G3_D + j];
        float igz = g_igates[(size_t)t * G3_D + 1024 + j];
        float ign = g_igates[(size_t)t * G3_D + 2048 + j];
        float r = sigf(igr);
        float z = sigf(igz);
        float n = tanhf(ign + r * b_n[j]);
        store_state(t, j, n - z * n);
    }
}

__global__ void fixA_kernel(const float* __restrict__ w_hh, const float* __restrict__ state) {
    if (g_flags[1]) return;
    int j = blockIdx.x * 8 + (threadIdx.x >> 5);
    int lane = threadIdx.x & 31;
    float acc = 0.0f;
    const float* wr = w_hh + (size_t)j * REC_D;
    for (int k = lane; k < REC_D; k += 32) acc += wr[k] * state[k];
#pragma unroll
    for (int o = 16; o > 0; o >>= 1) acc += __shfl_down_sync(0xffffffffu, acc, o);
    if (lane == 0) g_hg0[j] = acc;
}

__global__ void fixB_kernel(const float* __restrict__ state, const float* __restrict__ b_n) {
    if (g_flags[1]) return;
    int j = threadIdx.x;
    float igr = g_igates[j], igz = g_igates[1024 + j], ign = g_igates[2048 + j];
    float r = sigf(igr + g_hg0[j]);
    float z = sigf(igz + g_hg0[1024 + j]);
    float n = tanhf(ign + r * (g_hg0[2048 + j] + b_n[j]));
    float hp = state[j];
    store_state(0, j, n + z * (hp - n));
}

// gate math for GEMM steps (consumes g_hg)
__global__ void gru_gate(const float* __restrict__ b_n, int k) {
    int count = g_counts[k];
    int base = g_offsets[k];
    long total = (long)count * REC_D;
    long stride = (long)gridDim.x * blockDim.x;
    for (long idx = (long)blockIdx.x * blockDim.x + threadIdx.x; idx < total; idx += stride) {
        int i = (int)(idx >> 10);
        int j = (int)(idx & 1023);
        int t = g_perm[base + i];
        float hr = g_hg[(size_t)i * G3_D + j];
        float hz = g_hg[(size_t)i * G3_D + 1024 + j];
        float hn = g_hg[(size_t)i * G3_D + 2048 + j];
        float igr = g_igates[(size_t)t * G3_D + j];
        float igz = g_igates[(size_t)t * G3_D + 1024 + j];
        float ign = g_igates[(size_t)t * G3_D + 2048 + j];
        float hp = g_states[(size_t)(t - 1) * REC_D + j];
        float r = sigf(igr + hr);
        float z = sigf(igz + hz);
        float n = tanhf(ign + r * (hn + b_n[j]));
        store_state(t, j, n + z * (hp - n));
    }
}

// ---------------- persistent tail: steps GEMM_STEPS..STEPS-1, one launch ----------------
__global__ void __launch_bounds__(256)
gru_tail_persistent(const float* __restrict__ w_hh, const float* __restrict__ b_n) {
    int j = blockIdx.x * 8 + (threadIdx.x >> 5);
    int lane = threadIdx.x & 31;
    const float4* wrp = (const float4*)(w_hh + (size_t)j * REC_D);
    const float4* wzp = (const float4*)(w_hh + (size_t)(1024 + j) * REC_D);
    const float4* wnp = (const float4*)(w_hh + (size_t)(2048 + j) * REC_D);
    float4 wr[8], wz[8], wn[8];
#pragma unroll
    for (int q = 0; q < 8; q++) {
        wr[q] = wrp[lane + q * 32];
        wz[q] = wzp[lane + q * 32];
        wn[q] = wnp[lane + q * 32];
    }
    float bn = b_n[j];
    unsigned nb = gridDim.x;
    unsigned bc = 0;

    for (int k = GEMM_STEPS; k < STEPS; k++) {
        int count = g_counts[k];
        int base = g_offsets[k];
        for (int i = 0; i < count; i++) {
            int t = g_perm[base + i];
            const float4* h = (const float4*)(g_states + (size_t)(t - 1) * REC_D);
            float aR = 0.0f, aZ = 0.0f, aN = 0.0f;
#pragma unroll
            for (int q = 0; q < 8; q++) {
                float4 hv = __ldcg(&h[lane + q * 32]);
                aR += wr[q].x * hv.x + wr[q].y * hv.y + wr[q].z * hv.z + wr[q].w * hv.w;
                aZ += wz[q].x * hv.x + wz[q].y * hv.y + wz[q].z * hv.z + wz[q].w * hv.w;
                aN += wn[q].x * hv.x + wn[q].y * hv.y + wn[q].z * hv.z + wn[q].w * hv.w;
            }
#pragma unroll
            for (int o = 16; o > 0; o >>= 1) {
                aR += __shfl_xor_sync(0xffffffffu, aR, o);
                aZ += __shfl_xor_sync(0xffffffffu, aZ, o);
                aN += __shfl_xor_sync(0xffffffffu, aN, o);
            }
            if (lane == 0) {
                float igr = g_igates[(size_t)t * G3_D + j];
                float igz = g_igates[(size_t)t * G3_D + 1024 + j];
                float ign = g_igates[(size_t)t * G3_D + 2048 + j];
                float hp = g_states[(size_t)(t - 1) * REC_D + j];
                float r = sigf(igr + aR);
                float z = sigf(igz + aZ);
                float n = tanhf(ign + r * (aN + bn));
                store_state(t, j, n + z * (hp - n));
            }
        }
        bc++;
        __syncthreads();
        if (threadIdx.x == 0) {
            __threadfence();
            atomicAdd(&g_bar, 1u);
            while (*((volatile unsigned*)&g_bar) < bc * nb) {}
        }
        __syncthreads();
    }
}

// safety net for age >= STEPS (count ~0 in practice)
__global__ void __launch_bounds__(1024)
cleanup_kernel(const float* __restrict__ w_hh, const float* __restrict__ b_n) {
    if (g_counts[STEPS] == 0) return;
    __shared__ int s_t;
    __shared__ int s_cur;
    __shared__ float sh[REC_D];
    int tid = threadIdx.x;
    if (tid == 0) s_cur = STEPS;
    __syncthreads();
    while (true) {
        if (tid == 0) {
            s_t = -1;
            for (int u = s_cur; u < T_LEN; ++u)
                if (g_age[u] >= STEPS) { s_t = u; s_cur = u + 1; break; }
        }
        __syncthreads();
        int t = s_t;
        if (t < 0) break;
        sh[tid] = g_states[(size_t)(t - 1) * REC_D + tid];
        __syncthreads();
        float aRv = 0, aZv = 0, aNv = 0;
        const float* wr = w_hh + (size_t)tid * REC_D;
        const float* wz = w_hh + (size_t)(1024 + tid) * REC_D;
        const float* wn = w_hh + (size_t)(2048 + tid) * REC_D;
        for (int kk = 0; kk < REC_D; kk++) {
            float h = sh[kk];
            aRv += wr[kk] * h; aZv += wz[kk] * h; aNv += wn[kk] * h;
        }
        float igr = g_igates[(size_t)t * G3_D + tid];
        float igz = g_igates[(size_t)t * G3_D + 1024 + tid];
        float ign = g_igates[(size_t)t * G3_D + 2048 + tid];
        float r = sigf(igr + aRv);
        float z = sigf(igz + aZv);
        float n = tanhf(ign + r * (aNv + b_n[tid]));
        float hp = sh[tid];
        store_state(t, tid, n + z * (hp - n));
        __syncthreads();
    }
}

// ---------------- small head ----------------
__global__ void __launch_bounds__(192)
p3_kernel(const float* __restrict__ A, const float* __restrict__ Wt,
          const float* __restrict__ bias, float* __restrict__ out) {
    __shared__ __align__(16) float Ys[128][68];
    __shared__ float Ws[18][129];
    int tid = threadIdx.x;
    int rowBase = blockIdx.x * 64;
    int a = tid % 18, rg = tid / 18;
    float acc[8];
#pragma unroll
    for (int i = 0; i < 8; i++) acc[i] = 0.0f;

    for (int k0 = 0; k0 < MLP_D; k0 += 128) {
        __syncthreads();
        for (int l = tid; l < 18 * 128; l += 192) {
            int aa = l / 128, kk = l % 128;
            Ws[aa][kk] = Wt[(size_t)aa * MLP_D + k0 + kk];
        }
        for (int l = tid; l < 64 * 128; l += 192) {
            int r = l / 128, kk = l % 128;
            Ys[kk][r] = A[(size_t)(rowBase + r) * MLP_D + k0 + kk];
        }
        __syncthreads();
        if (tid < 144) {
#pragma unroll 4
            for (int kk = 0; kk < 128; kk++) {
                float w = Ws[a][kk];
                float4 y0 = *(const float4*)&Ys[kk][rg * 8];
                float4 y1v = *(const float4*)&Ys[kk][rg * 8 + 4];
                acc[0] += w * y0.x;  acc[1] += w * y0.y;
                acc[2] += w * y0.z;  acc[3] += w * y0.w;
                acc[4] += w * y1v.x; acc[5] += w * y1v.y;
                acc[6] += w * y1v.z; acc[7] += w * y1v.w;
            }
        }
    }
    if (tid < 144) {
        float b = bias[a];
#pragma unroll
        for (int i = 0; i < 8; i++)
            out[(size_t)(rowBase + rg * 8 + i) * ACT_D + a] = acc[i] + b;
    }
}

__global__ void copy_state_kernel(float* __restrict__ out) {
    out[threadIdx.x] = g_states[(size_t)(T_LEN - 1) * REC_D + threadIdx.x];
}

// ---------------- host ----------------
extern "C" void kernel_launch(void* const* d_in, const int* in_sizes, int n_in,
                              void* d_out, int out_size) {
    const float* x     = (const float*)d_in[0];
    const float* state = (const float*)d_in[1];
    const void*  start = d_in[2];
    const float* pre_w = (const float*)d_in[4];
    const float* pre_b = (const float*)d_in[5];
    const float* w_ih  = (const float*)d_in[6];
    const float* w_hh  = (const float*)d_in[7];
    const float* b_ih  = (const float*)d_in[8];
    const float* b_n   = (const float*)d_in[9];
    const float* p1_w  = (const float*)d_in[10];
    const float* p1_b  = (const float*)d_in[11];
    const float* p2_w  = (const float*)d_in[12];
    const float* p2_b  = (const float*)d_in[13];
    const float* p3_w  = (const float*)d_in[14];
    const float* p3_b  = (const float*)d_in[15];
    float* out = (float*)d_out;

    float *igates, *hg, *states, *y2;
    f16 *x2, *prew2, *feat2, *wih2, *whh2, *p1w2, *p2w2, *states2, *y12, *h2;
    int* counts_dev;
    cudaGetSymbolAddress((void**)&igates, g_igates);
    cudaGetSymbolAddress((void**)&hg, g_hg);
    cudaGetSymbolAddress((void**)&states, g_states);
    cudaGetSymbolAddress((void**)&y2, g_y2);
    cudaGetSymbolAddress((void**)&x2, g_x2);
    cudaGetSymbolAddress((void**)&prew2, g_prew2);
    cudaGetSymbolAddress((void**)&feat2, g_feat2);
    cudaGetSymbolAddress((void**)&wih2, g_wih2);
    cudaGetSymbolAddress((void**)&whh2, g_whh2);
    cudaGetSymbolAddress((void**)&p1w2, g_p1w2);
    cudaGetSymbolAddress((void**)&p2w2, g_p2w2);
    cudaGetSymbolAddress((void**)&states2, g_states2);
    cudaGetSymbolAddress((void**)&y12, g_y12);
    cudaGetSymbolAddress((void**)&h2, g_h2);
    cudaGetSymbolAddress((void**)&counts_dev, g_counts);

    cudaFuncSetAttribute(gemm_ca<1, 1>, cudaFuncAttributeMaxDynamicSharedMemorySize, SMEM_GEMM);
    cudaFuncSetAttribute(gemm_ca<0, 0>, cudaFuncAttributeMaxDynamicSharedMemorySize, SMEM_GEMM);
    cudaFuncSetAttribute(gemm_ca<1, 0>, cudaFuncAttributeMaxDynamicSharedMemorySize, SMEM_GEMM);

    // segment analysis
    init_kernel<<<1, 64>>>();
    sniff_kernel<<<1, 256>>>((const unsigned char*)start);
    age_kernel<<<64, 256>>>(start);
    offsets_kernel<<<1, 1>>>();
    scatter_kernel<<<64, 256>>>();

    // conversions (plain fp16)
    convert_f16<<<256, 256>>>(pre_w, prew2, (size_t)MLP_D * OBS_D);
    convert_f16<<<1024, 256>>>(w_ih, wih2, (size_t)G3_D * MLP_D);
    convert_f16<<<1024, 256>>>(w_hh, whh2, (size_t)G3_D * REC_D);
    convert_f16<<<512, 256>>>(p1_w, p1w2, (size_t)MLP_D * REC_D);
    convert_f16<<<512, 256>>>(p2_w, p2w2, (size_t)MLP_D * MLP_D);
    convert_f16<<<1024, 256>>>(x, x2, (size_t)T_LEN * OBS_D);

    // feat = mish(x @ pre_w^T + pre_b)
    gemm_ca<1, 1><<<dim3(MLP_D / 256, 128), 256, SMEM_GEMM>>>(
        x2, prew2, pre_b, nullptr, feat2, MLP_D, OBS_D, nullptr, T_LEN);
    // igates = feat @ w_ih^T + b_ih
    gemm_ca<0, 0><<<dim3(G3_D / 256, 128), 256, SMEM_GEMM>>>(
        feat2, wih2, b_ih, igates, nullptr, G3_D, MLP_D, nullptr, T_LEN);

    // segment-parallel GRU scan
    step0_kernel<<<2048, 256>>>(b_n);
    fixA_kernel<<<384, 256>>>(w_hh, state);
    fixB_kernel<<<1, 1024>>>(state, b_n);
    for (int k = 1; k < GEMM_STEPS; k++) {
        int est = T_LEN >> k;
        int gy = est / 128; if (gy < 1) gy = 1; if (gy > 64) gy = 64;
        gather_h2<<<1024, 256>>>(k);
        gemm_ca<0, 0><<<dim3(G3_D / 256, gy), 256, SMEM_GEMM>>>(
            h2, whh2, nullptr, hg, nullptr, G3_D, REC_D, counts_dev + k, 0);
        gru_gate<<<2048, 256>>>(b_n, k);
    }
    gru_tail_persistent<<<TAIL_BLOCKS, 256>>>(w_hh, b_n);
    cleanup_kernel<<<1, 1024>>>(w_hh, b_n);

    // post MLP
    gemm_ca<1, 1><<<dim3(MLP_D / 256, 128), 256, SMEM_GEMM>>>(
        states2, p1w2, p1_b, nullptr, y12, MLP_D, REC_D, nullptr, T_LEN);
    gemm_ca<1, 0><<<dim3(MLP_D / 256, 128), 256, SMEM_GEMM>>>(
        y12, p2w2, p2_b, y2, nullptr, MLP_D, MLP_D, nullptr, T_LEN);
    p3_kernel<<<T_LEN / 64, 192>>>(y2, p3_w, p3_b, out);

    if (out_size >= T_LEN * ACT_D + REC_D)
        copy_state_kernel<<<1, 1024>>>(out + (size_t)T_LEN * ACT_D);
}

// round 8
// speedup vs baseline: 4.0883x; 1.0411x over previous
#include <cuda_runtime.h>
#include <cuda_fp16.h>
#include <math.h>
#include <stdint.h>

#define T_LEN 16384
#define OBS_D 256
#define MLP_D 1024
#define REC_D 1024
#define G3_D  3072
#define ACT_D 18
#define STEPS 26
#define GEMM_STEPS 6
#define TAIL_BLOCKS 128

typedef __half f16;

// ---------------- scratch (device globals; no allocation allowed) ----------------
__device__ __align__(16) f16   g_x2[(size_t)T_LEN * OBS_D];
__device__ __align__(16) f16   g_prew2[(size_t)MLP_D * OBS_D];
__device__ __align__(16) f16   g_feat2[(size_t)T_LEN * MLP_D];
__device__ __align__(16) f16   g_wih2[(size_t)G3_D * MLP_D];
__device__ __align__(16) f16   g_whh2[(size_t)G3_D * REC_D];
__device__ __align__(16) f16   g_p1w2[(size_t)MLP_D * REC_D];
__device__ __align__(16) f16   g_p2w2[(size_t)MLP_D * MLP_D];
__device__ __align__(16) f16   g_states2[(size_t)T_LEN * REC_D];
__device__ __align__(16) f16   g_y12[(size_t)T_LEN * MLP_D];
__device__ __align__(16) f16   g_h2[(size_t)T_LEN * REC_D];
__device__ __align__(16) f16   g_igates[(size_t)T_LEN * G3_D];   // fp16 now
__device__ __align__(16) f16   g_hg[(size_t)T_LEN * G3_D];       // fp16 now
__device__ __align__(16) f16   g_y2h[(size_t)T_LEN * MLP_D];     // fp16 now
__device__ __align__(16) float g_states[(size_t)T_LEN * REC_D];
__device__ float g_hg0[G3_D];
__device__ int   g_age[T_LEN];
__device__ int   g_perm[T_LEN];
__device__ int   g_counts[STEPS + 1];
__device__ int   g_offsets[STEPS + 1];
__device__ int   g_cursor[STEPS + 1];
__device__ int   g_flags[4];
__device__ unsigned g_bar;

// ---------------- helpers ----------------
__device__ __forceinline__ float sigf(float x) { return 1.0f / (1.0f + expf(-x)); }
__device__ __forceinline__ float mishf(float x) {
    float sp = (x > 15.0f) ? x : log1pf(expf(x));
    return x * tanhf(sp);
}
__device__ __forceinline__ uint32_t smem_u32(const void* p) {
    return (uint32_t)__cvta_generic_to_shared(p);
}
__device__ __forceinline__ uint32_t pack2h(f16 a, f16 b) {
    __half2 t; t.x = a; t.y = b;
    return *(uint32_t*)&t;
}
__device__ __forceinline__ void store_state(int t, int j, float v) {
    g_states[(size_t)t * REC_D + j] = v;
    g_states2[(size_t)t * REC_D + j] = __float2half(v);
}
__device__ __forceinline__ float ldh(const f16* p) { return __half2float(*p); }

// ---------------- async / mma primitives (plain compute_100-legal) ----------------
__device__ __forceinline__ void cpasync16(uint32_t sa, const void* ga) {
    asm volatile("cp.async.cg.shared.global [%0], [%1], 16;" :: "r"(sa), "l"(ga));
}
__device__ __forceinline__ void cp_commit() { asm volatile("cp.async.commit_group;" ::: "memory"); }
__device__ __forceinline__ void cp_wait2() { asm volatile("cp.async.wait_group 2;" ::: "memory"); }
__device__ __forceinline__ void cp_wait0() { asm volatile("cp.async.wait_group 0;" ::: "memory"); }

__device__ __forceinline__ void ldmx4(uint32_t addr, uint32_t& r0, uint32_t& r1, uint32_t& r2, uint32_t& r3) {
    asm volatile("ldmatrix.sync.aligned.m8n8.x4.shared.b16 {%0,%1,%2,%3}, [%4];"
                 : "=r"(r0), "=r"(r1), "=r"(r2), "=r"(r3) : "r"(addr));
}
__device__ __forceinline__ void mma_h(float* c, const uint32_t* a, const uint32_t* b) {
    asm volatile("mma.sync.aligned.m16n8k16.row.col.f32.f16.f16.f32 "
                 "{%0,%1,%2,%3}, {%4,%5,%6,%7}, {%8,%9}, {%0,%1,%2,%3};"
                 : "+f"(c[0]), "+f"(c[1]), "+f"(c[2]), "+f"(c[3])
                 : "r"(a[0]), "r"(a[1]), "r"(a[2]), "r"(a[3]), "r"(b[0]), "r"(b[1]));
}

// ---------------- setup kernels ----------------
__global__ void init_kernel() {
    int t = threadIdx.x;
    if (t < STEPS + 1) { g_counts[t] = 0; g_cursor[t] = 0; }
    if (t < 4) g_flags[t] = 0;
    if (t == 0) g_bar = 0;
}

__global__ void sniff_kernel(const unsigned char* __restrict__ p) {
    __shared__ int s_nz[4];
    int tid = threadIdx.x;
    if (tid < 4) s_nz[tid] = 0;
    __syncthreads();
    int cnt = 0;
    for (int i = tid; i < T_LEN; i += blockDim.x) cnt += (p[i] != 0);
    atomicAdd(&s_nz[tid & 3], cnt);
    __syncthreads();
    if (tid == 0) {
        int rest = s_nz[1] + s_nz[2] + s_nz[3];
        int mode;
        if (rest > 0) mode = (s_nz[0] == 0) ? 2 : 0;
        else          mode = (s_nz[0] > 0) ? 1 : 0;
        g_flags[0] = mode;
        bool s0;
        if (mode == 0)      s0 = p[0] != 0;
        else if (mode == 1) s0 = ((const int*)p)[0] != 0;
        else                s0 = ((const float*)p)[0] != 0.0f;
        g_flags[1] = s0 ? 1 : 0;
    }
}

__device__ __forceinline__ bool start_val(const void* p, int mode, int u) {
    if (mode == 0) return ((const unsigned char*)p)[u] != 0;
    if (mode == 1) return ((const int*)p)[u] != 0;
    return ((const float*)p)[u] != 0.0f;
}

__global__ void age_kernel(const void* __restrict__ startp) {
    int mode = g_flags[0];
    int stride = gridDim.x * blockDim.x;
    for (int t = blockIdx.x * blockDim.x + threadIdx.x; t < T_LEN; t += stride) {
        int k = 0, tt = t;
        while (tt > 0 && !start_val(startp, mode, tt)) { tt--; k++; }
        g_age[t] = k;
        int b = k < STEPS ? k : STEPS;
        atomicAdd(&g_counts[b], 1);
    }
}

__global__ void offsets_kernel() {
    if (threadIdx.x == 0 && blockIdx.x == 0) {
        int acc = 0;
        for (int b = 0; b <= STEPS; b++) { g_offsets[b] = acc; acc += g_counts[b]; }
    }
}

__global__ void scatter_kernel() {
    int stride = gridDim.x * blockDim.x;
    for (int t = blockIdx.x * blockDim.x + threadIdx.x; t < T_LEN; t += stride) {
        int a = g_age[t];
        int b = a < STEPS ? a : STEPS;
        int pos = g_offsets[b] + atomicAdd(&g_cursor[b], 1);
        g_perm[pos] = t;
    }
}

// ---------------- merged fp32->fp16 conversions (one launch) ----------------
__global__ void conv_all(const float* s0, f16* d0, size_t n0,
                         const float* s1, f16* d1, size_t n1,
                         const float* s2, f16* d2, size_t n2,
                         const float* s3, f16* d3, size_t n3,
                         const float* s4, f16* d4, size_t n4,
                         const float* s5, f16* d5, size_t n5) {
    size_t stride = (size_t)gridDim.x * blockDim.x;
    size_t i0 = (size_t)blockIdx.x * blockDim.x + threadIdx.x;
    for (size_t i = i0; i < n0; i += stride) d0[i] = __float2half(s0[i]);
    for (size_t i = i0; i < n1; i += stride) d1[i] = __float2half(s1[i]);
    for (size_t i = i0; i < n2; i += stride) d2[i] = __float2half(s2[i]);
    for (size_t i = i0; i < n3; i += stride) d3[i] = __float2half(s3[i]);
    for (size_t i = i0; i < n4; i += stride) d4[i] = __float2half(s4[i]);
    for (size_t i = i0; i < n5; i += stride) d5[i] = __float2half(s5[i]);
}

// gather h_{t-1} rows -> fp16 A matrix
__global__ void gather_h2(int k) {
    int count = g_counts[k];
    int base = g_offsets[k];
    size_t total = (size_t)count * REC_D;
    size_t stride = (size_t)gridDim.x * blockDim.x;
    for (size_t idx = (size_t)blockIdx.x * blockDim.x + threadIdx.x; idx < total; idx += stride) {
        int i = (int)(idx >> 10);
        int c = (int)(idx & 1023);
        int t = g_perm[base + i];
        g_h2[(size_t)i * REC_D + c] = g_states2[(size_t)(t - 1) * REC_D + c];
    }
}

// ---------------- mma.sync GEMM with cp.async pipeline ----------------
#define STG_A_SZ 8192
#define STG_B_SZ 16384
#define STG_SZ (STG_A_SZ + STG_B_SZ)
#define NSTG 4
#define SMEM_GEMM (NSTG * STG_SZ)

__device__ __forceinline__ uint32_t swz(uint32_t base, int r, int seg) {
    return base + r * 64 + 16 * (seg ^ ((r >> 1) & 3));
}

__device__ __forceinline__ void load_stage(const f16* __restrict__ A, const f16* __restrict__ B,
                                           int rowBase, int colBase, int K, int chunk,
                                           uint32_t sA, uint32_t sB, int tid) {
    const f16* Ab = A + (size_t)rowBase * K + chunk * 32;
    const f16* Bb = B + (size_t)colBase * K + chunk * 32;
#pragma unroll
    for (int i = 0; i < 2; i++) {
        int o = tid + i * 256;
        int r = o >> 2, seg = o & 3;
        cpasync16(swz(sA, r, seg), Ab + (size_t)r * K + seg * 8);
    }
#pragma unroll
    for (int i = 0; i < 4; i++) {
        int o = tid + i * 256;
        int r = o >> 2, seg = o & 3;
        cpasync16(swz(sB, r, seg), Bb + (size_t)r * K + seg * 8);
    }
}

template <int MISH, int HALFOUT>
__global__ void __launch_bounds__(256)
gemm_ca(const f16* __restrict__ A, const f16* __restrict__ B,
        const float* __restrict__ bias, float* __restrict__ Cf, f16* __restrict__ Cs,
        int Ntot, int K, const int* __restrict__ Mptr, int Mfix) {
    extern __shared__ __align__(16) char dsm[];
    int tid = threadIdx.x, wid = tid >> 5, lane = tid & 31;
    int wm = wid >> 2, wn = wid & 3;
    int M = Mptr ? *Mptr : Mfix;
    int colBase = blockIdx.x * 256;
    int NC = K >> 5;
    uint32_t sbase = smem_u32(dsm);

    for (int mtile = blockIdx.y; mtile * 128 < M; mtile += gridDim.y) {
        int rowBase = mtile * 128;
        float acc[4][8][4];
#pragma unroll
        for (int mt = 0; mt < 4; mt++)
#pragma unroll
            for (int nt = 0; nt < 8; nt++)
#pragma unroll
                for (int q = 0; q < 4; q++) acc[mt][nt][q] = 0.0f;

#pragma unroll
        for (int p = 0; p < 3; p++) {
            uint32_t sg = sbase + p * STG_SZ;
            load_stage(A, B, rowBase, colBase, K, p, sg, sg + STG_A_SZ, tid);
            cp_commit();
        }

        for (int c = 0; c < NC; c++) {
            cp_wait2();
            __syncthreads();
            if (c + 3 < NC) {
                int s = (c + 3) & 3;
                uint32_t sg = sbase + s * STG_SZ;
                load_stage(A, B, rowBase, colBase, K, c + 3, sg, sg + STG_A_SZ, tid);
            }
            cp_commit();

            uint32_t sA = sbase + (c & 3) * STG_SZ;
            uint32_t sB = sA + STG_A_SZ;
#pragma unroll
            for (int kk2 = 0; kk2 < 2; kk2++) {
                int seg = kk2 * 2 + (lane >> 4);
                uint32_t af[4][4];
#pragma unroll
                for (int mt = 0; mt < 4; mt++) {
                    int r = wm * 64 + mt * 16 + (lane & 15);
                    ldmx4(swz(sA, r, seg), af[mt][0], af[mt][1], af[mt][2], af[mt][3]);
                }
                uint32_t bb[8][2];
#pragma unroll
                for (int nb = 0; nb < 4; nb++) {
                    int r = wn * 64 + nb * 16 + (lane & 15);
                    uint32_t r0, r1, r2, r3;
                    ldmx4(swz(sB, r, seg), r0, r1, r2, r3);
                    bb[2 * nb][0] = r0;     bb[2 * nb][1] = r2;
                    bb[2 * nb + 1][0] = r1; bb[2 * nb + 1][1] = r3;
                }
#pragma unroll
                for (int mt = 0; mt < 4; mt++)
#pragma unroll
                    for (int nt = 0; nt < 8; nt++)
                        mma_h(acc[mt][nt], af[mt], bb[nt]);
            }
        }
        cp_wait0();
        __syncthreads();

        int rg = lane >> 2, cg = (lane & 3) * 2;
#pragma unroll
        for (int mt = 0; mt < 4; mt++) {
            int R0 = rowBase + wm * 64 + mt * 16 + rg;
#pragma unroll
            for (int nt = 0; nt < 8; nt++) {
                int C = colBase + wn * 64 + nt * 8 + cg;
                float b0 = bias ? bias[C] : 0.0f;
                float b1 = bias ? bias[C + 1] : 0.0f;
                float v00 = acc[mt][nt][0] + b0, v01 = acc[mt][nt][1] + b1;
                float v10 = acc[mt][nt][2] + b0, v11 = acc[mt][nt][3] + b1;
                if (MISH) { v00 = mishf(v00); v01 = mishf(v01); v10 = mishf(v10); v11 = mishf(v11); }
                if (HALFOUT) {
                    *(uint32_t*)&Cs[(size_t)R0 * Ntot + C] =
                        pack2h(__float2half(v00), __float2half(v01));
                    *(uint32_t*)&Cs[(size_t)(R0 + 8) * Ntot + C] =
                        pack2h(__float2half(v10), __float2half(v11));
                } else {
                    float2 a; a.x = v00; a.y = v01;
                    float2 b; b.x = v10; b.y = v11;
                    *(float2*)&Cf[(size_t)R0 * Ntot + C] = a;
                    *(float2*)&Cf[(size_t)(R0 + 8) * Ntot + C] = b;
                }
            }
        }
    }
}

// ---------------- GRU step k==0 (h_prev == 0) ----------------
__global__ void step0_kernel(const float* __restrict__ b_n) {
    int count = g_counts[0];
    long total = (long)count * REC_D;
    long stride = (long)gridDim.x * blockDim.x;
    for (long idx = (long)blockIdx.x * blockDim.x + threadIdx.x; idx < total; idx += stride) {
        int i = (int)(idx >> 10);
        int j = (int)(idx & 1023);
        int t = g_perm[i];
        float igr = ldh(&g_igates[(size_t)t * G3_D + j]);
        float igz = ldh(&g_igates[(size_t)t * G3_D + 1024 + j]);
        float ign = ldh(&g_igates[(size_t)t * G3_D + 2048 + j]);
        float r = sigf(igr);
        float z = sigf(igz);
        float n = tanhf(ign + r * b_n[j]);
        store_state(t, j, n - z * n);
    }
}

__global__ void fixA_kernel(const float* __restrict__ w_hh, const float* __restrict__ state) {
    if (g_flags[1]) return;
    int j = blockIdx.x * 8 + (threadIdx.x >> 5);
    int lane = threadIdx.x & 31;
    float acc = 0.0f;
    const float* wr = w_hh + (size_t)j * REC_D;
    for (int k = lane; k < REC_D; k += 32) acc += wr[k] * state[k];
#pragma unroll
    for (int o = 16; o > 0; o >>= 1) acc += __shfl_down_sync(0xffffffffu, acc, o);
    if (lane == 0) g_hg0[j] = acc;
}

__global__ void fixB_kernel(const float* __restrict__ state, const float* __restrict__ b_n) {
    if (g_flags[1]) return;
    int j = threadIdx.x;
    float igr = ldh(&g_igates[j]), igz = ldh(&g_igates[1024 + j]), ign = ldh(&g_igates[2048 + j]);
    float r = sigf(igr + g_hg0[j]);
    float z = sigf(igz + g_hg0[1024 + j]);
    float n = tanhf(ign + r * (g_hg0[2048 + j] + b_n[j]));
    float hp = state[j];
    store_state(0, j, n + z * (hp - n));
}

// gate math for GEMM steps (consumes fp16 g_hg)
__global__ void gru_gate(const float* __restrict__ b_n, int k) {
    int count = g_counts[k];
    int base = g_offsets[k];
    long total = (long)count * REC_D;
    long stride = (long)gridDim.x * blockDim.x;
    for (long idx = (long)blockIdx.x * blockDim.x + threadIdx.x; idx < total; idx += stride) {
        int i = (int)(idx >> 10);
        int j = (int)(idx & 1023);
        int t = g_perm[base + i];
        float hr = ldh(&g_hg[(size_t)i * G3_D + j]);
        float hz = ldh(&g_hg[(size_t)i * G3_D + 1024 + j]);
        float hn = ldh(&g_hg[(size_t)i * G3_D + 2048 + j]);
        float igr = ldh(&g_igates[(size_t)t * G3_D + j]);
        float igz = ldh(&g_igates[(size_t)t * G3_D + 1024 + j]);
        float ign = ldh(&g_igates[(size_t)t * G3_D + 2048 + j]);
        float hp = g_states[(size_t)(t - 1) * REC_D + j];
        float r = sigf(igr + hr);
        float z = sigf(igz + hz);
        float n = tanhf(ign + r * (hn + b_n[j]));
        store_state(t, j, n + z * (hp - n));
    }
}

// ---------------- persistent tail: SMEM-staged h, fp16 weights ----------------
__global__ void __launch_bounds__(256)
gru_tail_persistent(const float* __restrict__ b_n) {
    __shared__ __align__(16) __half2 sh[REC_D / 2];
    int wid = threadIdx.x >> 5;
    int j = blockIdx.x * 8 + wid;
    int lane = threadIdx.x & 31;
    const __half2* wr2 = (const __half2*)(g_whh2 + (size_t)j * REC_D);
    const __half2* wz2 = (const __half2*)(g_whh2 + (size_t)(1024 + j) * REC_D);
    const __half2* wn2 = (const __half2*)(g_whh2 + (size_t)(2048 + j) * REC_D);
    __half2 wr[16], wz[16], wn[16];
#pragma unroll
    for (int q = 0; q < 16; q++) {
        wr[q] = wr2[lane + q * 32];
        wz[q] = wz2[lane + q * 32];
        wn[q] = wn2[lane + q * 32];
    }
    float bn = b_n[j];
    unsigned nb = gridDim.x;
    unsigned bc = 0;

    for (int k = GEMM_STEPS; k < STEPS; k++) {
        int count = g_counts[k];
        int base = g_offsets[k];
        for (int i = 0; i < count; i++) {
            int t = g_perm[base + i];
            // cooperative load of h_{t-1} (fp16, 2 KB) into SMEM; __ldcg for cross-block coherence
            {
                const uint2* src = (const uint2*)(g_states2 + (size_t)(t - 1) * REC_D);
                uint2 v = __ldcg(&src[threadIdx.x]);
                *(uint2*)&sh[threadIdx.x * 2] = v;
            }
            __syncthreads();
            float aR = 0.0f, aZ = 0.0f, aN = 0.0f;
#pragma unroll
            for (int q = 0; q < 16; q++) {
                float2 hf = __half22float2(sh[lane + q * 32]);
                float2 rf = __half22float2(wr[q]);
                float2 zf = __half22float2(wz[q]);
                float2 nf = __half22float2(wn[q]);
                aR += rf.x * hf.x + rf.y * hf.y;
                aZ += zf.x * hf.x + zf.y * hf.y;
                aN += nf.x * hf.x + nf.y * hf.y;
            }
#pragma unroll
            for (int o = 16; o > 0; o >>= 1) {
                aR += __shfl_xor_sync(0xffffffffu, aR, o);
                aZ += __shfl_xor_sync(0xffffffffu, aZ, o);
                aN += __shfl_xor_sync(0xffffffffu, aN, o);
            }
            if (lane == 0) {
                float igr = ldh(&g_igates[(size_t)t * G3_D + j]);
                float igz = ldh(&g_igates[(size_t)t * G3_D + 1024 + j]);
                float ign = ldh(&g_igates[(size_t)t * G3_D + 2048 + j]);
                float hp = __ldcg(&g_states[(size_t)(t - 1) * REC_D + j]);
                float r = sigf(igr + aR);
                float z = sigf(igz + aZ);
                float n = tanhf(ign + r * (aN + bn));
                store_state(t, j, n + z * (hp - n));
            }
            __syncthreads();   // protect sh before next item overwrites
        }
        bc++;
        __syncthreads();
        if (threadIdx.x == 0) {
            __threadfence();
            atomicAdd(&g_bar, 1u);
            while (*((volatile unsigned*)&g_bar) < bc * nb) {}
        }
        __syncthreads();
    }
}

// safety net for age >= STEPS (count ~0 in practice)
__global__ void __launch_bounds__(1024)
cleanup_kernel(const float* __restrict__ w_hh, const float* __restrict__ b_n) {
    if (g_counts[STEPS] == 0) return;
    __shared__ int s_t;
    __shared__ int s_cur;
    __shared__ float sh[REC_D];
    int tid = threadIdx.x;
    if (tid == 0) s_cur = STEPS;
    __syncthreads();
    while (true) {
        if (tid == 0) {
            s_t = -1;
            for (int u = s_cur; u < T_LEN; ++u)
                if (g_age[u] >= STEPS) { s_t = u; s_cur = u + 1; break; }
        }
        __syncthreads();
        int t = s_t;
        if (t < 0) break;
        sh[tid] = g_states[(size_t)(t - 1) * REC_D + tid];
        __syncthreads();
        float aRv = 0, aZv = 0, aNv = 0;
        const float* wr = w_hh + (size_t)tid * REC_D;
        const float* wz = w_hh + (size_t)(1024 + tid) * REC_D;
        const float* wn = w_hh + (size_t)(2048 + tid) * REC_D;
        for (int kk = 0; kk < REC_D; kk++) {
            float h = sh[kk];
            aRv += wr[kk] * h; aZv += wz[kk] * h; aNv += wn[kk] * h;
        }
        float igr = ldh(&g_igates[(size_t)t * G3_D + tid]);
        float igz = ldh(&g_igates[(size_t)t * G3_D + 1024 + tid]);
        float ign = ldh(&g_igates[(size_t)t * G3_D + 2048 + tid]);
        float r = sigf(igr + aRv);
        float z = sigf(igz + aZv);
        float n = tanhf(ign + r * (aNv + b_n[tid]));
        float hp = sh[tid];
        store_state(t, tid, n + z * (hp - n));
        __syncthreads();
    }
}

// ---------------- small head (reads fp16 y2) ----------------
__global__ void __launch_bounds__(192)
p3_kernel(const f16* __restrict__ A, const float* __restrict__ Wt,
          const float* __restrict__ bias, float* __restrict__ out) {
    __shared__ __align__(16) float Ys[128][68];
    __shared__ float Ws[18][129];
    int tid = threadIdx.x;
    int rowBase = blockIdx.x * 64;
    int a = tid % 18, rg = tid / 18;
    float acc[8];
#pragma unroll
    for (int i = 0; i < 8; i++) acc[i] = 0.0f;

    for (int k0 = 0; k0 < MLP_D; k0 += 128) {
        __syncthreads();
        for (int l = tid; l < 18 * 128; l += 192) {
            int aa = l / 128, kk = l % 128;
            Ws[aa][kk] = Wt[(size_t)aa * MLP_D + k0 + kk];
        }
        for (int l = tid; l < 64 * 128; l += 192) {
            int r = l / 128, kk = l % 128;
            Ys[kk][r] = __half2float(A[(size_t)(rowBase + r) * MLP_D + k0 + kk]);
        }
        __syncthreads();
        if (tid < 144) {
#pragma unroll 4
            for (int kk = 0; kk < 128; kk++) {
                float w = Ws[a][kk];
                float4 y0 = *(const float4*)&Ys[kk][rg * 8];
                float4 y1v = *(const float4*)&Ys[kk][rg * 8 + 4];
                acc[0] += w * y0.x;  acc[1] += w * y0.y;
                acc[2] += w * y0.z;  acc[3] += w * y0.w;
                acc[4] += w * y1v.x; acc[5] += w * y1v.y;
                acc[6] += w * y1v.z; acc[7] += w * y1v.w;
            }
        }
    }
    if (tid < 144) {
        float b = bias[a];
#pragma unroll
        for (int i = 0; i < 8; i++)
            out[(size_t)(rowBase + rg * 8 + i) * ACT_D + a] = acc[i] + b;
    }
}

__global__ void copy_state_kernel(float* __restrict__ out) {
    out[threadIdx.x] = g_states[(size_t)(T_LEN - 1) * REC_D + threadIdx.x];
}

// ---------------- host ----------------
extern "C" void kernel_launch(void* const* d_in, const int* in_sizes, int n_in,
                              void* d_out, int out_size) {
    const float* x     = (const float*)d_in[0];
    const float* state = (const float*)d_in[1];
    const void*  start = d_in[2];
    const float* pre_w = (const float*)d_in[4];
    const float* pre_b = (const float*)d_in[5];
    const float* w_ih  = (const float*)d_in[6];
    const float* w_hh  = (const float*)d_in[7];
    const float* b_ih  = (const float*)d_in[8];
    const float* b_n   = (const float*)d_in[9];
    const float* p1_w  = (const float*)d_in[10];
    const float* p1_b  = (const float*)d_in[11];
    const float* p2_w  = (const float*)d_in[12];
    const float* p2_b  = (const float*)d_in[13];
    const float* p3_w  = (const float*)d_in[14];
    const float* p3_b  = (const float*)d_in[15];
    float* out = (float*)d_out;

    f16 *x2, *prew2, *feat2, *wih2, *whh2, *p1w2, *p2w2, *states2, *y12, *h2;
    f16 *igates, *hg, *y2h;
    int* counts_dev;
    cudaGetSymbolAddress((void**)&igates, g_igates);
    cudaGetSymbolAddress((void**)&hg, g_hg);
    cudaGetSymbolAddress((void**)&y2h, g_y2h);
    cudaGetSymbolAddress((void**)&x2, g_x2);
    cudaGetSymbolAddress((void**)&prew2, g_prew2);
    cudaGetSymbolAddress((void**)&feat2, g_feat2);
    cudaGetSymbolAddress((void**)&wih2, g_wih2);
    cudaGetSymbolAddress((void**)&whh2, g_whh2);
    cudaGetSymbolAddress((void**)&p1w2, g_p1w2);
    cudaGetSymbolAddress((void**)&p2w2, g_p2w2);
    cudaGetSymbolAddress((void**)&states2, g_states2);
    cudaGetSymbolAddress((void**)&y12, g_y12);
    cudaGetSymbolAddress((void**)&h2, g_h2);
    cudaGetSymbolAddress((void**)&counts_dev, g_counts);

    cudaFuncSetAttribute(gemm_ca<1, 1>, cudaFuncAttributeMaxDynamicSharedMemorySize, SMEM_GEMM);
    cudaFuncSetAttribute(gemm_ca<0, 1>, cudaFuncAttributeMaxDynamicSharedMemorySize, SMEM_GEMM);

    // segment analysis
    init_kernel<<<1, 64>>>();
    sniff_kernel<<<1, 256>>>((const unsigned char*)start);
    age_kernel<<<64, 256>>>(start);
    offsets_kernel<<<1, 1>>>();
    scatter_kernel<<<64, 256>>>();

    // all conversions in one launch
    conv_all<<<1024, 256>>>(pre_w, prew2, (size_t)MLP_D * OBS_D,
                            w_ih, wih2, (size_t)G3_D * MLP_D,
                            w_hh, whh2, (size_t)G3_D * REC_D,
                            p1_w, p1w2, (size_t)MLP_D * REC_D,
                            p2_w, p2w2, (size_t)MLP_D * MLP_D,
                            x, x2, (size_t)T_LEN * OBS_D);

    // feat = mish(x @ pre_w^T + pre_b)
    gemm_ca<1, 1><<<dim3(MLP_D / 256, 128), 256, SMEM_GEMM>>>(
        x2, prew2, pre_b, nullptr, feat2, MLP_D, OBS_D, nullptr, T_LEN);
    // igates = feat @ w_ih^T + b_ih  (fp16 out)
    gemm_ca<0, 1><<<dim3(G3_D / 256, 128), 256, SMEM_GEMM>>>(
        feat2, wih2, b_ih, nullptr, igates, G3_D, MLP_D, nullptr, T_LEN);

    // segment-parallel GRU scan
    step0_kernel<<<2048, 256>>>(b_n);
    fixA_kernel<<<384, 256>>>(w_hh, state);
    fixB_kernel<<<1, 1024>>>(state, b_n);
    for (int k = 1; k < GEMM_STEPS; k++) {
        int est = T_LEN >> k;
        int gy = est / 128; if (gy < 1) gy = 1; if (gy > 64) gy = 64;
        gather_h2<<<1024, 256>>>(k);
        gemm_ca<0, 1><<<dim3(G3_D / 256, gy), 256, SMEM_GEMM>>>(
            h2, whh2, nullptr, nullptr, hg, G3_D, REC_D, counts_dev + k, 0);
        gru_gate<<<2048, 256>>>(b_n, k);
    }
    gru_tail_persistent<<<TAIL_BLOCKS, 256>>>(b_n);
    cleanup_kernel<<<1, 1024>>>(w_hh, b_n);

    // post MLP
    gemm_ca<1, 1><<<dim3(MLP_D / 256, 128), 256, SMEM_GEMM>>>(
        states2, p1w2, p1_b, nullptr, y12, MLP_D, REC_D, nullptr, T_LEN);
    gemm_ca<1, 1><<<dim3(MLP_D / 256, 128), 256, SMEM_GEMM>>>(
        y12, p2w2, p2_b, nullptr, y2h, MLP_D, MLP_D, nullptr, T_LEN);
    p3_kernel<<<T_LEN / 64, 192>>>(y2h, p3_w, p3_b, out);

    if (out_size >= T_LEN * ACT_D + REC_D)
        copy_state_kernel<<<1, 1024>>>(out + (size_t)T_LEN * ACT_D);
}

// round 9
// speedup vs baseline: 4.4635x; 1.0918x over previous
#include <cuda_runtime.h>
#include <cuda_fp16.h>
#include <math.h>
#include <stdint.h>

#define T_LEN 16384
#define OBS_D 256
#define MLP_D 1024
#define REC_D 1024
#define G3_D  3072
#define ACT_D 18
#define STEPS 26
#define GEMM_STEPS 8
#define TAIL_BLOCKS 128

typedef __half f16;

// ---------------- scratch (device globals; no allocation allowed) ----------------
__device__ __align__(16) f16   g_x2[(size_t)T_LEN * OBS_D];
__device__ __align__(16) f16   g_prew2[(size_t)MLP_D * OBS_D];
__device__ __align__(16) f16   g_feat2[(size_t)T_LEN * MLP_D];
__device__ __align__(16) f16   g_wih2[(size_t)G3_D * MLP_D];
__device__ __align__(16) f16   g_whh2[(size_t)G3_D * REC_D];
__device__ __align__(16) f16   g_p1w2[(size_t)MLP_D * REC_D];
__device__ __align__(16) f16   g_p2w2[(size_t)MLP_D * MLP_D];
__device__ __align__(16) f16   g_states2[(size_t)T_LEN * REC_D];
__device__ __align__(16) f16   g_y12[(size_t)T_LEN * MLP_D];
__device__ __align__(16) f16   g_igates[(size_t)T_LEN * G3_D];
__device__ __align__(16) f16   g_hg[(size_t)T_LEN * G3_D];
__device__ __align__(16) f16   g_y2h[(size_t)T_LEN * MLP_D];
__device__ __align__(16) float g_states[(size_t)T_LEN * REC_D];
__device__ float g_hg0[G3_D];
__device__ int   g_age[T_LEN];
__device__ int   g_perm[T_LEN];
__device__ int   g_counts[STEPS + 1];
__device__ int   g_offsets[STEPS + 1];
__device__ int   g_cursor[STEPS + 1];
__device__ int   g_flags[4];
__device__ unsigned g_bar;

// ---------------- helpers ----------------
__device__ __forceinline__ float sigf(float x) { return 1.0f / (1.0f + expf(-x)); }
__device__ __forceinline__ float mishf(float x) {
    float sp = (x > 15.0f) ? x : log1pf(expf(x));
    return x * tanhf(sp);
}
__device__ __forceinline__ uint32_t smem_u32(const void* p) {
    return (uint32_t)__cvta_generic_to_shared(p);
}
__device__ __forceinline__ uint32_t pack2h(f16 a, f16 b) {
    __half2 t; t.x = a; t.y = b;
    return *(uint32_t*)&t;
}
__device__ __forceinline__ void store_state(int t, int j, float v) {
    g_states[(size_t)t * REC_D + j] = v;
    g_states2[(size_t)t * REC_D + j] = __float2half(v);
}
__device__ __forceinline__ float ldh(const f16* p) { return __half2float(*p); }

// ---------------- async / mma primitives (plain compute_100-legal) ----------------
__device__ __forceinline__ void cpasync16(uint32_t sa, const void* ga) {
    asm volatile("cp.async.cg.shared.global [%0], [%1], 16;" :: "r"(sa), "l"(ga));
}
__device__ __forceinline__ void cp_commit() { asm volatile("cp.async.commit_group;" ::: "memory"); }
__device__ __forceinline__ void cp_wait2() { asm volatile("cp.async.wait_group 2;" ::: "memory"); }
__device__ __forceinline__ void cp_wait1() { asm volatile("cp.async.wait_group 1;" ::: "memory"); }
__device__ __forceinline__ void cp_wait0() { asm volatile("cp.async.wait_group 0;" ::: "memory"); }

__device__ __forceinline__ void ldmx4(uint32_t addr, uint32_t& r0, uint32_t& r1, uint32_t& r2, uint32_t& r3) {
    asm volatile("ldmatrix.sync.aligned.m8n8.x4.shared.b16 {%0,%1,%2,%3}, [%4];"
                 : "=r"(r0), "=r"(r1), "=r"(r2), "=r"(r3) : "r"(addr));
}
__device__ __forceinline__ void mma_h(float* c, const uint32_t* a, const uint32_t* b) {
    asm volatile("mma.sync.aligned.m16n8k16.row.col.f32.f16.f16.f32 "
                 "{%0,%1,%2,%3}, {%4,%5,%6,%7}, {%8,%9}, {%0,%1,%2,%3};"
                 : "+f"(c[0]), "+f"(c[1]), "+f"(c[2]), "+f"(c[3])
                 : "r"(a[0]), "r"(a[1]), "r"(a[2]), "r"(a[3]), "r"(b[0]), "r"(b[1]));
}

// ---------------- setup kernels ----------------
__global__ void init_kernel() {
    int t = threadIdx.x;
    if (t < STEPS + 1) { g_counts[t] = 0; g_cursor[t] = 0; }
    if (t < 4) g_flags[t] = 0;
    if (t == 0) g_bar = 0;
}

__global__ void sniff_kernel(const unsigned char* __restrict__ p) {
    __shared__ int s_nz[4];
    int tid = threadIdx.x;
    if (tid < 4) s_nz[tid] = 0;
    __syncthreads();
    int cnt = 0;
    for (int i = tid; i < T_LEN; i += blockDim.x) cnt += (p[i] != 0);
    atomicAdd(&s_nz[tid & 3], cnt);
    __syncthreads();
    if (tid == 0) {
        int rest = s_nz[1] + s_nz[2] + s_nz[3];
        int mode;
        if (rest > 0) mode = (s_nz[0] == 0) ? 2 : 0;
        else          mode = (s_nz[0] > 0) ? 1 : 0;
        g_flags[0] = mode;
        bool s0;
        if (mode == 0)      s0 = p[0] != 0;
        else if (mode == 1) s0 = ((const int*)p)[0] != 0;
        else                s0 = ((const float*)p)[0] != 0.0f;
        g_flags[1] = s0 ? 1 : 0;
    }
}

__device__ __forceinline__ bool start_val(const void* p, int mode, int u) {
    if (mode == 0) return ((const unsigned char*)p)[u] != 0;
    if (mode == 1) return ((const int*)p)[u] != 0;
    return ((const float*)p)[u] != 0.0f;
}

__global__ void age_kernel(const void* __restrict__ startp) {
    int mode = g_flags[0];
    int stride = gridDim.x * blockDim.x;
    for (int t = blockIdx.x * blockDim.x + threadIdx.x; t < T_LEN; t += stride) {
        int k = 0, tt = t;
        while (tt > 0 && !start_val(startp, mode, tt)) { tt--; k++; }
        g_age[t] = k;
        int b = k < STEPS ? k : STEPS;
        atomicAdd(&g_counts[b], 1);
    }
}

__global__ void offsets_kernel() {
    if (threadIdx.x == 0 && blockIdx.x == 0) {
        int acc = 0;
        for (int b = 0; b <= STEPS; b++) { g_offsets[b] = acc; acc += g_counts[b]; }
    }
}

__global__ void scatter_kernel() {
    int stride = gridDim.x * blockDim.x;
    for (int t = blockIdx.x * blockDim.x + threadIdx.x; t < T_LEN; t += stride) {
        int a = g_age[t];
        int b = a < STEPS ? a : STEPS;
        int pos = g_offsets[b] + atomicAdd(&g_cursor[b], 1);
        g_perm[pos] = t;
    }
}

// ---------------- merged fp32->fp16 conversions (one launch) ----------------
__global__ void conv_all(const float* s0, f16* d0, size_t n0,
                         const float* s1, f16* d1, size_t n1,
                         const float* s2, f16* d2, size_t n2,
                         const float* s3, f16* d3, size_t n3,
                         const float* s4, f16* d4, size_t n4,
                         const float* s5, f16* d5, size_t n5) {
    size_t stride = (size_t)gridDim.x * blockDim.x;
    size_t i0 = (size_t)blockIdx.x * blockDim.x + threadIdx.x;
    for (size_t i = i0; i < n0; i += stride) d0[i] = __float2half(s0[i]);
    for (size_t i = i0; i < n1; i += stride) d1[i] = __float2half(s1[i]);
    for (size_t i = i0; i < n2; i += stride) d2[i] = __float2half(s2[i]);
    for (size_t i = i0; i < n3; i += stride) d3[i] = __float2half(s3[i]);
    for (size_t i = i0; i < n4; i += stride) d4[i] = __float2half(s4[i]);
    for (size_t i = i0; i < n5; i += stride) d5[i] = __float2half(s5[i]);
}

// ---------------- mma.sync GEMM with cp.async pipeline (+ optional A-gather) ----------------
#define STG_A_SZ 8192
#define STG_B_SZ 16384
#define STG_SZ (STG_A_SZ + STG_B_SZ)
#define NSTG 4
#define SMEM_GEMM (NSTG * STG_SZ)

__device__ __forceinline__ uint32_t swz(uint32_t base, int r, int seg) {
    return base + r * 64 + 16 * (seg ^ ((r >> 1) & 3));
}

template <int GATHER>
__device__ __forceinline__ void load_stage(const f16* __restrict__ A, const f16* __restrict__ B,
                                           const int* __restrict__ perm, int M,
                                           int rowBase, int colBase, int K, int chunk,
                                           uint32_t sA, uint32_t sB, int tid) {
    const f16* Bb = B + (size_t)colBase * K + chunk * 32;
#pragma unroll
    for (int i = 0; i < 2; i++) {
        int o = tid + i * 256;
        int r = o >> 2, seg = o & 3;
        const f16* src;
        if (GATHER) {
            int gi = rowBase + r;
            gi = gi < M - 1 ? gi : M - 1;
            int t = __ldg(&perm[gi]);
            src = A + (size_t)(t - 1) * K + chunk * 32 + (size_t)seg * 8;
        } else {
            src = A + (size_t)(rowBase + r) * K + chunk * 32 + (size_t)seg * 8;
        }
        cpasync16(swz(sA, r, seg), src);
    }
#pragma unroll
    for (int i = 0; i < 4; i++) {
        int o = tid + i * 256;
        int r = o >> 2, seg = o & 3;
        cpasync16(swz(sB, r, seg), Bb + (size_t)r * K + seg * 8);
    }
}

template <int MISH, int HALFOUT, int GATHER>
__global__ void __launch_bounds__(256)
gemm_ca(const f16* __restrict__ A, const f16* __restrict__ B,
        const float* __restrict__ bias, float* __restrict__ Cf, f16* __restrict__ Cs,
        int Ntot, int K, const int* __restrict__ Mptr, int Mfix, int bucketK) {
    extern __shared__ __align__(16) char dsm[];
    int tid = threadIdx.x, wid = tid >> 5, lane = tid & 31;
    int wm = wid >> 2, wn = wid & 3;
    int M = Mptr ? *Mptr : Mfix;
    const int* perm = GATHER ? (g_perm + g_offsets[bucketK]) : (const int*)0;
    int colBase = blockIdx.x * 256;
    int NC = K >> 5;
    uint32_t sbase = smem_u32(dsm);

    for (int mtile = blockIdx.y; mtile * 128 < M; mtile += gridDim.y) {
        int rowBase = mtile * 128;
        float acc[4][8][4];
#pragma unroll
        for (int mt = 0; mt < 4; mt++)
#pragma unroll
            for (int nt = 0; nt < 8; nt++)
#pragma unroll
                for (int q = 0; q < 4; q++) acc[mt][nt][q] = 0.0f;

#pragma unroll
        for (int p = 0; p < 3; p++) {
            uint32_t sg = sbase + p * STG_SZ;
            load_stage<GATHER>(A, B, perm, M, rowBase, colBase, K, p, sg, sg + STG_A_SZ, tid);
            cp_commit();
        }

        for (int c = 0; c < NC; c++) {
            cp_wait2();
            __syncthreads();
            if (c + 3 < NC) {
                int s = (c + 3) & 3;
                uint32_t sg = sbase + s * STG_SZ;
                load_stage<GATHER>(A, B, perm, M, rowBase, colBase, K, c + 3, sg, sg + STG_A_SZ, tid);
            }
            cp_commit();

            uint32_t sA = sbase + (c & 3) * STG_SZ;
            uint32_t sB = sA + STG_A_SZ;
#pragma unroll
            for (int kk2 = 0; kk2 < 2; kk2++) {
                int seg = kk2 * 2 + (lane >> 4);
                uint32_t af[4][4];
#pragma unroll
                for (int mt = 0; mt < 4; mt++) {
                    int r = wm * 64 + mt * 16 + (lane & 15);
                    ldmx4(swz(sA, r, seg), af[mt][0], af[mt][1], af[mt][2], af[mt][3]);
                }
                uint32_t bb[8][2];
#pragma unroll
                for (int nb = 0; nb < 4; nb++) {
                    int r = wn * 64 + nb * 16 + (lane & 15);
                    uint32_t r0, r1, r2, r3;
                    ldmx4(swz(sB, r, seg), r0, r1, r2, r3);
                    bb[2 * nb][0] = r0;     bb[2 * nb][1] = r2;
                    bb[2 * nb + 1][0] = r1; bb[2 * nb + 1][1] = r3;
                }
#pragma unroll
                for (int mt = 0; mt < 4; mt++)
#pragma unroll
                    for (int nt = 0; nt < 8; nt++)
                        mma_h(acc[mt][nt], af[mt], bb[nt]);
            }
        }
        cp_wait0();
        __syncthreads();

        int rg = lane >> 2, cg = (lane & 3) * 2;
#pragma unroll
        for (int mt = 0; mt < 4; mt++) {
            int R0 = rowBase + wm * 64 + mt * 16 + rg;
#pragma unroll
            for (int nt = 0; nt < 8; nt++) {
                int C = colBase + wn * 64 + nt * 8 + cg;
                float b0 = bias ? bias[C] : 0.0f;
                float b1 = bias ? bias[C + 1] : 0.0f;
                float v00 = acc[mt][nt][0] + b0, v01 = acc[mt][nt][1] + b1;
                float v10 = acc[mt][nt][2] + b0, v11 = acc[mt][nt][3] + b1;
                if (MISH) { v00 = mishf(v00); v01 = mishf(v01); v10 = mishf(v10); v11 = mishf(v11); }
                if (HALFOUT) {
                    *(uint32_t*)&Cs[(size_t)R0 * Ntot + C] =
                        pack2h(__float2half(v00), __float2half(v01));
                    *(uint32_t*)&Cs[(size_t)(R0 + 8) * Ntot + C] =
                        pack2h(__float2half(v10), __float2half(v11));
                } else {
                    float2 a; a.x = v00; a.y = v01;
                    float2 b; b.x = v10; b.y = v11;
                    *(float2*)&Cf[(size_t)R0 * Ntot + C] = a;
                    *(float2*)&Cf[(size_t)(R0 + 8) * Ntot + C] = b;
                }
            }
        }
    }
}

// ---------------- GRU step k==0 (h_prev == 0) ----------------
__global__ void step0_kernel(const float* __restrict__ b_n) {
    int count = g_counts[0];
    long total = (long)count * REC_D;
    long stride = (long)gridDim.x * blockDim.x;
    for (long idx = (long)blockIdx.x * blockDim.x + threadIdx.x; idx < total; idx += stride) {
        int i = (int)(idx >> 10);
        int j = (int)(idx & 1023);
        int t = g_perm[i];
        float igr = ldh(&g_igates[(size_t)t * G3_D + j]);
        float igz = ldh(&g_igates[(size_t)t * G3_D + 1024 + j]);
        float ign = ldh(&g_igates[(size_t)t * G3_D + 2048 + j]);
        float r = sigf(igr);
        float z = sigf(igz);
        float n = tanhf(ign + r * b_n[j]);
        store_state(t, j, n - z * n);
    }
}

__global__ void fixA_kernel(const float* __restrict__ w_hh, const float* __restrict__ state) {
    if (g_flags[1]) return;
    int j = blockIdx.x * 8 + (threadIdx.x >> 5);
    int lane = threadIdx.x & 31;
    float acc = 0.0f;
    const float* wr = w_hh + (size_t)j * REC_D;
    for (int k = lane; k < REC_D; k += 32) acc += wr[k] * state[k];
#pragma unroll
    for (int o = 16; o > 0; o >>= 1) acc += __shfl_down_sync(0xffffffffu, acc, o);
    if (lane == 0) g_hg0[j] = acc;
}

__global__ void fixB_kernel(const float* __restrict__ state, const float* __restrict__ b_n) {
    if (g_flags[1]) return;
    int j = threadIdx.x;
    float igr = ldh(&g_igates[j]), igz = ldh(&g_igates[1024 + j]), ign = ldh(&g_igates[2048 + j]);
    float r = sigf(igr + g_hg0[j]);
    float z = sigf(igz + g_hg0[1024 + j]);
    float n = tanhf(ign + r * (g_hg0[2048 + j] + b_n[j]));
    float hp = state[j];
    store_state(0, j, n + z * (hp - n));
}

// gate math for GEMM steps (consumes fp16 g_hg)
__global__ void gru_gate(const float* __restrict__ b_n, int k) {
    int count = g_counts[k];
    int base = g_offsets[k];
    long total = (long)count * REC_D;
    long stride = (long)gridDim.x * blockDim.x;
    for (long idx = (long)blockIdx.x * blockDim.x + threadIdx.x; idx < total; idx += stride) {
        int i = (int)(idx >> 10);
        int j = (int)(idx & 1023);
        int t = g_perm[base + i];
        float hr = ldh(&g_hg[(size_t)i * G3_D + j]);
        float hz = ldh(&g_hg[(size_t)i * G3_D + 1024 + j]);
        float hn = ldh(&g_hg[(size_t)i * G3_D + 2048 + j]);
        float igr = ldh(&g_igates[(size_t)t * G3_D + j]);
        float igz = ldh(&g_igates[(size_t)t * G3_D + 1024 + j]);
        float ign = ldh(&g_igates[(size_t)t * G3_D + 2048 + j]);
        float hp = g_states[(size_t)(t - 1) * REC_D + j];
        float r = sigf(igr + hr);
        float z = sigf(igz + hz);
        float n = tanhf(ign + r * (hn + b_n[j]));
        store_state(t, j, n + z * (hp - n));
    }
}

// ---------------- persistent tail: double-buffered SMEM h, fp16 weights ----------------
__device__ __forceinline__ void tail_prefetch(int t, __half2* buf, int tid) {
    if (tid < 128) {
        const char* src = (const char*)(g_states2 + (size_t)(t - 1) * REC_D) + tid * 16;
        cpasync16(smem_u32((char*)buf + tid * 16), src);
    }
}

__global__ void __launch_bounds__(256)
gru_tail_persistent(const float* __restrict__ b_n) {
    __shared__ __align__(16) __half2 sh[2][REC_D / 2];
    int tid = threadIdx.x;
    int wid = tid >> 5;
    int j = blockIdx.x * 8 + wid;
    int lane = tid & 31;
    const __half2* wr2 = (const __half2*)(g_whh2 + (size_t)j * REC_D);
    const __half2* wz2 = (const __half2*)(g_whh2 + (size_t)(1024 + j) * REC_D);
    const __half2* wn2 = (const __half2*)(g_whh2 + (size_t)(2048 + j) * REC_D);
    __half2 wr[16], wz[16], wn[16];
#pragma unroll
    for (int q = 0; q < 16; q++) {
        wr[q] = wr2[lane + q * 32];
        wz[q] = wz2[lane + q * 32];
        wn[q] = wn2[lane + q * 32];
    }
    float bn = b_n[j];
    unsigned nb = gridDim.x;
    unsigned bc = 0;

    for (int k = GEMM_STEPS; k < STEPS; k++) {
        int count = g_counts[k];
        int base = g_offsets[k];
        if (count > 0) {
            tail_prefetch(g_perm[base], sh[0], tid);
            cp_commit();
            for (int i = 0; i < count; i++) {
                if (i + 1 < count) tail_prefetch(g_perm[base + i + 1], sh[(i + 1) & 1], tid);
                cp_commit();
                if (i + 1 < count) cp_wait1(); else cp_wait0();
                __syncthreads();
                const __half2* hb = sh[i & 1];
                int t = g_perm[base + i];
                float aR = 0.0f, aZ = 0.0f, aN = 0.0f;
#pragma unroll
                for (int q = 0; q < 16; q++) {
                    float2 hf = __half22float2(hb[lane + q * 32]);
                    float2 rf = __half22float2(wr[q]);
                    float2 zf = __half22float2(wz[q]);
                    float2 nf = __half22float2(wn[q]);
                    aR += rf.x * hf.x + rf.y * hf.y;
                    aZ += zf.x * hf.x + zf.y * hf.y;
                    aN += nf.x * hf.x + nf.y * hf.y;
                }
#pragma unroll
                for (int o = 16; o > 0; o >>= 1) {
                    aR += __shfl_xor_sync(0xffffffffu, aR, o);
                    aZ += __shfl_xor_sync(0xffffffffu, aZ, o);
                    aN += __shfl_xor_sync(0xffffffffu, aN, o);
                }
                if (lane == 0) {
                    float igr = ldh(&g_igates[(size_t)t * G3_D + j]);
                    float igz = ldh(&g_igates[(size_t)t * G3_D + 1024 + j]);
                    float ign = ldh(&g_igates[(size_t)t * G3_D + 2048 + j]);
                    float hp = __ldcg(&g_states[(size_t)(t - 1) * REC_D + j]);
                    float r = sigf(igr + aR);
                    float z = sigf(igz + aZ);
                    float n = tanhf(ign + r * (aN + bn));
                    store_state(t, j, n + z * (hp - n));
                }
                __syncthreads();
            }
        }
        bc++;
        __syncthreads();
        if (tid == 0) {
            __threadfence();
            atomicAdd(&g_bar, 1u);
            while (*((volatile unsigned*)&g_bar) < bc * nb) {}
        }
        __syncthreads();
    }
}

// safety net for age >= STEPS (count ~0 in practice)
__global__ void __launch_bounds__(1024)
cleanup_kernel(const float* __restrict__ w_hh, const float* __restrict__ b_n) {
    if (g_counts[STEPS] == 0) return;
    __shared__ int s_t;
    __shared__ int s_cur;
    __shared__ float sh[REC_D];
    int tid = threadIdx.x;
    if (tid == 0) s_cur = STEPS;
    __syncthreads();
    while (true) {
        if (tid == 0) {
            s_t = -1;
            for (int u = s_cur; u < T_LEN; ++u)
                if (g_age[u] >= STEPS) { s_t = u; s_cur = u + 1; break; }
        }
        __syncthreads();
        int t = s_t;
        if (t < 0) break;
        sh[tid] = g_states[(size_t)(t - 1) * REC_D + tid];
        __syncthreads();
        float aRv = 0, aZv = 0, aNv = 0;
        const float* wr = w_hh + (size_t)tid * REC_D;
        const float* wz = w_hh + (size_t)(1024 + tid) * REC_D;
        const float* wn = w_hh + (size_t)(2048 + tid) * REC_D;
        for (int kk = 0; kk < REC_D; kk++) {
            float h = sh[kk];
            aRv += wr[kk] * h; aZv += wz[kk] * h; aNv += wn[kk] * h;
        }
        float igr = ldh(&g_igates[(size_t)t * G3_D + tid]);
        float igz = ldh(&g_igates[(size_t)t * G3_D + 1024 + tid]);
        float ign = ldh(&g_igates[(size_t)t * G3_D + 2048 + tid]);
        float r = sigf(igr + aRv);
        float z = sigf(igz + aZv);
        float n = tanhf(ign + r * (aNv + b_n[tid]));
        float hp = sh[tid];
        store_state(t, tid, n + z * (hp - n));
        __syncthreads();
    }
}

// ---------------- small head (reads fp16 y2) ----------------
__global__ void __launch_bounds__(192)
p3_kernel(const f16* __restrict__ A, const float* __restrict__ Wt,
          const float* __restrict__ bias, float* __restrict__ out) {
    __shared__ __align__(16) float Ys[128][68];
    __shared__ float Ws[18][129];
    int tid = threadIdx.x;
    int rowBase = blockIdx.x * 64;
    int a = tid % 18, rg = tid / 18;
    float acc[8];
#pragma unroll
    for (int i = 0; i < 8; i++) acc[i] = 0.0f;

    for (int k0 = 0; k0 < MLP_D; k0 += 128) {
        __syncthreads();
        for (int l = tid; l < 18 * 128; l += 192) {
            int aa = l / 128, kk = l % 128;
            Ws[aa][kk] = Wt[(size_t)aa * MLP_D + k0 + kk];
        }
        for (int l = tid; l < 64 * 128; l += 192) {
            int r = l / 128, kk = l % 128;
            Ys[kk][r] = __half2float(A[(size_t)(rowBase + r) * MLP_D + k0 + kk]);
        }
        __syncthreads();
        if (tid < 144) {
#pragma unroll 4
            for (int kk = 0; kk < 128; kk++) {
                float w = Ws[a][kk];
                float4 y0 = *(const float4*)&Ys[kk][rg * 8];
                float4 y1v = *(const float4*)&Ys[kk][rg * 8 + 4];
                acc[0] += w * y0.x;  acc[1] += w * y0.y;
                acc[2] += w * y0.z;  acc[3] += w * y0.w;
                acc[4] += w * y1v.x; acc[5] += w * y1v.y;
                acc[6] += w * y1v.z; acc[7] += w * y1v.w;
            }
        }
    }
    if (tid < 144) {
        float b = bias[a];
#pragma unroll
        for (int i = 0; i < 8; i++)
            out[(size_t)(rowBase + rg * 8 + i) * ACT_D + a] = acc[i] + b;
    }
}

__global__ void copy_state_kernel(float* __restrict__ out) {
    out[threadIdx.x] = g_states[(size_t)(T_LEN - 1) * REC_D + threadIdx.x];
}

// ---------------- host ----------------
extern "C" void kernel_launch(void* const* d_in, const int* in_sizes, int n_in,
                              void* d_out, int out_size) {
    const float* x     = (const float*)d_in[0];
    const float* state = (const float*)d_in[1];
    const void*  start = d_in[2];
    const float* pre_w = (const float*)d_in[4];
    const float* pre_b = (const float*)d_in[5];
    const float* w_ih  = (const float*)d_in[6];
    const float* w_hh  = (const float*)d_in[7];
    const float* b_ih  = (const float*)d_in[8];
    const float* b_n   = (const float*)d_in[9];
    const float* p1_w  = (const float*)d_in[10];
    const float* p1_b  = (const float*)d_in[11];
    const float* p2_w  = (const float*)d_in[12];
    const float* p2_b  = (const float*)d_in[13];
    const float* p3_w  = (const float*)d_in[14];
    const float* p3_b  = (const float*)d_in[15];
    float* out = (float*)d_out;

    f16 *x2, *prew2, *feat2, *wih2, *whh2, *p1w2, *p2w2, *states2, *y12;
    f16 *igates, *hg, *y2h;
    int* counts_dev;
    cudaGetSymbolAddress((void**)&igates, g_igates);
    cudaGetSymbolAddress((void**)&hg, g_hg);
    cudaGetSymbolAddress((void**)&y2h, g_y2h);
    cudaGetSymbolAddress((void**)&x2, g_x2);
    cudaGetSymbolAddress((void**)&prew2, g_prew2);
    cudaGetSymbolAddress((void**)&feat2, g_feat2);
    cudaGetSymbolAddress((void**)&wih2, g_wih2);
    cudaGetSymbolAddress((void**)&whh2, g_whh2);
    cudaGetSymbolAddress((void**)&p1w2, g_p1w2);
    cudaGetSymbolAddress((void**)&p2w2, g_p2w2);
    cudaGetSymbolAddress((void**)&states2, g_states2);
    cudaGetSymbolAddress((void**)&y12, g_y12);
    cudaGetSymbolAddress((void**)&counts_dev, g_counts);

    cudaFuncSetAttribute(gemm_ca<1, 1, 0>, cudaFuncAttributeMaxDynamicSharedMemorySize, SMEM_GEMM);
    cudaFuncSetAttribute(gemm_ca<0, 1, 0>, cudaFuncAttributeMaxDynamicSharedMemorySize, SMEM_GEMM);
    cudaFuncSetAttribute(gemm_ca<0, 1, 1>, cudaFuncAttributeMaxDynamicSharedMemorySize, SMEM_GEMM);

    // segment analysis
    init_kernel<<<1, 64>>>();
    sniff_kernel<<<1, 256>>>((const unsigned char*)start);
    age_kernel<<<64, 256>>>(start);
    offsets_kernel<<<1, 1>>>();
    scatter_kernel<<<64, 256>>>();

    // all conversions in one launch
    conv_all<<<1024, 256>>>(pre_w, prew2, (size_t)MLP_D * OBS_D,
                            w_ih, wih2, (size_t)G3_D * MLP_D,
                            w_hh, whh2, (size_t)G3_D * REC_D,
                            p1_w, p1w2, (size_t)MLP_D * REC_D,
                            p2_w, p2w2, (size_t)MLP_D * MLP_D,
                            x, x2, (size_t)T_LEN * OBS_D);

    // feat = mish(x @ pre_w^T + pre_b)
    gemm_ca<1, 1, 0><<<dim3(MLP_D / 256, 128), 256, SMEM_GEMM>>>(
        x2, prew2, pre_b, nullptr, feat2, MLP_D, OBS_D, nullptr, T_LEN, 0);
    // igates = feat @ w_ih^T + b_ih (fp16 out)
    gemm_ca<0, 1, 0><<<dim3(G3_D / 256, 128), 256, SMEM_GEMM>>>(
        feat2, wih2, b_ih, nullptr, igates, G3_D, MLP_D, nullptr, T_LEN, 0);

    // segment-parallel GRU scan
    step0_kernel<<<2048, 256>>>(b_n);
    fixA_kernel<<<384, 256>>>(w_hh, state);
    fixB_kernel<<<1, 1024>>>(state, b_n);
    for (int k = 1; k < GEMM_STEPS; k++) {
        int est = T_LEN >> k;
        int gy = est / 128; if (gy < 1) gy = 1; if (gy > 64) gy = 64;
        gemm_ca<0, 1, 1><<<dim3(G3_D / 256, gy), 256, SMEM_GEMM>>>(
            states2, whh2, nullptr, nullptr, hg, G3_D, REC_D, counts_dev + k, 0, k);
        gru_gate<<<2048, 256>>>(b_n, k);
    }
    gru_tail_persistent<<<TAIL_BLOCKS, 256>>>(b_n);
    cleanup_kernel<<<1, 1024>>>(w_hh, b_n);

    // post MLP
    gemm_ca<1, 1, 0><<<dim3(MLP_D / 256, 128), 256, SMEM_GEMM>>>(
        states2, p1w2, p1_b, nullptr, y12, MLP_D, REC_D, nullptr, T_LEN, 0);
    gemm_ca<1, 1, 0><<<dim3(MLP_D / 256, 128), 256, SMEM_GEMM>>>(
        y12, p2w2, p2_b, nullptr, y2h, MLP_D, MLP_D, nullptr, T_LEN, 0);
    p3_kernel<<<T_LEN / 64, 192>>>(y2h, p3_w, p3_b, out);

    if (out_size >= T_LEN * ACT_D + REC_D)
        copy_state_kernel<<<1, 1024>>>(out + (size_t)T_LEN * ACT_D);
}

// round 10
// speedup vs baseline: 4.8001x; 1.0754x over previous
#include <cuda_runtime.h>
#include <cuda_fp16.h>
#include <math.h>
#include <stdint.h>

#define T_LEN 16384
#define OBS_D 256
#define MLP_D 1024
#define REC_D 1024
#define G3_D  3072
#define ACT_D 18
#define STEPS 26
#define GEMM_STEPS 8
#define TAIL_BLOCKS 128

typedef __half f16;

// ---------------- scratch (device globals; no allocation allowed) ----------------
__device__ __align__(16) f16   g_x2[(size_t)T_LEN * OBS_D];
__device__ __align__(16) f16   g_prew2[(size_t)MLP_D * OBS_D];
__device__ __align__(16) f16   g_feat2[(size_t)T_LEN * MLP_D];
__device__ __align__(16) f16   g_wih2[(size_t)G3_D * MLP_D];
__device__ __align__(16) f16   g_whh2[(size_t)G3_D * REC_D];
__device__ __align__(16) f16   g_p1w2[(size_t)MLP_D * REC_D];
__device__ __align__(16) f16   g_p2w2[(size_t)MLP_D * MLP_D];
__device__ __align__(16) f16   g_states2[(size_t)T_LEN * REC_D];
__device__ __align__(16) f16   g_y12[(size_t)T_LEN * MLP_D];
__device__ __align__(16) f16   g_igates[(size_t)T_LEN * G3_D];
__device__ __align__(16) f16   g_hg[(size_t)T_LEN * G3_D];
__device__ __align__(16) f16   g_y2h[(size_t)T_LEN * MLP_D];
__device__ __align__(16) float g_states[(size_t)T_LEN * REC_D];
__device__ float g_hg0[G3_D];
__device__ int   g_age[T_LEN];
__device__ int   g_perm[T_LEN];
__device__ int   g_counts[STEPS + 1];
__device__ int   g_offsets[STEPS + 1];
__device__ int   g_cursor[STEPS + 1];
__device__ int   g_flags[4];
__device__ unsigned g_bar;

// ---------------- helpers ----------------
__device__ __forceinline__ float sigf(float x) { return 1.0f / (1.0f + expf(-x)); }
__device__ __forceinline__ float mishf(float x) {
    float sp = (x > 15.0f) ? x : log1pf(expf(x));
    return x * tanhf(sp);
}
__device__ __forceinline__ uint32_t smem_u32(const void* p) {
    return (uint32_t)__cvta_generic_to_shared(p);
}
__device__ __forceinline__ uint32_t pack2h(f16 a, f16 b) {
    __half2 t; t.x = a; t.y = b;
    return *(uint32_t*)&t;
}
__device__ __forceinline__ void store_state(int t, int j, float v) {
    g_states[(size_t)t * REC_D + j] = v;
    g_states2[(size_t)t * REC_D + j] = __float2half(v);
}
__device__ __forceinline__ float ldh(const f16* p) { return __half2float(*p); }

// ---------------- async / mma primitives (plain compute_100-legal) ----------------
__device__ __forceinline__ void cpasync16(uint32_t sa, const void* ga) {
    asm volatile("cp.async.cg.shared.global [%0], [%1], 16;" :: "r"(sa), "l"(ga));
}
__device__ __forceinline__ void cp_commit() { asm volatile("cp.async.commit_group;" ::: "memory"); }
__device__ __forceinline__ void cp_wait2() { asm volatile("cp.async.wait_group 2;" ::: "memory"); }
__device__ __forceinline__ void cp_wait1() { asm volatile("cp.async.wait_group 1;" ::: "memory"); }
__device__ __forceinline__ void cp_wait0() { asm volatile("cp.async.wait_group 0;" ::: "memory"); }

__device__ __forceinline__ void ldmx4(uint32_t addr, uint32_t& r0, uint32_t& r1, uint32_t& r2, uint32_t& r3) {
    asm volatile("ldmatrix.sync.aligned.m8n8.x4.shared.b16 {%0,%1,%2,%3}, [%4];"
                 : "=r"(r0), "=r"(r1), "=r"(r2), "=r"(r3) : "r"(addr));
}
__device__ __forceinline__ void mma_h(float* c, const uint32_t* a, const uint32_t* b) {
    asm volatile("mma.sync.aligned.m16n8k16.row.col.f32.f16.f16.f32 "
                 "{%0,%1,%2,%3}, {%4,%5,%6,%7}, {%8,%9}, {%0,%1,%2,%3};"
                 : "+f"(c[0]), "+f"(c[1]), "+f"(c[2]), "+f"(c[3])
                 : "r"(a[0]), "r"(a[1]), "r"(a[2]), "r"(a[3]), "r"(b[0]), "r"(b[1]));
}

// ---------------- setup kernels ----------------
__global__ void init_kernel() {
    int t = threadIdx.x;
    if (t < STEPS + 1) { g_counts[t] = 0; g_cursor[t] = 0; }
    if (t < 4) g_flags[t] = 0;
    if (t == 0) g_bar = 0;
}

__global__ void sniff_kernel(const unsigned char* __restrict__ p) {
    __shared__ int s_nz[4];
    int tid = threadIdx.x;
    if (tid < 4) s_nz[tid] = 0;
    __syncthreads();
    int cnt = 0;
    for (int i = tid; i < T_LEN; i += blockDim.x) cnt += (p[i] != 0);
    atomicAdd(&s_nz[tid & 3], cnt);
    __syncthreads();
    if (tid == 0) {
        int rest = s_nz[1] + s_nz[2] + s_nz[3];
        int mode;
        if (rest > 0) mode = (s_nz[0] == 0) ? 2 : 0;
        else          mode = (s_nz[0] > 0) ? 1 : 0;
        g_flags[0] = mode;
        bool s0;
        if (mode == 0)      s0 = p[0] != 0;
        else if (mode == 1) s0 = ((const int*)p)[0] != 0;
        else                s0 = ((const float*)p)[0] != 0.0f;
        g_flags[1] = s0 ? 1 : 0;
    }
}

__device__ __forceinline__ bool start_val(const void* p, int mode, int u) {
    if (mode == 0) return ((const unsigned char*)p)[u] != 0;
    if (mode == 1) return ((const int*)p)[u] != 0;
    return ((const float*)p)[u] != 0.0f;
}

__global__ void age_kernel(const void* __restrict__ startp) {
    int mode = g_flags[0];
    int stride = gridDim.x * blockDim.x;
    for (int t = blockIdx.x * blockDim.x + threadIdx.x; t < T_LEN; t += stride) {
        int k = 0, tt = t;
        while (tt > 0 && !start_val(startp, mode, tt)) { tt--; k++; }
        g_age[t] = k;
        int b = k < STEPS ? k : STEPS;
        atomicAdd(&g_counts[b], 1);
    }
}

__global__ void offsets_kernel() {
    if (threadIdx.x == 0 && blockIdx.x == 0) {
        int acc = 0;
        for (int b = 0; b <= STEPS; b++) { g_offsets[b] = acc; acc += g_counts[b]; }
    }
}

__global__ void scatter_kernel() {
    int stride = gridDim.x * blockDim.x;
    for (int t = blockIdx.x * blockDim.x + threadIdx.x; t < T_LEN; t += stride) {
        int a = g_age[t];
        int b = a < STEPS ? a : STEPS;
        int pos = g_offsets[b] + atomicAdd(&g_cursor[b], 1);
        g_perm[pos] = t;
    }
}

// ---------------- merged fp32->fp16 conversions (one launch) ----------------
__global__ void conv_all(const float* s0, f16* d0, size_t n0,
                         const float* s1, f16* d1, size_t n1,
                         const float* s2, f16* d2, size_t n2,
                         const float* s3, f16* d3, size_t n3,
                         const float* s4, f16* d4, size_t n4,
                         const float* s5, f16* d5, size_t n5) {
    size_t stride = (size_t)gridDim.x * blockDim.x;
    size_t i0 = (size_t)blockIdx.x * blockDim.x + threadIdx.x;
    for (size_t i = i0; i < n0; i += stride) d0[i] = __float2half(s0[i]);
    for (size_t i = i0; i < n1; i += stride) d1[i] = __float2half(s1[i]);
    for (size_t i = i0; i < n2; i += stride) d2[i] = __float2half(s2[i]);
    for (size_t i = i0; i < n3; i += stride) d3[i] = __float2half(s3[i]);
    for (size_t i = i0; i < n4; i += stride) d4[i] = __float2half(s4[i]);
    for (size_t i = i0; i < n5; i += stride) d5[i] = __float2half(s5[i]);
}

// ---------------- mma.sync GEMM (128x256) with cp.async pipeline (+A-gather) ----------------
#define STG_A_SZ 8192
#define STG_B_SZ 16384
#define STG_SZ (STG_A_SZ + STG_B_SZ)
#define NSTG 4
#define SMEM_GEMM (NSTG * STG_SZ)

__device__ __forceinline__ uint32_t swz(uint32_t base, int r, int seg) {
    return base + r * 64 + 16 * (seg ^ ((r >> 1) & 3));
}

template <int GATHER>
__device__ __forceinline__ void load_stage(const f16* __restrict__ A, const f16* __restrict__ B,
                                           const int* __restrict__ perm, int M,
                                           int rowBase, int colBase, int K, int chunk,
                                           uint32_t sA, uint32_t sB, int tid) {
    const f16* Bb = B + (size_t)colBase * K + chunk * 32;
#pragma unroll
    for (int i = 0; i < 2; i++) {
        int o = tid + i * 256;
        int r = o >> 2, seg = o & 3;
        const f16* src;
        if (GATHER) {
            int gi = rowBase + r;
            gi = gi < M - 1 ? gi : M - 1;
            int t = __ldg(&perm[gi]);
            src = A + (size_t)(t - 1) * K + chunk * 32 + (size_t)seg * 8;
        } else {
            src = A + (size_t)(rowBase + r) * K + chunk * 32 + (size_t)seg * 8;
        }
        cpasync16(swz(sA, r, seg), src);
    }
#pragma unroll
    for (int i = 0; i < 4; i++) {
        int o = tid + i * 256;
        int r = o >> 2, seg = o & 3;
        cpasync16(swz(sB, r, seg), Bb + (size_t)r * K + seg * 8);
    }
}

template <int MISH, int HALFOUT, int GATHER>
__global__ void __launch_bounds__(256)
gemm_ca(const f16* __restrict__ A, const f16* __restrict__ B,
        const float* __restrict__ bias, float* __restrict__ Cf, f16* __restrict__ Cs,
        int Ntot, int K, const int* __restrict__ Mptr, int Mfix, int bucketK) {
    extern __shared__ __align__(16) char dsm[];
    int tid = threadIdx.x, wid = tid >> 5, lane = tid & 31;
    int wm = wid >> 2, wn = wid & 3;
    int M = Mptr ? *Mptr : Mfix;
    const int* perm = GATHER ? (g_perm + g_offsets[bucketK]) : (const int*)0;
    int colBase = blockIdx.x * 256;
    int NC = K >> 5;
    uint32_t sbase = smem_u32(dsm);

    for (int mtile = blockIdx.y; mtile * 128 < M; mtile += gridDim.y) {
        int rowBase = mtile * 128;
        float acc[4][8][4];
#pragma unroll
        for (int mt = 0; mt < 4; mt++)
#pragma unroll
            for (int nt = 0; nt < 8; nt++)
#pragma unroll
                for (int q = 0; q < 4; q++) acc[mt][nt][q] = 0.0f;

#pragma unroll
        for (int p = 0; p < 3; p++) {
            uint32_t sg = sbase + p * STG_SZ;
            load_stage<GATHER>(A, B, perm, M, rowBase, colBase, K, p, sg, sg + STG_A_SZ, tid);
            cp_commit();
        }

        for (int c = 0; c < NC; c++) {
            cp_wait2();
            __syncthreads();
            if (c + 3 < NC) {
                int s = (c + 3) & 3;
                uint32_t sg = sbase + s * STG_SZ;
                load_stage<GATHER>(A, B, perm, M, rowBase, colBase, K, c + 3, sg, sg + STG_A_SZ, tid);
            }
            cp_commit();

            uint32_t sA = sbase + (c & 3) * STG_SZ;
            uint32_t sB = sA + STG_A_SZ;
#pragma unroll
            for (int kk2 = 0; kk2 < 2; kk2++) {
                int seg = kk2 * 2 + (lane >> 4);
                uint32_t af[4][4];
#pragma unroll
                for (int mt = 0; mt < 4; mt++) {
                    int r = wm * 64 + mt * 16 + (lane & 15);
                    ldmx4(swz(sA, r, seg), af[mt][0], af[mt][1], af[mt][2], af[mt][3]);
                }
                uint32_t bb[8][2];
#pragma unroll
                for (int nb = 0; nb < 4; nb++) {
                    int r = wn * 64 + nb * 16 + (lane & 15);
                    uint32_t r0, r1, r2, r3;
                    ldmx4(swz(sB, r, seg), r0, r1, r2, r3);
                    bb[2 * nb][0] = r0;     bb[2 * nb][1] = r2;
                    bb[2 * nb + 1][0] = r1; bb[2 * nb + 1][1] = r3;
                }
#pragma unroll
                for (int mt = 0; mt < 4; mt++)
#pragma unroll
                    for (int nt = 0; nt < 8; nt++)
                        mma_h(acc[mt][nt], af[mt], bb[nt]);
            }
        }
        cp_wait0();
        __syncthreads();

        int rg = lane >> 2, cg = (lane & 3) * 2;
#pragma unroll
        for (int mt = 0; mt < 4; mt++) {
            int R0 = rowBase + wm * 64 + mt * 16 + rg;
#pragma unroll
            for (int nt = 0; nt < 8; nt++) {
                int C = colBase + wn * 64 + nt * 8 + cg;
                float b0 = bias ? bias[C] : 0.0f;
                float b1 = bias ? bias[C + 1] : 0.0f;
                float v00 = acc[mt][nt][0] + b0, v01 = acc[mt][nt][1] + b1;
                float v10 = acc[mt][nt][2] + b0, v11 = acc[mt][nt][3] + b1;
                if (MISH) { v00 = mishf(v00); v01 = mishf(v01); v10 = mishf(v10); v11 = mishf(v11); }
                if (HALFOUT) {
                    *(uint32_t*)&Cs[(size_t)R0 * Ntot + C] =
                        pack2h(__float2half(v00), __float2half(v01));
                    *(uint32_t*)&Cs[(size_t)(R0 + 8) * Ntot + C] =
                        pack2h(__float2half(v10), __float2half(v11));
                } else {
                    float2 a; a.x = v00; a.y = v01;
                    float2 b; b.x = v10; b.y = v11;
                    *(float2*)&Cf[(size_t)R0 * Ntot + C] = a;
                    *(float2*)&Cf[(size_t)(R0 + 8) * Ntot + C] = b;
                }
            }
        }
    }
}

// ---------------- small-tile GEMM (64x128) for small GRU steps: gather + fp16 out ----------------
#define SSTG_A_SZ 4096
#define SSTG_B_SZ 8192
#define SSTG_SZ (SSTG_A_SZ + SSTG_B_SZ)
#define SMEM_SGEMM (NSTG * SSTG_SZ)

__device__ __forceinline__ void load_stage_sm(const f16* __restrict__ A, const f16* __restrict__ B,
                                              const int* __restrict__ perm, int M,
                                              int rowBase, int colBase, int K, int chunk,
                                              uint32_t sA, uint32_t sB, int tid) {
    {
        int r = tid >> 2, seg = tid & 3;   // 64 rows x 4 segs = 256 ops
        int gi = rowBase + r;
        gi = gi < M - 1 ? gi : M - 1;
        int t = __ldg(&perm[gi]);
        cpasync16(swz(sA, r, seg), A + (size_t)(t - 1) * K + chunk * 32 + (size_t)seg * 8);
    }
    const f16* Bb = B + (size_t)colBase * K + chunk * 32;
#pragma unroll
    for (int i = 0; i < 2; i++) {
        int o = tid + i * 256;
        int r = o >> 2, seg = o & 3;
        cpasync16(swz(sB, r, seg), Bb + (size_t)r * K + seg * 8);
    }
}

__global__ void __launch_bounds__(256)
gemm_sm(const f16* __restrict__ A, const f16* __restrict__ B, f16* __restrict__ Cs,
        int Ntot, int K, const int* __restrict__ Mptr, int bucketK) {
    extern __shared__ __align__(16) char dsm[];
    int tid = threadIdx.x, wid = tid >> 5, lane = tid & 31;
    int wm = wid >> 2, wn = wid & 3;   // 2 x 4 warps, warp tile 32x32
    int M = *Mptr;
    const int* perm = g_perm + g_offsets[bucketK];
    int colBase = blockIdx.x * 128;
    int NC = K >> 5;
    uint32_t sbase = smem_u32(dsm);

    for (int mtile = blockIdx.y; mtile * 64 < M; mtile += gridDim.y) {
        int rowBase = mtile * 64;
        float acc[2][4][4];
#pragma unroll
        for (int mt = 0; mt < 2; mt++)
#pragma unroll
            for (int nt = 0; nt < 4; nt++)
#pragma unroll
                for (int q = 0; q < 4; q++) acc[mt][nt][q] = 0.0f;

#pragma unroll
        for (int p = 0; p < 3; p++) {
            uint32_t sg = sbase + p * SSTG_SZ;
            load_stage_sm(A, B, perm, M, rowBase, colBase, K, p, sg, sg + SSTG_A_SZ, tid);
            cp_commit();
        }

        for (int c = 0; c < NC; c++) {
            cp_wait2();
            __syncthreads();
            if (c + 3 < NC) {
                int s = (c + 3) & 3;
                uint32_t sg = sbase + s * SSTG_SZ;
                load_stage_sm(A, B, perm, M, rowBase, colBase, K, c + 3, sg, sg + SSTG_A_SZ, tid);
            }
            cp_commit();

            uint32_t sA = sbase + (c & 3) * SSTG_SZ;
            uint32_t sB = sA + SSTG_A_SZ;
#pragma unroll
            for (int kk2 = 0; kk2 < 2; kk2++) {
                int seg = kk2 * 2 + (lane >> 4);
                uint32_t af[2][4];
#pragma unroll
                for (int mt = 0; mt < 2; mt++) {
                    int r = wm * 32 + mt * 16 + (lane & 15);
                    ldmx4(swz(sA, r, seg), af[mt][0], af[mt][1], af[mt][2], af[mt][3]);
                }
                uint32_t bb[4][2];
#pragma unroll
                for (int nb = 0; nb < 2; nb++) {
                    int r = wn * 32 + nb * 16 + (lane & 15);
                    uint32_t r0, r1, r2, r3;
                    ldmx4(swz(sB, r, seg), r0, r1, r2, r3);
                    bb[2 * nb][0] = r0;     bb[2 * nb][1] = r2;
                    bb[2 * nb + 1][0] = r1; bb[2 * nb + 1][1] = r3;
                }
#pragma unroll
                for (int mt = 0; mt < 2; mt++)
#pragma unroll
                    for (int nt = 0; nt < 4; nt++)
                        mma_h(acc[mt][nt], af[mt], bb[nt]);
            }
        }
        cp_wait0();
        __syncthreads();

        int rg = lane >> 2, cg = (lane & 3) * 2;
#pragma unroll
        for (int mt = 0; mt < 2; mt++) {
            int R0 = rowBase + wm * 32 + mt * 16 + rg;
#pragma unroll
            for (int nt = 0; nt < 4; nt++) {
                int C = colBase + wn * 32 + nt * 8 + cg;
                *(uint32_t*)&Cs[(size_t)R0 * Ntot + C] =
                    pack2h(__float2half(acc[mt][nt][0]), __float2half(acc[mt][nt][1]));
                *(uint32_t*)&Cs[(size_t)(R0 + 8) * Ntot + C] =
                    pack2h(__float2half(acc[mt][nt][2]), __float2half(acc[mt][nt][3]));
            }
        }
    }
}

// ---------------- GRU step k==0 (h_prev == 0) ----------------
__global__ void step0_kernel(const float* __restrict__ b_n) {
    int count = g_counts[0];
    long total = (long)count * REC_D;
    long stride = (long)gridDim.x * blockDim.x;
    for (long idx = (long)blockIdx.x * blockDim.x + threadIdx.x; idx < total; idx += stride) {
        int i = (int)(idx >> 10);
        int j = (int)(idx & 1023);
        int t = g_perm[i];
        float igr = ldh(&g_igates[(size_t)t * G3_D + j]);
        float igz = ldh(&g_igates[(size_t)t * G3_D + 1024 + j]);
        float ign = ldh(&g_igates[(size_t)t * G3_D + 2048 + j]);
        float r = sigf(igr);
        float z = sigf(igz);
        float n = tanhf(ign + r * b_n[j]);
        store_state(t, j, n - z * n);
    }
}

__global__ void fixA_kernel(const float* __restrict__ w_hh, const float* __restrict__ state) {
    if (g_flags[1]) return;
    int j = blockIdx.x * 8 + (threadIdx.x >> 5);
    int lane = threadIdx.x & 31;
    float acc = 0.0f;
    const float* wr = w_hh + (size_t)j * REC_D;
    for (int k = lane; k < REC_D; k += 32) acc += wr[k] * state[k];
#pragma unroll
    for (int o = 16; o > 0; o >>= 1) acc += __shfl_down_sync(0xffffffffu, acc, o);
    if (lane == 0) g_hg0[j] = acc;
}

__global__ void fixB_kernel(const float* __restrict__ state, const float* __restrict__ b_n) {
    if (g_flags[1]) return;
    int j = threadIdx.x;
    float igr = ldh(&g_igates[j]), igz = ldh(&g_igates[1024 + j]), ign = ldh(&g_igates[2048 + j]);
    float r = sigf(igr + g_hg0[j]);
    float z = sigf(igz + g_hg0[1024 + j]);
    float n = tanhf(ign + r * (g_hg0[2048 + j] + b_n[j]));
    float hp = state[j];
    store_state(0, j, n + z * (hp - n));
}

// gate math for GEMM steps (consumes fp16 g_hg)
__global__ void gru_gate(const float* __restrict__ b_n, int k) {
    int count = g_counts[k];
    int base = g_offsets[k];
    long total = (long)count * REC_D;
    long stride = (long)gridDim.x * blockDim.x;
    for (long idx = (long)blockIdx.x * blockDim.x + threadIdx.x; idx < total; idx += stride) {
        int i = (int)(idx >> 10);
        int j = (int)(idx & 1023);
        int t = g_perm[base + i];
        float hr = ldh(&g_hg[(size_t)i * G3_D + j]);
        float hz = ldh(&g_hg[(size_t)i * G3_D + 1024 + j]);
        float hn = ldh(&g_hg[(size_t)i * G3_D + 2048 + j]);
        float igr = ldh(&g_igates[(size_t)t * G3_D + j]);
        float igz = ldh(&g_igates[(size_t)t * G3_D + 1024 + j]);
        float ign = ldh(&g_igates[(size_t)t * G3_D + 2048 + j]);
        float hp = g_states[(size_t)(t - 1) * REC_D + j];
        float r = sigf(igr + hr);
        float z = sigf(igz + hz);
        float n = tanhf(ign + r * (hn + b_n[j]));
        store_state(t, j, n + z * (hp - n));
    }
}

// ---------------- persistent tail: double-buffered SMEM h, fp16 weights ----------------
__device__ __forceinline__ void tail_prefetch(int t, __half2* buf, int tid) {
    if (tid < 128) {
        const char* src = (const char*)(g_states2 + (size_t)(t - 1) * REC_D) + tid * 16;
        cpasync16(smem_u32((char*)buf + tid * 16), src);
    }
}

__global__ void __launch_bounds__(256)
gru_tail_persistent(const float* __restrict__ b_n) {
    __shared__ __align__(16) __half2 sh[2][REC_D / 2];
    int tid = threadIdx.x;
    int wid = tid >> 5;
    int j = blockIdx.x * 8 + wid;
    int lane = tid & 31;
    const __half2* wr2 = (const __half2*)(g_whh2 + (size_t)j * REC_D);
    const __half2* wz2 = (const __half2*)(g_whh2 + (size_t)(1024 + j) * REC_D);
    const __half2* wn2 = (const __half2*)(g_whh2 + (size_t)(2048 + j) * REC_D);
    __half2 wr[16], wz[16], wn[16];
#pragma unroll
    for (int q = 0; q < 16; q++) {
        wr[q] = wr2[lane + q * 32];
        wz[q] = wz2[lane + q * 32];
        wn[q] = wn2[lane + q * 32];
    }
    float bn = b_n[j];
    unsigned nb = gridDim.x;
    unsigned bc = 0;

    for (int k = GEMM_STEPS; k < STEPS; k++) {
        int count = g_counts[k];
        int base = g_offsets[k];
        if (count <= 0) continue;   // nothing written -> no barrier needed (consistent across blocks)
        tail_prefetch(g_perm[base], sh[0], tid);
        cp_commit();
        for (int i = 0; i < count; i++) {
            if (i + 1 < count) tail_prefetch(g_perm[base + i + 1], sh[(i + 1) & 1], tid);
            cp_commit();
            if (i + 1 < count) cp_wait1(); else cp_wait0();
            __syncthreads();
            const __half2* hb = sh[i & 1];
            int t = g_perm[base + i];
            float aR = 0.0f, aZ = 0.0f, aN = 0.0f;
#pragma unroll
            for (int q = 0; q < 16; q++) {
                float2 hf = __half22float2(hb[lane + q * 32]);
                float2 rf = __half22float2(wr[q]);
                float2 zf = __half22float2(wz[q]);
                float2 nf = __half22float2(wn[q]);
                aR += rf.x * hf.x + rf.y * hf.y;
                aZ += zf.x * hf.x + zf.y * hf.y;
                aN += nf.x * hf.x + nf.y * hf.y;
            }
#pragma unroll
            for (int o = 16; o > 0; o >>= 1) {
                aR += __shfl_xor_sync(0xffffffffu, aR, o);
                aZ += __shfl_xor_sync(0xffffffffu, aZ, o);
                aN += __shfl_xor_sync(0xffffffffu, aN, o);
            }
            if (lane == 0) {
                float igr = ldh(&g_igates[(size_t)t * G3_D + j]);
                float igz = ldh(&g_igates[(size_t)t * G3_D + 1024 + j]);
                float ign = ldh(&g_igates[(size_t)t * G3_D + 2048 + j]);
                float hp = __ldcg(&g_states[(size_t)(t - 1) * REC_D + j]);
                float r = sigf(igr + aR);
                float z = sigf(igz + aZ);
                float n = tanhf(ign + r * (aN + bn));
                store_state(t, j, n + z * (hp - n));
            }
            __syncthreads();
        }
        bc++;
        __syncthreads();
        if (tid == 0) {
            __threadfence();
            atomicAdd(&g_bar, 1u);
            while (*((volatile unsigned*)&g_bar) < bc * nb) {}
        }
        __syncthreads();
    }
}

// safety net for age >= STEPS (count ~0 in practice)
__global__ void __launch_bounds__(1024)
cleanup_kernel(const float* __restrict__ w_hh, const float* __restrict__ b_n) {
    if (g_counts[STEPS] == 0) return;
    __shared__ int s_t;
    __shared__ int s_cur;
    __shared__ float sh[REC_D];
    int tid = threadIdx.x;
    if (tid == 0) s_cur = STEPS;
    __syncthreads();
    while (true) {
        if (tid == 0) {
            s_t = -1;
            for (int u = s_cur; u < T_LEN; ++u)
                if (g_age[u] >= STEPS) { s_t = u; s_cur = u + 1; break; }
        }
        __syncthreads();
        int t = s_t;
        if (t < 0) break;
        sh[tid] = g_states[(size_t)(t - 1) * REC_D + tid];
        __syncthreads();
        float aRv = 0, aZv = 0, aNv = 0;
        const float* wr = w_hh + (size_t)tid * REC_D;
        const float* wz = w_hh + (size_t)(1024 + tid) * REC_D;
        const float* wn = w_hh + (size_t)(2048 + tid) * REC_D;
        for (int kk = 0; kk < REC_D; kk++) {
            float h = sh[kk];
            aRv += wr[kk] * h; aZv += wz[kk] * h; aNv += wn[kk] * h;
        }
        float igr = ldh(&g_igates[(size_t)t * G3_D + tid]);
        float igz = ldh(&g_igates[(size_t)t * G3_D + 1024 + tid]);
        float ign = ldh(&g_igates[(size_t)t * G3_D + 2048 + tid]);
        float r = sigf(igr + aRv);
        float z = sigf(igz + aZv);
        float n = tanhf(ign + r * (aNv + b_n[tid]));
        float hp = sh[tid];
        store_state(t, tid, n + z * (hp - n));
        __syncthreads();
    }
}

// ---------------- small head (reads fp16 y2) ----------------
__global__ void __launch_bounds__(192)
p3_kernel(const f16* __restrict__ A, const float* __restrict__ Wt,
          const float* __restrict__ bias, float* __restrict__ out) {
    __shared__ __align__(16) float Ys[128][68];
    __shared__ float Ws[18][129];
    int tid = threadIdx.x;
    int rowBase = blockIdx.x * 64;
    int a = tid % 18, rg = tid / 18;
    float acc[8];
#pragma unroll
    for (int i = 0; i < 8; i++) acc[i] = 0.0f;

    for (int k0 = 0; k0 < MLP_D; k0 += 128) {
        __syncthreads();
        for (int l = tid; l < 18 * 128; l += 192) {
            int aa = l / 128, kk = l % 128;
            Ws[aa][kk] = Wt[(size_t)aa * MLP_D + k0 + kk];
        }
        for (int l = tid; l < 64 * 128; l += 192) {
            int r = l / 128, kk = l % 128;
            Ys[kk][r] = __half2float(A[(size_t)(rowBase + r) * MLP_D + k0 + kk]);
        }
        __syncthreads();
        if (tid < 144) {
#pragma unroll 4
            for (int kk = 0; kk < 128; kk++) {
                float w = Ws[a][kk];
                float4 y0 = *(const float4*)&Ys[kk][rg * 8];
                float4 y1v = *(const float4*)&Ys[kk][rg * 8 + 4];
                acc[0] += w * y0.x;  acc[1] += w * y0.y;
                acc[2] += w * y0.z;  acc[3] += w * y0.w;
                acc[4] += w * y1v.x; acc[5] += w * y1v.y;
                acc[6] += w * y1v.z; acc[7] += w * y1v.w;
            }
        }
    }
    if (tid < 144) {
        float b = bias[a];
#pragma unroll
        for (int i = 0; i < 8; i++)
            out[(size_t)(rowBase + rg * 8 + i) * ACT_D + a] = acc[i] + b;
    }
}

__global__ void copy_state_kernel(float* __restrict__ out) {
    out[threadIdx.x] = g_states[(size_t)(T_LEN - 1) * REC_D + threadIdx.x];
}

// ---------------- host ----------------
extern "C" void kernel_launch(void* const* d_in, const int* in_sizes, int n_in,
                              void* d_out, int out_size) {
    const float* x     = (const float*)d_in[0];
    const float* state = (const float*)d_in[1];
    const void*  start = d_in[2];
    const float* pre_w = (const float*)d_in[4];
    const float* pre_b = (const float*)d_in[5];
    const float* w_ih  = (const float*)d_in[6];
    const float* w_hh  = (const float*)d_in[7];
    const float* b_ih  = (const float*)d_in[8];
    const float* b_n   = (const float*)d_in[9];
    const float* p1_w  = (const float*)d_in[10];
    const float* p1_b  = (const float*)d_in[11];
    const float* p2_w  = (const float*)d_in[12];
    const float* p2_b  = (const float*)d_in[13];
    const float* p3_w  = (const float*)d_in[14];
    const float* p3_b  = (const float*)d_in[15];
    float* out = (float*)d_out;

    f16 *x2, *prew2, *feat2, *wih2, *whh2, *p1w2, *p2w2, *states2, *y12;
    f16 *igates, *hg, *y2h;
    int* counts_dev;
    cudaGetSymbolAddress((void**)&igates, g_igates);
    cudaGetSymbolAddress((void**)&hg, g_hg);
    cudaGetSymbolAddress((void**)&y2h, g_y2h);
    cudaGetSymbolAddress((void**)&x2, g_x2);
    cudaGetSymbolAddress((void**)&prew2, g_prew2);
    cudaGetSymbolAddress((void**)&feat2, g_feat2);
    cudaGetSymbolAddress((void**)&wih2, g_wih2);
    cudaGetSymbolAddress((void**)&whh2, g_whh2);
    cudaGetSymbolAddress((void**)&p1w2, g_p1w2);
    cudaGetSymbolAddress((void**)&p2w2, g_p2w2);
    cudaGetSymbolAddress((void**)&states2, g_states2);
    cudaGetSymbolAddress((void**)&y12, g_y12);
    cudaGetSymbolAddress((void**)&counts_dev, g_counts);

    cudaFuncSetAttribute(gemm_ca<1, 1, 0>, cudaFuncAttributeMaxDynamicSharedMemorySize, SMEM_GEMM);
    cudaFuncSetAttribute(gemm_ca<0, 1, 0>, cudaFuncAttributeMaxDynamicSharedMemorySize, SMEM_GEMM);
    cudaFuncSetAttribute(gemm_ca<0, 1, 1>, cudaFuncAttributeMaxDynamicSharedMemorySize, SMEM_GEMM);
    cudaFuncSetAttribute(gemm_sm, cudaFuncAttributeMaxDynamicSharedMemorySize, SMEM_SGEMM);

    // segment analysis
    init_kernel<<<1, 64>>>();
    sniff_kernel<<<1, 256>>>((const unsigned char*)start);
    age_kernel<<<64, 256>>>(start);
    offsets_kernel<<<1, 1>>>();
    scatter_kernel<<<64, 256>>>();

    // all conversions in one launch
    conv_all<<<1024, 256>>>(pre_w, prew2, (size_t)MLP_D * OBS_D,
                            w_ih, wih2, (size_t)G3_D * MLP_D,
                            w_hh, whh2, (size_t)G3_D * REC_D,
                            p1_w, p1w2, (size_t)MLP_D * REC_D,
                            p2_w, p2w2, (size_t)MLP_D * MLP_D,
                            x, x2, (size_t)T_LEN * OBS_D);

    // feat = mish(x @ pre_w^T + pre_b)
    gemm_ca<1, 1, 0><<<dim3(MLP_D / 256, 128), 256, SMEM_GEMM>>>(
        x2, prew2, pre_b, nullptr, feat2, MLP_D, OBS_D, nullptr, T_LEN, 0);
    // igates = feat @ w_ih^T + b_ih (fp16 out)
    gemm_ca<0, 1, 0><<<dim3(G3_D / 256, 128), 256, SMEM_GEMM>>>(
        feat2, wih2, b_ih, nullptr, igates, G3_D, MLP_D, nullptr, T_LEN, 0);

    // segment-parallel GRU scan
    step0_kernel<<<2048, 256>>>(b_n);
    fixA_kernel<<<384, 256>>>(w_hh, state);
    fixB_kernel<<<1, 1024>>>(state, b_n);
    for (int k = 1; k < GEMM_STEPS; k++) {
        int est = T_LEN >> k;
        if (k == 1) {
            int gy = est / 128; if (gy < 1) gy = 1; if (gy > 64) gy = 64;
            gemm_ca<0, 1, 1><<<dim3(G3_D / 256, gy), 256, SMEM_GEMM>>>(
                states2, whh2, nullptr, nullptr, hg, G3_D, REC_D, counts_dev + k, 0, k);
        } else {
            int gy = est / 64; if (gy < 1) gy = 1; if (gy > 32) gy = 32;
            gemm_sm<<<dim3(G3_D / 128, gy), 256, SMEM_SGEMM>>>(
                states2, whh2, hg, G3_D, REC_D, counts_dev + k, k);
        }
        gru_gate<<<2048, 256>>>(b_n, k);
    }
    gru_tail_persistent<<<TAIL_BLOCKS, 256>>>(b_n);
    cleanup_kernel<<<1, 1024>>>(w_hh, b_n);

    // post MLP
    gemm_ca<1, 1, 0><<<dim3(MLP_D / 256, 128), 256, SMEM_GEMM>>>(
        states2, p1w2, p1_b, nullptr, y12, MLP_D, REC_D, nullptr, T_LEN, 0);
    gemm_ca<1, 1, 0><<<dim3(MLP_D / 256, 128), 256, SMEM_GEMM>>>(
        y12, p2w2, p2_b, nullptr, y2h, MLP_D, MLP_D, nullptr, T_LEN, 0);
    p3_kernel<<<T_LEN / 64, 192>>>(y2h, p3_w, p3_b, out);

    if (out_size >= T_LEN * ACT_D + REC_D)
        copy_state_kernel<<<1, 1024>>>(out + (size_t)T_LEN * ACT_D);
}

// round 11
// speedup vs baseline: 5.0999x; 1.0624x over previous
#include <cuda_runtime.h>
#include <cuda_fp16.h>
#include <math.h>
#include <stdint.h>

#define T_LEN 16384
#define OBS_D 256
#define MLP_D 1024
#define REC_D 1024
#define G3_D  3072
#define ACT_D 18
#define P3N   24
#define STEPS 26
#define GEMM_STEPS 9
#define TAIL_BLOCKS 128

typedef __half f16;

// ---------------- scratch (device globals; no allocation allowed) ----------------
__device__ __align__(16) f16   g_x2[(size_t)T_LEN * OBS_D];
__device__ __align__(16) f16   g_prew2[(size_t)MLP_D * OBS_D];
__device__ __align__(16) f16   g_feat2[(size_t)T_LEN * MLP_D];
__device__ __align__(16) f16   g_wih2[(size_t)G3_D * MLP_D];
__device__ __align__(16) f16   g_whh2[(size_t)G3_D * REC_D];
__device__ __align__(16) f16   g_p1w2[(size_t)MLP_D * REC_D];
__device__ __align__(16) f16   g_p2w2[(size_t)MLP_D * MLP_D];
__device__ __align__(16) f16   g_p3w2[(size_t)P3N * MLP_D];
__device__ __align__(16) f16   g_states2[(size_t)T_LEN * REC_D];
__device__ __align__(16) f16   g_y12[(size_t)T_LEN * MLP_D];
__device__ __align__(16) f16   g_igates[(size_t)T_LEN * G3_D];
__device__ __align__(16) f16   g_hg[(size_t)T_LEN * G3_D];
__device__ __align__(16) f16   g_y2h[(size_t)T_LEN * MLP_D];
__device__ __align__(16) float g_states[(size_t)T_LEN * REC_D];
__device__ float g_hg0[G3_D];
__device__ int   g_age[T_LEN];
__device__ int   g_perm[T_LEN];
__device__ int   g_counts[STEPS + 1];
__device__ int   g_offsets[STEPS + 1];
__device__ int   g_flags[4];
__device__ unsigned g_bar;

// ---------------- helpers ----------------
__device__ __forceinline__ float sigf(float x) { return 1.0f / (1.0f + expf(-x)); }
__device__ __forceinline__ float mishf(float x) {
    float sp = (x > 15.0f) ? x : log1pf(expf(x));
    return x * tanhf(sp);
}
__device__ __forceinline__ uint32_t smem_u32(const void* p) {
    return (uint32_t)__cvta_generic_to_shared(p);
}
__device__ __forceinline__ uint32_t pack2h(f16 a, f16 b) {
    __half2 t; t.x = a; t.y = b;
    return *(uint32_t*)&t;
}
__device__ __forceinline__ void store_state(int t, int j, float v) {
    g_states[(size_t)t * REC_D + j] = v;
    g_states2[(size_t)t * REC_D + j] = __float2half(v);
}
__device__ __forceinline__ float ldh(const f16* p) { return __half2float(*p); }

// ---------------- async / mma primitives (plain compute_100-legal) ----------------
__device__ __forceinline__ void cpasync16(uint32_t sa, const void* ga) {
    asm volatile("cp.async.cg.shared.global [%0], [%1], 16;" :: "r"(sa), "l"(ga));
}
__device__ __forceinline__ void cp_commit() { asm volatile("cp.async.commit_group;" ::: "memory"); }
__device__ __forceinline__ void cp_wait2() { asm volatile("cp.async.wait_group 2;" ::: "memory"); }
__device__ __forceinline__ void cp_wait1() { asm volatile("cp.async.wait_group 1;" ::: "memory"); }
__device__ __forceinline__ void cp_wait0() { asm volatile("cp.async.wait_group 0;" ::: "memory"); }

__device__ __forceinline__ void ldmx4(uint32_t addr, uint32_t& r0, uint32_t& r1, uint32_t& r2, uint32_t& r3) {
    asm volatile("ldmatrix.sync.aligned.m8n8.x4.shared.b16 {%0,%1,%2,%3}, [%4];"
                 : "=r"(r0), "=r"(r1), "=r"(r2), "=r"(r3) : "r"(addr));
}
__device__ __forceinline__ void mma_h(float* c, const uint32_t* a, const uint32_t* b) {
    asm volatile("mma.sync.aligned.m16n8k16.row.col.f32.f16.f16.f32 "
                 "{%0,%1,%2,%3}, {%4,%5,%6,%7}, {%8,%9}, {%0,%1,%2,%3};"
                 : "+f"(c[0]), "+f"(c[1]), "+f"(c[2]), "+f"(c[3])
                 : "r"(a[0]), "r"(a[1]), "r"(a[2]), "r"(a[3]), "r"(b[0]), "r"(b[1]));
}

// ---------------- merged segment analysis (single launch) ----------------
__device__ __forceinline__ bool start_val(const void* p, int mode, int u) {
    if (mode == 0) return ((const unsigned char*)p)[u] != 0;
    if (mode == 1) return ((const int*)p)[u] != 0;
    return ((const float*)p)[u] != 0.0f;
}

__global__ void __launch_bounds__(1024)
analyze_kernel(const unsigned char* __restrict__ p) {
    __shared__ int s_nz[4];
    __shared__ int s_counts[STEPS + 1];
    __shared__ int s_off[STEPS + 1];
    __shared__ int s_cur[STEPS + 1];
    __shared__ int s_mode;
    int tid = threadIdx.x;
    if (tid < 4) s_nz[tid] = 0;
    if (tid < STEPS + 1) { s_counts[tid] = 0; s_cur[tid] = 0; }
    if (tid == 0) g_bar = 0;
    __syncthreads();
    // phase 1: dtype sniff (byte-position nonzero histogram mod 4)
    int cnt = 0;
    for (int i = tid; i < T_LEN; i += 1024) cnt += (p[i] != 0);
    atomicAdd(&s_nz[tid & 3], cnt);
    __syncthreads();
    if (tid == 0) {
        int rest = s_nz[1] + s_nz[2] + s_nz[3];
        int mode;
        if (rest > 0) mode = (s_nz[0] == 0) ? 2 : 0;
        else          mode = (s_nz[0] > 0) ? 1 : 0;
        g_flags[0] = mode;
        bool s0;
        if (mode == 0)      s0 = p[0] != 0;
        else if (mode == 1) s0 = ((const int*)p)[0] != 0;
        else                s0 = ((const float*)p)[0] != 0.0f;
        g_flags[1] = s0 ? 1 : 0;
        s_mode = mode;
    }
    __syncthreads();
    int mode = s_mode;
    // phase 2: age + bucket counts
    for (int t = tid; t < T_LEN; t += 1024) {
        int k = 0, tt = t;
        while (tt > 0 && !start_val(p, mode, tt)) { tt--; k++; }
        g_age[t] = k;
        int b = k < STEPS ? k : STEPS;
        atomicAdd(&s_counts[b], 1);
    }
    __syncthreads();
    // phase 3: offsets
    if (tid == 0) {
        int acc = 0;
        for (int b = 0; b <= STEPS; b++) { s_off[b] = acc; g_offsets[b] = acc; acc += s_counts[b]; }
    }
    if (tid < STEPS + 1) g_counts[tid] = s_counts[tid];
    __syncthreads();
    // phase 4: scatter
    for (int t = tid; t < T_LEN; t += 1024) {
        int a = g_age[t];
        int b = a < STEPS ? a : STEPS;
        int pos = s_off[b] + atomicAdd(&s_cur[b], 1);
        g_perm[pos] = t;
    }
}

// ---------------- merged fp32->fp16 conversions (one launch) ----------------
__global__ void conv_all(const float* s0, f16* d0, size_t n0,
                         const float* s1, f16* d1, size_t n1,
                         const float* s2, f16* d2, size_t n2,
                         const float* s3, f16* d3, size_t n3,
                         const float* s4, f16* d4, size_t n4,
                         const float* s5, f16* d5, size_t n5,
                         const float* s6, f16* d6) {
    size_t stride = (size_t)gridDim.x * blockDim.x;
    size_t i0 = (size_t)blockIdx.x * blockDim.x + threadIdx.x;
    for (size_t i = i0; i < n0; i += stride) d0[i] = __float2half(s0[i]);
    for (size_t i = i0; i < n1; i += stride) d1[i] = __float2half(s1[i]);
    for (size_t i = i0; i < n2; i += stride) d2[i] = __float2half(s2[i]);
    for (size_t i = i0; i < n3; i += stride) d3[i] = __float2half(s3[i]);
    for (size_t i = i0; i < n4; i += stride) d4[i] = __float2half(s4[i]);
    for (size_t i = i0; i < n5; i += stride) d5[i] = __float2half(s5[i]);
    // p3_w [18][1024] fp32 -> [24][1024] f16 zero-padded
    for (size_t i = i0; i < (size_t)P3N * MLP_D; i += stride) {
        int a = (int)(i >> 10);
        d6[i] = (a < ACT_D) ? __float2half(s6[(size_t)a * MLP_D + (i & 1023)]) : __float2half(0.0f);
    }
}

// ---------------- mma.sync GEMM (128x256) with cp.async pipeline (+A-gather) ----------------
#define STG_A_SZ 8192
#define STG_B_SZ 16384
#define STG_SZ (STG_A_SZ + STG_B_SZ)
#define NSTG 4
#define SMEM_GEMM (NSTG * STG_SZ)

__device__ __forceinline__ uint32_t swz(uint32_t base, int r, int seg) {
    return base + r * 64 + 16 * (seg ^ ((r >> 1) & 3));
}

template <int GATHER>
__device__ __forceinline__ void load_stage(const f16* __restrict__ A, const f16* __restrict__ B,
                                           const int* __restrict__ perm, int M,
                                           int rowBase, int colBase, int K, int chunk,
                                           uint32_t sA, uint32_t sB, int tid) {
    const f16* Bb = B + (size_t)colBase * K + chunk * 32;
#pragma unroll
    for (int i = 0; i < 2; i++) {
        int o = tid + i * 256;
        int r = o >> 2, seg = o & 3;
        const f16* src;
        if (GATHER) {
            int gi = rowBase + r;
            gi = gi < M - 1 ? gi : M - 1;
            int t = __ldg(&perm[gi]);
            src = A + (size_t)(t - 1) * K + chunk * 32 + (size_t)seg * 8;
        } else {
            src = A + (size_t)(rowBase + r) * K + chunk * 32 + (size_t)seg * 8;
        }
        cpasync16(swz(sA, r, seg), src);
    }
#pragma unroll
    for (int i = 0; i < 4; i++) {
        int o = tid + i * 256;
        int r = o >> 2, seg = o & 3;
        cpasync16(swz(sB, r, seg), Bb + (size_t)r * K + seg * 8);
    }
}

template <int MISH, int HALFOUT, int GATHER>
__global__ void __launch_bounds__(256)
gemm_ca(const f16* __restrict__ A, const f16* __restrict__ B,
        const float* __restrict__ bias, float* __restrict__ Cf, f16* __restrict__ Cs,
        int Ntot, int K, const int* __restrict__ Mptr, int Mfix, int bucketK) {
    extern __shared__ __align__(16) char dsm[];
    int tid = threadIdx.x, wid = tid >> 5, lane = tid & 31;
    int wm = wid >> 2, wn = wid & 3;
    int M = Mptr ? *Mptr : Mfix;
    const int* perm = GATHER ? (g_perm + g_offsets[bucketK]) : (const int*)0;
    int colBase = blockIdx.x * 256;
    int NC = K >> 5;
    uint32_t sbase = smem_u32(dsm);

    for (int mtile = blockIdx.y; mtile * 128 < M; mtile += gridDim.y) {
        int rowBase = mtile * 128;
        float acc[4][8][4];
#pragma unroll
        for (int mt = 0; mt < 4; mt++)
#pragma unroll
            for (int nt = 0; nt < 8; nt++)
#pragma unroll
                for (int q = 0; q < 4; q++) acc[mt][nt][q] = 0.0f;

#pragma unroll
        for (int p = 0; p < 3; p++) {
            uint32_t sg = sbase + p * STG_SZ;
            load_stage<GATHER>(A, B, perm, M, rowBase, colBase, K, p, sg, sg + STG_A_SZ, tid);
            cp_commit();
        }

        for (int c = 0; c < NC; c++) {
            cp_wait2();
            __syncthreads();
            if (c + 3 < NC) {
                int s = (c + 3) & 3;
                uint32_t sg = sbase + s * STG_SZ;
                load_stage<GATHER>(A, B, perm, M, rowBase, colBase, K, c + 3, sg, sg + STG_A_SZ, tid);
            }
            cp_commit();

            uint32_t sA = sbase + (c & 3) * STG_SZ;
            uint32_t sB = sA + STG_A_SZ;
#pragma unroll
            for (int kk2 = 0; kk2 < 2; kk2++) {
                int seg = kk2 * 2 + (lane >> 4);
                uint32_t af[4][4];
#pragma unroll
                for (int mt = 0; mt < 4; mt++) {
                    int r = wm * 64 + mt * 16 + (lane & 15);
                    ldmx4(swz(sA, r, seg), af[mt][0], af[mt][1], af[mt][2], af[mt][3]);
                }
                uint32_t bb[8][2];
#pragma unroll
                for (int nb = 0; nb < 4; nb++) {
                    int r = wn * 64 + nb * 16 + (lane & 15);
                    uint32_t r0, r1, r2, r3;
                    ldmx4(swz(sB, r, seg), r0, r1, r2, r3);
                    bb[2 * nb][0] = r0;     bb[2 * nb][1] = r2;
                    bb[2 * nb + 1][0] = r1; bb[2 * nb + 1][1] = r3;
                }
#pragma unroll
                for (int mt = 0; mt < 4; mt++)
#pragma unroll
                    for (int nt = 0; nt < 8; nt++)
                        mma_h(acc[mt][nt], af[mt], bb[nt]);
            }
        }
        cp_wait0();
        __syncthreads();

        int rg = lane >> 2, cg = (lane & 3) * 2;
#pragma unroll
        for (int mt = 0; mt < 4; mt++) {
            int R0 = rowBase + wm * 64 + mt * 16 + rg;
#pragma unroll
            for (int nt = 0; nt < 8; nt++) {
                int C = colBase + wn * 64 + nt * 8 + cg;
                float b0 = bias ? bias[C] : 0.0f;
                float b1 = bias ? bias[C + 1] : 0.0f;
                float v00 = acc[mt][nt][0] + b0, v01 = acc[mt][nt][1] + b1;
                float v10 = acc[mt][nt][2] + b0, v11 = acc[mt][nt][3] + b1;
                if (MISH) { v00 = mishf(v00); v01 = mishf(v01); v10 = mishf(v10); v11 = mishf(v11); }
                if (HALFOUT) {
                    *(uint32_t*)&Cs[(size_t)R0 * Ntot + C] =
                        pack2h(__float2half(v00), __float2half(v01));
                    *(uint32_t*)&Cs[(size_t)(R0 + 8) * Ntot + C] =
                        pack2h(__float2half(v10), __float2half(v11));
                } else {
                    float2 a; a.x = v00; a.y = v01;
                    float2 b; b.x = v10; b.y = v11;
                    *(float2*)&Cf[(size_t)R0 * Ntot + C] = a;
                    *(float2*)&Cf[(size_t)(R0 + 8) * Ntot + C] = b;
                }
            }
        }
    }
}

// ---------------- small-tile GEMM (64x128) for small GRU steps: gather + fp16 out ----------------
#define SSTG_A_SZ 4096
#define SSTG_B_SZ 8192
#define SSTG_SZ (SSTG_A_SZ + SSTG_B_SZ)
#define SMEM_SGEMM (NSTG * SSTG_SZ)

__device__ __forceinline__ void load_stage_sm(const f16* __restrict__ A, const f16* __restrict__ B,
                                              const int* __restrict__ perm, int M,
                                              int rowBase, int colBase, int K, int chunk,
                                              uint32_t sA, uint32_t sB, int tid) {
    {
        int r = tid >> 2, seg = tid & 3;
        int gi = rowBase + r;
        gi = gi < M - 1 ? gi : M - 1;
        int t = __ldg(&perm[gi]);
        cpasync16(swz(sA, r, seg), A + (size_t)(t - 1) * K + chunk * 32 + (size_t)seg * 8);
    }
    const f16* Bb = B + (size_t)colBase * K + chunk * 32;
#pragma unroll
    for (int i = 0; i < 2; i++) {
        int o = tid + i * 256;
        int r = o >> 2, seg = o & 3;
        cpasync16(swz(sB, r, seg), Bb + (size_t)r * K + seg * 8);
    }
}

__global__ void __launch_bounds__(256)
gemm_sm(const f16* __restrict__ A, const f16* __restrict__ B, f16* __restrict__ Cs,
        int Ntot, int K, const int* __restrict__ Mptr, int bucketK) {
    extern __shared__ __align__(16) char dsm[];
    int tid = threadIdx.x, wid = tid >> 5, lane = tid & 31;
    int wm = wid >> 2, wn = wid & 3;
    int M = *Mptr;
    const int* perm = g_perm + g_offsets[bucketK];
    int colBase = blockIdx.x * 128;
    int NC = K >> 5;
    uint32_t sbase = smem_u32(dsm);

    for (int mtile = blockIdx.y; mtile * 64 < M; mtile += gridDim.y) {
        int rowBase = mtile * 64;
        float acc[2][4][4];
#pragma unroll
        for (int mt = 0; mt < 2; mt++)
#pragma unroll
            for (int nt = 0; nt < 4; nt++)
#pragma unroll
                for (int q = 0; q < 4; q++) acc[mt][nt][q] = 0.0f;

#pragma unroll
        for (int p = 0; p < 3; p++) {
            uint32_t sg = sbase + p * SSTG_SZ;
            load_stage_sm(A, B, perm, M, rowBase, colBase, K, p, sg, sg + SSTG_A_SZ, tid);
            cp_commit();
        }

        for (int c = 0; c < NC; c++) {
            cp_wait2();
            __syncthreads();
            if (c + 3 < NC) {
                int s = (c + 3) & 3;
                uint32_t sg = sbase + s * SSTG_SZ;
                load_stage_sm(A, B, perm, M, rowBase, colBase, K, c + 3, sg, sg + SSTG_A_SZ, tid);
            }
            cp_commit();

            uint32_t sA = sbase + (c & 3) * SSTG_SZ;
            uint32_t sB = sA + SSTG_A_SZ;
#pragma unroll
            for (int kk2 = 0; kk2 < 2; kk2++) {
                int seg = kk2 * 2 + (lane >> 4);
                uint32_t af[2][4];
#pragma unroll
                for (int mt = 0; mt < 2; mt++) {
                    int r = wm * 32 + mt * 16 + (lane & 15);
                    ldmx4(swz(sA, r, seg), af[mt][0], af[mt][1], af[mt][2], af[mt][3]);
                }
                uint32_t bb[4][2];
#pragma unroll
                for (int nb = 0; nb < 2; nb++) {
                    int r = wn * 32 + nb * 16 + (lane & 15);
                    uint32_t r0, r1, r2, r3;
                    ldmx4(swz(sB, r, seg), r0, r1, r2, r3);
                    bb[2 * nb][0] = r0;     bb[2 * nb][1] = r2;
                    bb[2 * nb + 1][0] = r1; bb[2 * nb + 1][1] = r3;
                }
#pragma unroll
                for (int mt = 0; mt < 2; mt++)
#pragma unroll
                    for (int nt = 0; nt < 4; nt++)
                        mma_h(acc[mt][nt], af[mt], bb[nt]);
            }
        }
        cp_wait0();
        __syncthreads();

        int rg = lane >> 2, cg = (lane & 3) * 2;
#pragma unroll
        for (int mt = 0; mt < 2; mt++) {
            int R0 = rowBase + wm * 32 + mt * 16 + rg;
#pragma unroll
            for (int nt = 0; nt < 4; nt++) {
                int C = colBase + wn * 32 + nt * 8 + cg;
                *(uint32_t*)&Cs[(size_t)R0 * Ntot + C] =
                    pack2h(__float2half(acc[mt][nt][0]), __float2half(acc[mt][nt][1]));
                *(uint32_t*)&Cs[(size_t)(R0 + 8) * Ntot + C] =
                    pack2h(__float2half(acc[mt][nt][2]), __float2half(acc[mt][nt][3]));
            }
        }
    }
}

// ---------------- p3 head on tensor cores: out[T,18] = y2h @ p3w2^T + p3_b ----------------
#define P3_BS_OFF (NSTG * STG_A_SZ)              // 32768: A stages first
#define P3_BS_STRIDE 1032                        // f16 elems per B row (+8 pad: conflict-free)
#define SMEM_P3 (P3_BS_OFF + P3N * P3_BS_STRIDE * 2)

__global__ void __launch_bounds__(256)
gemm_p3(const f16* __restrict__ A, const f16* __restrict__ B,
        const float* __restrict__ bias, float* __restrict__ out) {
    extern __shared__ __align__(16) char dsm[];
    f16* Bs = (f16*)(dsm + P3_BS_OFF);
    int tid = threadIdx.x, wid = tid >> 5, lane = tid & 31;
    int rowBase = blockIdx.x * 128;
    uint32_t sbase = smem_u32(dsm);

    // load full B [24][1024] into padded smem rows
#pragma unroll
    for (int i = 0; i < 12; i++) {
        int o = tid + i * 256;              // 0..3071 (x 8 f16)
        int n = o >> 7, k8 = o & 127;
        *(uint4*)&Bs[n * P3_BS_STRIDE + k8 * 8] = *(const uint4*)&B[(size_t)n * MLP_D + k8 * 8];
    }

    // A pipeline prologue
#pragma unroll
    for (int p = 0; p < 3; p++) {
        uint32_t sg = sbase + p * STG_A_SZ;
        const f16* Ab = A + (size_t)rowBase * MLP_D + p * 32;
#pragma unroll
        for (int i = 0; i < 2; i++) {
            int o = tid + i * 256;
            int r = o >> 2, seg = o & 3;
            cpasync16(swz(sg, r, seg), Ab + (size_t)r * MLP_D + seg * 8);
        }
        cp_commit();
    }

    float acc[3][4];
#pragma unroll
    for (int nt = 0; nt < 3; nt++)
#pragma unroll
        for (int q = 0; q < 4; q++) acc[nt][q] = 0.0f;

    int cf = lane >> 2, k0 = (lane & 3) * 2;
    const int NC = MLP_D / 32;
    for (int c = 0; c < NC; c++) {
        cp_wait2();
        __syncthreads();
        if (c + 3 < NC) {
            uint32_t sg = sbase + ((c + 3) & 3) * STG_A_SZ;
            const f16* Ab = A + (size_t)rowBase * MLP_D + (c + 3) * 32;
#pragma unroll
            for (int i = 0; i < 2; i++) {
                int o = tid + i * 256;
                int r = o >> 2, seg = o & 3;
                cpasync16(swz(sg, r, seg), Ab + (size_t)r * MLP_D + seg * 8);
            }
        }
        cp_commit();

        uint32_t sA = sbase + (c & 3) * STG_A_SZ;
#pragma unroll
        for (int kk2 = 0; kk2 < 2; kk2++) {
            int seg = kk2 * 2 + (lane >> 4);
            uint32_t af[4];
            int r = wid * 16 + (lane & 15);
            ldmx4(swz(sA, r, seg), af[0], af[1], af[2], af[3]);
            int kbase = c * 32 + kk2 * 16;
#pragma unroll
            for (int nt = 0; nt < 3; nt++) {
                int n = nt * 8 + cf;
                uint32_t bfr[2];
                bfr[0] = *(const uint32_t*)&Bs[n * P3_BS_STRIDE + kbase + k0];
                bfr[1] = *(const uint32_t*)&Bs[n * P3_BS_STRIDE + kbase + k0 + 8];
                mma_h(acc[nt], af, bfr);
            }
        }
    }
    cp_wait0();

    int rg = lane >> 2, cg = (lane & 3) * 2;
#pragma unroll
    for (int nt = 0; nt < 3; nt++) {
        int col = nt * 8 + cg;
        int R0 = rowBase + wid * 16 + rg;
        if (col < ACT_D) {
            float b = bias[col];
            out[(size_t)R0 * ACT_D + col] = acc[nt][0] + b;
            out[(size_t)(R0 + 8) * ACT_D + col] = acc[nt][2] + b;
        }
        if (col + 1 < ACT_D) {
            float b = bias[col + 1];
            out[(size_t)R0 * ACT_D + col + 1] = acc[nt][1] + b;
            out[(size_t)(R0 + 8) * ACT_D + col + 1] = acc[nt][3] + b;
        }
    }
}

// ---------------- GRU step k==0 (h_prev == 0) ----------------
__global__ void step0_kernel(const float* __restrict__ b_n) {
    int count = g_counts[0];
    long total = (long)count * REC_D;
    long stride = (long)gridDim.x * blockDim.x;
    for (long idx = (long)blockIdx.x * blockDim.x + threadIdx.x; idx < total; idx += stride) {
        int i = (int)(idx >> 10);
        int j = (int)(idx & 1023);
        int t = g_perm[i];
        float igr = ldh(&g_igates[(size_t)t * G3_D + j]);
        float igz = ldh(&g_igates[(size_t)t * G3_D + 1024 + j]);
        float ign = ldh(&g_igates[(size_t)t * G3_D + 2048 + j]);
        float r = sigf(igr);
        float z = sigf(igz);
        float n = tanhf(ign + r * b_n[j]);
        store_state(t, j, n - z * n);
    }
}

__global__ void fixA_kernel(const float* __restrict__ w_hh, const float* __restrict__ state) {
    if (g_flags[1]) return;
    int j = blockIdx.x * 8 + (threadIdx.x >> 5);
    int lane = threadIdx.x & 31;
    float acc = 0.0f;
    const float* wr = w_hh + (size_t)j * REC_D;
    for (int k = lane; k < REC_D; k += 32) acc += wr[k] * state[k];
#pragma unroll
    for (int o = 16; o > 0; o >>= 1) acc += __shfl_down_sync(0xffffffffu, acc, o);
    if (lane == 0) g_hg0[j] = acc;
}

__global__ void fixB_kernel(const float* __restrict__ state, const float* __restrict__ b_n) {
    if (g_flags[1]) return;
    int j = threadIdx.x;
    float igr = ldh(&g_igates[j]), igz = ldh(&g_igates[1024 + j]), ign = ldh(&g_igates[2048 + j]);
    float r = sigf(igr + g_hg0[j]);
    float z = sigf(igz + g_hg0[1024 + j]);
    float n = tanhf(ign + r * (g_hg0[2048 + j] + b_n[j]));
    float hp = state[j];
    store_state(0, j, n + z * (hp - n));
}

// gate math for GEMM steps (consumes fp16 g_hg)
__global__ void gru_gate(const float* __restrict__ b_n, int k) {
    int count = g_counts[k];
    int base = g_offsets[k];
    long total = (long)count * REC_D;
    long stride = (long)gridDim.x * blockDim.x;
    for (long idx = (long)blockIdx.x * blockDim.x + threadIdx.x; idx < total; idx += stride) {
        int i = (int)(idx >> 10);
        int j = (int)(idx & 1023);
        int t = g_perm[base + i];
        float hr = ldh(&g_hg[(size_t)i * G3_D + j]);
        float hz = ldh(&g_hg[(size_t)i * G3_D + 1024 + j]);
        float hn = ldh(&g_hg[(size_t)i * G3_D + 2048 + j]);
        float igr = ldh(&g_igates[(size_t)t * G3_D + j]);
        float igz = ldh(&g_igates[(size_t)t * G3_D + 1024 + j]);
        float ign = ldh(&g_igates[(size_t)t * G3_D + 2048 + j]);
        float hp = g_states[(size_t)(t - 1) * REC_D + j];
        float r = sigf(igr + hr);
        float z = sigf(igz + hz);
        float n = tanhf(ign + r * (hn + b_n[j]));
        store_state(t, j, n + z * (hp - n));
    }
}

// ---------------- persistent tail: double-buffered SMEM h, fp16 weights ----------------
__device__ __forceinline__ void tail_prefetch(int t, __half2* buf, int tid) {
    if (tid < 128) {
        const char* src = (const char*)(g_states2 + (size_t)(t - 1) * REC_D) + tid * 16;
        cpasync16(smem_u32((char*)buf + tid * 16), src);
    }
}

__global__ void __launch_bounds__(256)
gru_tail_persistent(const float* __restrict__ b_n) {
    __shared__ __align__(16) __half2 sh[2][REC_D / 2];
    int tid = threadIdx.x;
    int wid = tid >> 5;
    int j = blockIdx.x * 8 + wid;
    int lane = tid & 31;
    const __half2* wr2 = (const __half2*)(g_whh2 + (size_t)j * REC_D);
    const __half2* wz2 = (const __half2*)(g_whh2 + (size_t)(1024 + j) * REC_D);
    const __half2* wn2 = (const __half2*)(g_whh2 + (size_t)(2048 + j) * REC_D);
    __half2 wr[16], wz[16], wn[16];
#pragma unroll
    for (int q = 0; q < 16; q++) {
        wr[q] = wr2[lane + q * 32];
        wz[q] = wz2[lane + q * 32];
        wn[q] = wn2[lane + q * 32];
    }
    float bn = b_n[j];
    unsigned nb = gridDim.x;
    unsigned bc = 0;

    for (int k = GEMM_STEPS; k < STEPS; k++) {
        int count = g_counts[k];
        int base = g_offsets[k];
        if (count <= 0) continue;   // consistent across blocks
        tail_prefetch(g_perm[base], sh[0], tid);
        cp_commit();
        for (int i = 0; i < count; i++) {
            if (i + 1 < count) tail_prefetch(g_perm[base + i + 1], sh[(i + 1) & 1], tid);
            cp_commit();
            if (i + 1 < count) cp_wait1(); else cp_wait0();
            __syncthreads();
            const __half2* hb = sh[i & 1];
            int t = g_perm[base + i];
            float aR = 0.0f, aZ = 0.0f, aN = 0.0f;
#pragma unroll
            for (int q = 0; q < 16; q++) {
                float2 hf = __half22float2(hb[lane + q * 32]);
                float2 rf = __half22float2(wr[q]);
                float2 zf = __half22float2(wz[q]);
                float2 nf = __half22float2(wn[q]);
                aR += rf.x * hf.x + rf.y * hf.y;
                aZ += zf.x * hf.x + zf.y * hf.y;
                aN += nf.x * hf.x + nf.y * hf.y;
            }
#pragma unroll
            for (int o = 16; o > 0; o >>= 1) {
                aR += __shfl_xor_sync(0xffffffffu, aR, o);
                aZ += __shfl_xor_sync(0xffffffffu, aZ, o);
                aN += __shfl_xor_sync(0xffffffffu, aN, o);
            }
            if (lane == 0) {
                float igr = ldh(&g_igates[(size_t)t * G3_D + j]);
                float igz = ldh(&g_igates[(size_t)t * G3_D + 1024 + j]);
                float ign = ldh(&g_igates[(size_t)t * G3_D + 2048 + j]);
                float hp = __ldcg(&g_states[(size_t)(t - 1) * REC_D + j]);
                float r = sigf(igr + aR);
                float z = sigf(igz + aZ);
                float n = tanhf(ign + r * (aN + bn));
                store_state(t, j, n + z * (hp - n));
            }
            __syncthreads();
        }
        bc++;
        __syncthreads();
        if (tid == 0) {
            __threadfence();
            atomicAdd(&g_bar, 1u);
            while (*((volatile unsigned*)&g_bar) < bc * nb) {}
        }
        __syncthreads();
    }
}

// safety net for age >= STEPS (count ~0 in practice)
__global__ void __launch_bounds__(1024)
cleanup_kernel(const float* __restrict__ w_hh, const float* __restrict__ b_n) {
    if (g_counts[STEPS] == 0) return;
    __shared__ int s_t;
    __shared__ int s_cur;
    __shared__ float sh[REC_D];
    int tid = threadIdx.x;
    if (tid == 0) s_cur = STEPS;
    __syncthreads();
    while (true) {
        if (tid == 0) {
            s_t = -1;
            for (int u = s_cur; u < T_LEN; ++u)
                if (g_age[u] >= STEPS) { s_t = u; s_cur = u + 1; break; }
        }
        __syncthreads();
        int t = s_t;
        if (t < 0) break;
        sh[tid] = g_states[(size_t)(t - 1) * REC_D + tid];
        __syncthreads();
        float aRv = 0, aZv = 0, aNv = 0;
        const float* wr = w_hh + (size_t)tid * REC_D;
        const float* wz = w_hh + (size_t)(1024 + tid) * REC_D;
        const float* wn = w_hh + (size_t)(2048 + tid) * REC_D;
        for (int kk = 0; kk < REC_D; kk++) {
            float h = sh[kk];
            aRv += wr[kk] * h; aZv += wz[kk] * h; aNv += wn[kk] * h;
        }
        float igr = ldh(&g_igates[(size_t)t * G3_D + tid]);
        float igz = ldh(&g_igates[(size_t)t * G3_D + 1024 + tid]);
        float ign = ldh(&g_igates[(size_t)t * G3_D + 2048 + tid]);
        float r = sigf(igr + aRv);
        float z = sigf(igz + aZv);
        float n = tanhf(ign + r * (aNv + b_n[tid]));
        float hp = sh[tid];
        store_state(t, tid, n + z * (hp - n));
        __syncthreads();
    }
}

__global__ void copy_state_kernel(float* __restrict__ out) {
    out[threadIdx.x] = g_states[(size_t)(T_LEN - 1) * REC_D + threadIdx.x];
}

// ---------------- host ----------------
extern "C" void kernel_launch(void* const* d_in, const int* in_sizes, int n_in,
                              void* d_out, int out_size) {
    const float* x     = (const float*)d_in[0];
    const float* state = (const float*)d_in[1];
    const void*  start = d_in[2];
    const float* pre_w = (const float*)d_in[4];
    const float* pre_b = (const float*)d_in[5];
    const float* w_ih  = (const float*)d_in[6];
    const float* w_hh  = (const float*)d_in[7];
    const float* b_ih  = (const float*)d_in[8];
    const float* b_n   = (const float*)d_in[9];
    const float* p1_w  = (const float*)d_in[10];
    const float* p1_b  = (const float*)d_in[11];
    const float* p2_w  = (const float*)d_in[12];
    const float* p2_b  = (const float*)d_in[13];
    const float* p3_w  = (const float*)d_in[14];
    const float* p3_b  = (const float*)d_in[15];
    float* out = (float*)d_out;

    f16 *x2, *prew2, *feat2, *wih2, *whh2, *p1w2, *p2w2, *p3w2, *states2, *y12;
    f16 *igates, *hg, *y2h;
    int* counts_dev;
    cudaGetSymbolAddress((void**)&igates, g_igates);
    cudaGetSymbolAddress((void**)&hg, g_hg);
    cudaGetSymbolAddress((void**)&y2h, g_y2h);
    cudaGetSymbolAddress((void**)&x2, g_x2);
    cudaGetSymbolAddress((void**)&prew2, g_prew2);
    cudaGetSymbolAddress((void**)&feat2, g_feat2);
    cudaGetSymbolAddress((void**)&wih2, g_wih2);
    cudaGetSymbolAddress((void**)&whh2, g_whh2);
    cudaGetSymbolAddress((void**)&p1w2, g_p1w2);
    cudaGetSymbolAddress((void**)&p2w2, g_p2w2);
    cudaGetSymbolAddress((void**)&p3w2, g_p3w2);
    cudaGetSymbolAddress((void**)&states2, g_states2);
    cudaGetSymbolAddress((void**)&y12, g_y12);
    cudaGetSymbolAddress((void**)&counts_dev, g_counts);

    cudaFuncSetAttribute(gemm_ca<1, 1, 0>, cudaFuncAttributeMaxDynamicSharedMemorySize, SMEM_GEMM);
    cudaFuncSetAttribute(gemm_ca<0, 1, 0>, cudaFuncAttributeMaxDynamicSharedMemorySize, SMEM_GEMM);
    cudaFuncSetAttribute(gemm_ca<0, 1, 1>, cudaFuncAttributeMaxDynamicSharedMemorySize, SMEM_GEMM);
    cudaFuncSetAttribute(gemm_sm, cudaFuncAttributeMaxDynamicSharedMemorySize, SMEM_SGEMM);
    cudaFuncSetAttribute(gemm_p3, cudaFuncAttributeMaxDynamicSharedMemorySize, SMEM_P3);

    // segment analysis (single launch)
    analyze_kernel<<<1, 1024>>>((const unsigned char*)start);

    // all conversions in one launch (incl. padded p3 weights)
    conv_all<<<1024, 256>>>(pre_w, prew2, (size_t)MLP_D * OBS_D,
                            w_ih, wih2, (size_t)G3_D * MLP_D,
                            w_hh, whh2, (size_t)G3_D * REC_D,
                            p1_w, p1w2, (size_t)MLP_D * REC_D,
                            p2_w, p2w2, (size_t)MLP_D * MLP_D,
                            x, x2, (size_t)T_LEN * OBS_D,
                            p3_w, p3w2);

    // feat = mish(x @ pre_w^T + pre_b)
    gemm_ca<1, 1, 0><<<dim3(MLP_D / 256, 128), 256, SMEM_GEMM>>>(
        x2, prew2, pre_b, nullptr, feat2, MLP_D, OBS_D, nullptr, T_LEN, 0);
    // igates = feat @ w_ih^T + b_ih (fp16 out)
    gemm_ca<0, 1, 0><<<dim3(G3_D / 256, 128), 256, SMEM_GEMM>>>(
        feat2, wih2, b_ih, nullptr, igates, G3_D, MLP_D, nullptr, T_LEN, 0);

    // segment-parallel GRU scan
    step0_kernel<<<2048, 256>>>(b_n);
    fixA_kernel<<<384, 256>>>(w_hh, state);
    fixB_kernel<<<1, 1024>>>(state, b_n);
    for (int k = 1; k < GEMM_STEPS; k++) {
        int est = T_LEN >> k;
        if (k == 1) {
            int gy = est / 128; if (gy < 1) gy = 1; if (gy > 64) gy = 64;
            gemm_ca<0, 1, 1><<<dim3(G3_D / 256, gy), 256, SMEM_GEMM>>>(
                states2, whh2, nullptr, nullptr, hg, G3_D, REC_D, counts_dev + k, 0, k);
        } else {
            int gy = est / 64; if (gy < 1) gy = 1; if (gy > 32) gy = 32;
            gemm_sm<<<dim3(G3_D / 128, gy), 256, SMEM_SGEMM>>>(
                states2, whh2, hg, G3_D, REC_D, counts_dev + k, k);
        }
        gru_gate<<<2048, 256>>>(b_n, k);
    }
    gru_tail_persistent<<<TAIL_BLOCKS, 256>>>(b_n);
    cleanup_kernel<<<1, 1024>>>(w_hh, b_n);

    // post MLP
    gemm_ca<1, 1, 0><<<dim3(MLP_D / 256, 128), 256, SMEM_GEMM>>>(
        states2, p1w2, p1_b, nullptr, y12, MLP_D, REC_D, nullptr, T_LEN, 0);
    gemm_ca<1, 1, 0><<<dim3(MLP_D / 256, 128), 256, SMEM_GEMM>>>(
        y12, p2w2, p2_b, nullptr, y2h, MLP_D, MLP_D, nullptr, T_LEN, 0);
    gemm_p3<<<T_LEN / 128, 256, SMEM_P3>>>(y2h, p3w2, p3_b, out);

    if (out_size >= T_LEN * ACT_D + REC_D)
        copy_state_kernel<<<1, 1024>>>(out + (size_t)T_LEN * ACT_D);
}

// round 12
// speedup vs baseline: 5.1012x; 1.0003x over previous
#include <cuda_runtime.h>
#include <cuda_fp16.h>
#include <math.h>
#include <stdint.h>

#define T_LEN 16384
#define OBS_D 256
#define MLP_D 1024
#define REC_D 1024
#define G3_D  3072
#define ACT_D 18
#define P3N   24
#define STEPS 26
#define GEMM_STEPS 9
#define TAIL_BLOCKS 128

typedef __half f16;

// ---------------- scratch (device globals; no allocation allowed) ----------------
__device__ __align__(16) f16   g_x2[(size_t)T_LEN * OBS_D];
__device__ __align__(16) f16   g_prew2[(size_t)MLP_D * OBS_D];
__device__ __align__(16) f16   g_feat2[(size_t)T_LEN * MLP_D];
__device__ __align__(16) f16   g_wih2[(size_t)G3_D * MLP_D];
__device__ __align__(16) f16   g_whh2[(size_t)G3_D * REC_D];
__device__ __align__(16) f16   g_p1w2[(size_t)MLP_D * REC_D];
__device__ __align__(16) f16   g_p2w2[(size_t)MLP_D * MLP_D];
__device__ __align__(16) f16   g_p3w2[(size_t)P3N * MLP_D];
__device__ __align__(16) f16   g_states2[(size_t)T_LEN * REC_D];
__device__ __align__(16) f16   g_y12[(size_t)T_LEN * MLP_D];
__device__ __align__(16) f16   g_igates[(size_t)T_LEN * G3_D];
__device__ __align__(16) f16   g_hg[(size_t)T_LEN * G3_D];
__device__ __align__(16) f16   g_y2h[(size_t)T_LEN * MLP_D];
__device__ __align__(16) float g_states[(size_t)T_LEN * REC_D];
__device__ float g_hg0[G3_D];
__device__ int   g_age[T_LEN];
__device__ int   g_perm[T_LEN];
__device__ int   g_counts[STEPS + 1];
__device__ int   g_offsets[STEPS + 1];
__device__ int   g_flags[4];
__device__ unsigned g_bar;

// ---------------- helpers ----------------
__device__ __forceinline__ float sigf(float x) { return 1.0f / (1.0f + expf(-x)); }
__device__ __forceinline__ float mishf(float x) {
    float sp = (x > 15.0f) ? x : log1pf(expf(x));
    return x * tanhf(sp);
}
__device__ __forceinline__ uint32_t smem_u32(const void* p) {
    return (uint32_t)__cvta_generic_to_shared(p);
}
__device__ __forceinline__ uint32_t pack2h(f16 a, f16 b) {
    __half2 t; t.x = a; t.y = b;
    return *(uint32_t*)&t;
}
__device__ __forceinline__ void store_state(int t, int j, float v) {
    g_states[(size_t)t * REC_D + j] = v;
    g_states2[(size_t)t * REC_D + j] = __float2half(v);
}
__device__ __forceinline__ float ldh(const f16* p) { return __half2float(*p); }

// ---------------- async / mma primitives (plain compute_100-legal) ----------------
__device__ __forceinline__ void cpasync16(uint32_t sa, const void* ga) {
    asm volatile("cp.async.cg.shared.global [%0], [%1], 16;" :: "r"(sa), "l"(ga));
}
__device__ __forceinline__ void cp_commit() { asm volatile("cp.async.commit_group;" ::: "memory"); }
__device__ __forceinline__ void cp_wait2() { asm volatile("cp.async.wait_group 2;" ::: "memory"); }
__device__ __forceinline__ void cp_wait1() { asm volatile("cp.async.wait_group 1;" ::: "memory"); }
__device__ __forceinline__ void cp_wait0() { asm volatile("cp.async.wait_group 0;" ::: "memory"); }

__device__ __forceinline__ void ldmx4(uint32_t addr, uint32_t& r0, uint32_t& r1, uint32_t& r2, uint32_t& r3) {
    asm volatile("ldmatrix.sync.aligned.m8n8.x4.shared.b16 {%0,%1,%2,%3}, [%4];"
                 : "=r"(r0), "=r"(r1), "=r"(r2), "=r"(r3) : "r"(addr));
}
__device__ __forceinline__ void mma_h(float* c, const uint32_t* a, const uint32_t* b) {
    asm volatile("mma.sync.aligned.m16n8k16.row.col.f32.f16.f16.f32 "
                 "{%0,%1,%2,%3}, {%4,%5,%6,%7}, {%8,%9}, {%0,%1,%2,%3};"
                 : "+f"(c[0]), "+f"(c[1]), "+f"(c[2]), "+f"(c[3])
                 : "r"(a[0]), "r"(a[1]), "r"(a[2]), "r"(a[3]), "r"(b[0]), "r"(b[1]));
}

// ---------------- merged segment analysis (single launch) ----------------
__device__ __forceinline__ bool start_val(const void* p, int mode, int u) {
    if (mode == 0) return ((const unsigned char*)p)[u] != 0;
    if (mode == 1) return ((const int*)p)[u] != 0;
    return ((const float*)p)[u] != 0.0f;
}

__global__ void __launch_bounds__(1024)
analyze_kernel(const unsigned char* __restrict__ p) {
    __shared__ int s_nz[4];
    __shared__ int s_counts[STEPS + 1];
    __shared__ int s_off[STEPS + 1];
    __shared__ int s_cur[STEPS + 1];
    __shared__ int s_mode;
    int tid = threadIdx.x;
    if (tid < 4) s_nz[tid] = 0;
    if (tid < STEPS + 1) { s_counts[tid] = 0; s_cur[tid] = 0; }
    if (tid == 0) g_bar = 0;
    __syncthreads();
    // phase 1: dtype sniff (byte-position nonzero histogram mod 4)
    int cnt = 0;
    for (int i = tid; i < T_LEN; i += 1024) cnt += (p[i] != 0);
    atomicAdd(&s_nz[tid & 3], cnt);
    __syncthreads();
    if (tid == 0) {
        int rest = s_nz[1] + s_nz[2] + s_nz[3];
        int mode;
        if (rest > 0) mode = (s_nz[0] == 0) ? 2 : 0;
        else          mode = (s_nz[0] > 0) ? 1 : 0;
        g_flags[0] = mode;
        bool s0;
        if (mode == 0)      s0 = p[0] != 0;
        else if (mode == 1) s0 = ((const int*)p)[0] != 0;
        else                s0 = ((const float*)p)[0] != 0.0f;
        g_flags[1] = s0 ? 1 : 0;
        s_mode = mode;
    }
    __syncthreads();
    int mode = s_mode;
    // phase 2: age + bucket counts
    for (int t = tid; t < T_LEN; t += 1024) {
        int k = 0, tt = t;
        while (tt > 0 && !start_val(p, mode, tt)) { tt--; k++; }
        g_age[t] = k;
        int b = k < STEPS ? k : STEPS;
        atomicAdd(&s_counts[b], 1);
    }
    __syncthreads();
    // phase 3: offsets
    if (tid == 0) {
        int acc = 0;
        for (int b = 0; b <= STEPS; b++) { s_off[b] = acc; g_offsets[b] = acc; acc += s_counts[b]; }
    }
    if (tid < STEPS + 1) g_counts[tid] = s_counts[tid];
    __syncthreads();
    // phase 4: scatter
    for (int t = tid; t < T_LEN; t += 1024) {
        int a = g_age[t];
        int b = a < STEPS ? a : STEPS;
        int pos = s_off[b] + atomicAdd(&s_cur[b], 1);
        g_perm[pos] = t;
    }
}

// ---------------- merged fp32->fp16 conversions (one launch) ----------------
__global__ void conv_all(const float* s0, f16* d0, size_t n0,
                         const float* s1, f16* d1, size_t n1,
                         const float* s2, f16* d2, size_t n2,
                         const float* s3, f16* d3, size_t n3,
                         const float* s4, f16* d4, size_t n4,
                         const float* s5, f16* d5, size_t n5,
                         const float* s6, f16* d6) {
    size_t stride = (size_t)gridDim.x * blockDim.x;
    size_t i0 = (size_t)blockIdx.x * blockDim.x + threadIdx.x;
    for (size_t i = i0; i < n0; i += stride) d0[i] = __float2half(s0[i]);
    for (size_t i = i0; i < n1; i += stride) d1[i] = __float2half(s1[i]);
    for (size_t i = i0; i < n2; i += stride) d2[i] = __float2half(s2[i]);
    for (size_t i = i0; i < n3; i += stride) d3[i] = __float2half(s3[i]);
    for (size_t i = i0; i < n4; i += stride) d4[i] = __float2half(s4[i]);
    for (size_t i = i0; i < n5; i += stride) d5[i] = __float2half(s5[i]);
    // p3_w [18][1024] fp32 -> [24][1024] f16 zero-padded
    for (size_t i = i0; i < (size_t)P3N * MLP_D; i += stride) {
        int a = (int)(i >> 10);
        d6[i] = (a < ACT_D) ? __float2half(s6[(size_t)a * MLP_D + (i & 1023)]) : __float2half(0.0f);
    }
}

// ---------------- mma.sync GEMM (128x256) with cp.async pipeline (+A-gather) ----------------
#define STG_A_SZ 8192
#define STG_B_SZ 16384
#define STG_SZ (STG_A_SZ + STG_B_SZ)
#define NSTG 4
#define SMEM_GEMM (NSTG * STG_SZ)

__device__ __forceinline__ uint32_t swz(uint32_t base, int r, int seg) {
    return base + r * 64 + 16 * (seg ^ ((r >> 1) & 3));
}

template <int GATHER>
__device__ __forceinline__ void load_stage(const f16* __restrict__ A, const f16* __restrict__ B,
                                           const int* __restrict__ perm, int M,
                                           int rowBase, int colBase, int K, int chunk,
                                           uint32_t sA, uint32_t sB, int tid) {
    const f16* Bb = B + (size_t)colBase * K + chunk * 32;
#pragma unroll
    for (int i = 0; i < 2; i++) {
        int o = tid + i * 256;
        int r = o >> 2, seg = o & 3;
        const f16* src;
        if (GATHER) {
            int gi = rowBase + r;
            gi = gi < M - 1 ? gi : M - 1;
            int t = __ldg(&perm[gi]);
            src = A + (size_t)(t - 1) * K + chunk * 32 + (size_t)seg * 8;
        } else {
            src = A + (size_t)(rowBase + r) * K + chunk * 32 + (size_t)seg * 8;
        }
        cpasync16(swz(sA, r, seg), src);
    }
#pragma unroll
    for (int i = 0; i < 4; i++) {
        int o = tid + i * 256;
        int r = o >> 2, seg = o & 3;
        cpasync16(swz(sB, r, seg), Bb + (size_t)r * K + seg * 8);
    }
}

template <int MISH, int HALFOUT, int GATHER>
__global__ void __launch_bounds__(256)
gemm_ca(const f16* __restrict__ A, const f16* __restrict__ B,
        const float* __restrict__ bias, float* __restrict__ Cf, f16* __restrict__ Cs,
        int Ntot, int K, const int* __restrict__ Mptr, int Mfix, int bucketK) {
    extern __shared__ __align__(16) char dsm[];
    int tid = threadIdx.x, wid = tid >> 5, lane = tid & 31;
    int wm = wid >> 2, wn = wid & 3;
    int M = Mptr ? *Mptr : Mfix;
    const int* perm = GATHER ? (g_perm + g_offsets[bucketK]) : (const int*)0;
    int colBase = blockIdx.x * 256;
    int NC = K >> 5;
    uint32_t sbase = smem_u32(dsm);

    for (int mtile = blockIdx.y; mtile * 128 < M; mtile += gridDim.y) {
        int rowBase = mtile * 128;
        float acc[4][8][4];
#pragma unroll
        for (int mt = 0; mt < 4; mt++)
#pragma unroll
            for (int nt = 0; nt < 8; nt++)
#pragma unroll
                for (int q = 0; q < 4; q++) acc[mt][nt][q] = 0.0f;

#pragma unroll
        for (int p = 0; p < 3; p++) {
            uint32_t sg = sbase + p * STG_SZ;
            load_stage<GATHER>(A, B, perm, M, rowBase, colBase, K, p, sg, sg + STG_A_SZ, tid);
            cp_commit();
        }

        for (int c = 0; c < NC; c++) {
            cp_wait2();
            __syncthreads();
            if (c + 3 < NC) {
                int s = (c + 3) & 3;
                uint32_t sg = sbase + s * STG_SZ;
                load_stage<GATHER>(A, B, perm, M, rowBase, colBase, K, c + 3, sg, sg + STG_A_SZ, tid);
            }
            cp_commit();

            uint32_t sA = sbase + (c & 3) * STG_SZ;
            uint32_t sB = sA + STG_A_SZ;
#pragma unroll
            for (int kk2 = 0; kk2 < 2; kk2++) {
                int seg = kk2 * 2 + (lane >> 4);
                uint32_t af[4][4];
#pragma unroll
                for (int mt = 0; mt < 4; mt++) {
                    int r = wm * 64 + mt * 16 + (lane & 15);
                    ldmx4(swz(sA, r, seg), af[mt][0], af[mt][1], af[mt][2], af[mt][3]);
                }
                uint32_t bb[8][2];
#pragma unroll
                for (int nb = 0; nb < 4; nb++) {
                    int r = wn * 64 + nb * 16 + (lane & 15);
                    uint32_t r0, r1, r2, r3;
                    ldmx4(swz(sB, r, seg), r0, r1, r2, r3);
                    bb[2 * nb][0] = r0;     bb[2 * nb][1] = r2;
                    bb[2 * nb + 1][0] = r1; bb[2 * nb + 1][1] = r3;
                }
#pragma unroll
                for (int mt = 0; mt < 4; mt++)
#pragma unroll
                    for (int nt = 0; nt < 8; nt++)
                        mma_h(acc[mt][nt], af[mt], bb[nt]);
            }
        }
        cp_wait0();
        __syncthreads();

        int rg = lane >> 2, cg = (lane & 3) * 2;
#pragma unroll
        for (int mt = 0; mt < 4; mt++) {
            int R0 = rowBase + wm * 64 + mt * 16 + rg;
#pragma unroll
            for (int nt = 0; nt < 8; nt++) {
                int C = colBase + wn * 64 + nt * 8 + cg;
                float b0 = bias ? bias[C] : 0.0f;
                float b1 = bias ? bias[C + 1] : 0.0f;
                float v00 = acc[mt][nt][0] + b0, v01 = acc[mt][nt][1] + b1;
                float v10 = acc[mt][nt][2] + b0, v11 = acc[mt][nt][3] + b1;
                if (MISH) { v00 = mishf(v00); v01 = mishf(v01); v10 = mishf(v10); v11 = mishf(v11); }
                if (HALFOUT) {
                    *(uint32_t*)&Cs[(size_t)R0 * Ntot + C] =
                        pack2h(__float2half(v00), __float2half(v01));
                    *(uint32_t*)&Cs[(size_t)(R0 + 8) * Ntot + C] =
                        pack2h(__float2half(v10), __float2half(v11));
                } else {
                    float2 a; a.x = v00; a.y = v01;
                    float2 b; b.x = v10; b.y = v11;
                    *(float2*)&Cf[(size_t)R0 * Ntot + C] = a;
                    *(float2*)&Cf[(size_t)(R0 + 8) * Ntot + C] = b;
                }
            }
        }
    }
}

// ---------------- small-tile GEMM (64x128) for small GRU steps: gather + fp16 out ----------------
#define SSTG_A_SZ 4096
#define SSTG_B_SZ 8192
#define SSTG_SZ (SSTG_A_SZ + SSTG_B_SZ)
#define SMEM_SGEMM (NSTG * SSTG_SZ)

__device__ __forceinline__ void load_stage_sm(const f16* __restrict__ A, const f16* __restrict__ B,
                                              const int* __restrict__ perm, int M,
                                              int rowBase, int colBase, int K, int chunk,
                                              uint32_t sA, uint32_t sB, int tid) {
    {
        int r = tid >> 2, seg = tid & 3;
        int gi = rowBase + r;
        gi = gi < M - 1 ? gi : M - 1;
        int t = __ldg(&perm[gi]);
        cpasync16(swz(sA, r, seg), A + (size_t)(t - 1) * K + chunk * 32 + (size_t)seg * 8);
    }
    const f16* Bb = B + (size_t)colBase * K + chunk * 32;
#pragma unroll
    for (int i = 0; i < 2; i++) {
        int o = tid + i * 256;
        int r = o >> 2, seg = o & 3;
        cpasync16(swz(sB, r, seg), Bb + (size_t)r * K + seg * 8);
    }
}

__global__ void __launch_bounds__(256)
gemm_sm(const f16* __restrict__ A, const f16* __restrict__ B, f16* __restrict__ Cs,
        int Ntot, int K, const int* __restrict__ Mptr, int bucketK) {
    extern __shared__ __align__(16) char dsm[];
    int tid = threadIdx.x, wid = tid >> 5, lane = tid & 31;
    int wm = wid >> 2, wn = wid & 3;
    int M = *Mptr;
    const int* perm = g_perm + g_offsets[bucketK];
    int colBase = blockIdx.x * 128;
    int NC = K >> 5;
    uint32_t sbase = smem_u32(dsm);

    for (int mtile = blockIdx.y; mtile * 64 < M; mtile += gridDim.y) {
        int rowBase = mtile * 64;
        float acc[2][4][4];
#pragma unroll
        for (int mt = 0; mt < 2; mt++)
#pragma unroll
            for (int nt = 0; nt < 4; nt++)
#pragma unroll
                for (int q = 0; q < 4; q++) acc[mt][nt][q] = 0.0f;

#pragma unroll
        for (int p = 0; p < 3; p++) {
            uint32_t sg = sbase + p * SSTG_SZ;
            load_stage_sm(A, B, perm, M, rowBase, colBase, K, p, sg, sg + SSTG_A_SZ, tid);
            cp_commit();
        }

        for (int c = 0; c < NC; c++) {
            cp_wait2();
            __syncthreads();
            if (c + 3 < NC) {
                int s = (c + 3) & 3;
                uint32_t sg = sbase + s * SSTG_SZ;
                load_stage_sm(A, B, perm, M, rowBase, colBase, K, c + 3, sg, sg + SSTG_A_SZ, tid);
            }
            cp_commit();

            uint32_t sA = sbase + (c & 3) * SSTG_SZ;
            uint32_t sB = sA + SSTG_A_SZ;
#pragma unroll
            for (int kk2 = 0; kk2 < 2; kk2++) {
                int seg = kk2 * 2 + (lane >> 4);
                uint32_t af[2][4];
#pragma unroll
                for (int mt = 0; mt < 2; mt++) {
                    int r = wm * 32 + mt * 16 + (lane & 15);
                    ldmx4(swz(sA, r, seg), af[mt][0], af[mt][1], af[mt][2], af[mt][3]);
                }
                uint32_t bb[4][2];
#pragma unroll
                for (int nb = 0; nb < 2; nb++) {
                    int r = wn * 32 + nb * 16 + (lane & 15);
                    uint32_t r0, r1, r2, r3;
                    ldmx4(swz(sB, r, seg), r0, r1, r2, r3);
                    bb[2 * nb][0] = r0;     bb[2 * nb][1] = r2;
                    bb[2 * nb + 1][0] = r1; bb[2 * nb + 1][1] = r3;
                }
#pragma unroll
                for (int mt = 0; mt < 2; mt++)
#pragma unroll
                    for (int nt = 0; nt < 4; nt++)
                        mma_h(acc[mt][nt], af[mt], bb[nt]);
            }
        }
        cp_wait0();
        __syncthreads();

        int rg = lane >> 2, cg = (lane & 3) * 2;
#pragma unroll
        for (int mt = 0; mt < 2; mt++) {
            int R0 = rowBase + wm * 32 + mt * 16 + rg;
#pragma unroll
            for (int nt = 0; nt < 4; nt++) {
                int C = colBase + wn * 32 + nt * 8 + cg;
                *(uint32_t*)&Cs[(size_t)R0 * Ntot + C] =
                    pack2h(__float2half(acc[mt][nt][0]), __float2half(acc[mt][nt][1]));
                *(uint32_t*)&Cs[(size_t)(R0 + 8) * Ntot + C] =
                    pack2h(__float2half(acc[mt][nt][2]), __float2half(acc[mt][nt][3]));
            }
        }
    }
}

// ---------------- p3 head on tensor cores: out[T,18] = y2h @ p3w2^T + p3_b ----------------
#define P3_BS_OFF (NSTG * STG_A_SZ)              // 32768: A stages first
#define P3_BS_STRIDE 1032                        // f16 elems per B row (+8 pad: conflict-free)
#define SMEM_P3 (P3_BS_OFF + P3N * P3_BS_STRIDE * 2)

__global__ void __launch_bounds__(256)
gemm_p3(const f16* __restrict__ A, const f16* __restrict__ B,
        const float* __restrict__ bias, float* __restrict__ out) {
    extern __shared__ __align__(16) char dsm[];
    f16* Bs = (f16*)(dsm + P3_BS_OFF);
    int tid = threadIdx.x, wid = tid >> 5, lane = tid & 31;
    int rowBase = blockIdx.x * 128;
    uint32_t sbase = smem_u32(dsm);

    // load full B [24][1024] into padded smem rows
#pragma unroll
    for (int i = 0; i < 12; i++) {
        int o = tid + i * 256;              // 0..3071 (x 8 f16)
        int n = o >> 7, k8 = o & 127;
        *(uint4*)&Bs[n * P3_BS_STRIDE + k8 * 8] = *(const uint4*)&B[(size_t)n * MLP_D + k8 * 8];
    }

    // A pipeline prologue
#pragma unroll
    for (int p = 0; p < 3; p++) {
        uint32_t sg = sbase + p * STG_A_SZ;
        const f16* Ab = A + (size_t)rowBase * MLP_D + p * 32;
#pragma unroll
        for (int i = 0; i < 2; i++) {
            int o = tid + i * 256;
            int r = o >> 2, seg = o & 3;
            cpasync16(swz(sg, r, seg), Ab + (size_t)r * MLP_D + seg * 8);
        }
        cp_commit();
    }

    float acc[3][4];
#pragma unroll
    for (int nt = 0; nt < 3; nt++)
#pragma unroll
        for (int q = 0; q < 4; q++) acc[nt][q] = 0.0f;

    int cf = lane >> 2, k0 = (lane & 3) * 2;
    const int NC = MLP_D / 32;
    for (int c = 0; c < NC; c++) {
        cp_wait2();
        __syncthreads();
        if (c + 3 < NC) {
            uint32_t sg = sbase + ((c + 3) & 3) * STG_A_SZ;
            const f16* Ab = A + (size_t)rowBase * MLP_D + (c + 3) * 32;
#pragma unroll
            for (int i = 0; i < 2; i++) {
                int o = tid + i * 256;
                int r = o >> 2, seg = o & 3;
                cpasync16(swz(sg, r, seg), Ab + (size_t)r * MLP_D + seg * 8);
            }
        }
        cp_commit();

        uint32_t sA = sbase + (c & 3) * STG_A_SZ;
#pragma unroll
        for (int kk2 = 0; kk2 < 2; kk2++) {
            int seg = kk2 * 2 + (lane >> 4);
            uint32_t af[4];
            int r = wid * 16 + (lane & 15);
            ldmx4(swz(sA, r, seg), af[0], af[1], af[2], af[3]);
            int kbase = c * 32 + kk2 * 16;
#pragma unroll
            for (int nt = 0; nt < 3; nt++) {
                int n = nt * 8 + cf;
                uint32_t bfr[2];
                bfr[0] = *(const uint32_t*)&Bs[n * P3_BS_STRIDE + kbase + k0];
                bfr[1] = *(const uint32_t*)&Bs[n * P3_BS_STRIDE + kbase + k0 + 8];
                mma_h(acc[nt], af, bfr);
            }
        }
    }
    cp_wait0();

    int rg = lane >> 2, cg = (lane & 3) * 2;
#pragma unroll
    for (int nt = 0; nt < 3; nt++) {
        int col = nt * 8 + cg;
        int R0 = rowBase + wid * 16 + rg;
        if (col < ACT_D) {
            float b = bias[col];
            out[(size_t)R0 * ACT_D + col] = acc[nt][0] + b;
            out[(size_t)(R0 + 8) * ACT_D + col] = acc[nt][2] + b;
        }
        if (col + 1 < ACT_D) {
            float b = bias[col + 1];
            out[(size_t)R0 * ACT_D + col + 1] = acc[nt][1] + b;
            out[(size_t)(R0 + 8) * ACT_D + col + 1] = acc[nt][3] + b;
        }
    }
}

// ---------------- GRU step k==0 (h_prev == 0) ----------------
__global__ void step0_kernel(const float* __restrict__ b_n) {
    int count = g_counts[0];
    long total = (long)count * REC_D;
    long stride = (long)gridDim.x * blockDim.x;
    for (long idx = (long)blockIdx.x * blockDim.x + threadIdx.x; idx < total; idx += stride) {
        int i = (int)(idx >> 10);
        int j = (int)(idx & 1023);
        int t = g_perm[i];
        float igr = ldh(&g_igates[(size_t)t * G3_D + j]);
        float igz = ldh(&g_igates[(size_t)t * G3_D + 1024 + j]);
        float ign = ldh(&g_igates[(size_t)t * G3_D + 2048 + j]);
        float r = sigf(igr);
        float z = sigf(igz);
        float n = tanhf(ign + r * b_n[j]);
        store_state(t, j, n - z * n);
    }
}

__global__ void fixA_kernel(const float* __restrict__ w_hh, const float* __restrict__ state) {
    if (g_flags[1]) return;
    int j = blockIdx.x * 8 + (threadIdx.x >> 5);
    int lane = threadIdx.x & 31;
    float acc = 0.0f;
    const float* wr = w_hh + (size_t)j * REC_D;
    for (int k = lane; k < REC_D; k += 32) acc += wr[k] * state[k];
#pragma unroll
    for (int o = 16; o > 0; o >>= 1) acc += __shfl_down_sync(0xffffffffu, acc, o);
    if (lane == 0) g_hg0[j] = acc;
}

__global__ void fixB_kernel(const float* __restrict__ state, const float* __restrict__ b_n) {
    if (g_flags[1]) return;
    int j = threadIdx.x;
    float igr = ldh(&g_igates[j]), igz = ldh(&g_igates[1024 + j]), ign = ldh(&g_igates[2048 + j]);
    float r = sigf(igr + g_hg0[j]);
    float z = sigf(igz + g_hg0[1024 + j]);
    float n = tanhf(ign + r * (g_hg0[2048 + j] + b_n[j]));
    float hp = state[j];
    store_state(0, j, n + z * (hp - n));
}

// gate math for GEMM steps (consumes fp16 g_hg)
__global__ void gru_gate(const float* __restrict__ b_n, int k) {
    int count = g_counts[k];
    int base = g_offsets[k];
    long total = (long)count * REC_D;
    long stride = (long)gridDim.x * blockDim.x;
    for (long idx = (long)blockIdx.x * blockDim.x + threadIdx.x; idx < total; idx += stride) {
        int i = (int)(idx >> 10);
        int j = (int)(idx & 1023);
        int t = g_perm[base + i];
        float hr = ldh(&g_hg[(size_t)i * G3_D + j]);
        float hz = ldh(&g_hg[(size_t)i * G3_D + 1024 + j]);
        float hn = ldh(&g_hg[(size_t)i * G3_D + 2048 + j]);
        float igr = ldh(&g_igates[(size_t)t * G3_D + j]);
        float igz = ldh(&g_igates[(size_t)t * G3_D + 1024 + j]);
        float ign = ldh(&g_igates[(size_t)t * G3_D + 2048 + j]);
        float hp = g_states[(size_t)(t - 1) * REC_D + j];
        float r = sigf(igr + hr);
        float z = sigf(igz + hz);
        float n = tanhf(ign + r * (hn + b_n[j]));
        store_state(t, j, n + z * (hp - n));
    }
}

// ---------------- persistent tail: double-buffered SMEM h, fp16 weights ----------------
__device__ __forceinline__ void tail_prefetch(int t, __half2* buf, int tid) {
    if (tid < 128) {
        const char* src = (const char*)(g_states2 + (size_t)(t - 1) * REC_D) + tid * 16;
        cpasync16(smem_u32((char*)buf + tid * 16), src);
    }
}

__global__ void __launch_bounds__(256)
gru_tail_persistent(const float* __restrict__ b_n) {
    __shared__ __align__(16) __half2 sh[2][REC_D / 2];
    int tid = threadIdx.x;
    int wid = tid >> 5;
    int j = blockIdx.x * 8 + wid;
    int lane = tid & 31;
    const __half2* wr2 = (const __half2*)(g_whh2 + (size_t)j * REC_D);
    const __half2* wz2 = (const __half2*)(g_whh2 + (size_t)(1024 + j) * REC_D);
    const __half2* wn2 = (const __half2*)(g_whh2 + (size_t)(2048 + j) * REC_D);
    __half2 wr[16], wz[16], wn[16];
#pragma unroll
    for (int q = 0; q < 16; q++) {
        wr[q] = wr2[lane + q * 32];
        wz[q] = wz2[lane + q * 32];
        wn[q] = wn2[lane + q * 32];
    }
    float bn = b_n[j];
    unsigned nb = gridDim.x;
    unsigned bc = 0;

    for (int k = GEMM_STEPS; k < STEPS; k++) {
        int count = g_counts[k];
        int base = g_offsets[k];
        if (count <= 0) continue;   // consistent across blocks
        tail_prefetch(g_perm[base], sh[0], tid);
        cp_commit();
        for (int i = 0; i < count; i++) {
            if (i + 1 < count) tail_prefetch(g_perm[base + i + 1], sh[(i + 1) & 1], tid);
            cp_commit();
            if (i + 1 < count) cp_wait1(); else cp_wait0();
            __syncthreads();
            const __half2* hb = sh[i & 1];
            int t = g_perm[base + i];
            float aR = 0.0f, aZ = 0.0f, aN = 0.0f;
#pragma unroll
            for (int q = 0; q < 16; q++) {
                float2 hf = __half22float2(hb[lane + q * 32]);
                float2 rf = __half22float2(wr[q]);
                float2 zf = __half22float2(wz[q]);
                float2 nf = __half22float2(wn[q]);
                aR += rf.x * hf.x + rf.y * hf.y;
                aZ += zf.x * hf.x + zf.y * hf.y;
                aN += nf.x * hf.x + nf.y * hf.y;
            }
#pragma unroll
            for (int o = 16; o > 0; o >>= 1) {
                aR += __shfl_xor_sync(0xffffffffu, aR, o);
                aZ += __shfl_xor_sync(0xffffffffu, aZ, o);
                aN += __shfl_xor_sync(0xffffffffu, aN, o);
            }
            if (lane == 0) {
                float igr = ldh(&g_igates[(size_t)t * G3_D + j]);
                float igz = ldh(&g_igates[(size_t)t * G3_D + 1024 + j]);
                float ign = ldh(&g_igates[(size_t)t * G3_D + 2048 + j]);
                float hp = __ldcg(&g_states[(size_t)(t - 1) * REC_D + j]);
                float r = sigf(igr + aR);
                float z = sigf(igz + aZ);
                float n = tanhf(ign + r * (aN + bn));
                store_state(t, j, n + z * (hp - n));
            }
            __syncthreads();
        }
        bc++;
        __syncthreads();
        if (tid == 0) {
            __threadfence();
            atomicAdd(&g_bar, 1u);
            while (*((volatile unsigned*)&g_bar) < bc * nb) {}
        }
        __syncthreads();
    }
}

// safety net for age >= STEPS (count ~0 in practice)
__global__ void __launch_bounds__(1024)
cleanup_kernel(const float* __restrict__ w_hh, const float* __restrict__ b_n) {
    if (g_counts[STEPS] == 0) return;
    __shared__ int s_t;
    __shared__ int s_cur;
    __shared__ float sh[REC_D];
    int tid = threadIdx.x;
    if (tid == 0) s_cur = STEPS;
    __syncthreads();
    while (true) {
        if (tid == 0) {
            s_t = -1;
            for (int u = s_cur; u < T_LEN; ++u)
                if (g_age[u] >= STEPS) { s_t = u; s_cur = u + 1; break; }
        }
        __syncthreads();
        int t = s_t;
        if (t < 0) break;
        sh[tid] = g_states[(size_t)(t - 1) * REC_D + tid];
        __syncthreads();
        float aRv = 0, aZv = 0, aNv = 0;
        const float* wr = w_hh + (size_t)tid * REC_D;
        const float* wz = w_hh + (size_t)(1024 + tid) * REC_D;
        const float* wn = w_hh + (size_t)(2048 + tid) * REC_D;
        for (int kk = 0; kk < REC_D; kk++) {
            float h = sh[kk];
            aRv += wr[kk] * h; aZv += wz[kk] * h; aNv += wn[kk] * h;
        }
        float igr = ldh(&g_igates[(size_t)t * G3_D + tid]);
        float igz = ldh(&g_igates[(size_t)t * G3_D + 1024 + tid]);
        float ign = ldh(&g_igates[(size_t)t * G3_D + 2048 + tid]);
        float r = sigf(igr + aRv);
        float z = sigf(igz + aZv);
        float n = tanhf(ign + r * (aNv + b_n[tid]));
        float hp = sh[tid];
        store_state(t, tid, n + z * (hp - n));
        __syncthreads();
    }
}

__global__ void copy_state_kernel(float* __restrict__ out) {
    out[threadIdx.x] = g_states[(size_t)(T_LEN - 1) * REC_D + threadIdx.x];
}

// ---------------- host ----------------
extern "C" void kernel_launch(void* const* d_in, const int* in_sizes, int n_in,
                              void* d_out, int out_size) {
    const float* x     = (const float*)d_in[0];
    const float* state = (const float*)d_in[1];
    const void*  start = d_in[2];
    const float* pre_w = (const float*)d_in[4];
    const float* pre_b = (const float*)d_in[5];
    const float* w_ih  = (const float*)d_in[6];
    const float* w_hh  = (const float*)d_in[7];
    const float* b_ih  = (const float*)d_in[8];
    const float* b_n   = (const float*)d_in[9];
    const float* p1_w  = (const float*)d_in[10];
    const float* p1_b  = (const float*)d_in[11];
    const float* p2_w  = (const float*)d_in[12];
    const float* p2_b  = (const float*)d_in[13];
    const float* p3_w  = (const float*)d_in[14];
    const float* p3_b  = (const float*)d_in[15];
    float* out = (float*)d_out;

    f16 *x2, *prew2, *feat2, *wih2, *whh2, *p1w2, *p2w2, *p3w2, *states2, *y12;
    f16 *igates, *hg, *y2h;
    int* counts_dev;
    cudaGetSymbolAddress((void**)&igates, g_igates);
    cudaGetSymbolAddress((void**)&hg, g_hg);
    cudaGetSymbolAddress((void**)&y2h, g_y2h);
    cudaGetSymbolAddress((void**)&x2, g_x2);
    cudaGetSymbolAddress((void**)&prew2, g_prew2);
    cudaGetSymbolAddress((void**)&feat2, g_feat2);
    cudaGetSymbolAddress((void**)&wih2, g_wih2);
    cudaGetSymbolAddress((void**)&whh2, g_whh2);
    cudaGetSymbolAddress((void**)&p1w2, g_p1w2);
    cudaGetSymbolAddress((void**)&p2w2, g_p2w2);
    cudaGetSymbolAddress((void**)&p3w2, g_p3w2);
    cudaGetSymbolAddress((void**)&states2, g_states2);
    cudaGetSymbolAddress((void**)&y12, g_y12);
    cudaGetSymbolAddress((void**)&counts_dev, g_counts);

    cudaFuncSetAttribute(gemm_ca<1, 1, 0>, cudaFuncAttributeMaxDynamicSharedMemorySize, SMEM_GEMM);
    cudaFuncSetAttribute(gemm_ca<0, 1, 0>, cudaFuncAttributeMaxDynamicSharedMemorySize, SMEM_GEMM);
    cudaFuncSetAttribute(gemm_ca<0, 1, 1>, cudaFuncAttributeMaxDynamicSharedMemorySize, SMEM_GEMM);
    cudaFuncSetAttribute(gemm_sm, cudaFuncAttributeMaxDynamicSharedMemorySize, SMEM_SGEMM);
    cudaFuncSetAttribute(gemm_p3, cudaFuncAttributeMaxDynamicSharedMemorySize, SMEM_P3);

    // segment analysis (single launch)
    analyze_kernel<<<1, 1024>>>((const unsigned char*)start);

    // all conversions in one launch (incl. padded p3 weights)
    conv_all<<<1024, 256>>>(pre_w, prew2, (size_t)MLP_D * OBS_D,
                            w_ih, wih2, (size_t)G3_D * MLP_D,
                            w_hh, whh2, (size_t)G3_D * REC_D,
                            p1_w, p1w2, (size_t)MLP_D * REC_D,
                            p2_w, p2w2, (size_t)MLP_D * MLP_D,
                            x, x2, (size_t)T_LEN * OBS_D,
                            p3_w, p3w2);

    // feat = mish(x @ pre_w^T + pre_b)
    gemm_ca<1, 1, 0><<<dim3(MLP_D / 256, 128), 256, SMEM_GEMM>>>(
        x2, prew2, pre_b, nullptr, feat2, MLP_D, OBS_D, nullptr, T_LEN, 0);
    // igates = feat @ w_ih^T + b_ih (fp16 out)
    gemm_ca<0, 1, 0><<<dim3(G3_D / 256, 128), 256, SMEM_GEMM>>>(
        feat2, wih2, b_ih, nullptr, igates, G3_D, MLP_D, nullptr, T_LEN, 0);

    // segment-parallel GRU scan
    step0_kernel<<<2048, 256>>>(b_n);
    fixA_kernel<<<384, 256>>>(w_hh, state);
    fixB_kernel<<<1, 1024>>>(state, b_n);
    for (int k = 1; k < GEMM_STEPS; k++) {
        int est = T_LEN >> k;
        if (k == 1) {
            int gy = est / 128; if (gy < 1) gy = 1; if (gy > 64) gy = 64;
            gemm_ca<0, 1, 1><<<dim3(G3_D / 256, gy), 256, SMEM_GEMM>>>(
                states2, whh2, nullptr, nullptr, hg, G3_D, REC_D, counts_dev + k, 0, k);
        } else {
            int gy = est / 64; if (gy < 1) gy = 1; if (gy > 32) gy = 32;
            gemm_sm<<<dim3(G3_D / 128, gy), 256, SMEM_SGEMM>>>(
                states2, whh2, hg, G3_D, REC_D, counts_dev + k, k);
        }
        gru_gate<<<2048, 256>>>(b_n, k);
    }
    gru_tail_persistent<<<TAIL_BLOCKS, 256>>>(b_n);
    cleanup_kernel<<<1, 1024>>>(w_hh, b_n);

    // post MLP
    gemm_ca<1, 1, 0><<<dim3(MLP_D / 256, 128), 256, SMEM_GEMM>>>(
        states2, p1w2, p1_b, nullptr, y12, MLP_D, REC_D, nullptr, T_LEN, 0);
    gemm_ca<1, 1, 0><<<dim3(MLP_D / 256, 128), 256, SMEM_GEMM>>>(
        y12, p2w2, p2_b, nullptr, y2h, MLP_D, MLP_D, nullptr, T_LEN, 0);
    gemm_p3<<<T_LEN / 128, 256, SMEM_P3>>>(y2h, p3w2, p3_b, out);

    if (out_size >= T_LEN * ACT_D + REC_D)
        copy_state_kernel<<<1, 1024>>>(out + (size_t)T_LEN * ACT_D);
}

// round 13
// speedup vs baseline: 6.0376x; 1.1836x over previous
#include <cuda_runtime.h>
#include <cuda_fp16.h>
#include <math.h>
#include <stdint.h>

#define T_LEN 16384
#define OBS_D 256
#define MLP_D 1024
#define REC_D 1024
#define G3_D  3072
#define ACT_D 18
#define P3N   24
#define STEPS 26
#define GEMM_STEPS 9
#define TAIL_BLOCKS 128

typedef __half f16;

// ---------------- scratch (device globals; no allocation allowed) ----------------
__device__ __align__(16) f16   g_x2[(size_t)T_LEN * OBS_D];
__device__ __align__(16) f16   g_prew2[(size_t)MLP_D * OBS_D];
__device__ __align__(16) f16   g_feat2[(size_t)T_LEN * MLP_D];
__device__ __align__(16) f16   g_wih2[(size_t)G3_D * MLP_D];
__device__ __align__(16) f16   g_whh2[(size_t)G3_D * REC_D];
__device__ __align__(16) f16   g_p1w2[(size_t)MLP_D * REC_D];
__device__ __align__(16) f16   g_p2w2[(size_t)MLP_D * MLP_D];
__device__ __align__(16) f16   g_p3w2[(size_t)P3N * MLP_D];
__device__ __align__(16) f16   g_states2[(size_t)T_LEN * REC_D];
__device__ __align__(16) f16   g_y12[(size_t)T_LEN * MLP_D];
__device__ __align__(16) f16   g_igates[(size_t)T_LEN * G3_D];
__device__ __align__(16) f16   g_hg[(size_t)T_LEN * G3_D];
__device__ __align__(16) f16   g_y2h[(size_t)T_LEN * MLP_D];
__device__ __align__(16) float g_states[(size_t)T_LEN * REC_D];
__device__ float g_hg0[G3_D];
__device__ int   g_age[T_LEN];
__device__ int   g_perm[T_LEN];
__device__ int   g_counts[STEPS + 1];
__device__ int   g_offsets[STEPS + 1];
__device__ int   g_flags[4];
__device__ unsigned g_bar;

// ---------------- helpers ----------------
__device__ __forceinline__ float sigf(float x) { return 1.0f / (1.0f + expf(-x)); }
__device__ __forceinline__ float mishf(float x) {
    float sp = (x > 15.0f) ? x : log1pf(expf(x));
    return x * tanhf(sp);
}
__device__ __forceinline__ uint32_t smem_u32(const void* p) {
    return (uint32_t)__cvta_generic_to_shared(p);
}
__device__ __forceinline__ uint32_t pack2h(f16 a, f16 b) {
    __half2 t; t.x = a; t.y = b;
    return *(uint32_t*)&t;
}
__device__ __forceinline__ void store_state(int t, int j, float v) {
    g_states[(size_t)t * REC_D + j] = v;
    g_states2[(size_t)t * REC_D + j] = __float2half(v);
}
__device__ __forceinline__ float ldh(const f16* p) { return __half2float(*p); }

// ---------------- async / mma primitives (plain compute_100-legal) ----------------
__device__ __forceinline__ void cpasync16(uint32_t sa, const void* ga) {
    asm volatile("cp.async.cg.shared.global [%0], [%1], 16;" :: "r"(sa), "l"(ga));
}
__device__ __forceinline__ void cp_commit() { asm volatile("cp.async.commit_group;" ::: "memory"); }
__device__ __forceinline__ void cp_wait2() { asm volatile("cp.async.wait_group 2;" ::: "memory"); }
__device__ __forceinline__ void cp_wait1() { asm volatile("cp.async.wait_group 1;" ::: "memory"); }
__device__ __forceinline__ void cp_wait0() { asm volatile("cp.async.wait_group 0;" ::: "memory"); }

__device__ __forceinline__ void ldmx4(uint32_t addr, uint32_t& r0, uint32_t& r1, uint32_t& r2, uint32_t& r3) {
    asm volatile("ldmatrix.sync.aligned.m8n8.x4.shared.b16 {%0,%1,%2,%3}, [%4];"
                 : "=r"(r0), "=r"(r1), "=r"(r2), "=r"(r3) : "r"(addr));
}
__device__ __forceinline__ void mma_h(float* c, const uint32_t* a, const uint32_t* b) {
    asm volatile("mma.sync.aligned.m16n8k16.row.col.f32.f16.f16.f32 "
                 "{%0,%1,%2,%3}, {%4,%5,%6,%7}, {%8,%9}, {%0,%1,%2,%3};"
                 : "+f"(c[0]), "+f"(c[1]), "+f"(c[2]), "+f"(c[3])
                 : "r"(a[0]), "r"(a[1]), "r"(a[2]), "r"(a[3]), "r"(b[0]), "r"(b[1]));
}

// ---------------- merged segment analysis (single launch) ----------------
__device__ __forceinline__ bool start_val(const void* p, int mode, int u) {
    if (mode == 0) return ((const unsigned char*)p)[u] != 0;
    if (mode == 1) return ((const int*)p)[u] != 0;
    return ((const float*)p)[u] != 0.0f;
}

__global__ void __launch_bounds__(1024)
analyze_kernel(const unsigned char* __restrict__ p) {
    __shared__ int s_nz[4];
    __shared__ int s_counts[STEPS + 1];
    __shared__ int s_off[STEPS + 1];
    __shared__ int s_cur[STEPS + 1];
    __shared__ int s_mode;
    int tid = threadIdx.x;
    if (tid < 4) s_nz[tid] = 0;
    if (tid < STEPS + 1) { s_counts[tid] = 0; s_cur[tid] = 0; }
    if (tid == 0) g_bar = 0;
    __syncthreads();
    int cnt = 0;
    for (int i = tid; i < T_LEN; i += 1024) cnt += (p[i] != 0);
    atomicAdd(&s_nz[tid & 3], cnt);
    __syncthreads();
    if (tid == 0) {
        int rest = s_nz[1] + s_nz[2] + s_nz[3];
        int mode;
        if (rest > 0) mode = (s_nz[0] == 0) ? 2 : 0;
        else          mode = (s_nz[0] > 0) ? 1 : 0;
        g_flags[0] = mode;
        bool s0;
        if (mode == 0)      s0 = p[0] != 0;
        else if (mode == 1) s0 = ((const int*)p)[0] != 0;
        else                s0 = ((const float*)p)[0] != 0.0f;
        g_flags[1] = s0 ? 1 : 0;
        s_mode = mode;
    }
    __syncthreads();
    int mode = s_mode;
    for (int t = tid; t < T_LEN; t += 1024) {
        int k = 0, tt = t;
        while (tt > 0 && !start_val(p, mode, tt)) { tt--; k++; }
        g_age[t] = k;
        int b = k < STEPS ? k : STEPS;
        atomicAdd(&s_counts[b], 1);
    }
    __syncthreads();
    if (tid == 0) {
        int acc = 0;
        for (int b = 0; b <= STEPS; b++) { s_off[b] = acc; g_offsets[b] = acc; acc += s_counts[b]; }
    }
    if (tid < STEPS + 1) g_counts[tid] = s_counts[tid];
    __syncthreads();
    for (int t = tid; t < T_LEN; t += 1024) {
        int a = g_age[t];
        int b = a < STEPS ? a : STEPS;
        int pos = s_off[b] + atomicAdd(&s_cur[b], 1);
        g_perm[pos] = t;
    }
}

// ---------------- merged fp32->fp16 conversions (one launch) ----------------
__global__ void conv_all(const float* s0, f16* d0, size_t n0,
                         const float* s1, f16* d1, size_t n1,
                         const float* s2, f16* d2, size_t n2,
                         const float* s3, f16* d3, size_t n3,
                         const float* s4, f16* d4, size_t n4,
                         const float* s5, f16* d5, size_t n5,
                         const float* s6, f16* d6) {
    size_t stride = (size_t)gridDim.x * blockDim.x;
    size_t i0 = (size_t)blockIdx.x * blockDim.x + threadIdx.x;
    for (size_t i = i0; i < n0; i += stride) d0[i] = __float2half(s0[i]);
    for (size_t i = i0; i < n1; i += stride) d1[i] = __float2half(s1[i]);
    for (size_t i = i0; i < n2; i += stride) d2[i] = __float2half(s2[i]);
    for (size_t i = i0; i < n3; i += stride) d3[i] = __float2half(s3[i]);
    for (size_t i = i0; i < n4; i += stride) d4[i] = __float2half(s4[i]);
    for (size_t i = i0; i < n5; i += stride) d5[i] = __float2half(s5[i]);
    for (size_t i = i0; i < (size_t)P3N * MLP_D; i += stride) {
        int a = (int)(i >> 10);
        d6[i] = (a < ACT_D) ? __float2half(s6[(size_t)a * MLP_D + (i & 1023)]) : __float2half(0.0f);
    }
}

// ---------------- mma.sync GEMM (128x256, 512 threads) with cp.async pipeline ----------------
#define STG_A_SZ 8192
#define STG_B_SZ 16384
#define STG_SZ (STG_A_SZ + STG_B_SZ)
#define NSTG 4
#define SMEM_GEMM (NSTG * STG_SZ)

__device__ __forceinline__ uint32_t swz(uint32_t base, int r, int seg) {
    return base + r * 64 + 16 * (seg ^ ((r >> 1) & 3));
}

template <int GATHER>
__device__ __forceinline__ void load_stage(const f16* __restrict__ A, const f16* __restrict__ B,
                                           const int* __restrict__ perm, int M,
                                           int rowBase, int colBase, int K, int chunk,
                                           uint32_t sA, uint32_t sB, int tid) {
    {
        int r = tid >> 2, seg = tid & 3;   // 128 rows x 4 segs = 512 = blockDim
        const f16* src;
        if (GATHER) {
            int gi = rowBase + r;
            gi = gi < M - 1 ? gi : M - 1;
            int t = __ldg(&perm[gi]);
            src = A + (size_t)(t - 1) * K + chunk * 32 + (size_t)seg * 8;
        } else {
            src = A + (size_t)(rowBase + r) * K + chunk * 32 + (size_t)seg * 8;
        }
        cpasync16(swz(sA, r, seg), src);
    }
    const f16* Bb = B + (size_t)colBase * K + chunk * 32;
#pragma unroll
    for (int i = 0; i < 2; i++) {
        int o = tid + i * 512;
        int r = o >> 2, seg = o & 3;
        cpasync16(swz(sB, r, seg), Bb + (size_t)r * K + seg * 8);
    }
}

template <int MISH, int HALFOUT, int GATHER>
__global__ void __launch_bounds__(512)
gemm_ca(const f16* __restrict__ A, const f16* __restrict__ B,
        const float* __restrict__ bias, float* __restrict__ Cf, f16* __restrict__ Cs,
        int Ntot, int K, const int* __restrict__ Mptr, int Mfix, int bucketK) {
    extern __shared__ __align__(16) char dsm[];
    int tid = threadIdx.x, wid = tid >> 5, lane = tid & 31;
    int wm = wid >> 2, wn = wid & 3;   // 4 x 4 warps, warp tile 32x64
    int M = Mptr ? *Mptr : Mfix;
    const int* perm = GATHER ? (g_perm + g_offsets[bucketK]) : (const int*)0;
    int colBase = blockIdx.x * 256;
    int NC = K >> 5;
    uint32_t sbase = smem_u32(dsm);

    for (int mtile = blockIdx.y; mtile * 128 < M; mtile += gridDim.y) {
        int rowBase = mtile * 128;
        float acc[2][8][4];
#pragma unroll
        for (int mt = 0; mt < 2; mt++)
#pragma unroll
            for (int nt = 0; nt < 8; nt++)
#pragma unroll
                for (int q = 0; q < 4; q++) acc[mt][nt][q] = 0.0f;

#pragma unroll
        for (int p = 0; p < 3; p++) {
            uint32_t sg = sbase + p * STG_SZ;
            load_stage<GATHER>(A, B, perm, M, rowBase, colBase, K, p, sg, sg + STG_A_SZ, tid);
            cp_commit();
        }

        for (int c = 0; c < NC; c++) {
            cp_wait2();
            __syncthreads();
            if (c + 3 < NC) {
                int s = (c + 3) & 3;
                uint32_t sg = sbase + s * STG_SZ;
                load_stage<GATHER>(A, B, perm, M, rowBase, colBase, K, c + 3, sg, sg + STG_A_SZ, tid);
            }
            cp_commit();

            uint32_t sA = sbase + (c & 3) * STG_SZ;
            uint32_t sB = sA + STG_A_SZ;
#pragma unroll
            for (int kk2 = 0; kk2 < 2; kk2++) {
                int seg = kk2 * 2 + (lane >> 4);
                uint32_t af[2][4];
#pragma unroll
                for (int mt = 0; mt < 2; mt++) {
                    int r = wm * 32 + mt * 16 + (lane & 15);
                    ldmx4(swz(sA, r, seg), af[mt][0], af[mt][1], af[mt][2], af[mt][3]);
                }
                uint32_t bb[8][2];
#pragma unroll
                for (int nb = 0; nb < 4; nb++) {
                    int r = wn * 64 + nb * 16 + (lane & 15);
                    uint32_t r0, r1, r2, r3;
                    ldmx4(swz(sB, r, seg), r0, r1, r2, r3);
                    bb[2 * nb][0] = r0;     bb[2 * nb][1] = r2;
                    bb[2 * nb + 1][0] = r1; bb[2 * nb + 1][1] = r3;
                }
#pragma unroll
                for (int mt = 0; mt < 2; mt++)
#pragma unroll
                    for (int nt = 0; nt < 8; nt++)
                        mma_h(acc[mt][nt], af[mt], bb[nt]);
            }
        }
        cp_wait0();
        __syncthreads();

        int rg = lane >> 2, cg = (lane & 3) * 2;
#pragma unroll
        for (int mt = 0; mt < 2; mt++) {
            int R0 = rowBase + wm * 32 + mt * 16 + rg;
#pragma unroll
            for (int nt = 0; nt < 8; nt++) {
                int C = colBase + wn * 64 + nt * 8 + cg;
                float b0 = bias ? bias[C] : 0.0f;
                float b1 = bias ? bias[C + 1] : 0.0f;
                float v00 = acc[mt][nt][0] + b0, v01 = acc[mt][nt][1] + b1;
                float v10 = acc[mt][nt][2] + b0, v11 = acc[mt][nt][3] + b1;
                if (MISH) { v00 = mishf(v00); v01 = mishf(v01); v10 = mishf(v10); v11 = mishf(v11); }
                if (HALFOUT) {
                    *(uint32_t*)&Cs[(size_t)R0 * Ntot + C] =
                        pack2h(__float2half(v00), __float2half(v01));
                    *(uint32_t*)&Cs[(size_t)(R0 + 8) * Ntot + C] =
                        pack2h(__float2half(v10), __float2half(v11));
                } else {
                    float2 a; a.x = v00; a.y = v01;
                    float2 b; b.x = v10; b.y = v11;
                    *(float2*)&Cf[(size_t)R0 * Ntot + C] = a;
                    *(float2*)&Cf[(size_t)(R0 + 8) * Ntot + C] = b;
                }
            }
        }
    }
}

// ---------------- small-tile GEMM (64x128) for small GRU steps ----------------
#define SSTG_A_SZ 4096
#define SSTG_B_SZ 8192
#define SSTG_SZ (SSTG_A_SZ + SSTG_B_SZ)
#define SMEM_SGEMM (NSTG * SSTG_SZ)

__device__ __forceinline__ void load_stage_sm(const f16* __restrict__ A, const f16* __restrict__ B,
                                              const int* __restrict__ perm, int M,
                                              int rowBase, int colBase, int K, int chunk,
                                              uint32_t sA, uint32_t sB, int tid) {
    {
        int r = tid >> 2, seg = tid & 3;
        int gi = rowBase + r;
        gi = gi < M - 1 ? gi : M - 1;
        int t = __ldg(&perm[gi]);
        cpasync16(swz(sA, r, seg), A + (size_t)(t - 1) * K + chunk * 32 + (size_t)seg * 8);
    }
    const f16* Bb = B + (size_t)colBase * K + chunk * 32;
#pragma unroll
    for (int i = 0; i < 2; i++) {
        int o = tid + i * 256;
        int r = o >> 2, seg = o & 3;
        cpasync16(swz(sB, r, seg), Bb + (size_t)r * K + seg * 8);
    }
}

__global__ void __launch_bounds__(256)
gemm_sm(const f16* __restrict__ A, const f16* __restrict__ B, f16* __restrict__ Cs,
        int Ntot, int K, const int* __restrict__ Mptr, int bucketK) {
    extern __shared__ __align__(16) char dsm[];
    int tid = threadIdx.x, wid = tid >> 5, lane = tid & 31;
    int wm = wid >> 2, wn = wid & 3;
    int M = *Mptr;
    const int* perm = g_perm + g_offsets[bucketK];
    int colBase = blockIdx.x * 128;
    int NC = K >> 5;
    uint32_t sbase = smem_u32(dsm);

    for (int mtile = blockIdx.y; mtile * 64 < M; mtile += gridDim.y) {
        int rowBase = mtile * 64;
        float acc[2][4][4];
#pragma unroll
        for (int mt = 0; mt < 2; mt++)
#pragma unroll
            for (int nt = 0; nt < 4; nt++)
#pragma unroll
                for (int q = 0; q < 4; q++) acc[mt][nt][q] = 0.0f;

#pragma unroll
        for (int p = 0; p < 3; p++) {
            uint32_t sg = sbase + p * SSTG_SZ;
            load_stage_sm(A, B, perm, M, rowBase, colBase, K, p, sg, sg + SSTG_A_SZ, tid);
            cp_commit();
        }

        for (int c = 0; c < NC; c++) {
            cp_wait2();
            __syncthreads();
            if (c + 3 < NC) {
                int s = (c + 3) & 3;
                uint32_t sg = sbase + s * SSTG_SZ;
                load_stage_sm(A, B, perm, M, rowBase, colBase, K, c + 3, sg, sg + SSTG_A_SZ, tid);
            }
            cp_commit();

            uint32_t sA = sbase + (c & 3) * SSTG_SZ;
            uint32_t sB = sA + SSTG_A_SZ;
#pragma unroll
            for (int kk2 = 0; kk2 < 2; kk2++) {
                int seg = kk2 * 2 + (lane >> 4);
                uint32_t af[2][4];
#pragma unroll
                for (int mt = 0; mt < 2; mt++) {
                    int r = wm * 32 + mt * 16 + (lane & 15);
                    ldmx4(swz(sA, r, seg), af[mt][0], af[mt][1], af[mt][2], af[mt][3]);
                }
                uint32_t bb[4][2];
#pragma unroll
                for (int nb = 0; nb < 2; nb++) {
                    int r = wn * 32 + nb * 16 + (lane & 15);
                    uint32_t r0, r1, r2, r3;
                    ldmx4(swz(sB, r, seg), r0, r1, r2, r3);
                    bb[2 * nb][0] = r0;     bb[2 * nb][1] = r2;
                    bb[2 * nb + 1][0] = r1; bb[2 * nb + 1][1] = r3;
                }
#pragma unroll
                for (int mt = 0; mt < 2; mt++)
#pragma unroll
                    for (int nt = 0; nt < 4; nt++)
                        mma_h(acc[mt][nt], af[mt], bb[nt]);
            }
        }
        cp_wait0();
        __syncthreads();

        int rg = lane >> 2, cg = (lane & 3) * 2;
#pragma unroll
        for (int mt = 0; mt < 2; mt++) {
            int R0 = rowBase + wm * 32 + mt * 16 + rg;
#pragma unroll
            for (int nt = 0; nt < 4; nt++) {
                int C = colBase + wn * 32 + nt * 8 + cg;
                *(uint32_t*)&Cs[(size_t)R0 * Ntot + C] =
                    pack2h(__float2half(acc[mt][nt][0]), __float2half(acc[mt][nt][1]));
                *(uint32_t*)&Cs[(size_t)(R0 + 8) * Ntot + C] =
                    pack2h(__float2half(acc[mt][nt][2]), __float2half(acc[mt][nt][3]));
            }
        }
    }
}

// ---------------- p3 head on tensor cores ----------------
#define P3_BS_OFF (NSTG * STG_A_SZ)
#define P3_BS_STRIDE 1032
#define SMEM_P3 (P3_BS_OFF + P3N * P3_BS_STRIDE * 2)

__global__ void __launch_bounds__(256)
gemm_p3(const f16* __restrict__ A, const f16* __restrict__ B,
        const float* __restrict__ bias, float* __restrict__ out) {
    extern __shared__ __align__(16) char dsm[];
    f16* Bs = (f16*)(dsm + P3_BS_OFF);
    int tid = threadIdx.x, wid = tid >> 5, lane = tid & 31;
    int rowBase = blockIdx.x * 128;
    uint32_t sbase = smem_u32(dsm);

#pragma unroll
    for (int i = 0; i < 12; i++) {
        int o = tid + i * 256;
        int n = o >> 7, k8 = o & 127;
        *(uint4*)&Bs[n * P3_BS_STRIDE + k8 * 8] = *(const uint4*)&B[(size_t)n * MLP_D + k8 * 8];
    }

#pragma unroll
    for (int p = 0; p < 3; p++) {
        uint32_t sg = sbase + p * STG_A_SZ;
        const f16* Ab = A + (size_t)rowBase * MLP_D + p * 32;
#pragma unroll
        for (int i = 0; i < 2; i++) {
            int o = tid + i * 256;
            int r = o >> 2, seg = o & 3;
            cpasync16(swz(sg, r, seg), Ab + (size_t)r * MLP_D + seg * 8);
        }
        cp_commit();
    }

    float acc[3][4];
#pragma unroll
    for (int nt = 0; nt < 3; nt++)
#pragma unroll
        for (int q = 0; q < 4; q++) acc[nt][q] = 0.0f;

    int cf = lane >> 2, k0 = (lane & 3) * 2;
    const int NC = MLP_D / 32;
    for (int c = 0; c < NC; c++) {
        cp_wait2();
        __syncthreads();
        if (c + 3 < NC) {
            uint32_t sg = sbase + ((c + 3) & 3) * STG_A_SZ;
            const f16* Ab = A + (size_t)rowBase * MLP_D + (c + 3) * 32;
#pragma unroll
            for (int i = 0; i < 2; i++) {
                int o = tid + i * 256;
                int r = o >> 2, seg = o & 3;
                cpasync16(swz(sg, r, seg), Ab + (size_t)r * MLP_D + seg * 8);
            }
        }
        cp_commit();

        uint32_t sA = sbase + (c & 3) * STG_A_SZ;
#pragma unroll
        for (int kk2 = 0; kk2 < 2; kk2++) {
            int seg = kk2 * 2 + (lane >> 4);
            uint32_t af[4];
            int r = wid * 16 + (lane & 15);
            ldmx4(swz(sA, r, seg), af[0], af[1], af[2], af[3]);
            int kbase = c * 32 + kk2 * 16;
#pragma unroll
            for (int nt = 0; nt < 3; nt++) {
                int n = nt * 8 + cf;
                uint32_t bfr[2];
                bfr[0] = *(const uint32_t*)&Bs[n * P3_BS_STRIDE + kbase + k0];
                bfr[1] = *(const uint32_t*)&Bs[n * P3_BS_STRIDE + kbase + k0 + 8];
                mma_h(acc[nt], af, bfr);
            }
        }
    }
    cp_wait0();

    int rg = lane >> 2, cg = (lane & 3) * 2;
#pragma unroll
    for (int nt = 0; nt < 3; nt++) {
        int col = nt * 8 + cg;
        int R0 = rowBase + wid * 16 + rg;
        if (col < ACT_D) {
            float b = bias[col];
            out[(size_t)R0 * ACT_D + col] = acc[nt][0] + b;
            out[(size_t)(R0 + 8) * ACT_D + col] = acc[nt][2] + b;
        }
        if (col + 1 < ACT_D) {
            float b = bias[col + 1];
            out[(size_t)R0 * ACT_D + col + 1] = acc[nt][1] + b;
            out[(size_t)(R0 + 8) * ACT_D + col + 1] = acc[nt][3] + b;
        }
    }
}

// ---------------- GRU step k==0 (h_prev == 0) ----------------
__global__ void step0_kernel(const float* __restrict__ b_n) {
    int count = g_counts[0];
    long total = (long)count * REC_D;
    long stride = (long)gridDim.x * blockDim.x;
    for (long idx = (long)blockIdx.x * blockDim.x + threadIdx.x; idx < total; idx += stride) {
        int i = (int)(idx >> 10);
        int j = (int)(idx & 1023);
        int t = g_perm[i];
        float igr = ldh(&g_igates[(size_t)t * G3_D + j]);
        float igz = ldh(&g_igates[(size_t)t * G3_D + 1024 + j]);
        float ign = ldh(&g_igates[(size_t)t * G3_D + 2048 + j]);
        float r = sigf(igr);
        float z = sigf(igz);
        float n = tanhf(ign + r * b_n[j]);
        store_state(t, j, n - z * n);
    }
}

__global__ void fixA_kernel(const float* __restrict__ w_hh, const float* __restrict__ state) {
    if (g_flags[1]) return;
    int j = blockIdx.x * 8 + (threadIdx.x >> 5);
    int lane = threadIdx.x & 31;
    float acc = 0.0f;
    const float* wr = w_hh + (size_t)j * REC_D;
    for (int k = lane; k < REC_D; k += 32) acc += wr[k] * state[k];
#pragma unroll
    for (int o = 16; o > 0; o >>= 1) acc += __shfl_down_sync(0xffffffffu, acc, o);
    if (lane == 0) g_hg0[j] = acc;
}

__global__ void fixB_kernel(const float* __restrict__ state, const float* __restrict__ b_n) {
    if (g_flags[1]) return;
    int j = threadIdx.x;
    float igr = ldh(&g_igates[j]), igz = ldh(&g_igates[1024 + j]), ign = ldh(&g_igates[2048 + j]);
    float r = sigf(igr + g_hg0[j]);
    float z = sigf(igz + g_hg0[1024 + j]);
    float n = tanhf(ign + r * (g_hg0[2048 + j] + b_n[j]));
    float hp = state[j];
    store_state(0, j, n + z * (hp - n));
}

__global__ void gru_gate(const float* __restrict__ b_n, int k) {
    int count = g_counts[k];
    int base = g_offsets[k];
    long total = (long)count * REC_D;
    long stride = (long)gridDim.x * blockDim.x;
    for (long idx = (long)blockIdx.x * blockDim.x + threadIdx.x; idx < total; idx += stride) {
        int i = (int)(idx >> 10);
        int j = (int)(idx & 1023);
        int t = g_perm[base + i];
        float hr = ldh(&g_hg[(size_t)i * G3_D + j]);
        float hz = ldh(&g_hg[(size_t)i * G3_D + 1024 + j]);
        float hn = ldh(&g_hg[(size_t)i * G3_D + 2048 + j]);
        float igr = ldh(&g_igates[(size_t)t * G3_D + j]);
        float igz = ldh(&g_igates[(size_t)t * G3_D + 1024 + j]);
        float ign = ldh(&g_igates[(size_t)t * G3_D + 2048 + j]);
        float hp = g_states[(size_t)(t - 1) * REC_D + j];
        float r = sigf(igr + hr);
        float z = sigf(igz + hz);
        float n = tanhf(ign + r * (hn + b_n[j]));
        store_state(t, j, n + z * (hp - n));
    }
}

// ---------------- persistent tail ----------------
__device__ __forceinline__ void tail_prefetch(int t, __half2* buf, int tid) {
    if (tid < 128) {
        const char* src = (const char*)(g_states2 + (size_t)(t - 1) * REC_D) + tid * 16;
        cpasync16(smem_u32((char*)buf + tid * 16), src);
    }
}

__global__ void __launch_bounds__(256)
gru_tail_persistent(const float* __restrict__ b_n) {
    __shared__ __align__(16) __half2 sh[2][REC_D / 2];
    int tid = threadIdx.x;
    int wid = tid >> 5;
    int j = blockIdx.x * 8 + wid;
    int lane = tid & 31;
    const __half2* wr2 = (const __half2*)(g_whh2 + (size_t)j * REC_D);
    const __half2* wz2 = (const __half2*)(g_whh2 + (size_t)(1024 + j) * REC_D);
    const __half2* wn2 = (const __half2*)(g_whh2 + (size_t)(2048 + j) * REC_D);
    __half2 wr[16], wz[16], wn[16];
#pragma unroll
    for (int q = 0; q < 16; q++) {
        wr[q] = wr2[lane + q * 32];
        wz[q] = wz2[lane + q * 32];
        wn[q] = wn2[lane + q * 32];
    }
    float bn = b_n[j];
    unsigned nb = gridDim.x;
    unsigned bc = 0;

    for (int k = GEMM_STEPS; k < STEPS; k++) {
        int count = g_counts[k];
        int base = g_offsets[k];
        if (count <= 0) continue;
        tail_prefetch(g_perm[base], sh[0], tid);
        cp_commit();
        for (int i = 0; i < count; i++) {
            if (i + 1 < count) tail_prefetch(g_perm[base + i + 1], sh[(i + 1) & 1], tid);
            cp_commit();
            if (i + 1 < count) cp_wait1(); else cp_wait0();
            __syncthreads();
            const __half2* hb = sh[i & 1];
            int t = g_perm[base + i];
            float aR = 0.0f, aZ = 0.0f, aN = 0.0f;
#pragma unroll
            for (int q = 0; q < 16; q++) {
                float2 hf = __half22float2(hb[lane + q * 32]);
                float2 rf = __half22float2(wr[q]);
                float2 zf = __half22float2(wz[q]);
                float2 nf = __half22float2(wn[q]);
                aR += rf.x * hf.x + rf.y * hf.y;
                aZ += zf.x * hf.x + zf.y * hf.y;
                aN += nf.x * hf.x + nf.y * hf.y;
            }
#pragma unroll
            for (int o = 16; o > 0; o >>= 1) {
                aR += __shfl_xor_sync(0xffffffffu, aR, o);
                aZ += __shfl_xor_sync(0xffffffffu, aZ, o);
                aN += __shfl_xor_sync(0xffffffffu, aN, o);
            }
            if (lane == 0) {
                float igr = ldh(&g_igates[(size_t)t * G3_D + j]);
                float igz = ldh(&g_igates[(size_t)t * G3_D + 1024 + j]);
                float ign = ldh(&g_igates[(size_t)t * G3_D + 2048 + j]);
                float hp = __ldcg(&g_states[(size_t)(t - 1) * REC_D + j]);
                float r = sigf(igr + aR);
                float z = sigf(igz + aZ);
                float n = tanhf(ign + r * (aN + bn));
                store_state(t, j, n + z * (hp - n));
            }
            __syncthreads();
        }
        bc++;
        __syncthreads();
        if (tid == 0) {
            __threadfence();
            atomicAdd(&g_bar, 1u);
            while (*((volatile unsigned*)&g_bar) < bc * nb) {}
        }
        __syncthreads();
    }
}

// safety net for age >= STEPS
__global__ void __launch_bounds__(1024)
cleanup_kernel(const float* __restrict__ w_hh, const float* __restrict__ b_n) {
    if (g_counts[STEPS] == 0) return;
    __shared__ int s_t;
    __shared__ int s_cur;
    __shared__ float sh[REC_D];
    int tid = threadIdx.x;
    if (tid == 0) s_cur = STEPS;
    __syncthreads();
    while (true) {
        if (tid == 0) {
            s_t = -1;
            for (int u = s_cur; u < T_LEN; ++u)
                if (g_age[u] >= STEPS) { s_t = u; s_cur = u + 1; break; }
        }
        __syncthreads();
        int t = s_t;
        if (t < 0) break;
        sh[tid] = g_states[(size_t)(t - 1) * REC_D + tid];
        __syncthreads();
        float aRv = 0, aZv = 0, aNv = 0;
        const float* wr = w_hh + (size_t)tid * REC_D;
        const float* wz = w_hh + (size_t)(1024 + tid) * REC_D;
        const float* wn = w_hh + (size_t)(2048 + tid) * REC_D;
        for (int kk = 0; kk < REC_D; kk++) {
            float h = sh[kk];
            aRv += wr[kk] * h; aZv += wz[kk] * h; aNv += wn[kk] * h;
        }
        float igr = ldh(&g_igates[(size_t)t * G3_D + tid]);
        float igz = ldh(&g_igates[(size_t)t * G3_D + 1024 + tid]);
        float ign = ldh(&g_igates[(size_t)t * G3_D + 2048 + tid]);
        float r = sigf(igr + aRv);
        float z = sigf(igz + aZv);
        float n = tanhf(ign + r * (aNv + b_n[tid]));
        float hp = sh[tid];
        store_state(t, tid, n + z * (hp - n));
        __syncthreads();
    }
}

__global__ void copy_state_kernel(float* __restrict__ out) {
    out[threadIdx.x] = g_states[(size_t)(T_LEN - 1) * REC_D + threadIdx.x];
}

// ---------------- host ----------------
extern "C" void kernel_launch(void* const* d_in, const int* in_sizes, int n_in,
                              void* d_out, int out_size) {
    const float* x     = (const float*)d_in[0];
    const float* state = (const float*)d_in[1];
    const void*  start = d_in[2];
    const float* pre_w = (const float*)d_in[4];
    const float* pre_b = (const float*)d_in[5];
    const float* w_ih  = (const float*)d_in[6];
    const float* w_hh  = (const float*)d_in[7];
    const float* b_ih  = (const float*)d_in[8];
    const float* b_n   = (const float*)d_in[9];
    const float* p1_w  = (const float*)d_in[10];
    const float* p1_b  = (const float*)d_in[11];
    const float* p2_w  = (const float*)d_in[12];
    const float* p2_b  = (const float*)d_in[13];
    const float* p3_w  = (const float*)d_in[14];
    const float* p3_b  = (const float*)d_in[15];
    float* out = (float*)d_out;

    f16 *x2, *prew2, *feat2, *wih2, *whh2, *p1w2, *p2w2, *p3w2, *states2, *y12;
    f16 *igates, *hg, *y2h;
    int* counts_dev;
    cudaGetSymbolAddress((void**)&igates, g_igates);
    cudaGetSymbolAddress((void**)&hg, g_hg);
    cudaGetSymbolAddress((void**)&y2h, g_y2h);
    cudaGetSymbolAddress((void**)&x2, g_x2);
    cudaGetSymbolAddress((void**)&prew2, g_prew2);
    cudaGetSymbolAddress((void**)&feat2, g_feat2);
    cudaGetSymbolAddress((void**)&wih2, g_wih2);
    cudaGetSymbolAddress((void**)&whh2, g_whh2);
    cudaGetSymbolAddress((void**)&p1w2, g_p1w2);
    cudaGetSymbolAddress((void**)&p2w2, g_p2w2);
    cudaGetSymbolAddress((void**)&p3w2, g_p3w2);
    cudaGetSymbolAddress((void**)&states2, g_states2);
    cudaGetSymbolAddress((void**)&y12, g_y12);
    cudaGetSymbolAddress((void**)&counts_dev, g_counts);

    cudaFuncSetAttribute(gemm_ca<1, 1, 0>, cudaFuncAttributeMaxDynamicSharedMemorySize, SMEM_GEMM);
    cudaFuncSetAttribute(gemm_ca<0, 1, 0>, cudaFuncAttributeMaxDynamicSharedMemorySize, SMEM_GEMM);
    cudaFuncSetAttribute(gemm_ca<0, 1, 1>, cudaFuncAttributeMaxDynamicSharedMemorySize, SMEM_GEMM);
    cudaFuncSetAttribute(gemm_sm, cudaFuncAttributeMaxDynamicSharedMemorySize, SMEM_SGEMM);
    cudaFuncSetAttribute(gemm_p3, cudaFuncAttributeMaxDynamicSharedMemorySize, SMEM_P3);

    // segment analysis (single launch)
    analyze_kernel<<<1, 1024>>>((const unsigned char*)start);

    // all conversions in one launch
    conv_all<<<1024, 256>>>(pre_w, prew2, (size_t)MLP_D * OBS_D,
                            w_ih, wih2, (size_t)G3_D * MLP_D,
                            w_hh, whh2, (size_t)G3_D * REC_D,
                            p1_w, p1w2, (size_t)MLP_D * REC_D,
                            p2_w, p2w2, (size_t)MLP_D * MLP_D,
                            x, x2, (size_t)T_LEN * OBS_D,
                            p3_w, p3w2);

    // feat = mish(x @ pre_w^T + pre_b)
    gemm_ca<1, 1, 0><<<dim3(MLP_D / 256, 128), 512, SMEM_GEMM>>>(
        x2, prew2, pre_b, nullptr, feat2, MLP_D, OBS_D, nullptr, T_LEN, 0);
    // igates = feat @ w_ih^T + b_ih (fp16 out)
    gemm_ca<0, 1, 0><<<dim3(G3_D / 256, 128), 512, SMEM_GEMM>>>(
        feat2, wih2, b_ih, nullptr, igates, G3_D, MLP_D, nullptr, T_LEN, 0);

    // segment-parallel GRU scan
    step0_kernel<<<2048, 256>>>(b_n);
    fixA_kernel<<<384, 256>>>(w_hh, state);
    fixB_kernel<<<1, 1024>>>(state, b_n);
    for (int k = 1; k < GEMM_STEPS; k++) {
        int est = T_LEN >> k;
        if (k == 1) {
            int gy = est / 128; if (gy < 1) gy = 1; if (gy > 64) gy = 64;
            gemm_ca<0, 1, 1><<<dim3(G3_D / 256, gy), 512, SMEM_GEMM>>>(
                states2, whh2, nullptr, nullptr, hg, G3_D, REC_D, counts_dev + k, 0, k);
        } else {
            int gy = est / 64; if (gy < 1) gy = 1; if (gy > 32) gy = 32;
            gemm_sm<<<dim3(G3_D / 128, gy), 256, SMEM_SGEMM>>>(
                states2, whh2, hg, G3_D, REC_D, counts_dev + k, k);
        }
        gru_gate<<<2048, 256>>>(b_n, k);
    }
    gru_tail_persistent<<<TAIL_BLOCKS, 256>>>(b_n);
    cleanup_kernel<<<1, 1024>>>(w_hh, b_n);

    // post MLP
    gemm_ca<1, 1, 0><<<dim3(MLP_D / 256, 128), 512, SMEM_GEMM>>>(
        states2, p1w2, p1_b, nullptr, y12, MLP_D, REC_D, nullptr, T_LEN, 0);
    gemm_ca<1, 1, 0><<<dim3(MLP_D / 256, 128), 512, SMEM_GEMM>>>(
        y12, p2w2, p2_b, nullptr, y2h, MLP_D, MLP_D, nullptr, T_LEN, 0);
    gemm_p3<<<T_LEN / 128, 256, SMEM_P3>>>(y2h, p3w2, p3_b, out);

    if (out_size >= T_LEN * ACT_D + REC_D)
        copy_state_kernel<<<1, 1024>>>(out + (size_t)T_LEN * ACT_D);
}

// round 14
// speedup vs baseline: 6.3016x; 1.0437x over previous
#include <cuda_runtime.h>
#include <cuda_fp16.h>
#include <math.h>
#include <stdint.h>

#define T_LEN 16384
#define OBS_D 256
#define MLP_D 1024
#define REC_D 1024
#define G3_D  3072
#define ACT_D 18
#define P3N   24
#define STEPS 26
#define GEMM_STEPS 9
#define TAIL_BLOCKS 128

typedef __half f16;

// ---------------- scratch (device globals; no allocation allowed) ----------------
__device__ __align__(16) f16   g_x2[(size_t)T_LEN * OBS_D];
__device__ __align__(16) f16   g_prew2[(size_t)MLP_D * OBS_D];
__device__ __align__(16) f16   g_feat2[(size_t)T_LEN * MLP_D];
__device__ __align__(16) f16   g_wih2[(size_t)G3_D * MLP_D];
__device__ __align__(16) f16   g_whh2[(size_t)G3_D * REC_D];
__device__ __align__(16) f16   g_p1w2[(size_t)MLP_D * REC_D];
__device__ __align__(16) f16   g_p2w2[(size_t)MLP_D * MLP_D];
__device__ __align__(16) f16   g_p3w2[(size_t)P3N * MLP_D];
__device__ __align__(16) f16   g_states2[(size_t)T_LEN * REC_D];
__device__ __align__(16) f16   g_y12[(size_t)T_LEN * MLP_D];
__device__ __align__(16) f16   g_igates[(size_t)T_LEN * G3_D];
__device__ __align__(16) f16   g_hg[(size_t)T_LEN * G3_D];
__device__ __align__(16) f16   g_y2h[(size_t)T_LEN * MLP_D];
__device__ __align__(16) float g_states[(size_t)T_LEN * REC_D];
__device__ float g_hg0[G3_D];
__device__ int   g_age[T_LEN];
__device__ int   g_perm[T_LEN];
__device__ int   g_counts[STEPS + 1];
__device__ int   g_offsets[STEPS + 1];
__device__ int   g_flags[4];
__device__ unsigned g_bar;

// ---------------- helpers ----------------
__device__ __forceinline__ float sigf(float x) { return 1.0f / (1.0f + expf(-x)); }
__device__ __forceinline__ float mishf(float x) {
    float sp = (x > 15.0f) ? x : log1pf(expf(x));
    return x * tanhf(sp);
}
__device__ __forceinline__ uint32_t smem_u32(const void* p) {
    return (uint32_t)__cvta_generic_to_shared(p);
}
__device__ __forceinline__ uint32_t pack2h(f16 a, f16 b) {
    __half2 t; t.x = a; t.y = b;
    return *(uint32_t*)&t;
}
__device__ __forceinline__ void store_state(int t, int j, float v) {
    g_states[(size_t)t * REC_D + j] = v;
    g_states2[(size_t)t * REC_D + j] = __float2half(v);
}
__device__ __forceinline__ float ldh(const f16* p) { return __half2float(*p); }

// ---------------- async / mma primitives (plain compute_100-legal) ----------------
__device__ __forceinline__ void cpasync16(uint32_t sa, const void* ga) {
    asm volatile("cp.async.cg.shared.global [%0], [%1], 16;" :: "r"(sa), "l"(ga));
}
__device__ __forceinline__ void cp_commit() { asm volatile("cp.async.commit_group;" ::: "memory"); }
__device__ __forceinline__ void cp_wait2() { asm volatile("cp.async.wait_group 2;" ::: "memory"); }
__device__ __forceinline__ void cp_wait1() { asm volatile("cp.async.wait_group 1;" ::: "memory"); }
__device__ __forceinline__ void cp_wait0() { asm volatile("cp.async.wait_group 0;" ::: "memory"); }

__device__ __forceinline__ void ldmx4(uint32_t addr, uint32_t& r0, uint32_t& r1, uint32_t& r2, uint32_t& r3) {
    asm volatile("ldmatrix.sync.aligned.m8n8.x4.shared.b16 {%0,%1,%2,%3}, [%4];"
                 : "=r"(r0), "=r"(r1), "=r"(r2), "=r"(r3) : "r"(addr));
}
__device__ __forceinline__ void mma_h(float* c, const uint32_t* a, const uint32_t* b) {
    asm volatile("mma.sync.aligned.m16n8k16.row.col.f32.f16.f16.f32 "
                 "{%0,%1,%2,%3}, {%4,%5,%6,%7}, {%8,%9}, {%0,%1,%2,%3};"
                 : "+f"(c[0]), "+f"(c[1]), "+f"(c[2]), "+f"(c[3])
                 : "r"(a[0]), "r"(a[1]), "r"(a[2]), "r"(a[3]), "r"(b[0]), "r"(b[1]));
}

// ---------------- merged segment analysis (single launch) ----------------
__device__ __forceinline__ bool start_val(const void* p, int mode, int u) {
    if (mode == 0) return ((const unsigned char*)p)[u] != 0;
    if (mode == 1) return ((const int*)p)[u] != 0;
    return ((const float*)p)[u] != 0.0f;
}

__global__ void __launch_bounds__(1024)
analyze_kernel(const unsigned char* __restrict__ p) {
    __shared__ int s_nz[4];
    __shared__ int s_counts[STEPS + 1];
    __shared__ int s_off[STEPS + 1];
    __shared__ int s_cur[STEPS + 1];
    __shared__ int s_mode;
    int tid = threadIdx.x;
    if (tid < 4) s_nz[tid] = 0;
    if (tid < STEPS + 1) { s_counts[tid] = 0; s_cur[tid] = 0; }
    if (tid == 0) g_bar = 0;
    __syncthreads();
    int cnt = 0;
    for (int i = tid; i < T_LEN; i += 1024) cnt += (p[i] != 0);
    atomicAdd(&s_nz[tid & 3], cnt);
    __syncthreads();
    if (tid == 0) {
        int rest = s_nz[1] + s_nz[2] + s_nz[3];
        int mode;
        if (rest > 0) mode = (s_nz[0] == 0) ? 2 : 0;
        else          mode = (s_nz[0] > 0) ? 1 : 0;
        g_flags[0] = mode;
        bool s0;
        if (mode == 0)      s0 = p[0] != 0;
        else if (mode == 1) s0 = ((const int*)p)[0] != 0;
        else                s0 = ((const float*)p)[0] != 0.0f;
        g_flags[1] = s0 ? 1 : 0;
        s_mode = mode;
    }
    __syncthreads();
    int mode = s_mode;
    for (int t = tid; t < T_LEN; t += 1024) {
        int k = 0, tt = t;
        while (tt > 0 && !start_val(p, mode, tt)) { tt--; k++; }
        g_age[t] = k;
        int b = k < STEPS ? k : STEPS;
        atomicAdd(&s_counts[b], 1);
    }
    __syncthreads();
    if (tid == 0) {
        int acc = 0;
        for (int b = 0; b <= STEPS; b++) { s_off[b] = acc; g_offsets[b] = acc; acc += s_counts[b]; }
    }
    if (tid < STEPS + 1) g_counts[tid] = s_counts[tid];
    __syncthreads();
    for (int t = tid; t < T_LEN; t += 1024) {
        int a = g_age[t];
        int b = a < STEPS ? a : STEPS;
        int pos = s_off[b] + atomicAdd(&s_cur[b], 1);
        g_perm[pos] = t;
    }
}

// ---------------- merged fp32->fp16 conversions (one launch) ----------------
__global__ void conv_all(const float* s0, f16* d0, size_t n0,
                         const float* s1, f16* d1, size_t n1,
                         const float* s2, f16* d2, size_t n2,
                         const float* s3, f16* d3, size_t n3,
                         const float* s4, f16* d4, size_t n4,
                         const float* s5, f16* d5, size_t n5,
                         const float* s6, f16* d6) {
    size_t stride = (size_t)gridDim.x * blockDim.x;
    size_t i0 = (size_t)blockIdx.x * blockDim.x + threadIdx.x;
    for (size_t i = i0; i < n0; i += stride) d0[i] = __float2half(s0[i]);
    for (size_t i = i0; i < n1; i += stride) d1[i] = __float2half(s1[i]);
    for (size_t i = i0; i < n2; i += stride) d2[i] = __float2half(s2[i]);
    for (size_t i = i0; i < n3; i += stride) d3[i] = __float2half(s3[i]);
    for (size_t i = i0; i < n4; i += stride) d4[i] = __float2half(s4[i]);
    for (size_t i = i0; i < n5; i += stride) d5[i] = __float2half(s5[i]);
    for (size_t i = i0; i < (size_t)P3N * MLP_D; i += stride) {
        int a = (int)(i >> 10);
        d6[i] = (a < ACT_D) ? __float2half(s6[(size_t)a * MLP_D + (i & 1023)]) : __float2half(0.0f);
    }
}

// ---------------- mma.sync GEMM (128x256, 512 threads, BK=64) ----------------
#define STG_A_SZ 16384
#define STG_B_SZ 32768
#define STG_SZ (STG_A_SZ + STG_B_SZ)
#define NSTG 4
#define SMEM_GEMM (NSTG * STG_SZ)

// 64B-row swizzle (4 segs) — used by small-tile + p3 kernels
__device__ __forceinline__ uint32_t swz(uint32_t base, int r, int seg) {
    return base + r * 64 + 16 * (seg ^ ((r >> 1) & 3));
}
// 128B-row swizzle (8 segs, 8-row atom) — conflict-free for cp.async stores & ldmatrix
__device__ __forceinline__ uint32_t swz128(uint32_t base, int r, int seg) {
    return base + r * 128 + 16 * (seg ^ (r & 7));
}

template <int GATHER>
__device__ __forceinline__ void load_stage(const f16* __restrict__ A, const f16* __restrict__ B,
                                           const int* __restrict__ perm, int M,
                                           int rowBase, int colBase, int K, int chunk,
                                           uint32_t sA, uint32_t sB, int tid) {
    // A: 128 rows x 8 segs = 1024 cp.async (2 per thread)
#pragma unroll
    for (int i = 0; i < 2; i++) {
        int o = tid + i * 512;
        int r = o >> 3, seg = o & 7;
        const f16* src;
        if (GATHER) {
            int gi = rowBase + r;
            gi = gi < M - 1 ? gi : M - 1;
            int t = __ldg(&perm[gi]);
            src = A + (size_t)(t - 1) * K + chunk * 64 + (size_t)seg * 8;
        } else {
            src = A + (size_t)(rowBase + r) * K + chunk * 64 + (size_t)seg * 8;
        }
        cpasync16(swz128(sA, r, seg), src);
    }
    // B: 256 rows x 8 segs = 2048 cp.async (4 per thread)
    const f16* Bb = B + (size_t)colBase * K + chunk * 64;
#pragma unroll
    for (int i = 0; i < 4; i++) {
        int o = tid + i * 512;
        int r = o >> 3, seg = o & 7;
        cpasync16(swz128(sB, r, seg), Bb + (size_t)r * K + seg * 8);
    }
}

template <int MISH, int HALFOUT, int GATHER>
__global__ void __launch_bounds__(512)
gemm_ca(const f16* __restrict__ A, const f16* __restrict__ B,
        const float* __restrict__ bias, float* __restrict__ Cf, f16* __restrict__ Cs,
        int Ntot, int K, const int* __restrict__ Mptr, int Mfix, int bucketK) {
    extern __shared__ __align__(16) char dsm[];
    int tid = threadIdx.x, wid = tid >> 5, lane = tid & 31;
    int wm = wid >> 2, wn = wid & 3;   // 4 x 4 warps, warp tile 32x64
    int M = Mptr ? *Mptr : Mfix;
    const int* perm = GATHER ? (g_perm + g_offsets[bucketK]) : (const int*)0;
    int colBase = blockIdx.x * 256;
    int NC = K >> 6;
    uint32_t sbase = smem_u32(dsm);

    for (int mtile = blockIdx.y; mtile * 128 < M; mtile += gridDim.y) {
        int rowBase = mtile * 128;
        float acc[2][8][4];
#pragma unroll
        for (int mt = 0; mt < 2; mt++)
#pragma unroll
            for (int nt = 0; nt < 8; nt++)
#pragma unroll
                for (int q = 0; q < 4; q++) acc[mt][nt][q] = 0.0f;

#pragma unroll
        for (int p = 0; p < 3; p++) {
            uint32_t sg = sbase + p * STG_SZ;
            load_stage<GATHER>(A, B, perm, M, rowBase, colBase, K, p, sg, sg + STG_A_SZ, tid);
            cp_commit();
        }

        for (int c = 0; c < NC; c++) {
            cp_wait2();
            __syncthreads();
            if (c + 3 < NC) {
                int s = (c + 3) & 3;
                uint32_t sg = sbase + s * STG_SZ;
                load_stage<GATHER>(A, B, perm, M, rowBase, colBase, K, c + 3, sg, sg + STG_A_SZ, tid);
            }
            cp_commit();

            uint32_t sA = sbase + (c & 3) * STG_SZ;
            uint32_t sB = sA + STG_A_SZ;
#pragma unroll
            for (int kk2 = 0; kk2 < 4; kk2++) {
                int seg = kk2 * 2 + (lane >> 4);
                uint32_t af[2][4];
#pragma unroll
                for (int mt = 0; mt < 2; mt++) {
                    int r = wm * 32 + mt * 16 + (lane & 15);
                    ldmx4(swz128(sA, r, seg), af[mt][0], af[mt][1], af[mt][2], af[mt][3]);
                }
                uint32_t bb[8][2];
#pragma unroll
                for (int nb = 0; nb < 4; nb++) {
                    int r = wn * 64 + nb * 16 + (lane & 15);
                    uint32_t r0, r1, r2, r3;
                    ldmx4(swz128(sB, r, seg), r0, r1, r2, r3);
                    bb[2 * nb][0] = r0;     bb[2 * nb][1] = r2;
                    bb[2 * nb + 1][0] = r1; bb[2 * nb + 1][1] = r3;
                }
#pragma unroll
                for (int mt = 0; mt < 2; mt++)
#pragma unroll
                    for (int nt = 0; nt < 8; nt++)
                        mma_h(acc[mt][nt], af[mt], bb[nt]);
            }
        }
        cp_wait0();
        __syncthreads();

        int rg = lane >> 2, cg = (lane & 3) * 2;
#pragma unroll
        for (int mt = 0; mt < 2; mt++) {
            int R0 = rowBase + wm * 32 + mt * 16 + rg;
#pragma unroll
            for (int nt = 0; nt < 8; nt++) {
                int C = colBase + wn * 64 + nt * 8 + cg;
                float b0 = bias ? bias[C] : 0.0f;
                float b1 = bias ? bias[C + 1] : 0.0f;
                float v00 = acc[mt][nt][0] + b0, v01 = acc[mt][nt][1] + b1;
                float v10 = acc[mt][nt][2] + b0, v11 = acc[mt][nt][3] + b1;
                if (MISH) { v00 = mishf(v00); v01 = mishf(v01); v10 = mishf(v10); v11 = mishf(v11); }
                if (HALFOUT) {
                    *(uint32_t*)&Cs[(size_t)R0 * Ntot + C] =
                        pack2h(__float2half(v00), __float2half(v01));
                    *(uint32_t*)&Cs[(size_t)(R0 + 8) * Ntot + C] =
                        pack2h(__float2half(v10), __float2half(v11));
                } else {
                    float2 a; a.x = v00; a.y = v01;
                    float2 b; b.x = v10; b.y = v11;
                    *(float2*)&Cf[(size_t)R0 * Ntot + C] = a;
                    *(float2*)&Cf[(size_t)(R0 + 8) * Ntot + C] = b;
                }
            }
        }
    }
}

// ---------------- small-tile GEMM (64x128) for small GRU steps ----------------
#define SSTG_A_SZ 4096
#define SSTG_B_SZ 8192
#define SSTG_SZ (SSTG_A_SZ + SSTG_B_SZ)
#define SMEM_SGEMM (NSTG * SSTG_SZ)

__device__ __forceinline__ void load_stage_sm(const f16* __restrict__ A, const f16* __restrict__ B,
                                              const int* __restrict__ perm, int M,
                                              int rowBase, int colBase, int K, int chunk,
                                              uint32_t sA, uint32_t sB, int tid) {
    {
        int r = tid >> 2, seg = tid & 3;
        int gi = rowBase + r;
        gi = gi < M - 1 ? gi : M - 1;
        int t = __ldg(&perm[gi]);
        cpasync16(swz(sA, r, seg), A + (size_t)(t - 1) * K + chunk * 32 + (size_t)seg * 8);
    }
    const f16* Bb = B + (size_t)colBase * K + chunk * 32;
#pragma unroll
    for (int i = 0; i < 2; i++) {
        int o = tid + i * 256;
        int r = o >> 2, seg = o & 3;
        cpasync16(swz(sB, r, seg), Bb + (size_t)r * K + seg * 8);
    }
}

__global__ void __launch_bounds__(256)
gemm_sm(const f16* __restrict__ A, const f16* __restrict__ B, f16* __restrict__ Cs,
        int Ntot, int K, const int* __restrict__ Mptr, int bucketK) {
    extern __shared__ __align__(16) char dsm[];
    int tid = threadIdx.x, wid = tid >> 5, lane = tid & 31;
    int wm = wid >> 2, wn = wid & 3;
    int M = *Mptr;
    const int* perm = g_perm + g_offsets[bucketK];
    int colBase = blockIdx.x * 128;
    int NC = K >> 5;
    uint32_t sbase = smem_u32(dsm);

    for (int mtile = blockIdx.y; mtile * 64 < M; mtile += gridDim.y) {
        int rowBase = mtile * 64;
        float acc[2][4][4];
#pragma unroll
        for (int mt = 0; mt < 2; mt++)
#pragma unroll
            for (int nt = 0; nt < 4; nt++)
#pragma unroll
                for (int q = 0; q < 4; q++) acc[mt][nt][q] = 0.0f;

#pragma unroll
        for (int p = 0; p < 3; p++) {
            uint32_t sg = sbase + p * SSTG_SZ;
            load_stage_sm(A, B, perm, M, rowBase, colBase, K, p, sg, sg + SSTG_A_SZ, tid);
            cp_commit();
        }

        for (int c = 0; c < NC; c++) {
            cp_wait2();
            __syncthreads();
            if (c + 3 < NC) {
                int s = (c + 3) & 3;
                uint32_t sg = sbase + s * SSTG_SZ;
                load_stage_sm(A, B, perm, M, rowBase, colBase, K, c + 3, sg, sg + SSTG_A_SZ, tid);
            }
            cp_commit();

            uint32_t sA = sbase + (c & 3) * SSTG_SZ;
            uint32_t sB = sA + SSTG_A_SZ;
#pragma unroll
            for (int kk2 = 0; kk2 < 2; kk2++) {
                int seg = kk2 * 2 + (lane >> 4);
                uint32_t af[2][4];
#pragma unroll
                for (int mt = 0; mt < 2; mt++) {
                    int r = wm * 32 + mt * 16 + (lane & 15);
                    ldmx4(swz(sA, r, seg), af[mt][0], af[mt][1], af[mt][2], af[mt][3]);
                }
                uint32_t bb[4][2];
#pragma unroll
                for (int nb = 0; nb < 2; nb++) {
                    int r = wn * 32 + nb * 16 + (lane & 15);
                    uint32_t r0, r1, r2, r3;
                    ldmx4(swz(sB, r, seg), r0, r1, r2, r3);
                    bb[2 * nb][0] = r0;     bb[2 * nb][1] = r2;
                    bb[2 * nb + 1][0] = r1; bb[2 * nb + 1][1] = r3;
                }
#pragma unroll
                for (int mt = 0; mt < 2; mt++)
#pragma unroll
                    for (int nt = 0; nt < 4; nt++)
                        mma_h(acc[mt][nt], af[mt], bb[nt]);
            }
        }
        cp_wait0();
        __syncthreads();

        int rg = lane >> 2, cg = (lane & 3) * 2;
#pragma unroll
        for (int mt = 0; mt < 2; mt++) {
            int R0 = rowBase + wm * 32 + mt * 16 + rg;
#pragma unroll
            for (int nt = 0; nt < 4; nt++) {
                int C = colBase + wn * 32 + nt * 8 + cg;
                *(uint32_t*)&Cs[(size_t)R0 * Ntot + C] =
                    pack2h(__float2half(acc[mt][nt][0]), __float2half(acc[mt][nt][1]));
                *(uint32_t*)&Cs[(size_t)(R0 + 8) * Ntot + C] =
                    pack2h(__float2half(acc[mt][nt][2]), __float2half(acc[mt][nt][3]));
            }
        }
    }
}

// ---------------- p3 head on tensor cores ----------------
#define P3A_SZ 8192
#define P3_BS_OFF (NSTG * P3A_SZ)
#define P3_BS_STRIDE 1032
#define SMEM_P3 (P3_BS_OFF + P3N * P3_BS_STRIDE * 2)

__global__ void __launch_bounds__(256)
gemm_p3(const f16* __restrict__ A, const f16* __restrict__ B,
        const float* __restrict__ bias, float* __restrict__ out) {
    extern __shared__ __align__(16) char dsm[];
    f16* Bs = (f16*)(dsm + P3_BS_OFF);
    int tid = threadIdx.x, wid = tid >> 5, lane = tid & 31;
    int rowBase = blockIdx.x * 128;
    uint32_t sbase = smem_u32(dsm);

#pragma unroll
    for (int i = 0; i < 12; i++) {
        int o = tid + i * 256;
        int n = o >> 7, k8 = o & 127;
        *(uint4*)&Bs[n * P3_BS_STRIDE + k8 * 8] = *(const uint4*)&B[(size_t)n * MLP_D + k8 * 8];
    }

#pragma unroll
    for (int p = 0; p < 3; p++) {
        uint32_t sg = sbase + p * P3A_SZ;
        const f16* Ab = A + (size_t)rowBase * MLP_D + p * 32;
#pragma unroll
        for (int i = 0; i < 2; i++) {
            int o = tid + i * 256;
            int r = o >> 2, seg = o & 3;
            cpasync16(swz(sg, r, seg), Ab + (size_t)r * MLP_D + seg * 8);
        }
        cp_commit();
    }

    float acc[3][4];
#pragma unroll
    for (int nt = 0; nt < 3; nt++)
#pragma unroll
        for (int q = 0; q < 4; q++) acc[nt][q] = 0.0f;

    int cf = lane >> 2, k0 = (lane & 3) * 2;
    const int NC = MLP_D / 32;
    for (int c = 0; c < NC; c++) {
        cp_wait2();
        __syncthreads();
        if (c + 3 < NC) {
            uint32_t sg = sbase + ((c + 3) & 3) * P3A_SZ;
            const f16* Ab = A + (size_t)rowBase * MLP_D + (c + 3) * 32;
#pragma unroll
            for (int i = 0; i < 2; i++) {
                int o = tid + i * 256;
                int r = o >> 2, seg = o & 3;
                cpasync16(swz(sg, r, seg), Ab + (size_t)r * MLP_D + seg * 8);
            }
        }
        cp_commit();

        uint32_t sA = sbase + (c & 3) * P3A_SZ;
#pragma unroll
        for (int kk2 = 0; kk2 < 2; kk2++) {
            int seg = kk2 * 2 + (lane >> 4);
            uint32_t af[4];
            int r = wid * 16 + (lane & 15);
            ldmx4(swz(sA, r, seg), af[0], af[1], af[2], af[3]);
            int kbase = c * 32 + kk2 * 16;
#pragma unroll
            for (int nt = 0; nt < 3; nt++) {
                int n = nt * 8 + cf;
                uint32_t bfr[2];
                bfr[0] = *(const uint32_t*)&Bs[n * P3_BS_STRIDE + kbase + k0];
                bfr[1] = *(const uint32_t*)&Bs[n * P3_BS_STRIDE + kbase + k0 + 8];
                mma_h(acc[nt], af, bfr);
            }
        }
    }
    cp_wait0();

    int rg = lane >> 2, cg = (lane & 3) * 2;
#pragma unroll
    for (int nt = 0; nt < 3; nt++) {
        int col = nt * 8 + cg;
        int R0 = rowBase + wid * 16 + rg;
        if (col < ACT_D) {
            float b = bias[col];
            out[(size_t)R0 * ACT_D + col] = acc[nt][0] + b;
            out[(size_t)(R0 + 8) * ACT_D + col] = acc[nt][2] + b;
        }
        if (col + 1 < ACT_D) {
            float b = bias[col + 1];
            out[(size_t)R0 * ACT_D + col + 1] = acc[nt][1] + b;
            out[(size_t)(R0 + 8) * ACT_D + col + 1] = acc[nt][3] + b;
        }
    }
}

// ---------------- GRU step k==0 (h_prev == 0) ----------------
__global__ void step0_kernel(const float* __restrict__ b_n) {
    int count = g_counts[0];
    long total = (long)count * REC_D;
    long stride = (long)gridDim.x * blockDim.x;
    for (long idx = (long)blockIdx.x * blockDim.x + threadIdx.x; idx < total; idx += stride) {
        int i = (int)(idx >> 10);
        int j = (int)(idx & 1023);
        int t = g_perm[i];
        float igr = ldh(&g_igates[(size_t)t * G3_D + j]);
        float igz = ldh(&g_igates[(size_t)t * G3_D + 1024 + j]);
        float ign = ldh(&g_igates[(size_t)t * G3_D + 2048 + j]);
        float r = sigf(igr);
        float z = sigf(igz);
        float n = tanhf(ign + r * b_n[j]);
        store_state(t, j, n - z * n);
    }
}

__global__ void fixA_kernel(const float* __restrict__ w_hh, const float* __restrict__ state) {
    if (g_flags[1]) return;
    int j = blockIdx.x * 8 + (threadIdx.x >> 5);
    int lane = threadIdx.x & 31;
    float acc = 0.0f;
    const float* wr = w_hh + (size_t)j * REC_D;
    for (int k = lane; k < REC_D; k += 32) acc += wr[k] * state[k];
#pragma unroll
    for (int o = 16; o > 0; o >>= 1) acc += __shfl_down_sync(0xffffffffu, acc, o);
    if (lane == 0) g_hg0[j] = acc;
}

__global__ void fixB_kernel(const float* __restrict__ state, const float* __restrict__ b_n) {
    if (g_flags[1]) return;
    int j = threadIdx.x;
    float igr = ldh(&g_igates[j]), igz = ldh(&g_igates[1024 + j]), ign = ldh(&g_igates[2048 + j]);
    float r = sigf(igr + g_hg0[j]);
    float z = sigf(igz + g_hg0[1024 + j]);
    float n = tanhf(ign + r * (g_hg0[2048 + j] + b_n[j]));
    float hp = state[j];
    store_state(0, j, n + z * (hp - n));
}

__global__ void gru_gate(const float* __restrict__ b_n, int k) {
    int count = g_counts[k];
    int base = g_offsets[k];
    long total = (long)count * REC_D;
    long stride = (long)gridDim.x * blockDim.x;
    for (long idx = (long)blockIdx.x * blockDim.x + threadIdx.x; idx < total; idx += stride) {
        int i = (int)(idx >> 10);
        int j = (int)(idx & 1023);
        int t = g_perm[base + i];
        float hr = ldh(&g_hg[(size_t)i * G3_D + j]);
        float hz = ldh(&g_hg[(size_t)i * G3_D + 1024 + j]);
        float hn = ldh(&g_hg[(size_t)i * G3_D + 2048 + j]);
        float igr = ldh(&g_igates[(size_t)t * G3_D + j]);
        float igz = ldh(&g_igates[(size_t)t * G3_D + 1024 + j]);
        float ign = ldh(&g_igates[(size_t)t * G3_D + 2048 + j]);
        float hp = g_states[(size_t)(t - 1) * REC_D + j];
        float r = sigf(igr + hr);
        float z = sigf(igz + hz);
        float n = tanhf(ign + r * (hn + b_n[j]));
        store_state(t, j, n + z * (hp - n));
    }
}

// ---------------- persistent tail ----------------
__device__ __forceinline__ void tail_prefetch(int t, __half2* buf, int tid) {
    if (tid < 128) {
        const char* src = (const char*)(g_states2 + (size_t)(t - 1) * REC_D) + tid * 16;
        cpasync16(smem_u32((char*)buf + tid * 16), src);
    }
}

__global__ void __launch_bounds__(256)
gru_tail_persistent(const float* __restrict__ b_n) {
    __shared__ __align__(16) __half2 sh[2][REC_D / 2];
    int tid = threadIdx.x;
    int wid = tid >> 5;
    int j = blockIdx.x * 8 + wid;
    int lane = tid & 31;
    const __half2* wr2 = (const __half2*)(g_whh2 + (size_t)j * REC_D);
    const __half2* wz2 = (const __half2*)(g_whh2 + (size_t)(1024 + j) * REC_D);
    const __half2* wn2 = (const __half2*)(g_whh2 + (size_t)(2048 + j) * REC_D);
    __half2 wr[16], wz[16], wn[16];
#pragma unroll
    for (int q = 0; q < 16; q++) {
        wr[q] = wr2[lane + q * 32];
        wz[q] = wz2[lane + q * 32];
        wn[q] = wn2[lane + q * 32];
    }
    float bn = b_n[j];
    unsigned nb = gridDim.x;
    unsigned bc = 0;

    for (int k = GEMM_STEPS; k < STEPS; k++) {
        int count = g_counts[k];
        int base = g_offsets[k];
        if (count <= 0) continue;
        tail_prefetch(g_perm[base], sh[0], tid);
        cp_commit();
        for (int i = 0; i < count; i++) {
            if (i + 1 < count) tail_prefetch(g_perm[base + i + 1], sh[(i + 1) & 1], tid);
            cp_commit();
            if (i + 1 < count) cp_wait1(); else cp_wait0();
            __syncthreads();
            const __half2* hb = sh[i & 1];
            int t = g_perm[base + i];
            float aR = 0.0f, aZ = 0.0f, aN = 0.0f;
#pragma unroll
            for (int q = 0; q < 16; q++) {
                float2 hf = __half22float2(hb[lane + q * 32]);
                float2 rf = __half22float2(wr[q]);
                float2 zf = __half22float2(wz[q]);
                float2 nf = __half22float2(wn[q]);
                aR += rf.x * hf.x + rf.y * hf.y;
                aZ += zf.x * hf.x + zf.y * hf.y;
                aN += nf.x * hf.x + nf.y * hf.y;
            }
#pragma unroll
            for (int o = 16; o > 0; o >>= 1) {
                aR += __shfl_xor_sync(0xffffffffu, aR, o);
                aZ += __shfl_xor_sync(0xffffffffu, aZ, o);
                aN += __shfl_xor_sync(0xffffffffu, aN, o);
            }
            if (lane == 0) {
                float igr = ldh(&g_igates[(size_t)t * G3_D + j]);
                float igz = ldh(&g_igates[(size_t)t * G3_D + 1024 + j]);
                float ign = ldh(&g_igates[(size_t)t * G3_D + 2048 + j]);
                float hp = __ldcg(&g_states[(size_t)(t - 1) * REC_D + j]);
                float r = sigf(igr + aR);
                float z = sigf(igz + aZ);
                float n = tanhf(ign + r * (aN + bn));
                store_state(t, j, n + z * (hp - n));
            }
            __syncthreads();
        }
        bc++;
        __syncthreads();
        if (tid == 0) {
            __threadfence();
            atomicAdd(&g_bar, 1u);
            while (*((volatile unsigned*)&g_bar) < bc * nb) {}
        }
        __syncthreads();
    }
}

// safety net for age >= STEPS
__global__ void __launch_bounds__(1024)
cleanup_kernel(const float* __restrict__ w_hh, const float* __restrict__ b_n) {
    if (g_counts[STEPS] == 0) return;
    __shared__ int s_t;
    __shared__ int s_cur;
    __shared__ float sh[REC_D];
    int tid = threadIdx.x;
    if (tid == 0) s_cur = STEPS;
    __syncthreads();
    while (true) {
        if (tid == 0) {
            s_t = -1;
            for (int u = s_cur; u < T_LEN; ++u)
                if (g_age[u] >= STEPS) { s_t = u; s_cur = u + 1; break; }
        }
        __syncthreads();
        int t = s_t;
        if (t < 0) break;
        sh[tid] = g_states[(size_t)(t - 1) * REC_D + tid];
        __syncthreads();
        float aRv = 0, aZv = 0, aNv = 0;
        const float* wr = w_hh + (size_t)tid * REC_D;
        const float* wz = w_hh + (size_t)(1024 + tid) * REC_D;
        const float* wn = w_hh + (size_t)(2048 + tid) * REC_D;
        for (int kk = 0; kk < REC_D; kk++) {
            float h = sh[kk];
            aRv += wr[kk] * h; aZv += wz[kk] * h; aNv += wn[kk] * h;
        }
        float igr = ldh(&g_igates[(size_t)t * G3_D + tid]);
        float igz = ldh(&g_igates[(size_t)t * G3_D + 1024 + tid]);
        float ign = ldh(&g_igates[(size_t)t * G3_D + 2048 + tid]);
        float r = sigf(igr + aRv);
        float z = sigf(igz + aZv);
        float n = tanhf(ign + r * (aNv + b_n[tid]));
        float hp = sh[tid];
        store_state(t, tid, n + z * (hp - n));
        __syncthreads();
    }
}

__global__ void copy_state_kernel(float* __restrict__ out) {
    out[threadIdx.x] = g_states[(size_t)(T_LEN - 1) * REC_D + threadIdx.x];
}

// ---------------- host ----------------
extern "C" void kernel_launch(void* const* d_in, const int* in_sizes, int n_in,
                              void* d_out, int out_size) {
    const float* x     = (const float*)d_in[0];
    const float* state = (const float*)d_in[1];
    const void*  start = d_in[2];
    const float* pre_w = (const float*)d_in[4];
    const float* pre_b = (const float*)d_in[5];
    const float* w_ih  = (const float*)d_in[6];
    const float* w_hh  = (const float*)d_in[7];
    const float* b_ih  = (const float*)d_in[8];
    const float* b_n   = (const float*)d_in[9];
    const float* p1_w  = (const float*)d_in[10];
    const float* p1_b  = (const float*)d_in[11];
    const float* p2_w  = (const float*)d_in[12];
    const float* p2_b  = (const float*)d_in[13];
    const float* p3_w  = (const float*)d_in[14];
    const float* p3_b  = (const float*)d_in[15];
    float* out = (float*)d_out;

    f16 *x2, *prew2, *feat2, *wih2, *whh2, *p1w2, *p2w2, *p3w2, *states2, *y12;
    f16 *igates, *hg, *y2h;
    int* counts_dev;
    cudaGetSymbolAddress((void**)&igates, g_igates);
    cudaGetSymbolAddress((void**)&hg, g_hg);
    cudaGetSymbolAddress((void**)&y2h, g_y2h);
    cudaGetSymbolAddress((void**)&x2, g_x2);
    cudaGetSymbolAddress((void**)&prew2, g_prew2);
    cudaGetSymbolAddress((void**)&feat2, g_feat2);
    cudaGetSymbolAddress((void**)&wih2, g_wih2);
    cudaGetSymbolAddress((void**)&whh2, g_whh2);
    cudaGetSymbolAddress((void**)&p1w2, g_p1w2);
    cudaGetSymbolAddress((void**)&p2w2, g_p2w2);
    cudaGetSymbolAddress((void**)&p3w2, g_p3w2);
    cudaGetSymbolAddress((void**)&states2, g_states2);
    cudaGetSymbolAddress((void**)&y12, g_y12);
    cudaGetSymbolAddress((void**)&counts_dev, g_counts);

    cudaFuncSetAttribute(gemm_ca<1, 1, 0>, cudaFuncAttributeMaxDynamicSharedMemorySize, SMEM_GEMM);
    cudaFuncSetAttribute(gemm_ca<0, 1, 0>, cudaFuncAttributeMaxDynamicSharedMemorySize, SMEM_GEMM);
    cudaFuncSetAttribute(gemm_ca<0, 1, 1>, cudaFuncAttributeMaxDynamicSharedMemorySize, SMEM_GEMM);
    cudaFuncSetAttribute(gemm_sm, cudaFuncAttributeMaxDynamicSharedMemorySize, SMEM_SGEMM);
    cudaFuncSetAttribute(gemm_p3, cudaFuncAttributeMaxDynamicSharedMemorySize, SMEM_P3);

    // segment analysis (single launch)
    analyze_kernel<<<1, 1024>>>((const unsigned char*)start);

    // all conversions in one launch
    conv_all<<<1024, 256>>>(pre_w, prew2, (size_t)MLP_D * OBS_D,
                            w_ih, wih2, (size_t)G3_D * MLP_D,
                            w_hh, whh2, (size_t)G3_D * REC_D,
                            p1_w, p1w2, (size_t)MLP_D * REC_D,
                            p2_w, p2w2, (size_t)MLP_D * MLP_D,
                            x, x2, (size_t)T_LEN * OBS_D,
                            p3_w, p3w2);

    // feat = mish(x @ pre_w^T + pre_b)
    gemm_ca<1, 1, 0><<<dim3(MLP_D / 256, 128), 512, SMEM_GEMM>>>(
        x2, prew2, pre_b, nullptr, feat2, MLP_D, OBS_D, nullptr, T_LEN, 0);
    // igates = feat @ w_ih^T + b_ih (fp16 out)
    gemm_ca<0, 1, 0><<<dim3(G3_D / 256, 128), 512, SMEM_GEMM>>>(
        feat2, wih2, b_ih, nullptr, igates, G3_D, MLP_D, nullptr, T_LEN, 0);

    // segment-parallel GRU scan
    step0_kernel<<<2048, 256>>>(b_n);
    fixA_kernel<<<384, 256>>>(w_hh, state);
    fixB_kernel<<<1, 1024>>>(state, b_n);
    for (int k = 1; k < GEMM_STEPS; k++) {
        int est = T_LEN >> k;
        if (k == 1) {
            int gy = est / 128; if (gy < 1) gy = 1; if (gy > 64) gy = 64;
            gemm_ca<0, 1, 1><<<dim3(G3_D / 256, gy), 512, SMEM_GEMM>>>(
                states2, whh2, nullptr, nullptr, hg, G3_D, REC_D, counts_dev + k, 0, k);
        } else {
            int gy = est / 64; if (gy < 1) gy = 1; if (gy > 32) gy = 32;
            gemm_sm<<<dim3(G3_D / 128, gy), 256, SMEM_SGEMM>>>(
                states2, whh2, hg, G3_D, REC_D, counts_dev + k, k);
        }
        gru_gate<<<2048, 256>>>(b_n, k);
    }
    gru_tail_persistent<<<TAIL_BLOCKS, 256>>>(b_n);
    cleanup_kernel<<<1, 1024>>>(w_hh, b_n);

    // post MLP
    gemm_ca<1, 1, 0><<<dim3(MLP_D / 256, 128), 512, SMEM_GEMM>>>(
        states2, p1w2, p1_b, nullptr, y12, MLP_D, REC_D, nullptr, T_LEN, 0);
    gemm_ca<1, 1, 0><<<dim3(MLP_D / 256, 128), 512, SMEM_GEMM>>>(
        y12, p2w2, p2_b, nullptr, y2h, MLP_D, MLP_D, nullptr, T_LEN, 0);
    gemm_p3<<<T_LEN / 128, 256, SMEM_P3>>>(y2h, p3w2, p3_b, out);

    if (out_size >= T_LEN * ACT_D + REC_D)
        copy_state_kernel<<<1, 1024>>>(out + (size_t)T_LEN * ACT_D);
}

// round 15
// speedup vs baseline: 6.9304x; 1.0998x over previous
#include <cuda_runtime.h>
#include <cuda_fp16.h>
#include <math.h>
#include <stdint.h>

#define T_LEN 16384
#define OBS_D 256
#define MLP_D 1024
#define REC_D 1024
#define G3_D  3072
#define ACT_D 18
#define P3N   24
#define STEPS 26
#define GEMM_STEPS 9
#define TAIL_BLOCKS 128

typedef __half f16;

// ---------------- scratch (device globals; no allocation allowed) ----------------
__device__ __align__(16) f16   g_x2[(size_t)T_LEN * OBS_D];
__device__ __align__(16) f16   g_prew2[(size_t)MLP_D * OBS_D];
__device__ __align__(16) f16   g_feat2[(size_t)T_LEN * MLP_D];
__device__ __align__(16) f16   g_wih2[(size_t)G3_D * MLP_D];
__device__ __align__(16) f16   g_whh2[(size_t)G3_D * REC_D];
__device__ __align__(16) f16   g_p1w2[(size_t)MLP_D * REC_D];
__device__ __align__(16) f16   g_p2w2[(size_t)MLP_D * MLP_D];
__device__ __align__(16) f16   g_p3w2[(size_t)P3N * MLP_D];
__device__ __align__(16) f16   g_states2[(size_t)T_LEN * REC_D];
__device__ __align__(16) f16   g_y12[(size_t)T_LEN * MLP_D];
__device__ __align__(16) f16   g_igates[(size_t)T_LEN * G3_D];
__device__ __align__(16) f16   g_hg[(size_t)T_LEN * G3_D];
__device__ __align__(16) f16   g_y2h[(size_t)T_LEN * MLP_D];
__device__ __align__(16) float g_states[(size_t)T_LEN * REC_D];
__device__ float g_hg0[G3_D];
__device__ int   g_age[T_LEN];
__device__ int   g_perm[T_LEN];
__device__ int   g_counts[STEPS + 1];
__device__ int   g_offsets[STEPS + 1];
__device__ int   g_flags[4];
__device__ unsigned g_bar;

// ---------------- helpers ----------------
__device__ __forceinline__ float sigf(float x) { return 1.0f / (1.0f + expf(-x)); }
__device__ __forceinline__ float mishf(float x) {
    float sp = (x > 15.0f) ? x : log1pf(expf(x));
    return x * tanhf(sp);
}
__device__ __forceinline__ uint32_t smem_u32(const void* p) {
    return (uint32_t)__cvta_generic_to_shared(p);
}
__device__ __forceinline__ uint32_t pack2h(f16 a, f16 b) {
    __half2 t; t.x = a; t.y = b;
    return *(uint32_t*)&t;
}
__device__ __forceinline__ void store_state(int t, int j, float v) {
    g_states[(size_t)t * REC_D + j] = v;
    g_states2[(size_t)t * REC_D + j] = __float2half(v);
}
__device__ __forceinline__ float ldh(const f16* p) { return __half2float(*p); }

// ---------------- async / mma primitives (plain compute_100-legal) ----------------
__device__ __forceinline__ void cpasync16(uint32_t sa, const void* ga) {
    asm volatile("cp.async.cg.shared.global [%0], [%1], 16;" :: "r"(sa), "l"(ga));
}
__device__ __forceinline__ void cp_commit() { asm volatile("cp.async.commit_group;" ::: "memory"); }
__device__ __forceinline__ void cp_wait2() { asm volatile("cp.async.wait_group 2;" ::: "memory"); }
__device__ __forceinline__ void cp_wait1() { asm volatile("cp.async.wait_group 1;" ::: "memory"); }
__device__ __forceinline__ void cp_wait0() { asm volatile("cp.async.wait_group 0;" ::: "memory"); }

__device__ __forceinline__ void ldmx4(uint32_t addr, uint32_t& r0, uint32_t& r1, uint32_t& r2, uint32_t& r3) {
    asm volatile("ldmatrix.sync.aligned.m8n8.x4.shared.b16 {%0,%1,%2,%3}, [%4];"
                 : "=r"(r0), "=r"(r1), "=r"(r2), "=r"(r3) : "r"(addr));
}
__device__ __forceinline__ void mma_h(float* c, const uint32_t* a, const uint32_t* b) {
    asm volatile("mma.sync.aligned.m16n8k16.row.col.f32.f16.f16.f32 "
                 "{%0,%1,%2,%3}, {%4,%5,%6,%7}, {%8,%9}, {%0,%1,%2,%3};"
                 : "+f"(c[0]), "+f"(c[1]), "+f"(c[2]), "+f"(c[3])
                 : "r"(a[0]), "r"(a[1]), "r"(a[2]), "r"(a[3]), "r"(b[0]), "r"(b[1]));
}

// ---------------- merged segment analysis (single launch) ----------------
__device__ __forceinline__ bool start_val(const void* p, int mode, int u) {
    if (mode == 0) return ((const unsigned char*)p)[u] != 0;
    if (mode == 1) return ((const int*)p)[u] != 0;
    return ((const float*)p)[u] != 0.0f;
}

__global__ void __launch_bounds__(1024)
analyze_kernel(const unsigned char* __restrict__ p) {
    __shared__ int s_nz[4];
    __shared__ int s_counts[STEPS + 1];
    __shared__ int s_off[STEPS + 1];
    __shared__ int s_cur[STEPS + 1];
    __shared__ int s_mode;
    int tid = threadIdx.x;
    if (tid < 4) s_nz[tid] = 0;
    if (tid < STEPS + 1) { s_counts[tid] = 0; s_cur[tid] = 0; }
    if (tid == 0) g_bar = 0;
    __syncthreads();
    int cnt = 0;
    for (int i = tid; i < T_LEN; i += 1024) cnt += (p[i] != 0);
    atomicAdd(&s_nz[tid & 3], cnt);
    __syncthreads();
    if (tid == 0) {
        int rest = s_nz[1] + s_nz[2] + s_nz[3];
        int mode;
        if (rest > 0) mode = (s_nz[0] == 0) ? 2 : 0;
        else          mode = (s_nz[0] > 0) ? 1 : 0;
        g_flags[0] = mode;
        bool s0;
        if (mode == 0)      s0 = p[0] != 0;
        else if (mode == 1) s0 = ((const int*)p)[0] != 0;
        else                s0 = ((const float*)p)[0] != 0.0f;
        g_flags[1] = s0 ? 1 : 0;
        s_mode = mode;
    }
    __syncthreads();
    int mode = s_mode;
    for (int t = tid; t < T_LEN; t += 1024) {
        int k = 0, tt = t;
        while (tt > 0 && !start_val(p, mode, tt)) { tt--; k++; }
        g_age[t] = k;
        int b = k < STEPS ? k : STEPS;
        atomicAdd(&s_counts[b], 1);
    }
    __syncthreads();
    if (tid == 0) {
        int acc = 0;
        for (int b = 0; b <= STEPS; b++) { s_off[b] = acc; g_offsets[b] = acc; acc += s_counts[b]; }
    }
    if (tid < STEPS + 1) g_counts[tid] = s_counts[tid];
    __syncthreads();
    for (int t = tid; t < T_LEN; t += 1024) {
        int a = g_age[t];
        int b = a < STEPS ? a : STEPS;
        int pos = s_off[b] + atomicAdd(&s_cur[b], 1);
        g_perm[pos] = t;
    }
}

// ---------------- merged fp32->fp16 conversions (one launch) ----------------
__global__ void conv_all(const float* s0, f16* d0, size_t n0,
                         const float* s1, f16* d1, size_t n1,
                         const float* s2, f16* d2, size_t n2,
                         const float* s3, f16* d3, size_t n3,
                         const float* s4, f16* d4, size_t n4,
                         const float* s5, f16* d5, size_t n5,
                         const float* s6, f16* d6) {
    size_t stride = (size_t)gridDim.x * blockDim.x;
    size_t i0 = (size_t)blockIdx.x * blockDim.x + threadIdx.x;
    for (size_t i = i0; i < n0; i += stride) d0[i] = __float2half(s0[i]);
    for (size_t i = i0; i < n1; i += stride) d1[i] = __float2half(s1[i]);
    for (size_t i = i0; i < n2; i += stride) d2[i] = __float2half(s2[i]);
    for (size_t i = i0; i < n3; i += stride) d3[i] = __float2half(s3[i]);
    for (size_t i = i0; i < n4; i += stride) d4[i] = __float2half(s4[i]);
    for (size_t i = i0; i < n5; i += stride) d5[i] = __float2half(s5[i]);
    for (size_t i = i0; i < (size_t)P3N * MLP_D; i += stride) {
        int a = (int)(i >> 10);
        d6[i] = (a < ACT_D) ? __float2half(s6[(size_t)a * MLP_D + (i & 1023)]) : __float2half(0.0f);
    }
}

// ---------------- mma.sync GEMM (128x128, 256 threads, BK=64, 3 stages, 2 CTAs/SM) -------
#define STG_A_SZ 16384
#define STG_B_SZ 16384
#define STG_SZ (STG_A_SZ + STG_B_SZ)
#define NSTG 3
#define SMEM_GEMM (NSTG * STG_SZ)

// 64B-row swizzle (4 segs) — used by small-tile + p3 kernels
__device__ __forceinline__ uint32_t swz(uint32_t base, int r, int seg) {
    return base + r * 64 + 16 * (seg ^ ((r >> 1) & 3));
}
// 128B-row swizzle (8 segs, 8-row atom)
__device__ __forceinline__ uint32_t swz128(uint32_t base, int r, int seg) {
    return base + r * 128 + 16 * (seg ^ (r & 7));
}

template <int GATHER>
__device__ __forceinline__ void load_stage(const f16* __restrict__ A, const f16* __restrict__ B,
                                           const int* __restrict__ perm, int M,
                                           int rowBase, int colBase, int K, int chunk,
                                           uint32_t sA, uint32_t sB, int tid) {
    // A: 128 rows x 8 segs = 1024 cp.async (4 per thread)
#pragma unroll
    for (int i = 0; i < 4; i++) {
        int o = tid + i * 256;
        int r = o >> 3, seg = o & 7;
        const f16* src;
        if (GATHER) {
            int gi = rowBase + r;
            gi = gi < M - 1 ? gi : M - 1;
            int t = __ldg(&perm[gi]);
            src = A + (size_t)(t - 1) * K + chunk * 64 + (size_t)seg * 8;
        } else {
            src = A + (size_t)(rowBase + r) * K + chunk * 64 + (size_t)seg * 8;
        }
        cpasync16(swz128(sA, r, seg), src);
    }
    // B: 128 rows x 8 segs = 1024 cp.async (4 per thread)
    const f16* Bb = B + (size_t)colBase * K + chunk * 64;
#pragma unroll
    for (int i = 0; i < 4; i++) {
        int o = tid + i * 256;
        int r = o >> 3, seg = o & 7;
        cpasync16(swz128(sB, r, seg), Bb + (size_t)r * K + seg * 8);
    }
}

template <int MISH, int HALFOUT, int GATHER>
__global__ void __launch_bounds__(256, 2)
gemm_ca(const f16* __restrict__ A, const f16* __restrict__ B,
        const float* __restrict__ bias, float* __restrict__ Cf, f16* __restrict__ Cs,
        int Ntot, int K, const int* __restrict__ Mptr, int Mfix, int bucketK) {
    extern __shared__ __align__(16) char dsm[];
    int tid = threadIdx.x, wid = tid >> 5, lane = tid & 31;
    int wm = wid >> 1, wn = wid & 1;   // 4 x 2 warps, warp tile 32x64
    int M = Mptr ? *Mptr : Mfix;
    const int* perm = GATHER ? (g_perm + g_offsets[bucketK]) : (const int*)0;
    int colBase = blockIdx.x * 128;
    int NC = K >> 6;
    uint32_t sbase = smem_u32(dsm);

    for (int mtile = blockIdx.y; mtile * 128 < M; mtile += gridDim.y) {
        int rowBase = mtile * 128;
        float acc[2][8][4];
#pragma unroll
        for (int mt = 0; mt < 2; mt++)
#pragma unroll
            for (int nt = 0; nt < 8; nt++)
#pragma unroll
                for (int q = 0; q < 4; q++) acc[mt][nt][q] = 0.0f;

#pragma unroll
        for (int p = 0; p < 2; p++) {
            uint32_t sg = sbase + p * STG_SZ;
            load_stage<GATHER>(A, B, perm, M, rowBase, colBase, K, p, sg, sg + STG_A_SZ, tid);
            cp_commit();
        }

        int slot = 0, nslot = 2;
        for (int c = 0; c < NC; c++) {
            cp_wait1();
            __syncthreads();
            if (c + 2 < NC) {
                uint32_t sg = sbase + nslot * STG_SZ;
                load_stage<GATHER>(A, B, perm, M, rowBase, colBase, K, c + 2, sg, sg + STG_A_SZ, tid);
            }
            cp_commit();

            uint32_t sA = sbase + slot * STG_SZ;
            uint32_t sB = sA + STG_A_SZ;
#pragma unroll
            for (int kk2 = 0; kk2 < 4; kk2++) {
                int seg = kk2 * 2 + (lane >> 4);
                uint32_t af[2][4];
#pragma unroll
                for (int mt = 0; mt < 2; mt++) {
                    int r = wm * 32 + mt * 16 + (lane & 15);
                    ldmx4(swz128(sA, r, seg), af[mt][0], af[mt][1], af[mt][2], af[mt][3]);
                }
                uint32_t bb[8][2];
#pragma unroll
                for (int nb = 0; nb < 4; nb++) {
                    int r = wn * 64 + nb * 16 + (lane & 15);
                    uint32_t r0, r1, r2, r3;
                    ldmx4(swz128(sB, r, seg), r0, r1, r2, r3);
                    bb[2 * nb][0] = r0;     bb[2 * nb][1] = r2;
                    bb[2 * nb + 1][0] = r1; bb[2 * nb + 1][1] = r3;
                }
#pragma unroll
                for (int mt = 0; mt < 2; mt++)
#pragma unroll
                    for (int nt = 0; nt < 8; nt++)
                        mma_h(acc[mt][nt], af[mt], bb[nt]);
            }
            slot = slot + 1 == NSTG ? 0 : slot + 1;
            nslot = nslot + 1 == NSTG ? 0 : nslot + 1;
        }
        cp_wait0();
        __syncthreads();

        int rg = lane >> 2, cg = (lane & 3) * 2;
#pragma unroll
        for (int mt = 0; mt < 2; mt++) {
            int R0 = rowBase + wm * 32 + mt * 16 + rg;
#pragma unroll
            for (int nt = 0; nt < 8; nt++) {
                int C = colBase + wn * 64 + nt * 8 + cg;
                float b0 = bias ? bias[C] : 0.0f;
                float b1 = bias ? bias[C + 1] : 0.0f;
                float v00 = acc[mt][nt][0] + b0, v01 = acc[mt][nt][1] + b1;
                float v10 = acc[mt][nt][2] + b0, v11 = acc[mt][nt][3] + b1;
                if (MISH) { v00 = mishf(v00); v01 = mishf(v01); v10 = mishf(v10); v11 = mishf(v11); }
                if (HALFOUT) {
                    *(uint32_t*)&Cs[(size_t)R0 * Ntot + C] =
                        pack2h(__float2half(v00), __float2half(v01));
                    *(uint32_t*)&Cs[(size_t)(R0 + 8) * Ntot + C] =
                        pack2h(__float2half(v10), __float2half(v11));
                } else {
                    float2 a; a.x = v00; a.y = v01;
                    float2 b; b.x = v10; b.y = v11;
                    *(float2*)&Cf[(size_t)R0 * Ntot + C] = a;
                    *(float2*)&Cf[(size_t)(R0 + 8) * Ntot + C] = b;
                }
            }
        }
    }
}

// ---------------- small-tile GEMM (64x128) for small GRU steps ----------------
#define SSTG_A_SZ 4096
#define SSTG_B_SZ 8192
#define SSTG_SZ (SSTG_A_SZ + SSTG_B_SZ)
#define SMEM_SGEMM (4 * SSTG_SZ)

__device__ __forceinline__ void load_stage_sm(const f16* __restrict__ A, const f16* __restrict__ B,
                                              const int* __restrict__ perm, int M,
                                              int rowBase, int colBase, int K, int chunk,
                                              uint32_t sA, uint32_t sB, int tid) {
    {
        int r = tid >> 2, seg = tid & 3;
        int gi = rowBase + r;
        gi = gi < M - 1 ? gi : M - 1;
        int t = __ldg(&perm[gi]);
        cpasync16(swz(sA, r, seg), A + (size_t)(t - 1) * K + chunk * 32 + (size_t)seg * 8);
    }
    const f16* Bb = B + (size_t)colBase * K + chunk * 32;
#pragma unroll
    for (int i = 0; i < 2; i++) {
        int o = tid + i * 256;
        int r = o >> 2, seg = o & 3;
        cpasync16(swz(sB, r, seg), Bb + (size_t)r * K + seg * 8);
    }
}

__global__ void __launch_bounds__(256)
gemm_sm(const f16* __restrict__ A, const f16* __restrict__ B, f16* __restrict__ Cs,
        int Ntot, int K, const int* __restrict__ Mptr, int bucketK) {
    extern __shared__ __align__(16) char dsm[];
    int tid = threadIdx.x, wid = tid >> 5, lane = tid & 31;
    int wm = wid >> 2, wn = wid & 3;
    int M = *Mptr;
    const int* perm = g_perm + g_offsets[bucketK];
    int colBase = blockIdx.x * 128;
    int NC = K >> 5;
    uint32_t sbase = smem_u32(dsm);

    for (int mtile = blockIdx.y; mtile * 64 < M; mtile += gridDim.y) {
        int rowBase = mtile * 64;
        float acc[2][4][4];
#pragma unroll
        for (int mt = 0; mt < 2; mt++)
#pragma unroll
            for (int nt = 0; nt < 4; nt++)
#pragma unroll
                for (int q = 0; q < 4; q++) acc[mt][nt][q] = 0.0f;

#pragma unroll
        for (int p = 0; p < 3; p++) {
            uint32_t sg = sbase + p * SSTG_SZ;
            load_stage_sm(A, B, perm, M, rowBase, colBase, K, p, sg, sg + SSTG_A_SZ, tid);
            cp_commit();
        }

        for (int c = 0; c < NC; c++) {
            cp_wait2();
            __syncthreads();
            if (c + 3 < NC) {
                int s = (c + 3) & 3;
                uint32_t sg = sbase + s * SSTG_SZ;
                load_stage_sm(A, B, perm, M, rowBase, colBase, K, c + 3, sg, sg + SSTG_A_SZ, tid);
            }
            cp_commit();

            uint32_t sA = sbase + (c & 3) * SSTG_SZ;
            uint32_t sB = sA + SSTG_A_SZ;
#pragma unroll
            for (int kk2 = 0; kk2 < 2; kk2++) {
                int seg = kk2 * 2 + (lane >> 4);
                uint32_t af[2][4];
#pragma unroll
                for (int mt = 0; mt < 2; mt++) {
                    int r = wm * 32 + mt * 16 + (lane & 15);
                    ldmx4(swz(sA, r, seg), af[mt][0], af[mt][1], af[mt][2], af[mt][3]);
                }
                uint32_t bb[4][2];
#pragma unroll
                for (int nb = 0; nb < 2; nb++) {
                    int r = wn * 32 + nb * 16 + (lane & 15);
                    uint32_t r0, r1, r2, r3;
                    ldmx4(swz(sB, r, seg), r0, r1, r2, r3);
                    bb[2 * nb][0] = r0;     bb[2 * nb][1] = r2;
                    bb[2 * nb + 1][0] = r1; bb[2 * nb + 1][1] = r3;
                }
#pragma unroll
                for (int mt = 0; mt < 2; mt++)
#pragma unroll
                    for (int nt = 0; nt < 4; nt++)
                        mma_h(acc[mt][nt], af[mt], bb[nt]);
            }
        }
        cp_wait0();
        __syncthreads();

        int rg = lane >> 2, cg = (lane & 3) * 2;
#pragma unroll
        for (int mt = 0; mt < 2; mt++) {
            int R0 = rowBase + wm * 32 + mt * 16 + rg;
#pragma unroll
            for (int nt = 0; nt < 4; nt++) {
                int C = colBase + wn * 32 + nt * 8 + cg;
                *(uint32_t*)&Cs[(size_t)R0 * Ntot + C] =
                    pack2h(__float2half(acc[mt][nt][0]), __float2half(acc[mt][nt][1]));
                *(uint32_t*)&Cs[(size_t)(R0 + 8) * Ntot + C] =
                    pack2h(__float2half(acc[mt][nt][2]), __float2half(acc[mt][nt][3]));
            }
        }
    }
}

// ---------------- p3 head on tensor cores ----------------
#define P3A_SZ 8192
#define P3_BS_OFF (4 * P3A_SZ)
#define P3_BS_STRIDE 1032
#define SMEM_P3 (P3_BS_OFF + P3N * P3_BS_STRIDE * 2)

__global__ void __launch_bounds__(256)
gemm_p3(const f16* __restrict__ A, const f16* __restrict__ B,
        const float* __restrict__ bias, float* __restrict__ out) {
    extern __shared__ __align__(16) char dsm[];
    f16* Bs = (f16*)(dsm + P3_BS_OFF);
    int tid = threadIdx.x, wid = tid >> 5, lane = tid & 31;
    int rowBase = blockIdx.x * 128;
    uint32_t sbase = smem_u32(dsm);

#pragma unroll
    for (int i = 0; i < 12; i++) {
        int o = tid + i * 256;
        int n = o >> 7, k8 = o & 127;
        *(uint4*)&Bs[n * P3_BS_STRIDE + k8 * 8] = *(const uint4*)&B[(size_t)n * MLP_D + k8 * 8];
    }

#pragma unroll
    for (int p = 0; p < 3; p++) {
        uint32_t sg = sbase + p * P3A_SZ;
        const f16* Ab = A + (size_t)rowBase * MLP_D + p * 32;
#pragma unroll
        for (int i = 0; i < 2; i++) {
            int o = tid + i * 256;
            int r = o >> 2, seg = o & 3;
            cpasync16(swz(sg, r, seg), Ab + (size_t)r * MLP_D + seg * 8);
        }
        cp_commit();
    }

    float acc[3][4];
#pragma unroll
    for (int nt = 0; nt < 3; nt++)
#pragma unroll
        for (int q = 0; q < 4; q++) acc[nt][q] = 0.0f;

    int cf = lane >> 2, k0 = (lane & 3) * 2;
    const int NC = MLP_D / 32;
    for (int c = 0; c < NC; c++) {
        cp_wait2();
        __syncthreads();
        if (c + 3 < NC) {
            uint32_t sg = sbase + ((c + 3) & 3) * P3A_SZ;
            const f16* Ab = A + (size_t)rowBase * MLP_D + (c + 3) * 32;
#pragma unroll
            for (int i = 0; i < 2; i++) {
                int o = tid + i * 256;
                int r = o >> 2, seg = o & 3;
                cpasync16(swz(sg, r, seg), Ab + (size_t)r * MLP_D + seg * 8);
            }
        }
        cp_commit();

        uint32_t sA = sbase + (c & 3) * P3A_SZ;
#pragma unroll
        for (int kk2 = 0; kk2 < 2; kk2++) {
            int seg = kk2 * 2 + (lane >> 4);
            uint32_t af[4];
            int r = wid * 16 + (lane & 15);
            ldmx4(swz(sA, r, seg), af[0], af[1], af[2], af[3]);
            int kbase = c * 32 + kk2 * 16;
#pragma unroll
            for (int nt = 0; nt < 3; nt++) {
                int n = nt * 8 + cf;
                uint32_t bfr[2];
                bfr[0] = *(const uint32_t*)&Bs[n * P3_BS_STRIDE + kbase + k0];
                bfr[1] = *(const uint32_t*)&Bs[n * P3_BS_STRIDE + kbase + k0 + 8];
                mma_h(acc[nt], af, bfr);
            }
        }
    }
    cp_wait0();

    int rg = lane >> 2, cg = (lane & 3) * 2;
#pragma unroll
    for (int nt = 0; nt < 3; nt++) {
        int col = nt * 8 + cg;
        int R0 = rowBase + wid * 16 + rg;
        if (col < ACT_D) {
            float b = bias[col];
            out[(size_t)R0 * ACT_D + col] = acc[nt][0] + b;
            out[(size_t)(R0 + 8) * ACT_D + col] = acc[nt][2] + b;
        }
        if (col + 1 < ACT_D) {
            float b = bias[col + 1];
            out[(size_t)R0 * ACT_D + col + 1] = acc[nt][1] + b;
            out[(size_t)(R0 + 8) * ACT_D + col + 1] = acc[nt][3] + b;
        }
    }
}

// ---------------- GRU step k==0 (h_prev == 0) ----------------
__global__ void step0_kernel(const float* __restrict__ b_n) {
    int count = g_counts[0];
    long total = (long)count * REC_D;
    long stride = (long)gridDim.x * blockDim.x;
    for (long idx = (long)blockIdx.x * blockDim.x + threadIdx.x; idx < total; idx += stride) {
        int i = (int)(idx >> 10);
        int j = (int)(idx & 1023);
        int t = g_perm[i];
        float igr = ldh(&g_igates[(size_t)t * G3_D + j]);
        float igz = ldh(&g_igates[(size_t)t * G3_D + 1024 + j]);
        float ign = ldh(&g_igates[(size_t)t * G3_D + 2048 + j]);
        float r = sigf(igr);
        float z = sigf(igz);
        float n = tanhf(ign + r * b_n[j]);
        store_state(t, j, n - z * n);
    }
}

__global__ void fixA_kernel(const float* __restrict__ w_hh, const float* __restrict__ state) {
    if (g_flags[1]) return;
    int j = blockIdx.x * 8 + (threadIdx.x >> 5);
    int lane = threadIdx.x & 31;
    float acc = 0.0f;
    const float* wr = w_hh + (size_t)j * REC_D;
    for (int k = lane; k < REC_D; k += 32) acc += wr[k] * state[k];
#pragma unroll
    for (int o = 16; o > 0; o >>= 1) acc += __shfl_down_sync(0xffffffffu, acc, o);
    if (lane == 0) g_hg0[j] = acc;
}

__global__ void fixB_kernel(const float* __restrict__ state, const float* __restrict__ b_n) {
    if (g_flags[1]) return;
    int j = threadIdx.x;
    float igr = ldh(&g_igates[j]), igz = ldh(&g_igates[1024 + j]), ign = ldh(&g_igates[2048 + j]);
    float r = sigf(igr + g_hg0[j]);
    float z = sigf(igz + g_hg0[1024 + j]);
    float n = tanhf(ign + r * (g_hg0[2048 + j] + b_n[j]));
    float hp = state[j];
    store_state(0, j, n + z * (hp - n));
}

__global__ void gru_gate(const float* __restrict__ b_n, int k) {
    int count = g_counts[k];
    int base = g_offsets[k];
    long total = (long)count * REC_D;
    long stride = (long)gridDim.x * blockDim.x;
    for (long idx = (long)blockIdx.x * blockDim.x + threadIdx.x; idx < total; idx += stride) {
        int i = (int)(idx >> 10);
        int j = (int)(idx & 1023);
        int t = g_perm[base + i];
        float hr = ldh(&g_hg[(size_t)i * G3_D + j]);
        float hz = ldh(&g_hg[(size_t)i * G3_D + 1024 + j]);
        float hn = ldh(&g_hg[(size_t)i * G3_D + 2048 + j]);
        float igr = ldh(&g_igates[(size_t)t * G3_D + j]);
        float igz = ldh(&g_igates[(size_t)t * G3_D + 1024 + j]);
        float ign = ldh(&g_igates[(size_t)t * G3_D + 2048 + j]);
        float hp = g_states[(size_t)(t - 1) * REC_D + j];
        float r = sigf(igr + hr);
        float z = sigf(igz + hz);
        float n = tanhf(ign + r * (hn + b_n[j]));
        store_state(t, j, n + z * (hp - n));
    }
}

// ---------------- persistent tail ----------------
__device__ __forceinline__ void tail_prefetch(int t, __half2* buf, int tid) {
    if (tid < 128) {
        const char* src = (const char*)(g_states2 + (size_t)(t - 1) * REC_D) + tid * 16;
        cpasync16(smem_u32((char*)buf + tid * 16), src);
    }
}

__global__ void __launch_bounds__(256)
gru_tail_persistent(const float* __restrict__ b_n) {
    __shared__ __align__(16) __half2 sh[2][REC_D / 2];
    int tid = threadIdx.x;
    int wid = tid >> 5;
    int j = blockIdx.x * 8 + wid;
    int lane = tid & 31;
    const __half2* wr2 = (const __half2*)(g_whh2 + (size_t)j * REC_D);
    const __half2* wz2 = (const __half2*)(g_whh2 + (size_t)(1024 + j) * REC_D);
    const __half2* wn2 = (const __half2*)(g_whh2 + (size_t)(2048 + j) * REC_D);
    __half2 wr[16], wz[16], wn[16];
#pragma unroll
    for (int q = 0; q < 16; q++) {
        wr[q] = wr2[lane + q * 32];
        wz[q] = wz2[lane + q * 32];
        wn[q] = wn2[lane + q * 32];
    }
    float bn = b_n[j];
    unsigned nb = gridDim.x;
    unsigned bc = 0;

    for (int k = GEMM_STEPS; k < STEPS; k++) {
        int count = g_counts[k];
        int base = g_offsets[k];
        if (count <= 0) continue;
        tail_prefetch(g_perm[base], sh[0], tid);
        cp_commit();
        for (int i = 0; i < count; i++) {
            if (i + 1 < count) tail_prefetch(g_perm[base + i + 1], sh[(i + 1) & 1], tid);
            cp_commit();
            if (i + 1 < count) cp_wait1(); else cp_wait0();
            __syncthreads();
            const __half2* hb = sh[i & 1];
            int t = g_perm[base + i];
            float aR = 0.0f, aZ = 0.0f, aN = 0.0f;
#pragma unroll
            for (int q = 0; q < 16; q++) {
                float2 hf = __half22float2(hb[lane + q * 32]);
                float2 rf = __half22float2(wr[q]);
                float2 zf = __half22float2(wz[q]);
                float2 nf = __half22float2(wn[q]);
                aR += rf.x * hf.x + rf.y * hf.y;
                aZ += zf.x * hf.x + zf.y * hf.y;
                aN += nf.x * hf.x + nf.y * hf.y;
            }
#pragma unroll
            for (int o = 16; o > 0; o >>= 1) {
                aR += __shfl_xor_sync(0xffffffffu, aR, o);
                aZ += __shfl_xor_sync(0xffffffffu, aZ, o);
                aN += __shfl_xor_sync(0xffffffffu, aN, o);
            }
            if (lane == 0) {
                float igr = ldh(&g_igates[(size_t)t * G3_D + j]);
                float igz = ldh(&g_igates[(size_t)t * G3_D + 1024 + j]);
                float ign = ldh(&g_igates[(size_t)t * G3_D + 2048 + j]);
                float hp = __ldcg(&g_states[(size_t)(t - 1) * REC_D + j]);
                float r = sigf(igr + aR);
                float z = sigf(igz + aZ);
                float n = tanhf(ign + r * (aN + bn));
                store_state(t, j, n + z * (hp - n));
            }
            __syncthreads();
        }
        bc++;
        __syncthreads();
        if (tid == 0) {
            __threadfence();
            atomicAdd(&g_bar, 1u);
            while (*((volatile unsigned*)&g_bar) < bc * nb) {}
        }
        __syncthreads();
    }
}

// safety net for age >= STEPS
__global__ void __launch_bounds__(1024)
cleanup_kernel(const float* __restrict__ w_hh, const float* __restrict__ b_n) {
    if (g_counts[STEPS] == 0) return;
    __shared__ int s_t;
    __shared__ int s_cur;
    __shared__ float sh[REC_D];
    int tid = threadIdx.x;
    if (tid == 0) s_cur = STEPS;
    __syncthreads();
    while (true) {
        if (tid == 0) {
            s_t = -1;
            for (int u = s_cur; u < T_LEN; ++u)
                if (g_age[u] >= STEPS) { s_t = u; s_cur = u + 1; break; }
        }
        __syncthreads();
        int t = s_t;
        if (t < 0) break;
        sh[tid] = g_states[(size_t)(t - 1) * REC_D + tid];
        __syncthreads();
        float aRv = 0, aZv = 0, aNv = 0;
        const float* wr = w_hh + (size_t)tid * REC_D;
        const float* wz = w_hh + (size_t)(1024 + tid) * REC_D;
        const float* wn = w_hh + (size_t)(2048 + tid) * REC_D;
        for (int kk = 0; kk < REC_D; kk++) {
            float h = sh[kk];
            aRv += wr[kk] * h; aZv += wz[kk] * h; aNv += wn[kk] * h;
        }
        float igr = ldh(&g_igates[(size_t)t * G3_D + tid]);
        float igz = ldh(&g_igates[(size_t)t * G3_D + 1024 + tid]);
        float ign = ldh(&g_igates[(size_t)t * G3_D + 2048 + tid]);
        float r = sigf(igr + aRv);
        float z = sigf(igz + aZv);
        float n = tanhf(ign + r * (aNv + b_n[tid]));
        float hp = sh[tid];
        store_state(t, tid, n + z * (hp - n));
        __syncthreads();
    }
}

__global__ void copy_state_kernel(float* __restrict__ out) {
    out[threadIdx.x] = g_states[(size_t)(T_LEN - 1) * REC_D + threadIdx.x];
}

// ---------------- host ----------------
extern "C" void kernel_launch(void* const* d_in, const int* in_sizes, int n_in,
                              void* d_out, int out_size) {
    const float* x     = (const float*)d_in[0];
    const float* state = (const float*)d_in[1];
    const void*  start = d_in[2];
    const float* pre_w = (const float*)d_in[4];
    const float* pre_b = (const float*)d_in[5];
    const float* w_ih  = (const float*)d_in[6];
    const float* w_hh  = (const float*)d_in[7];
    const float* b_ih  = (const float*)d_in[8];
    const float* b_n   = (const float*)d_in[9];
    const float* p1_w  = (const float*)d_in[10];
    const float* p1_b  = (const float*)d_in[11];
    const float* p2_w  = (const float*)d_in[12];
    const float* p2_b  = (const float*)d_in[13];
    const float* p3_w  = (const float*)d_in[14];
    const float* p3_b  = (const float*)d_in[15];
    float* out = (float*)d_out;

    f16 *x2, *prew2, *feat2, *wih2, *whh2, *p1w2, *p2w2, *p3w2, *states2, *y12;
    f16 *igates, *hg, *y2h;
    int* counts_dev;
    cudaGetSymbolAddress((void**)&igates, g_igates);
    cudaGetSymbolAddress((void**)&hg, g_hg);
    cudaGetSymbolAddress((void**)&y2h, g_y2h);
    cudaGetSymbolAddress((void**)&x2, g_x2);
    cudaGetSymbolAddress((void**)&prew2, g_prew2);
    cudaGetSymbolAddress((void**)&feat2, g_feat2);
    cudaGetSymbolAddress((void**)&wih2, g_wih2);
    cudaGetSymbolAddress((void**)&whh2, g_whh2);
    cudaGetSymbolAddress((void**)&p1w2, g_p1w2);
    cudaGetSymbolAddress((void**)&p2w2, g_p2w2);
    cudaGetSymbolAddress((void**)&p3w2, g_p3w2);
    cudaGetSymbolAddress((void**)&states2, g_states2);
    cudaGetSymbolAddress((void**)&y12, g_y12);
    cudaGetSymbolAddress((void**)&counts_dev, g_counts);

    cudaFuncSetAttribute(gemm_ca<1, 1, 0>, cudaFuncAttributeMaxDynamicSharedMemorySize, SMEM_GEMM);
    cudaFuncSetAttribute(gemm_ca<0, 1, 0>, cudaFuncAttributeMaxDynamicSharedMemorySize, SMEM_GEMM);
    cudaFuncSetAttribute(gemm_ca<0, 1, 1>, cudaFuncAttributeMaxDynamicSharedMemorySize, SMEM_GEMM);
    cudaFuncSetAttribute(gemm_sm, cudaFuncAttributeMaxDynamicSharedMemorySize, SMEM_SGEMM);
    cudaFuncSetAttribute(gemm_p3, cudaFuncAttributeMaxDynamicSharedMemorySize, SMEM_P3);

    // segment analysis (single launch)
    analyze_kernel<<<1, 1024>>>((const unsigned char*)start);

    // all conversions in one launch
    conv_all<<<1024, 256>>>(pre_w, prew2, (size_t)MLP_D * OBS_D,
                            w_ih, wih2, (size_t)G3_D * MLP_D,
                            w_hh, whh2, (size_t)G3_D * REC_D,
                            p1_w, p1w2, (size_t)MLP_D * REC_D,
                            p2_w, p2w2, (size_t)MLP_D * MLP_D,
                            x, x2, (size_t)T_LEN * OBS_D,
                            p3_w, p3w2);

    // feat = mish(x @ pre_w^T + pre_b)
    gemm_ca<1, 1, 0><<<dim3(MLP_D / 128, 128), 256, SMEM_GEMM>>>(
        x2, prew2, pre_b, nullptr, feat2, MLP_D, OBS_D, nullptr, T_LEN, 0);
    // igates = feat @ w_ih^T + b_ih (fp16 out)
    gemm_ca<0, 1, 0><<<dim3(G3_D / 128, 128), 256, SMEM_GEMM>>>(
        feat2, wih2, b_ih, nullptr, igates, G3_D, MLP_D, nullptr, T_LEN, 0);

    // segment-parallel GRU scan
    step0_kernel<<<2048, 256>>>(b_n);
    fixA_kernel<<<384, 256>>>(w_hh, state);
    fixB_kernel<<<1, 1024>>>(state, b_n);
    for (int k = 1; k < GEMM_STEPS; k++) {
        int est = T_LEN >> k;
        if (k == 1) {
            int gy = est / 128; if (gy < 1) gy = 1; if (gy > 64) gy = 64;
            gemm_ca<0, 1, 1><<<dim3(G3_D / 128, gy), 256, SMEM_GEMM>>>(
                states2, whh2, nullptr, nullptr, hg, G3_D, REC_D, counts_dev + k, 0, k);
        } else {
            int gy = est / 64; if (gy < 1) gy = 1; if (gy > 32) gy = 32;
            gemm_sm<<<dim3(G3_D / 128, gy), 256, SMEM_SGEMM>>>(
                states2, whh2, hg, G3_D, REC_D, counts_dev + k, k);
        }
        gru_gate<<<2048, 256>>>(b_n, k);
    }
    gru_tail_persistent<<<TAIL_BLOCKS, 256>>>(b_n);
    cleanup_kernel<<<1, 1024>>>(w_hh, b_n);

    // post MLP
    gemm_ca<1, 1, 0><<<dim3(MLP_D / 128, 128), 256, SMEM_GEMM>>>(
        states2, p1w2, p1_b, nullptr, y12, MLP_D, REC_D, nullptr, T_LEN, 0);
    gemm_ca<1, 1, 0><<<dim3(MLP_D / 128, 128), 256, SMEM_GEMM>>>(
        y12, p2w2, p2_b, nullptr, y2h, MLP_D, MLP_D, nullptr, T_LEN, 0);
    gemm_p3<<<T_LEN / 128, 256, SMEM_P3>>>(y2h, p3w2, p3_b, out);

    if (out_size >= T_LEN * ACT_D + REC_D)
        copy_state_kernel<<<1, 1024>>>(out + (size_t)T_LEN * ACT_D);
}